// round 1
// baseline (speedup 1.0000x reference)
#include <cuda_runtime.h>
#include <cstddef>

#define N_SENT 100000
#define N_DOC  10000
#define NGRAPH 32
#define D_IN   768
#define D_H    256
#define D_O    128
#define E_SS   400000
#define E_SD   100000
#define E_DS   100000

// ---------------- scratch (device globals: allocation-free) ----------------
__device__ float g_W1s[D_IN * (3 * D_H)];   // cols [0:256]=W1_0(sd) [256:512]=W1_2(ss) [512:768]=loop1
__device__ float g_W1d[D_IN * (2 * D_H)];   // cols [0:256]=W1_1(ds) [256:512]=loop1
__device__ float g_W2s[D_H * (3 * D_O)];    // cols [0:128]=W2_0 [128:256]=W2_2 [256:384]=loop2
__device__ float g_W2d[D_H * (2 * D_O)];    // cols [0:128]=W2_1 [128:256]=loop2
__device__ float g_Ps [(size_t)N_SENT * (3 * D_H)];
__device__ float g_Pd [(size_t)N_DOC  * (2 * D_H)];
__device__ float g_acc_s1[(size_t)N_SENT * D_H];
__device__ float g_acc_d1[(size_t)N_DOC  * D_H];
__device__ float g_hs [(size_t)N_SENT * D_H];
__device__ float g_hd [(size_t)N_DOC  * D_H];
__device__ float g_Ps2[(size_t)N_SENT * (3 * D_O)];
__device__ float g_Pd2[(size_t)N_DOC  * (2 * D_O)];
__device__ float g_acc_s2[(size_t)N_SENT * D_O];
__device__ float g_acc_d2[(size_t)N_DOC  * D_O];
__device__ float g_inv_ss[N_SENT];
__device__ float g_inv_ds[N_SENT];
__device__ float g_inv_sd[N_DOC];

// ---------------- helpers ----------------
__device__ __forceinline__ void redAdd4(float* addr, float4 v) {
    asm volatile("red.global.add.v4.f32 [%0], {%1, %2, %3, %4};"
                 :: "l"(addr), "f"(v.x), "f"(v.y), "f"(v.z), "f"(v.w) : "memory");
}

// ---------------- zero all per-launch accumulators ----------------
__global__ void zero_scratch() {
    size_t t = (size_t)blockIdx.x * blockDim.x + threadIdx.x;
    size_t stride = (size_t)gridDim.x * blockDim.x;
    float4 z = make_float4(0.f, 0.f, 0.f, 0.f);
    for (size_t i = t; i < (size_t)N_SENT * D_H / 4; i += stride) ((float4*)g_acc_s1)[i] = z;
    for (size_t i = t; i < (size_t)N_DOC  * D_H / 4; i += stride) ((float4*)g_acc_d1)[i] = z;
    for (size_t i = t; i < (size_t)N_SENT * D_O / 4; i += stride) ((float4*)g_acc_s2)[i] = z;
    for (size_t i = t; i < (size_t)N_DOC  * D_O / 4; i += stride) ((float4*)g_acc_d2)[i] = z;
    for (size_t i = t; i < N_SENT / 4; i += stride) ((float4*)g_inv_ss)[i] = z;
    for (size_t i = t; i < N_SENT / 4; i += stride) ((float4*)g_inv_ds)[i] = z;
    for (size_t i = t; i < N_DOC  / 4; i += stride) ((float4*)g_inv_sd)[i] = z;
}

// ---------------- degree count + invert ----------------
__global__ void count_deg(const int* __restrict__ dst, int E, float* __restrict__ deg) {
    int i = blockIdx.x * blockDim.x + threadIdx.x;
    if (i < E) atomicAdd(&deg[dst[i]], 1.0f);
}
__global__ void invert_deg(float* __restrict__ deg, int n) {
    int i = blockIdx.x * blockDim.x + threadIdx.x;
    if (i < n) deg[i] = 1.0f / fmaxf(deg[i], 1.0f);
}

// ---------------- weight materialization (coeff x basis, concatenated cols) ----------------
// dst [K][3D]: seg0 -> relation r0, seg1 -> relation r1, seg2 -> loop
__global__ void build_w3(const float* __restrict__ coeff, const float* __restrict__ basis,
                         const float* __restrict__ loopw, float* __restrict__ dst,
                         int K, int D, int r0, int r1) {
    int idx = blockIdx.x * blockDim.x + threadIdx.x;
    int total = K * 3 * D;
    if (idx >= total) return;
    int i  = idx / (3 * D);
    int o2 = idx % (3 * D);
    int seg = o2 / D;
    int o   = o2 % D;
    float v;
    if (seg == 2) {
        v = loopw[i * D + o];
    } else {
        int r = (seg == 0) ? r0 : r1;
        v = coeff[r * 2 + 0] * basis[(size_t)0 * K * D + (size_t)i * D + o]
          + coeff[r * 2 + 1] * basis[(size_t)1 * K * D + (size_t)i * D + o];
    }
    dst[idx] = v;
}
// dst [K][2D]: seg0 -> relation r0, seg1 -> loop
__global__ void build_w2(const float* __restrict__ coeff, const float* __restrict__ basis,
                         const float* __restrict__ loopw, float* __restrict__ dst,
                         int K, int D, int r0) {
    int idx = blockIdx.x * blockDim.x + threadIdx.x;
    int total = K * 2 * D;
    if (idx >= total) return;
    int i  = idx / (2 * D);
    int o2 = idx % (2 * D);
    int seg = o2 / D;
    int o   = o2 % D;
    float v;
    if (seg == 1) {
        v = loopw[i * D + o];
    } else {
        v = coeff[r0 * 2 + 0] * basis[(size_t)0 * K * D + (size_t)i * D + o]
          + coeff[r0 * 2 + 1] * basis[(size_t)1 * K * D + (size_t)i * D + o];
    }
    dst[idx] = v;
}

// ---------------- SGEMM: C[M,N] = A[M,K] @ B[K,N], fp32, 128x128x16 tile ----------------
#define BM 128
#define BN 128
#define BK 16
__global__ __launch_bounds__(256) void sgemm(const float* __restrict__ A,
                                             const float* __restrict__ B,
                                             float* __restrict__ C,
                                             int M, int N, int K) {
    __shared__ float As[BK][BM + 4];   // stored transposed; +4 keeps 16B alignment, eases conflicts
    __shared__ float Bs[BK][BN];

    int tid = threadIdx.x;
    int tr = tid / 16;             // 0..15
    int tc = tid % 16;             // 0..15
    int rowBase = blockIdx.y * BM + tr * 8;
    int colBase = blockIdx.x * BN + tc * 8;

    int la_r = tid >> 2;           // 0..63 (A tile row, 2 passes of +64)
    int la_c = (tid & 3) << 2;     // 0,4,8,12
    int lb_r = tid >> 5;           // 0..7  (B tile row, 2 passes of +8)
    int lb_c = (tid & 31) << 2;

    float acc[8][8];
    #pragma unroll
    for (int i = 0; i < 8; i++)
        #pragma unroll
        for (int j = 0; j < 8; j++) acc[i][j] = 0.f;

    for (int k0 = 0; k0 < K; k0 += BK) {
        #pragma unroll
        for (int p = 0; p < 2; p++) {
            int r  = la_r + p * 64;
            int gr = blockIdx.y * BM + r;
            float4 v = (gr < M) ? *(const float4*)(A + (size_t)gr * K + k0 + la_c)
                                : make_float4(0.f, 0.f, 0.f, 0.f);
            As[la_c + 0][r] = v.x;
            As[la_c + 1][r] = v.y;
            As[la_c + 2][r] = v.z;
            As[la_c + 3][r] = v.w;
        }
        #pragma unroll
        for (int p = 0; p < 2; p++) {
            int r = lb_r + p * 8;
            *(float4*)&Bs[r][lb_c] = *(const float4*)(B + (size_t)(k0 + r) * N + blockIdx.x * BN + lb_c);
        }
        __syncthreads();

        #pragma unroll
        for (int kk = 0; kk < BK; kk++) {
            float4 a0 = *(const float4*)&As[kk][tr * 8];
            float4 a1 = *(const float4*)&As[kk][tr * 8 + 4];
            float4 b0 = *(const float4*)&Bs[kk][tc * 8];
            float4 b1 = *(const float4*)&Bs[kk][tc * 8 + 4];
            float ar[8] = {a0.x, a0.y, a0.z, a0.w, a1.x, a1.y, a1.z, a1.w};
            float br[8] = {b0.x, b0.y, b0.z, b0.w, b1.x, b1.y, b1.z, b1.w};
            #pragma unroll
            for (int i = 0; i < 8; i++)
                #pragma unroll
                for (int j = 0; j < 8; j++)
                    acc[i][j] += ar[i] * br[j];
        }
        __syncthreads();
    }

    #pragma unroll
    for (int i = 0; i < 8; i++) {
        int gr = rowBase + i;
        if (gr < M) {
            *(float4*)(C + (size_t)gr * N + colBase)     = make_float4(acc[i][0], acc[i][1], acc[i][2], acc[i][3]);
            *(float4*)(C + (size_t)gr * N + colBase + 4) = make_float4(acc[i][4], acc[i][5], acc[i][6], acc[i][7]);
        }
    }
}

// ---------------- edge scatter: acc[dst] += P[src, colOff:colOff+D] * invdeg[dst] ----------------
__global__ void scatter_scaled(const int* __restrict__ src, const int* __restrict__ dst, int E,
                               const float* __restrict__ P, int ldp, int colOff,
                               float* __restrict__ acc, int lda,
                               const float* __restrict__ invdeg, int D4) {
    long long t = (long long)blockIdx.x * blockDim.x + threadIdx.x;
    int e = (int)(t / D4);
    int j = (int)(t % D4);
    if (e >= E) return;
    int s = src[e];
    int d = dst[e];
    float sc = invdeg[d];
    float4 v = *(const float4*)(P + (size_t)s * ldp + colOff + 4 * j);
    redAdd4(acc + (size_t)d * lda + 4 * j, make_float4(v.x * sc, v.y * sc, v.z * sc, v.w * sc));
}

// ---------------- layer-1 combine: h = relu(acc + P[:,loopOff:] + bias) ----------------
__global__ void combine_relu(const float* __restrict__ acc, const float* __restrict__ P,
                             int ldp, int colOff, const float* __restrict__ bias,
                             float* __restrict__ h, int N, int D4, int D) {
    int t = blockIdx.x * blockDim.x + threadIdx.x;
    if (t >= N * D4) return;
    int i = t / D4;
    int j = t % D4;
    float4 a = *(const float4*)(acc + (size_t)i * D + 4 * j);
    float4 p = *(const float4*)(P + (size_t)i * ldp + colOff + 4 * j);
    float4 b = *(const float4*)(bias + 4 * j);
    float4 r;
    r.x = fmaxf(a.x + p.x + b.x, 0.f);
    r.y = fmaxf(a.y + p.y + b.y, 0.f);
    r.z = fmaxf(a.z + p.z + b.z, 0.f);
    r.w = fmaxf(a.w + p.w + b.w, 0.f);
    *(float4*)(h + (size_t)i * D + 4 * j) = r;
}

// ---------------- out init ----------------
__global__ void init_out(float* __restrict__ out, const float* __restrict__ b_score) {
    int g = threadIdx.x;
    if (g < NGRAPH) out[g] = b_score[0];
}

// ---------------- layer-2 combine + relu + score + per-graph reduce (warp per node) ----------------
__global__ void combine2_readout(const float* __restrict__ acc, const float* __restrict__ P,
                                 int ldp, int colOff, const float* __restrict__ bias,
                                 const float* __restrict__ wscore,
                                 const int* __restrict__ gid,
                                 float* __restrict__ out, int N) {
    int warp = (blockIdx.x * blockDim.x + threadIdx.x) >> 5;
    int lane = threadIdx.x & 31;
    if (warp >= N) return;
    float4 a = *(const float4*)(acc + (size_t)warp * D_O + lane * 4);
    float4 p = *(const float4*)(P + (size_t)warp * ldp + colOff + lane * 4);
    float4 b = *(const float4*)(bias + lane * 4);
    float4 w = *(const float4*)(wscore + lane * 4);
    float s = fmaxf(a.x + p.x + b.x, 0.f) * w.x
            + fmaxf(a.y + p.y + b.y, 0.f) * w.y
            + fmaxf(a.z + p.z + b.z, 0.f) * w.z
            + fmaxf(a.w + p.w + b.w, 0.f) * w.w;
    #pragma unroll
    for (int off = 16; off; off >>= 1) s += __shfl_down_sync(0xffffffffu, s, off);
    if (lane == 0) atomicAdd(&out[gid[warp]], s);
}

// ---------------- host launcher ----------------
static float* symaddr(const void* sym) {
    void* p = nullptr;
    cudaGetSymbolAddress(&p, sym);
    return (float*)p;
}

extern "C" void kernel_launch(void* const* d_in, const int* in_sizes, int n_in,
                              void* d_out, int out_size) {
    const float* x_sent  = (const float*)d_in[0];
    const float* x_doc   = (const float*)d_in[1];
    const float* coeff1  = (const float*)d_in[2];
    const float* basis1  = (const float*)d_in[3];
    const float* loop_w1 = (const float*)d_in[4];
    const float* bias1   = (const float*)d_in[5];
    const float* coeff2  = (const float*)d_in[6];
    const float* basis2  = (const float*)d_in[7];
    const float* loop_w2 = (const float*)d_in[8];
    const float* bias2   = (const float*)d_in[9];
    const float* w_score = (const float*)d_in[10];
    const float* b_score = (const float*)d_in[11];
    const int*   src_ss  = (const int*)d_in[12];
    const int*   dst_ss  = (const int*)d_in[13];
    const int*   src_sd  = (const int*)d_in[14];
    const int*   dst_sd  = (const int*)d_in[15];
    const int*   src_ds  = (const int*)d_in[16];
    const int*   dst_ds  = (const int*)d_in[17];
    const int*   gid_sent= (const int*)d_in[18];
    const int*   gid_doc = (const int*)d_in[19];
    float* out = (float*)d_out;

    float* pW1s = symaddr(g_W1s);
    float* pW1d = symaddr(g_W1d);
    float* pW2s = symaddr(g_W2s);
    float* pW2d = symaddr(g_W2d);
    float* pPs  = symaddr(g_Ps);
    float* pPd  = symaddr(g_Pd);
    float* pA1s = symaddr(g_acc_s1);
    float* pA1d = symaddr(g_acc_d1);
    float* pHs  = symaddr(g_hs);
    float* pHd  = symaddr(g_hd);
    float* pPs2 = symaddr(g_Ps2);
    float* pPd2 = symaddr(g_Pd2);
    float* pA2s = symaddr(g_acc_s2);
    float* pA2d = symaddr(g_acc_d2);
    float* pIss = symaddr(g_inv_ss);
    float* pIds = symaddr(g_inv_ds);
    float* pIsd = symaddr(g_inv_sd);

    cudaStream_t st = 0;

    // 0) zero accumulators + degree buffers
    zero_scratch<<<1184, 256, 0, st>>>();

    // 1) degrees -> inverse
    count_deg<<<(E_SS + 255) / 256, 256, 0, st>>>(dst_ss, E_SS, pIss);
    count_deg<<<(E_DS + 255) / 256, 256, 0, st>>>(dst_ds, E_DS, pIds);
    count_deg<<<(E_SD + 255) / 256, 256, 0, st>>>(dst_sd, E_SD, pIsd);
    invert_deg<<<(N_SENT + 255) / 256, 256, 0, st>>>(pIss, N_SENT);
    invert_deg<<<(N_SENT + 255) / 256, 256, 0, st>>>(pIds, N_SENT);
    invert_deg<<<(N_DOC + 255) / 256, 256, 0, st>>>(pIsd, N_DOC);

    // 2) weights
    build_w3<<<(D_IN * 3 * D_H + 255) / 256, 256, 0, st>>>(coeff1, basis1, loop_w1, pW1s, D_IN, D_H, 0, 2);
    build_w2<<<(D_IN * 2 * D_H + 255) / 256, 256, 0, st>>>(coeff1, basis1, loop_w1, pW1d, D_IN, D_H, 1);
    build_w3<<<(D_H * 3 * D_O + 255) / 256, 256, 0, st>>>(coeff2, basis2, loop_w2, pW2s, D_H, D_O, 0, 2);
    build_w2<<<(D_H * 2 * D_O + 255) / 256, 256, 0, st>>>(coeff2, basis2, loop_w2, pW2d, D_H, D_O, 1);

    // 3) layer-1 projections
    {
        dim3 grid((3 * D_H) / BN, (N_SENT + BM - 1) / BM);
        sgemm<<<grid, 256, 0, st>>>(x_sent, pW1s, pPs, N_SENT, 3 * D_H, D_IN);
    }
    {
        dim3 grid((2 * D_H) / BN, (N_DOC + BM - 1) / BM);
        sgemm<<<grid, 256, 0, st>>>(x_doc, pW1d, pPd, N_DOC, 2 * D_H, D_IN);
    }

    // 4) layer-1 aggregation (mean folded in via invdeg)
    {
        long long T = (long long)E_SS * (D_H / 4);
        scatter_scaled<<<(unsigned)((T + 255) / 256), 256, 0, st>>>(src_ss, dst_ss, E_SS, pPs, 3 * D_H, D_H, pA1s, D_H, pIss, D_H / 4);
    }
    {
        long long T = (long long)E_DS * (D_H / 4);
        scatter_scaled<<<(unsigned)((T + 255) / 256), 256, 0, st>>>(src_ds, dst_ds, E_DS, pPd, 2 * D_H, 0, pA1s, D_H, pIds, D_H / 4);
    }
    {
        long long T = (long long)E_SD * (D_H / 4);
        scatter_scaled<<<(unsigned)((T + 255) / 256), 256, 0, st>>>(src_sd, dst_sd, E_SD, pPs, 3 * D_H, 0, pA1d, D_H, pIsd, D_H / 4);
    }

    // 5) layer-1 combine
    combine_relu<<<(N_SENT * (D_H / 4) + 255) / 256, 256, 0, st>>>(pA1s, pPs, 3 * D_H, 2 * D_H, bias1, pHs, N_SENT, D_H / 4, D_H);
    combine_relu<<<(N_DOC * (D_H / 4) + 255) / 256, 256, 0, st>>>(pA1d, pPd, 2 * D_H, D_H, bias1, pHd, N_DOC, D_H / 4, D_H);

    // 6) layer-2 projections
    {
        dim3 grid((3 * D_O) / BN, (N_SENT + BM - 1) / BM);
        sgemm<<<grid, 256, 0, st>>>(pHs, pW2s, pPs2, N_SENT, 3 * D_O, D_H);
    }
    {
        dim3 grid((2 * D_O) / BN, (N_DOC + BM - 1) / BM);
        sgemm<<<grid, 256, 0, st>>>(pHd, pW2d, pPd2, N_DOC, 2 * D_O, D_H);
    }

    // 7) layer-2 aggregation
    {
        long long T = (long long)E_SS * (D_O / 4);
        scatter_scaled<<<(unsigned)((T + 255) / 256), 256, 0, st>>>(src_ss, dst_ss, E_SS, pPs2, 3 * D_O, D_O, pA2s, D_O, pIss, D_O / 4);
    }
    {
        long long T = (long long)E_DS * (D_O / 4);
        scatter_scaled<<<(unsigned)((T + 255) / 256), 256, 0, st>>>(src_ds, dst_ds, E_DS, pPd2, 2 * D_O, 0, pA2s, D_O, pIds, D_O / 4);
    }
    {
        long long T = (long long)E_SD * (D_O / 4);
        scatter_scaled<<<(unsigned)((T + 255) / 256), 256, 0, st>>>(src_sd, dst_sd, E_SD, pPs2, 3 * D_O, 0, pA2d, D_O, pIsd, D_O / 4);
    }

    // 8) readout: relu(combine) . w_score, segment-summed per graph, + b_score
    init_out<<<1, 32, 0, st>>>(out, b_score);
    combine2_readout<<<(N_SENT + 7) / 8, 256, 0, st>>>(pA2s, pPs2, 3 * D_O, 2 * D_O, bias2, w_score, gid_sent, out, N_SENT);
    combine2_readout<<<(N_DOC + 7) / 8, 256, 0, st>>>(pA2d, pPd2, 2 * D_O, D_O, bias2, w_score, gid_doc, out, N_DOC);
}

// round 3
// speedup vs baseline: 1.6670x; 1.6670x over previous
#include <cuda_runtime.h>
#include <cuda_bf16.h>
#include <cstdint>
#include <cstddef>

#define N_SENT 100000
#define N_DOC  10000
#define NGRAPH 32
#define D_IN   768
#define D_H    256
#define D_O    128
#define E_SS   400000
#define E_SD   100000
#define E_DS   100000

// ---------------- scratch (device globals: allocation-free) ----------------
// transposed, bf16-split weights: Bt[n][k] (K contiguous)
__device__ __nv_bfloat16 g_B1s_h[768 * 768], g_B1s_l[768 * 768];   // layer1 sent: N=768(3*256),K=768
__device__ __nv_bfloat16 g_B1d_h[512 * 768], g_B1d_l[512 * 768];   // layer1 doc:  N=512,K=768
__device__ __nv_bfloat16 g_B2s_h[384 * 256], g_B2s_l[384 * 256];   // layer2 sent: N=384,K=256
__device__ __nv_bfloat16 g_B2d_h[256 * 256], g_B2d_l[256 * 256];   // layer2 doc:  N=256,K=256

__device__ float g_Ps [(size_t)N_SENT * (3 * D_H)];
__device__ float g_Pd [(size_t)N_DOC  * (2 * D_H)];
__device__ float g_acc_s1[(size_t)N_SENT * D_H];
__device__ float g_acc_d1[(size_t)N_DOC  * D_H];
__device__ float g_hs [(size_t)N_SENT * D_H];
__device__ float g_hd [(size_t)N_DOC  * D_H];
__device__ float g_Ps2[(size_t)N_SENT * (3 * D_O)];
__device__ float g_Pd2[(size_t)N_DOC  * (2 * D_O)];
__device__ float g_acc_s2[(size_t)N_SENT * D_O];
__device__ float g_acc_d2[(size_t)N_DOC  * D_O];
__device__ float g_inv_ss[N_SENT];
__device__ float g_inv_ds[N_SENT];
__device__ float g_inv_sd[N_DOC];

// ---------------- PTX helpers ----------------
__device__ __forceinline__ uint32_t smem_u32(const void* p) {
    uint32_t a;
    asm("{ .reg .u64 t; cvta.to.shared.u64 t, %1; cvt.u32.u64 %0, t; }" : "=r"(a) : "l"(p));
    return a;
}

#define CP_ASYNC16(saddr, gaddr) \
    asm volatile("cp.async.ca.shared.global [%0], [%1], 16;" :: "r"(saddr), "l"(gaddr) : "memory")
#define CP_COMMIT() asm volatile("cp.async.commit_group;" ::: "memory")
#define CP_WAIT0()  asm volatile("cp.async.wait_group 0;" ::: "memory")

#define LDMX4(r0, r1, r2, r3, addr) \
    asm volatile("ldmatrix.sync.aligned.m8n8.x4.shared.b16 {%0,%1,%2,%3}, [%4];" \
                 : "=r"(r0), "=r"(r1), "=r"(r2), "=r"(r3) : "r"(addr))

#define MMA16816(d, a, b) \
    asm volatile("mma.sync.aligned.m16n8k16.row.col.f32.bf16.bf16.f32 " \
                 "{%0,%1,%2,%3}, {%4,%5,%6,%7}, {%8,%9}, {%0,%1,%2,%3};" \
                 : "+f"((d)[0]), "+f"((d)[1]), "+f"((d)[2]), "+f"((d)[3]) \
                 : "r"((a)[0]), "r"((a)[1]), "r"((a)[2]), "r"((a)[3]), "r"((b)[0]), "r"((b)[1]))

#define STS128(addr, v) \
    asm volatile("st.shared.v4.b32 [%0], {%1, %2, %3, %4};" \
                 :: "r"((uint32_t)(addr)), "r"((v).x), "r"((v).y), "r"((v).z), "r"((v).w) : "memory")

// ---------------- bf16 split helper ----------------
__device__ __forceinline__ void split8(const float* f, uint4& H, uint4& L) {
    uint32_t hs[8], ls[8];
    #pragma unroll
    for (int i = 0; i < 8; i++) {
        __nv_bfloat16 h = __float2bfloat16(f[i]);
        __nv_bfloat16 l = __float2bfloat16(f[i] - __bfloat162float(h));
        hs[i] = (uint32_t)__bfloat16_as_ushort(h);
        ls[i] = (uint32_t)__bfloat16_as_ushort(l);
    }
    H = make_uint4(hs[0] | (hs[1] << 16), hs[2] | (hs[3] << 16), hs[4] | (hs[5] << 16), hs[6] | (hs[7] << 16));
    L = make_uint4(ls[0] | (ls[1] << 16), ls[2] | (ls[3] << 16), ls[4] | (ls[5] << 16), ls[6] | (ls[7] << 16));
}

// ---------------- mma.sync GEMM: C[M,N] = A[M,K](fp32) @ Bt[N,K](bf16 hi/lo)^T --------------
// 3-term bf16 split: C = Ah*Bh + Al*Bh + Ah*Bl (fp32 accum).
// Block tile 128x128, BK=32, 256 threads (8 warps: 2 m x 4 n, warp tile 64x32).
// Smem rows padded to 80B (conflict-free ldmatrix at 8-row phase granularity).
#define ROWB   80
#define ST_SZ  40960                 // per-stage bytes: 4 arrays * 128*80
#define OFF_AH 0
#define OFF_AL 10240
#define OFF_BH 20480
#define OFF_BL 30720
#define GEMM_SMEM (2 * ST_SZ)

__global__ __launch_bounds__(256, 1) void gemm_mma(
    const float* __restrict__ A,
    const __nv_bfloat16* __restrict__ Bth,
    const __nv_bfloat16* __restrict__ Btl,
    float* __restrict__ C, int M, int N, int K)
{
    extern __shared__ char smem[];
    uint32_t sb = smem_u32(smem);
    int tid = threadIdx.x;
    int lane = tid & 31, wid = tid >> 5;
    int warp_m = (wid & 1) * 64;
    int warp_n = (wid >> 1) * 32;
    int mrow0 = blockIdx.y * 128;
    int ncol0 = blockIdx.x * 128;
    int nk = K >> 5;

    // ---- producer indices ----
    int arow = tid >> 1;                 // 0..127
    int aseg = (tid & 1) << 4;           // 0 or 16 floats
    int agrow = mrow0 + arow;
    bool avalid = agrow < M;
    const float* aptr = A + (size_t)agrow * K + aseg;
    uint32_t a_sts = sb + arow * ROWB + aseg * 2;   // bf16 bytes

    int brow = tid >> 1;                 // 0..127
    int bcc  = (tid & 1) * 2;            // chunk pair 0/1 or 2/3 (16B units)
    const __nv_bfloat16* bhptr = Bth + (size_t)(ncol0 + brow) * K + bcc * 8;
    const __nv_bfloat16* blptr = Btl + (size_t)(ncol0 + brow) * K + bcc * 8;
    uint32_t b_sts = sb + brow * ROWB + bcc * 16;

    // ---- ldmatrix lane addresses (byte offsets within arrays) ----
    int ra = warp_m + (lane & 7) + (lane & 8);
    int ca = ((lane >> 4) << 3);
    uint32_t a_lm = (uint32_t)(ra * ROWB + ca * 2);
    int rb = warp_n + (lane & 7) + ((lane >> 4) << 3);
    int cb = (((lane >> 3) & 1) << 3);
    uint32_t b_lm = (uint32_t)(rb * ROWB + cb * 2);

    float acc[4][4][4];
    #pragma unroll
    for (int mi = 0; mi < 4; mi++)
        #pragma unroll
        for (int ni = 0; ni < 4; ni++)
            #pragma unroll
            for (int q = 0; q < 4; q++) acc[mi][ni][q] = 0.f;

    float areg[16];

    // ---- prologue: stage 0 ----
    {
        #pragma unroll
        for (int q = 0; q < 4; q++) {
            float4 v = avalid ? *(const float4*)(aptr + q * 4) : make_float4(0.f, 0.f, 0.f, 0.f);
            areg[q * 4 + 0] = v.x; areg[q * 4 + 1] = v.y; areg[q * 4 + 2] = v.z; areg[q * 4 + 3] = v.w;
        }
        CP_ASYNC16(b_sts + OFF_BH, (const void*)bhptr);
        CP_ASYNC16(b_sts + OFF_BH + 16, (const void*)(bhptr + 8));
        CP_ASYNC16(b_sts + OFF_BL, (const void*)blptr);
        CP_ASYNC16(b_sts + OFF_BL + 16, (const void*)(blptr + 8));
        CP_COMMIT();
        uint4 H, L;
        split8(areg, H, L);       STS128(a_sts + OFF_AH, H);      STS128(a_sts + OFF_AL, L);
        split8(areg + 8, H, L);   STS128(a_sts + OFF_AH + 16, H); STS128(a_sts + OFF_AL + 16, L);
        CP_WAIT0();
        __syncthreads();
    }

    for (int kt = 0; kt < nk; kt++) {
        int cur = kt & 1;
        int nxt = cur ^ 1;
        uint32_t bcur = sb + cur * ST_SZ;
        uint32_t bnxt_off = (uint32_t)(nxt * ST_SZ);
        bool more = (kt + 1) < nk;

        if (more) {
            const float* ap = aptr + (kt + 1) * 32;
            #pragma unroll
            for (int q = 0; q < 4; q++) {
                float4 v = avalid ? *(const float4*)(ap + q * 4) : make_float4(0.f, 0.f, 0.f, 0.f);
                areg[q * 4 + 0] = v.x; areg[q * 4 + 1] = v.y; areg[q * 4 + 2] = v.z; areg[q * 4 + 3] = v.w;
            }
            const __nv_bfloat16* bh = bhptr + (kt + 1) * 32;
            const __nv_bfloat16* bl = blptr + (kt + 1) * 32;
            CP_ASYNC16(b_sts + bnxt_off + OFF_BH, (const void*)bh);
            CP_ASYNC16(b_sts + bnxt_off + OFF_BH + 16, (const void*)(bh + 8));
            CP_ASYNC16(b_sts + bnxt_off + OFF_BL, (const void*)bl);
            CP_ASYNC16(b_sts + bnxt_off + OFF_BL + 16, (const void*)(bl + 8));
            CP_COMMIT();
        }

        // ---- compute current stage: two k16 steps ----
        #pragma unroll
        for (int ks = 0; ks < 2; ks++) {
            uint32_t koff = ks * 32;   // 16 bf16 = 32 bytes
            uint32_t ah[4][4], al[4][4], bh[4][2], bl[4][2];
            #pragma unroll
            for (int mi = 0; mi < 4; mi++) {
                uint32_t addr = bcur + OFF_AH + a_lm + mi * (16 * ROWB) + koff;
                LDMX4(ah[mi][0], ah[mi][1], ah[mi][2], ah[mi][3], addr);
            }
            #pragma unroll
            for (int mi = 0; mi < 4; mi++) {
                uint32_t addr = bcur + OFF_AL + a_lm + mi * (16 * ROWB) + koff;
                LDMX4(al[mi][0], al[mi][1], al[mi][2], al[mi][3], addr);
            }
            #pragma unroll
            for (int bg = 0; bg < 2; bg++) {
                uint32_t addr = bcur + OFF_BH + b_lm + bg * (16 * ROWB) + koff;
                LDMX4(bh[bg * 2][0], bh[bg * 2][1], bh[bg * 2 + 1][0], bh[bg * 2 + 1][1], addr);
            }
            #pragma unroll
            for (int bg = 0; bg < 2; bg++) {
                uint32_t addr = bcur + OFF_BL + b_lm + bg * (16 * ROWB) + koff;
                LDMX4(bl[bg * 2][0], bl[bg * 2][1], bl[bg * 2 + 1][0], bl[bg * 2 + 1][1], addr);
            }
            // term order keeps same-acc mmas maximally separated
            #pragma unroll
            for (int mi = 0; mi < 4; mi++)
                #pragma unroll
                for (int ni = 0; ni < 4; ni++)
                    MMA16816(acc[mi][ni], ah[mi], bh[ni]);
            #pragma unroll
            for (int mi = 0; mi < 4; mi++)
                #pragma unroll
                for (int ni = 0; ni < 4; ni++)
                    MMA16816(acc[mi][ni], al[mi], bh[ni]);
            #pragma unroll
            for (int mi = 0; mi < 4; mi++)
                #pragma unroll
                for (int ni = 0; ni < 4; ni++)
                    MMA16816(acc[mi][ni], ah[mi], bl[ni]);
        }

        if (more) {
            uint4 H, L;
            split8(areg, H, L);
            STS128(a_sts + bnxt_off + OFF_AH, H);      STS128(a_sts + bnxt_off + OFF_AL, L);
            split8(areg + 8, H, L);
            STS128(a_sts + bnxt_off + OFF_AH + 16, H); STS128(a_sts + bnxt_off + OFF_AL + 16, L);
            CP_WAIT0();
        }
        __syncthreads();
    }

    // ---- epilogue ----
    int g = lane >> 2, t = lane & 3;
    #pragma unroll
    for (int mi = 0; mi < 4; mi++) {
        int r0 = mrow0 + warp_m + mi * 16 + g;
        #pragma unroll
        for (int ni = 0; ni < 4; ni++) {
            int col = ncol0 + warp_n + ni * 8 + t * 2;
            if (r0 < M)
                *(float2*)(C + (size_t)r0 * N + col) = make_float2(acc[mi][ni][0], acc[mi][ni][1]);
            if (r0 + 8 < M)
                *(float2*)(C + (size_t)(r0 + 8) * N + col) = make_float2(acc[mi][ni][2], acc[mi][ni][3]);
        }
    }
}

// ---------------- zero accumulators + degree buffers ----------------
__global__ void zero_scratch() {
    size_t t = (size_t)blockIdx.x * blockDim.x + threadIdx.x;
    size_t stride = (size_t)gridDim.x * blockDim.x;
    float4 z = make_float4(0.f, 0.f, 0.f, 0.f);
    for (size_t i = t; i < (size_t)N_SENT * D_H / 4; i += stride) ((float4*)g_acc_s1)[i] = z;
    for (size_t i = t; i < (size_t)N_DOC  * D_H / 4; i += stride) ((float4*)g_acc_d1)[i] = z;
    for (size_t i = t; i < (size_t)N_SENT * D_O / 4; i += stride) ((float4*)g_acc_s2)[i] = z;
    for (size_t i = t; i < (size_t)N_DOC  * D_O / 4; i += stride) ((float4*)g_acc_d2)[i] = z;
    for (size_t i = t; i < N_SENT / 4; i += stride) ((float4*)g_inv_ss)[i] = z;
    for (size_t i = t; i < N_SENT / 4; i += stride) ((float4*)g_inv_ds)[i] = z;
    for (size_t i = t; i < N_DOC  / 4; i += stride) ((float4*)g_inv_sd)[i] = z;
}

// ---------------- degree count + invert ----------------
__global__ void count_deg(const int* __restrict__ dst, int E, float* __restrict__ deg) {
    int i = blockIdx.x * blockDim.x + threadIdx.x;
    if (i < E) atomicAdd(&deg[dst[i]], 1.0f);
}
__global__ void invert_deg(float* __restrict__ deg, int n) {
    int i = blockIdx.x * blockDim.x + threadIdx.x;
    if (i < n) deg[i] = 1.0f / fmaxf(deg[i], 1.0f);
}

// ---------------- weight build: transposed + bf16-split ----------------
__global__ void build_w3t(const float* __restrict__ coeff, const float* __restrict__ basis,
                          const float* __restrict__ loopw,
                          __nv_bfloat16* __restrict__ outH, __nv_bfloat16* __restrict__ outL,
                          int K, int D, int Npad, int r0, int r1) {
    int idx = blockIdx.x * blockDim.x + threadIdx.x;
    if (idx >= Npad * K) return;
    int o = idx / K;
    int k = idx % K;
    float v = 0.f;
    if (o < 3 * D) {
        int seg = o / D, od = o % D;
        if (seg == 2) v = loopw[k * D + od];
        else {
            int r = (seg == 0) ? r0 : r1;
            v = coeff[r * 2 + 0] * basis[(size_t)k * D + od]
              + coeff[r * 2 + 1] * basis[(size_t)K * D + (size_t)k * D + od];
        }
    }
    __nv_bfloat16 h = __float2bfloat16(v);
    outH[idx] = h;
    outL[idx] = __float2bfloat16(v - __bfloat162float(h));
}
__global__ void build_w2t(const float* __restrict__ coeff, const float* __restrict__ basis,
                          const float* __restrict__ loopw,
                          __nv_bfloat16* __restrict__ outH, __nv_bfloat16* __restrict__ outL,
                          int K, int D, int Npad, int r0) {
    int idx = blockIdx.x * blockDim.x + threadIdx.x;
    if (idx >= Npad * K) return;
    int o = idx / K;
    int k = idx % K;
    float v = 0.f;
    if (o < 2 * D) {
        int seg = o / D, od = o % D;
        if (seg == 1) v = loopw[k * D + od];
        else {
            v = coeff[r0 * 2 + 0] * basis[(size_t)k * D + od]
              + coeff[r0 * 2 + 1] * basis[(size_t)K * D + (size_t)k * D + od];
        }
    }
    __nv_bfloat16 h = __float2bfloat16(v);
    outH[idx] = h;
    outL[idx] = __float2bfloat16(v - __bfloat162float(h));
}

// ---------------- edge scatter: acc[dst] += P[src, colOff:colOff+D] * invdeg[dst] ----------------
__device__ __forceinline__ void redAdd4(float* addr, float4 v) {
    asm volatile("red.global.add.v4.f32 [%0], {%1, %2, %3, %4};"
                 :: "l"(addr), "f"(v.x), "f"(v.y), "f"(v.z), "f"(v.w) : "memory");
}
__global__ void scatter_scaled(const int* __restrict__ src, const int* __restrict__ dst, int E,
                               const float* __restrict__ P, int ldp, int colOff,
                               float* __restrict__ acc, int lda,
                               const float* __restrict__ invdeg, int D4) {
    long long t = (long long)blockIdx.x * blockDim.x + threadIdx.x;
    int e = (int)(t / D4);
    int j = (int)(t % D4);
    if (e >= E) return;
    int s = src[e];
    int d = dst[e];
    float sc = invdeg[d];
    float4 v = *(const float4*)(P + (size_t)s * ldp + colOff + 4 * j);
    redAdd4(acc + (size_t)d * lda + 4 * j, make_float4(v.x * sc, v.y * sc, v.z * sc, v.w * sc));
}

// ---------------- layer-1 combine: h = relu(acc + P[:,loopOff:] + bias) ----------------
__global__ void combine_relu(const float* __restrict__ acc, const float* __restrict__ P,
                             int ldp, int colOff, const float* __restrict__ bias,
                             float* __restrict__ h, int N, int D4, int D) {
    int t = blockIdx.x * blockDim.x + threadIdx.x;
    if (t >= N * D4) return;
    int i = t / D4;
    int j = t % D4;
    float4 a = *(const float4*)(acc + (size_t)i * D + 4 * j);
    float4 p = *(const float4*)(P + (size_t)i * ldp + colOff + 4 * j);
    float4 b = *(const float4*)(bias + 4 * j);
    float4 r;
    r.x = fmaxf(a.x + p.x + b.x, 0.f);
    r.y = fmaxf(a.y + p.y + b.y, 0.f);
    r.z = fmaxf(a.z + p.z + b.z, 0.f);
    r.w = fmaxf(a.w + p.w + b.w, 0.f);
    *(float4*)(h + (size_t)i * D + 4 * j) = r;
}

// ---------------- out init ----------------
__global__ void init_out(float* __restrict__ out, const float* __restrict__ b_score) {
    int g = threadIdx.x;
    if (g < NGRAPH) out[g] = b_score[0];
}

// ---------------- layer-2 combine + relu + score + per-graph reduce (warp per node) ----------------
__global__ void combine2_readout(const float* __restrict__ acc, const float* __restrict__ P,
                                 int ldp, int colOff, const float* __restrict__ bias,
                                 const float* __restrict__ wscore,
                                 const int* __restrict__ gid,
                                 float* __restrict__ out, int N) {
    int warp = (blockIdx.x * blockDim.x + threadIdx.x) >> 5;
    int lane = threadIdx.x & 31;
    if (warp >= N) return;
    float4 a = *(const float4*)(acc + (size_t)warp * D_O + lane * 4);
    float4 p = *(const float4*)(P + (size_t)warp * ldp + colOff + lane * 4);
    float4 b = *(const float4*)(bias + lane * 4);
    float4 w = *(const float4*)(wscore + lane * 4);
    float s = fmaxf(a.x + p.x + b.x, 0.f) * w.x
            + fmaxf(a.y + p.y + b.y, 0.f) * w.y
            + fmaxf(a.z + p.z + b.z, 0.f) * w.z
            + fmaxf(a.w + p.w + b.w, 0.f) * w.w;
    #pragma unroll
    for (int off = 16; off; off >>= 1) s += __shfl_down_sync(0xffffffffu, s, off);
    if (lane == 0) atomicAdd(&out[gid[warp]], s);
}

// ---------------- host launcher ----------------
static void* symaddr(const void* sym) {
    void* p = nullptr;
    cudaGetSymbolAddress(&p, sym);
    return p;
}

extern "C" void kernel_launch(void* const* d_in, const int* in_sizes, int n_in,
                              void* d_out, int out_size) {
    const float* x_sent  = (const float*)d_in[0];
    const float* x_doc   = (const float*)d_in[1];
    const float* coeff1  = (const float*)d_in[2];
    const float* basis1  = (const float*)d_in[3];
    const float* loop_w1 = (const float*)d_in[4];
    const float* bias1   = (const float*)d_in[5];
    const float* coeff2  = (const float*)d_in[6];
    const float* basis2  = (const float*)d_in[7];
    const float* loop_w2 = (const float*)d_in[8];
    const float* bias2   = (const float*)d_in[9];
    const float* w_score = (const float*)d_in[10];
    const float* b_score = (const float*)d_in[11];
    const int*   src_ss  = (const int*)d_in[12];
    const int*   dst_ss  = (const int*)d_in[13];
    const int*   src_sd  = (const int*)d_in[14];
    const int*   dst_sd  = (const int*)d_in[15];
    const int*   src_ds  = (const int*)d_in[16];
    const int*   dst_ds  = (const int*)d_in[17];
    const int*   gid_sent= (const int*)d_in[18];
    const int*   gid_doc = (const int*)d_in[19];
    float* out = (float*)d_out;

    __nv_bfloat16* pB1sh = (__nv_bfloat16*)symaddr(g_B1s_h);
    __nv_bfloat16* pB1sl = (__nv_bfloat16*)symaddr(g_B1s_l);
    __nv_bfloat16* pB1dh = (__nv_bfloat16*)symaddr(g_B1d_h);
    __nv_bfloat16* pB1dl = (__nv_bfloat16*)symaddr(g_B1d_l);
    __nv_bfloat16* pB2sh = (__nv_bfloat16*)symaddr(g_B2s_h);
    __nv_bfloat16* pB2sl = (__nv_bfloat16*)symaddr(g_B2s_l);
    __nv_bfloat16* pB2dh = (__nv_bfloat16*)symaddr(g_B2d_h);
    __nv_bfloat16* pB2dl = (__nv_bfloat16*)symaddr(g_B2d_l);

    float* pPs  = (float*)symaddr(g_Ps);
    float* pPd  = (float*)symaddr(g_Pd);
    float* pA1s = (float*)symaddr(g_acc_s1);
    float* pA1d = (float*)symaddr(g_acc_d1);
    float* pHs  = (float*)symaddr(g_hs);
    float* pHd  = (float*)symaddr(g_hd);
    float* pPs2 = (float*)symaddr(g_Ps2);
    float* pPd2 = (float*)symaddr(g_Pd2);
    float* pA2s = (float*)symaddr(g_acc_s2);
    float* pA2d = (float*)symaddr(g_acc_d2);
    float* pIss = (float*)symaddr(g_inv_ss);
    float* pIds = (float*)symaddr(g_inv_ds);
    float* pIsd = (float*)symaddr(g_inv_sd);

    cudaFuncSetAttribute(gemm_mma, cudaFuncAttributeMaxDynamicSharedMemorySize, GEMM_SMEM);

    cudaStream_t st = 0;

    // 0) zero accumulators + degree buffers
    zero_scratch<<<1184, 256, 0, st>>>();

    // 1) degrees -> inverse
    count_deg<<<(E_SS + 255) / 256, 256, 0, st>>>(dst_ss, E_SS, pIss);
    count_deg<<<(E_DS + 255) / 256, 256, 0, st>>>(dst_ds, E_DS, pIds);
    count_deg<<<(E_SD + 255) / 256, 256, 0, st>>>(dst_sd, E_SD, pIsd);
    invert_deg<<<(N_SENT + 255) / 256, 256, 0, st>>>(pIss, N_SENT);
    invert_deg<<<(N_SENT + 255) / 256, 256, 0, st>>>(pIds, N_SENT);
    invert_deg<<<(N_DOC + 255) / 256, 256, 0, st>>>(pIsd, N_DOC);

    // 2) weights: transposed + split
    build_w3t<<<(768 * 768 + 255) / 256, 256, 0, st>>>(coeff1, basis1, loop_w1, pB1sh, pB1sl, D_IN, D_H, 768, 0, 2);
    build_w2t<<<(512 * 768 + 255) / 256, 256, 0, st>>>(coeff1, basis1, loop_w1, pB1dh, pB1dl, D_IN, D_H, 512, 1);
    build_w3t<<<(384 * 256 + 255) / 256, 256, 0, st>>>(coeff2, basis2, loop_w2, pB2sh, pB2sl, D_H, D_O, 384, 0, 2);
    build_w2t<<<(256 * 256 + 255) / 256, 256, 0, st>>>(coeff2, basis2, loop_w2, pB2dh, pB2dl, D_H, D_O, 256, 1);

    // 3) layer-1 projections (mma.sync)
    {
        dim3 g(768 / 128, (N_SENT + 127) / 128);
        gemm_mma<<<g, 256, GEMM_SMEM, st>>>(x_sent, pB1sh, pB1sl, pPs, N_SENT, 3 * D_H, D_IN);
    }
    {
        dim3 g(512 / 128, (N_DOC + 127) / 128);
        gemm_mma<<<g, 256, GEMM_SMEM, st>>>(x_doc, pB1dh, pB1dl, pPd, N_DOC, 2 * D_H, D_IN);
    }

    // 4) layer-1 aggregation (mean folded via invdeg)
    {
        long long T = (long long)E_SS * (D_H / 4);
        scatter_scaled<<<(unsigned)((T + 255) / 256), 256, 0, st>>>(src_ss, dst_ss, E_SS, pPs, 3 * D_H, D_H, pA1s, D_H, pIss, D_H / 4);
    }
    {
        long long T = (long long)E_DS * (D_H / 4);
        scatter_scaled<<<(unsigned)((T + 255) / 256), 256, 0, st>>>(src_ds, dst_ds, E_DS, pPd, 2 * D_H, 0, pA1s, D_H, pIds, D_H / 4);
    }
    {
        long long T = (long long)E_SD * (D_H / 4);
        scatter_scaled<<<(unsigned)((T + 255) / 256), 256, 0, st>>>(src_sd, dst_sd, E_SD, pPs, 3 * D_H, 0, pA1d, D_H, pIsd, D_H / 4);
    }

    // 5) layer-1 combine
    combine_relu<<<(N_SENT * (D_H / 4) + 255) / 256, 256, 0, st>>>(pA1s, pPs, 3 * D_H, 2 * D_H, bias1, pHs, N_SENT, D_H / 4, D_H);
    combine_relu<<<(N_DOC * (D_H / 4) + 255) / 256, 256, 0, st>>>(pA1d, pPd, 2 * D_H, D_H, bias1, pHd, N_DOC, D_H / 4, D_H);

    // 6) layer-2 projections (mma.sync)
    {
        dim3 g(384 / 128, (N_SENT + 127) / 128);
        gemm_mma<<<g, 256, GEMM_SMEM, st>>>(pHs, pB2sh, pB2sl, pPs2, N_SENT, 3 * D_O, D_H);
    }
    {
        dim3 g(256 / 128, (N_DOC + 127) / 128);
        gemm_mma<<<g, 256, GEMM_SMEM, st>>>(pHd, pB2dh, pB2dl, pPd2, N_DOC, 2 * D_O, D_H);
    }

    // 7) layer-2 aggregation
    {
        long long T = (long long)E_SS * (D_O / 4);
        scatter_scaled<<<(unsigned)((T + 255) / 256), 256, 0, st>>>(src_ss, dst_ss, E_SS, pPs2, 3 * D_O, D_O, pA2s, D_O, pIss, D_O / 4);
    }
    {
        long long T = (long long)E_DS * (D_O / 4);
        scatter_scaled<<<(unsigned)((T + 255) / 256), 256, 0, st>>>(src_ds, dst_ds, E_DS, pPd2, 2 * D_O, 0, pA2s, D_O, pIds, D_O / 4);
    }
    {
        long long T = (long long)E_SD * (D_O / 4);
        scatter_scaled<<<(unsigned)((T + 255) / 256), 256, 0, st>>>(src_sd, dst_sd, E_SD, pPs2, 3 * D_O, 0, pA2d, D_O, pIsd, D_O / 4);
    }

    // 8) readout
    init_out<<<1, 32, 0, st>>>(out, b_score);
    combine2_readout<<<(N_SENT + 7) / 8, 256, 0, st>>>(pA2s, pPs2, 3 * D_O, 2 * D_O, bias2, w_score, gid_sent, out, N_SENT);
    combine2_readout<<<(N_DOC + 7) / 8, 256, 0, st>>>(pA2d, pPd2, 2 * D_O, D_O, bias2, w_score, gid_doc, out, N_DOC);
}

// round 4
// speedup vs baseline: 1.6861x; 1.0115x over previous
#include <cuda_runtime.h>
#include <cuda_bf16.h>
#include <cstdint>
#include <cstddef>

#define N_SENT 100000
#define N_DOC  10000
#define NGRAPH 32
#define D_IN   768
#define D_H    256
#define D_O    128
#define E_SS   400000
#define E_SD   100000
#define E_DS   100000

// ---------------- scratch (device globals: allocation-free) ----------------
__device__ __nv_bfloat16 g_B1s_h[768 * 768], g_B1s_l[768 * 768];   // layer1 sent: N=768,K=768
__device__ __nv_bfloat16 g_B1d_h[512 * 768], g_B1d_l[512 * 768];   // layer1 doc:  N=512,K=768
__device__ __nv_bfloat16 g_B2s_h[384 * 256], g_B2s_l[384 * 256];   // layer2 sent: N=384,K=256
__device__ __nv_bfloat16 g_B2d_h[256 * 256], g_B2d_l[256 * 256];   // layer2 doc:  N=256,K=256

__device__ float g_Ps [(size_t)N_SENT * (3 * D_H)];
__device__ float g_Pd [(size_t)N_DOC  * (2 * D_H)];
__device__ float g_acc_s1[(size_t)N_SENT * D_H];
__device__ float g_acc_d1[(size_t)N_DOC  * D_H];
__device__ float g_hs [(size_t)N_SENT * D_H];
__device__ float g_hd [(size_t)N_DOC  * D_H];
__device__ float g_Ps2[(size_t)N_SENT * (3 * D_O)];
__device__ float g_Pd2[(size_t)N_DOC  * (2 * D_O)];
__device__ float g_acc_s2[(size_t)N_SENT * D_O];
__device__ float g_acc_d2[(size_t)N_DOC  * D_O];
__device__ float g_inv_ss[N_SENT];
__device__ float g_inv_ds[N_SENT];
__device__ float g_inv_sd[N_DOC];

// ---------------- PTX helpers ----------------
__device__ __forceinline__ uint32_t smem_u32(const void* p) {
    uint32_t a;
    asm("{ .reg .u64 t; cvta.to.shared.u64 t, %1; cvt.u32.u64 %0, t; }" : "=r"(a) : "l"(p));
    return a;
}

#define CP_ASYNC16(saddr, gaddr) \
    asm volatile("cp.async.ca.shared.global [%0], [%1], 16;" :: "r"(saddr), "l"(gaddr) : "memory")
#define CP_COMMIT() asm volatile("cp.async.commit_group;" ::: "memory")
#define CP_WAIT0()  asm volatile("cp.async.wait_group 0;" ::: "memory")

#define LDMX4(r0, r1, r2, r3, addr) \
    asm volatile("ldmatrix.sync.aligned.m8n8.x4.shared.b16 {%0,%1,%2,%3}, [%4];" \
                 : "=r"(r0), "=r"(r1), "=r"(r2), "=r"(r3) : "r"(addr))

#define MMA16816(d, a, b) \
    asm volatile("mma.sync.aligned.m16n8k16.row.col.f32.bf16.bf16.f32 " \
                 "{%0,%1,%2,%3}, {%4,%5,%6,%7}, {%8,%9}, {%0,%1,%2,%3};" \
                 : "+f"((d)[0]), "+f"((d)[1]), "+f"((d)[2]), "+f"((d)[3]) \
                 : "r"((a)[0]), "r"((a)[1]), "r"((a)[2]), "r"((a)[3]), "r"((b)[0]), "r"((b)[1]))

#define STS128(addr, v) \
    asm volatile("st.shared.v4.b32 [%0], {%1, %2, %3, %4};" \
                 :: "r"((uint32_t)(addr)), "r"((v).x), "r"((v).y), "r"((v).z), "r"((v).w) : "memory")

// ---------------- bf16 split helper ----------------
__device__ __forceinline__ void split8(const float* f, uint4& H, uint4& L) {
    uint32_t hs[8], ls[8];
    #pragma unroll
    for (int i = 0; i < 8; i++) {
        __nv_bfloat16 h = __float2bfloat16(f[i]);
        __nv_bfloat16 l = __float2bfloat16(f[i] - __bfloat162float(h));
        hs[i] = (uint32_t)__bfloat16_as_ushort(h);
        ls[i] = (uint32_t)__bfloat16_as_ushort(l);
    }
    H = make_uint4(hs[0] | (hs[1] << 16), hs[2] | (hs[3] << 16), hs[4] | (hs[5] << 16), hs[6] | (hs[7] << 16));
    L = make_uint4(ls[0] | (ls[1] << 16), ls[2] | (ls[3] << 16), ls[4] | (ls[5] << 16), ls[6] | (ls[7] << 16));
}

#define ROWB   80

// ================= WIDE GEMM: block 128x256, 8 warps, warp tile 64x64 =================
// C[M,N] = A[M,K](fp32) @ Bt[N,K](bf16 hi/lo)^T, 3-term split. Requires N % 256 == 0.
#define WST_SZ   61440               // per stage: AH 10240 + AL 10240 + BH 20480 + BL 20480
#define W_OFF_AH 0
#define W_OFF_AL 10240
#define W_OFF_BH 20480
#define W_OFF_BL 40960
#define WIDE_SMEM (2 * WST_SZ)

__global__ __launch_bounds__(256, 1) void gemm_mma_wide(
    const float* __restrict__ A,
    const __nv_bfloat16* __restrict__ Bth,
    const __nv_bfloat16* __restrict__ Btl,
    float* __restrict__ C, int M, int N, int K)
{
    extern __shared__ char smem[];
    uint32_t sb = smem_u32(smem);
    int tid = threadIdx.x;
    int lane = tid & 31, wid = tid >> 5;
    int warp_m = (wid & 1) * 64;
    int warp_n = (wid >> 1) * 64;
    int mrow0 = blockIdx.y * 128;
    int ncol0 = blockIdx.x * 256;
    int nk = K >> 5;

    // A producer: thread t -> row t>>1, 16-float segment (t&1)
    int arow = tid >> 1;
    int aseg = (tid & 1) << 4;
    int agrow = mrow0 + arow;
    bool avalid = agrow < M;
    const float* aptr = A + (size_t)agrow * K + aseg;
    uint32_t a_sts = sb + arow * ROWB + aseg * 2;

    // B producer: thread t -> row t (256 rows), 4 chunks of 16B per term
    const __nv_bfloat16* bhptr = Bth + (size_t)(ncol0 + tid) * K;
    const __nv_bfloat16* blptr = Btl + (size_t)(ncol0 + tid) * K;
    uint32_t b_sts = sb + tid * ROWB;

    // ldmatrix lane addresses
    int ra = warp_m + (lane & 7) + (lane & 8);
    int ca = ((lane >> 4) << 3);
    uint32_t a_lm = (uint32_t)(ra * ROWB + ca * 2);
    int rb = warp_n + (lane & 7) + ((lane >> 4) << 3);
    int cb = (((lane >> 3) & 1) << 3);
    uint32_t b_lm = (uint32_t)(rb * ROWB + cb * 2);

    float acc[4][8][4];
    #pragma unroll
    for (int mi = 0; mi < 4; mi++)
        #pragma unroll
        for (int ni = 0; ni < 8; ni++)
            #pragma unroll
            for (int q = 0; q < 4; q++) acc[mi][ni][q] = 0.f;

    float areg[16];

    // ---- prologue: stage 0 ----
    {
        #pragma unroll
        for (int q = 0; q < 4; q++) {
            float4 v = avalid ? *(const float4*)(aptr + q * 4) : make_float4(0.f, 0.f, 0.f, 0.f);
            areg[q * 4 + 0] = v.x; areg[q * 4 + 1] = v.y; areg[q * 4 + 2] = v.z; areg[q * 4 + 3] = v.w;
        }
        #pragma unroll
        for (int c = 0; c < 4; c++) {
            CP_ASYNC16(b_sts + W_OFF_BH + c * 16, (const void*)(bhptr + c * 8));
            CP_ASYNC16(b_sts + W_OFF_BL + c * 16, (const void*)(blptr + c * 8));
        }
        CP_COMMIT();
        uint4 H, L;
        split8(areg, H, L);       STS128(a_sts + W_OFF_AH, H);      STS128(a_sts + W_OFF_AL, L);
        split8(areg + 8, H, L);   STS128(a_sts + W_OFF_AH + 16, H); STS128(a_sts + W_OFF_AL + 16, L);
        CP_WAIT0();
        __syncthreads();
    }

    for (int kt = 0; kt < nk; kt++) {
        int cur = kt & 1;
        uint32_t bcur = sb + cur * WST_SZ;
        uint32_t bnxt_off = (uint32_t)((cur ^ 1) * WST_SZ);
        bool more = (kt + 1) < nk;

        if (more) {
            const float* ap = aptr + (kt + 1) * 32;
            #pragma unroll
            for (int q = 0; q < 4; q++) {
                float4 v = avalid ? *(const float4*)(ap + q * 4) : make_float4(0.f, 0.f, 0.f, 0.f);
                areg[q * 4 + 0] = v.x; areg[q * 4 + 1] = v.y; areg[q * 4 + 2] = v.z; areg[q * 4 + 3] = v.w;
            }
            const __nv_bfloat16* bh = bhptr + (kt + 1) * 32;
            const __nv_bfloat16* bl = blptr + (kt + 1) * 32;
            #pragma unroll
            for (int c = 0; c < 4; c++) {
                CP_ASYNC16(b_sts + bnxt_off + W_OFF_BH + c * 16, (const void*)(bh + c * 8));
                CP_ASYNC16(b_sts + bnxt_off + W_OFF_BL + c * 16, (const void*)(bl + c * 8));
            }
            CP_COMMIT();
        }

        #pragma unroll
        for (int ks = 0; ks < 2; ks++) {
            uint32_t koff = ks * 32;
            uint32_t ah[4][4], al[4][4], bh[8][2], bl[8][2];
            #pragma unroll
            for (int mi = 0; mi < 4; mi++)
                LDMX4(ah[mi][0], ah[mi][1], ah[mi][2], ah[mi][3],
                      bcur + W_OFF_AH + a_lm + mi * (16 * ROWB) + koff);
            #pragma unroll
            for (int mi = 0; mi < 4; mi++)
                LDMX4(al[mi][0], al[mi][1], al[mi][2], al[mi][3],
                      bcur + W_OFF_AL + a_lm + mi * (16 * ROWB) + koff);
            #pragma unroll
            for (int bg = 0; bg < 4; bg++)
                LDMX4(bh[bg * 2][0], bh[bg * 2][1], bh[bg * 2 + 1][0], bh[bg * 2 + 1][1],
                      bcur + W_OFF_BH + b_lm + bg * (16 * ROWB) + koff);
            #pragma unroll
            for (int bg = 0; bg < 4; bg++)
                LDMX4(bl[bg * 2][0], bl[bg * 2][1], bl[bg * 2 + 1][0], bl[bg * 2 + 1][1],
                      bcur + W_OFF_BL + b_lm + bg * (16 * ROWB) + koff);

            #pragma unroll
            for (int mi = 0; mi < 4; mi++)
                #pragma unroll
                for (int ni = 0; ni < 8; ni++)
                    MMA16816(acc[mi][ni], ah[mi], bh[ni]);
            #pragma unroll
            for (int mi = 0; mi < 4; mi++)
                #pragma unroll
                for (int ni = 0; ni < 8; ni++)
                    MMA16816(acc[mi][ni], al[mi], bh[ni]);
            #pragma unroll
            for (int mi = 0; mi < 4; mi++)
                #pragma unroll
                for (int ni = 0; ni < 8; ni++)
                    MMA16816(acc[mi][ni], ah[mi], bl[ni]);
        }

        if (more) {
            uint4 H, L;
            split8(areg, H, L);
            STS128(a_sts + bnxt_off + W_OFF_AH, H);      STS128(a_sts + bnxt_off + W_OFF_AL, L);
            split8(areg + 8, H, L);
            STS128(a_sts + bnxt_off + W_OFF_AH + 16, H); STS128(a_sts + bnxt_off + W_OFF_AL + 16, L);
            CP_WAIT0();
        }
        __syncthreads();
    }

    // ---- epilogue ----
    int g = lane >> 2, t4 = lane & 3;
    #pragma unroll
    for (int mi = 0; mi < 4; mi++) {
        int r0 = mrow0 + warp_m + mi * 16 + g;
        #pragma unroll
        for (int ni = 0; ni < 8; ni++) {
            int col = ncol0 + warp_n + ni * 8 + t4 * 2;
            if (r0 < M)
                *(float2*)(C + (size_t)r0 * N + col) = make_float2(acc[mi][ni][0], acc[mi][ni][1]);
            if (r0 + 8 < M)
                *(float2*)(C + (size_t)(r0 + 8) * N + col) = make_float2(acc[mi][ni][2], acc[mi][ni][3]);
        }
    }
}

// ================= GEMM: block 128x128, 8 warps (2x4), warp tile 64x32 =================
#define ST_SZ  40960
#define OFF_AH 0
#define OFF_AL 10240
#define OFF_BH 20480
#define OFF_BL 30720
#define GEMM_SMEM (2 * ST_SZ)

__global__ __launch_bounds__(256, 1) void gemm_mma(
    const float* __restrict__ A,
    const __nv_bfloat16* __restrict__ Bth,
    const __nv_bfloat16* __restrict__ Btl,
    float* __restrict__ C, int M, int N, int K)
{
    extern __shared__ char smem[];
    uint32_t sb = smem_u32(smem);
    int tid = threadIdx.x;
    int lane = tid & 31, wid = tid >> 5;
    int warp_m = (wid & 1) * 64;
    int warp_n = (wid >> 1) * 32;
    int mrow0 = blockIdx.y * 128;
    int ncol0 = blockIdx.x * 128;
    int nk = K >> 5;

    int arow = tid >> 1;
    int aseg = (tid & 1) << 4;
    int agrow = mrow0 + arow;
    bool avalid = agrow < M;
    const float* aptr = A + (size_t)agrow * K + aseg;
    uint32_t a_sts = sb + arow * ROWB + aseg * 2;

    int brow = tid >> 1;
    int bcc  = (tid & 1) * 2;
    const __nv_bfloat16* bhptr = Bth + (size_t)(ncol0 + brow) * K + bcc * 8;
    const __nv_bfloat16* blptr = Btl + (size_t)(ncol0 + brow) * K + bcc * 8;
    uint32_t b_sts = sb + brow * ROWB + bcc * 16;

    int ra = warp_m + (lane & 7) + (lane & 8);
    int ca = ((lane >> 4) << 3);
    uint32_t a_lm = (uint32_t)(ra * ROWB + ca * 2);
    int rb = warp_n + (lane & 7) + ((lane >> 4) << 3);
    int cb = (((lane >> 3) & 1) << 3);
    uint32_t b_lm = (uint32_t)(rb * ROWB + cb * 2);

    float acc[4][4][4];
    #pragma unroll
    for (int mi = 0; mi < 4; mi++)
        #pragma unroll
        for (int ni = 0; ni < 4; ni++)
            #pragma unroll
            for (int q = 0; q < 4; q++) acc[mi][ni][q] = 0.f;

    float areg[16];

    {
        #pragma unroll
        for (int q = 0; q < 4; q++) {
            float4 v = avalid ? *(const float4*)(aptr + q * 4) : make_float4(0.f, 0.f, 0.f, 0.f);
            areg[q * 4 + 0] = v.x; areg[q * 4 + 1] = v.y; areg[q * 4 + 2] = v.z; areg[q * 4 + 3] = v.w;
        }
        CP_ASYNC16(b_sts + OFF_BH, (const void*)bhptr);
        CP_ASYNC16(b_sts + OFF_BH + 16, (const void*)(bhptr + 8));
        CP_ASYNC16(b_sts + OFF_BL, (const void*)blptr);
        CP_ASYNC16(b_sts + OFF_BL + 16, (const void*)(blptr + 8));
        CP_COMMIT();
        uint4 H, L;
        split8(areg, H, L);       STS128(a_sts + OFF_AH, H);      STS128(a_sts + OFF_AL, L);
        split8(areg + 8, H, L);   STS128(a_sts + OFF_AH + 16, H); STS128(a_sts + OFF_AL + 16, L);
        CP_WAIT0();
        __syncthreads();
    }

    for (int kt = 0; kt < nk; kt++) {
        int cur = kt & 1;
        uint32_t bcur = sb + cur * ST_SZ;
        uint32_t bnxt_off = (uint32_t)((cur ^ 1) * ST_SZ);
        bool more = (kt + 1) < nk;

        if (more) {
            const float* ap = aptr + (kt + 1) * 32;
            #pragma unroll
            for (int q = 0; q < 4; q++) {
                float4 v = avalid ? *(const float4*)(ap + q * 4) : make_float4(0.f, 0.f, 0.f, 0.f);
                areg[q * 4 + 0] = v.x; areg[q * 4 + 1] = v.y; areg[q * 4 + 2] = v.z; areg[q * 4 + 3] = v.w;
            }
            const __nv_bfloat16* bh = bhptr + (kt + 1) * 32;
            const __nv_bfloat16* bl = blptr + (kt + 1) * 32;
            CP_ASYNC16(b_sts + bnxt_off + OFF_BH, (const void*)bh);
            CP_ASYNC16(b_sts + bnxt_off + OFF_BH + 16, (const void*)(bh + 8));
            CP_ASYNC16(b_sts + bnxt_off + OFF_BL, (const void*)bl);
            CP_ASYNC16(b_sts + bnxt_off + OFF_BL + 16, (const void*)(bl + 8));
            CP_COMMIT();
        }

        #pragma unroll
        for (int ks = 0; ks < 2; ks++) {
            uint32_t koff = ks * 32;
            uint32_t ah[4][4], al[4][4], bh[4][2], bl[4][2];
            #pragma unroll
            for (int mi = 0; mi < 4; mi++)
                LDMX4(ah[mi][0], ah[mi][1], ah[mi][2], ah[mi][3],
                      bcur + OFF_AH + a_lm + mi * (16 * ROWB) + koff);
            #pragma unroll
            for (int mi = 0; mi < 4; mi++)
                LDMX4(al[mi][0], al[mi][1], al[mi][2], al[mi][3],
                      bcur + OFF_AL + a_lm + mi * (16 * ROWB) + koff);
            #pragma unroll
            for (int bg = 0; bg < 2; bg++)
                LDMX4(bh[bg * 2][0], bh[bg * 2][1], bh[bg * 2 + 1][0], bh[bg * 2 + 1][1],
                      bcur + OFF_BH + b_lm + bg * (16 * ROWB) + koff);
            #pragma unroll
            for (int bg = 0; bg < 2; bg++)
                LDMX4(bl[bg * 2][0], bl[bg * 2][1], bl[bg * 2 + 1][0], bl[bg * 2 + 1][1],
                      bcur + OFF_BL + b_lm + bg * (16 * ROWB) + koff);
            #pragma unroll
            for (int mi = 0; mi < 4; mi++)
                #pragma unroll
                for (int ni = 0; ni < 4; ni++)
                    MMA16816(acc[mi][ni], ah[mi], bh[ni]);
            #pragma unroll
            for (int mi = 0; mi < 4; mi++)
                #pragma unroll
                for (int ni = 0; ni < 4; ni++)
                    MMA16816(acc[mi][ni], al[mi], bh[ni]);
            #pragma unroll
            for (int mi = 0; mi < 4; mi++)
                #pragma unroll
                for (int ni = 0; ni < 4; ni++)
                    MMA16816(acc[mi][ni], ah[mi], bl[ni]);
        }

        if (more) {
            uint4 H, L;
            split8(areg, H, L);
            STS128(a_sts + bnxt_off + OFF_AH, H);      STS128(a_sts + bnxt_off + OFF_AL, L);
            split8(areg + 8, H, L);
            STS128(a_sts + bnxt_off + OFF_AH + 16, H); STS128(a_sts + bnxt_off + OFF_AL + 16, L);
            CP_WAIT0();
        }
        __syncthreads();
    }

    int g = lane >> 2, t4 = lane & 3;
    #pragma unroll
    for (int mi = 0; mi < 4; mi++) {
        int r0 = mrow0 + warp_m + mi * 16 + g;
        #pragma unroll
        for (int ni = 0; ni < 4; ni++) {
            int col = ncol0 + warp_n + ni * 8 + t4 * 2;
            if (r0 < M)
                *(float2*)(C + (size_t)r0 * N + col) = make_float2(acc[mi][ni][0], acc[mi][ni][1]);
            if (r0 + 8 < M)
                *(float2*)(C + (size_t)(r0 + 8) * N + col) = make_float2(acc[mi][ni][2], acc[mi][ni][3]);
        }
    }
}

// ---------------- zero accumulators + degree buffers ----------------
__global__ void zero_scratch() {
    size_t t = (size_t)blockIdx.x * blockDim.x + threadIdx.x;
    size_t stride = (size_t)gridDim.x * blockDim.x;
    float4 z = make_float4(0.f, 0.f, 0.f, 0.f);
    for (size_t i = t; i < (size_t)N_SENT * D_H / 4; i += stride) ((float4*)g_acc_s1)[i] = z;
    for (size_t i = t; i < (size_t)N_DOC  * D_H / 4; i += stride) ((float4*)g_acc_d1)[i] = z;
    for (size_t i = t; i < (size_t)N_SENT * D_O / 4; i += stride) ((float4*)g_acc_s2)[i] = z;
    for (size_t i = t; i < (size_t)N_DOC  * D_O / 4; i += stride) ((float4*)g_acc_d2)[i] = z;
    for (size_t i = t; i < N_SENT / 4; i += stride) ((float4*)g_inv_ss)[i] = z;
    for (size_t i = t; i < N_SENT / 4; i += stride) ((float4*)g_inv_ds)[i] = z;
    for (size_t i = t; i < N_DOC  / 4; i += stride) ((float4*)g_inv_sd)[i] = z;
}

// ---------------- degree count + invert ----------------
__global__ void count_deg(const int* __restrict__ dst, int E, float* __restrict__ deg) {
    int i = blockIdx.x * blockDim.x + threadIdx.x;
    if (i < E) atomicAdd(&deg[dst[i]], 1.0f);
}
__global__ void invert_deg(float* __restrict__ deg, int n) {
    int i = blockIdx.x * blockDim.x + threadIdx.x;
    if (i < n) deg[i] = 1.0f / fmaxf(deg[i], 1.0f);
}

// ---------------- weight build: transposed + bf16-split ----------------
__global__ void build_w3t(const float* __restrict__ coeff, const float* __restrict__ basis,
                          const float* __restrict__ loopw,
                          __nv_bfloat16* __restrict__ outH, __nv_bfloat16* __restrict__ outL,
                          int K, int D, int Npad, int r0, int r1) {
    int idx = blockIdx.x * blockDim.x + threadIdx.x;
    if (idx >= Npad * K) return;
    int o = idx / K;
    int k = idx % K;
    float v = 0.f;
    if (o < 3 * D) {
        int seg = o / D, od = o % D;
        if (seg == 2) v = loopw[k * D + od];
        else {
            int r = (seg == 0) ? r0 : r1;
            v = coeff[r * 2 + 0] * basis[(size_t)k * D + od]
              + coeff[r * 2 + 1] * basis[(size_t)K * D + (size_t)k * D + od];
        }
    }
    __nv_bfloat16 h = __float2bfloat16(v);
    outH[idx] = h;
    outL[idx] = __float2bfloat16(v - __bfloat162float(h));
}
__global__ void build_w2t(const float* __restrict__ coeff, const float* __restrict__ basis,
                          const float* __restrict__ loopw,
                          __nv_bfloat16* __restrict__ outH, __nv_bfloat16* __restrict__ outL,
                          int K, int D, int Npad, int r0) {
    int idx = blockIdx.x * blockDim.x + threadIdx.x;
    if (idx >= Npad * K) return;
    int o = idx / K;
    int k = idx % K;
    float v = 0.f;
    if (o < 2 * D) {
        int seg = o / D, od = o % D;
        if (seg == 1) v = loopw[k * D + od];
        else {
            v = coeff[r0 * 2 + 0] * basis[(size_t)k * D + od]
              + coeff[r0 * 2 + 1] * basis[(size_t)K * D + (size_t)k * D + od];
        }
    }
    __nv_bfloat16 h = __float2bfloat16(v);
    outH[idx] = h;
    outL[idx] = __float2bfloat16(v - __bfloat162float(h));
}

// ---------------- edge scatter: acc[dst] += P[src, colOff:colOff+D] * invdeg[dst] ----------------
__device__ __forceinline__ void redAdd4(float* addr, float4 v) {
    asm volatile("red.global.add.v4.f32 [%0], {%1, %2, %3, %4};"
                 :: "l"(addr), "f"(v.x), "f"(v.y), "f"(v.z), "f"(v.w) : "memory");
}
__global__ void scatter_scaled(const int* __restrict__ src, const int* __restrict__ dst, int E,
                               const float* __restrict__ P, int ldp, int colOff,
                               float* __restrict__ acc, int lda,
                               const float* __restrict__ invdeg, int D4) {
    long long t = (long long)blockIdx.x * blockDim.x + threadIdx.x;
    int e = (int)(t / D4);
    int j = (int)(t % D4);
    if (e >= E) return;
    int s = src[e];
    int d = dst[e];
    float sc = invdeg[d];
    float4 v = *(const float4*)(P + (size_t)s * ldp + colOff + 4 * j);
    redAdd4(acc + (size_t)d * lda + 4 * j, make_float4(v.x * sc, v.y * sc, v.z * sc, v.w * sc));
}

// ---------------- layer-1 combine ----------------
__global__ void combine_relu(const float* __restrict__ acc, const float* __restrict__ P,
                             int ldp, int colOff, const float* __restrict__ bias,
                             float* __restrict__ h, int N, int D4, int D) {
    int t = blockIdx.x * blockDim.x + threadIdx.x;
    if (t >= N * D4) return;
    int i = t / D4;
    int j = t % D4;
    float4 a = *(const float4*)(acc + (size_t)i * D + 4 * j);
    float4 p = *(const float4*)(P + (size_t)i * ldp + colOff + 4 * j);
    float4 b = *(const float4*)(bias + 4 * j);
    float4 r;
    r.x = fmaxf(a.x + p.x + b.x, 0.f);
    r.y = fmaxf(a.y + p.y + b.y, 0.f);
    r.z = fmaxf(a.z + p.z + b.z, 0.f);
    r.w = fmaxf(a.w + p.w + b.w, 0.f);
    *(float4*)(h + (size_t)i * D + 4 * j) = r;
}

// ---------------- out init ----------------
__global__ void init_out(float* __restrict__ out, const float* __restrict__ b_score) {
    int g = threadIdx.x;
    if (g < NGRAPH) out[g] = b_score[0];
}

// ---------------- layer-2 combine + relu + score + per-graph reduce ----------------
__global__ void combine2_readout(const float* __restrict__ acc, const float* __restrict__ P,
                                 int ldp, int colOff, const float* __restrict__ bias,
                                 const float* __restrict__ wscore,
                                 const int* __restrict__ gid,
                                 float* __restrict__ out, int N) {
    int warp = (blockIdx.x * blockDim.x + threadIdx.x) >> 5;
    int lane = threadIdx.x & 31;
    if (warp >= N) return;
    float4 a = *(const float4*)(acc + (size_t)warp * D_O + lane * 4);
    float4 p = *(const float4*)(P + (size_t)warp * ldp + colOff + lane * 4);
    float4 b = *(const float4*)(bias + lane * 4);
    float4 w = *(const float4*)(wscore + lane * 4);
    float s = fmaxf(a.x + p.x + b.x, 0.f) * w.x
            + fmaxf(a.y + p.y + b.y, 0.f) * w.y
            + fmaxf(a.z + p.z + b.z, 0.f) * w.z
            + fmaxf(a.w + p.w + b.w, 0.f) * w.w;
    #pragma unroll
    for (int off = 16; off; off >>= 1) s += __shfl_down_sync(0xffffffffu, s, off);
    if (lane == 0) atomicAdd(&out[gid[warp]], s);
}

// ---------------- host launcher ----------------
static void* symaddr(const void* sym) {
    void* p = nullptr;
    cudaGetSymbolAddress(&p, sym);
    return p;
}

extern "C" void kernel_launch(void* const* d_in, const int* in_sizes, int n_in,
                              void* d_out, int out_size) {
    const float* x_sent  = (const float*)d_in[0];
    const float* x_doc   = (const float*)d_in[1];
    const float* coeff1  = (const float*)d_in[2];
    const float* basis1  = (const float*)d_in[3];
    const float* loop_w1 = (const float*)d_in[4];
    const float* bias1   = (const float*)d_in[5];
    const float* coeff2  = (const float*)d_in[6];
    const float* basis2  = (const float*)d_in[7];
    const float* loop_w2 = (const float*)d_in[8];
    const float* bias2   = (const float*)d_in[9];
    const float* w_score = (const float*)d_in[10];
    const float* b_score = (const float*)d_in[11];
    const int*   src_ss  = (const int*)d_in[12];
    const int*   dst_ss  = (const int*)d_in[13];
    const int*   src_sd  = (const int*)d_in[14];
    const int*   dst_sd  = (const int*)d_in[15];
    const int*   src_ds  = (const int*)d_in[16];
    const int*   dst_ds  = (const int*)d_in[17];
    const int*   gid_sent= (const int*)d_in[18];
    const int*   gid_doc = (const int*)d_in[19];
    float* out = (float*)d_out;

    __nv_bfloat16* pB1sh = (__nv_bfloat16*)symaddr(g_B1s_h);
    __nv_bfloat16* pB1sl = (__nv_bfloat16*)symaddr(g_B1s_l);
    __nv_bfloat16* pB1dh = (__nv_bfloat16*)symaddr(g_B1d_h);
    __nv_bfloat16* pB1dl = (__nv_bfloat16*)symaddr(g_B1d_l);
    __nv_bfloat16* pB2sh = (__nv_bfloat16*)symaddr(g_B2s_h);
    __nv_bfloat16* pB2sl = (__nv_bfloat16*)symaddr(g_B2s_l);
    __nv_bfloat16* pB2dh = (__nv_bfloat16*)symaddr(g_B2d_h);
    __nv_bfloat16* pB2dl = (__nv_bfloat16*)symaddr(g_B2d_l);

    float* pPs  = (float*)symaddr(g_Ps);
    float* pPd  = (float*)symaddr(g_Pd);
    float* pA1s = (float*)symaddr(g_acc_s1);
    float* pA1d = (float*)symaddr(g_acc_d1);
    float* pHs  = (float*)symaddr(g_hs);
    float* pHd  = (float*)symaddr(g_hd);
    float* pPs2 = (float*)symaddr(g_Ps2);
    float* pPd2 = (float*)symaddr(g_Pd2);
    float* pA2s = (float*)symaddr(g_acc_s2);
    float* pA2d = (float*)symaddr(g_acc_d2);
    float* pIss = (float*)symaddr(g_inv_ss);
    float* pIds = (float*)symaddr(g_inv_ds);
    float* pIsd = (float*)symaddr(g_inv_sd);

    cudaFuncSetAttribute(gemm_mma, cudaFuncAttributeMaxDynamicSharedMemorySize, GEMM_SMEM);
    cudaFuncSetAttribute(gemm_mma_wide, cudaFuncAttributeMaxDynamicSharedMemorySize, WIDE_SMEM);

    cudaStream_t st = 0;

    // 0) zero accumulators + degree buffers
    zero_scratch<<<1184, 256, 0, st>>>();

    // 1) degrees -> inverse
    count_deg<<<(E_SS + 255) / 256, 256, 0, st>>>(dst_ss, E_SS, pIss);
    count_deg<<<(E_DS + 255) / 256, 256, 0, st>>>(dst_ds, E_DS, pIds);
    count_deg<<<(E_SD + 255) / 256, 256, 0, st>>>(dst_sd, E_SD, pIsd);
    invert_deg<<<(N_SENT + 255) / 256, 256, 0, st>>>(pIss, N_SENT);
    invert_deg<<<(N_SENT + 255) / 256, 256, 0, st>>>(pIds, N_SENT);
    invert_deg<<<(N_DOC + 255) / 256, 256, 0, st>>>(pIsd, N_DOC);

    // 2) weights: transposed + split
    build_w3t<<<(768 * 768 + 255) / 256, 256, 0, st>>>(coeff1, basis1, loop_w1, pB1sh, pB1sl, D_IN, D_H, 768, 0, 2);
    build_w2t<<<(512 * 768 + 255) / 256, 256, 0, st>>>(coeff1, basis1, loop_w1, pB1dh, pB1dl, D_IN, D_H, 512, 1);
    build_w3t<<<(384 * 256 + 255) / 256, 256, 0, st>>>(coeff2, basis2, loop_w2, pB2sh, pB2sl, D_H, D_O, 384, 0, 2);
    build_w2t<<<(256 * 256 + 255) / 256, 256, 0, st>>>(coeff2, basis2, loop_w2, pB2dh, pB2dl, D_H, D_O, 256, 1);

    // 3) layer-1 projections (wide tcgen-style mma kernel)
    {
        dim3 g(768 / 256, (N_SENT + 127) / 128);
        gemm_mma_wide<<<g, 256, WIDE_SMEM, st>>>(x_sent, pB1sh, pB1sl, pPs, N_SENT, 3 * D_H, D_IN);
    }
    {
        dim3 g(512 / 256, (N_DOC + 127) / 128);
        gemm_mma_wide<<<g, 256, WIDE_SMEM, st>>>(x_doc, pB1dh, pB1dl, pPd, N_DOC, 2 * D_H, D_IN);
    }

    // 4) layer-1 aggregation
    {
        long long T = (long long)E_SS * (D_H / 4);
        scatter_scaled<<<(unsigned)((T + 255) / 256), 256, 0, st>>>(src_ss, dst_ss, E_SS, pPs, 3 * D_H, D_H, pA1s, D_H, pIss, D_H / 4);
    }
    {
        long long T = (long long)E_DS * (D_H / 4);
        scatter_scaled<<<(unsigned)((T + 255) / 256), 256, 0, st>>>(src_ds, dst_ds, E_DS, pPd, 2 * D_H, 0, pA1s, D_H, pIds, D_H / 4);
    }
    {
        long long T = (long long)E_SD * (D_H / 4);
        scatter_scaled<<<(unsigned)((T + 255) / 256), 256, 0, st>>>(src_sd, dst_sd, E_SD, pPs, 3 * D_H, 0, pA1d, D_H, pIsd, D_H / 4);
    }

    // 5) layer-1 combine
    combine_relu<<<(N_SENT * (D_H / 4) + 255) / 256, 256, 0, st>>>(pA1s, pPs, 3 * D_H, 2 * D_H, bias1, pHs, N_SENT, D_H / 4, D_H);
    combine_relu<<<(N_DOC * (D_H / 4) + 255) / 256, 256, 0, st>>>(pA1d, pPd, 2 * D_H, D_H, bias1, pHd, N_DOC, D_H / 4, D_H);

    // 6) layer-2 projections
    {
        dim3 g(384 / 128, (N_SENT + 127) / 128);
        gemm_mma<<<g, 256, GEMM_SMEM, st>>>(pHs, pB2sh, pB2sl, pPs2, N_SENT, 3 * D_O, D_H);
    }
    {
        dim3 g(256 / 256, (N_DOC + 127) / 128);
        gemm_mma_wide<<<g, 256, WIDE_SMEM, st>>>(pHd, pB2dh, pB2dl, pPd2, N_DOC, 2 * D_O, D_H);
    }

    // 7) layer-2 aggregation
    {
        long long T = (long long)E_SS * (D_O / 4);
        scatter_scaled<<<(unsigned)((T + 255) / 256), 256, 0, st>>>(src_ss, dst_ss, E_SS, pPs2, 3 * D_O, D_O, pA2s, D_O, pIss, D_O / 4);
    }
    {
        long long T = (long long)E_DS * (D_O / 4);
        scatter_scaled<<<(unsigned)((T + 255) / 256), 256, 0, st>>>(src_ds, dst_ds, E_DS, pPd2, 2 * D_O, 0, pA2s, D_O, pIds, D_O / 4);
    }
    {
        long long T = (long long)E_SD * (D_O / 4);
        scatter_scaled<<<(unsigned)((T + 255) / 256), 256, 0, st>>>(src_sd, dst_sd, E_SD, pPs2, 3 * D_O, 0, pA2d, D_O, pIsd, D_O / 4);
    }

    // 8) readout
    init_out<<<1, 32, 0, st>>>(out, b_score);
    combine2_readout<<<(N_SENT + 7) / 8, 256, 0, st>>>(pA2s, pPs2, 3 * D_O, 2 * D_O, bias2, w_score, gid_sent, out, N_SENT);
    combine2_readout<<<(N_DOC + 7) / 8, 256, 0, st>>>(pA2d, pPd2, 2 * D_O, D_O, bias2, w_score, gid_doc, out, N_DOC);
}

// round 5
// speedup vs baseline: 2.2326x; 1.3241x over previous
#include <cuda_runtime.h>
#include <cuda_fp16.h>
#include <cstdint>
#include <cstddef>

#define N_SENT 100000
#define N_DOC  10000
#define NGRAPH 32
#define D_IN   768
#define D_H    256
#define D_O    128
#define E_SS   400000
#define E_SD   100000
#define E_DS   100000

// ---------------- scratch (device globals: allocation-free) ----------------
// transposed fp16 weights: Bt[n][k] (K contiguous)
__device__ __half g_B1s_h[768 * 768];   // layer1 sent: N=768,K=768
__device__ __half g_B1d_h[512 * 768];   // layer1 doc:  N=512,K=768
__device__ __half g_B2s_h[384 * 256];   // layer2 sent: N=384,K=256
__device__ __half g_B2d_h[256 * 256];   // layer2 doc:  N=256,K=256

__device__ float g_Ps [(size_t)N_SENT * (3 * D_H)];
__device__ float g_Pd [(size_t)N_DOC  * (2 * D_H)];
__device__ float g_acc_s1[(size_t)N_SENT * D_H];
__device__ float g_acc_d1[(size_t)N_DOC  * D_H];
__device__ float g_hs [(size_t)N_SENT * D_H];
__device__ float g_hd [(size_t)N_DOC  * D_H];
__device__ float g_Ps2[(size_t)N_SENT * (3 * D_O)];
__device__ float g_Pd2[(size_t)N_DOC  * (2 * D_O)];
__device__ float g_acc_s2[(size_t)N_SENT * D_O];
__device__ float g_acc_d2[(size_t)N_DOC  * D_O];
__device__ float g_inv_ss[N_SENT];
__device__ float g_inv_ds[N_SENT];
__device__ float g_inv_sd[N_DOC];

// ---------------- PTX helpers ----------------
__device__ __forceinline__ uint32_t smem_u32(const void* p) {
    uint32_t a;
    asm("{ .reg .u64 t; cvta.to.shared.u64 t, %1; cvt.u32.u64 %0, t; }" : "=r"(a) : "l"(p));
    return a;
}

#define CP_ASYNC16(saddr, gaddr) \
    asm volatile("cp.async.ca.shared.global [%0], [%1], 16;" :: "r"(saddr), "l"(gaddr) : "memory")
#define CP_COMMIT() asm volatile("cp.async.commit_group;" ::: "memory")
#define CP_WAIT0()  asm volatile("cp.async.wait_group 0;" ::: "memory")

#define LDMX4(r0, r1, r2, r3, addr) \
    asm volatile("ldmatrix.sync.aligned.m8n8.x4.shared.b16 {%0,%1,%2,%3}, [%4];" \
                 : "=r"(r0), "=r"(r1), "=r"(r2), "=r"(r3) : "r"(addr))

#define MMA16816(d, a, b) \
    asm volatile("mma.sync.aligned.m16n8k16.row.col.f32.f16.f16.f32 " \
                 "{%0,%1,%2,%3}, {%4,%5,%6,%7}, {%8,%9}, {%0,%1,%2,%3};" \
                 : "+f"((d)[0]), "+f"((d)[1]), "+f"((d)[2]), "+f"((d)[3]) \
                 : "r"((a)[0]), "r"((a)[1]), "r"((a)[2]), "r"((a)[3]), "r"((b)[0]), "r"((b)[1]))

#define STS128(addr, v) \
    asm volatile("st.shared.v4.b32 [%0], {%1, %2, %3, %4};" \
                 :: "r"((uint32_t)(addr)), "r"((v).x), "r"((v).y), "r"((v).z), "r"((v).w) : "memory")

// ---------------- fp16 split helper: a = hi + lo ----------------
__device__ __forceinline__ void split8h(const float* f, uint4& H, uint4& L) {
    uint32_t hs[8], ls[8];
    #pragma unroll
    for (int i = 0; i < 8; i++) {
        __half h = __float2half(f[i]);
        __half l = __float2half(f[i] - __half2float(h));
        hs[i] = (uint32_t)__half_as_ushort(h);
        ls[i] = (uint32_t)__half_as_ushort(l);
    }
    H = make_uint4(hs[0] | (hs[1] << 16), hs[2] | (hs[3] << 16), hs[4] | (hs[5] << 16), hs[6] | (hs[7] << 16));
    L = make_uint4(ls[0] | (ls[1] << 16), ls[2] | (ls[3] << 16), ls[4] | (ls[5] << 16), ls[6] | (ls[7] << 16));
}

#define ROWB   80

// ================= WIDE GEMM: block 128x256, 8 warps, warp tile 64x64 =================
// C[M,N] = A[M,K](fp32) @ Bt[N,K](fp16)^T, 2-term split: AhBh + AlBh. N % 256 == 0.
#define WST_SZ   40960               // per stage: AH 10240 + AL 10240 + BH 20480
#define W_OFF_AH 0
#define W_OFF_AL 10240
#define W_OFF_BH 20480
#define WIDE_SMEM (2 * WST_SZ)

__global__ __launch_bounds__(256, 1) void gemm_mma_wide(
    const float* __restrict__ A,
    const __half* __restrict__ Bth,
    float* __restrict__ C, int M, int N, int K)
{
    extern __shared__ char smem[];
    uint32_t sb = smem_u32(smem);
    int tid = threadIdx.x;
    int lane = tid & 31, wid = tid >> 5;
    int warp_m = (wid & 1) * 64;
    int warp_n = (wid >> 1) * 64;
    int mrow0 = blockIdx.y * 128;
    int ncol0 = blockIdx.x * 256;
    int nk = K >> 5;

    int arow = tid >> 1;
    int aseg = (tid & 1) << 4;
    int agrow = mrow0 + arow;
    bool avalid = agrow < M;
    const float* aptr = A + (size_t)agrow * K + aseg;
    uint32_t a_sts = sb + arow * ROWB + aseg * 2;

    const __half* bhptr = Bth + (size_t)(ncol0 + tid) * K;
    uint32_t b_sts = sb + tid * ROWB;

    int ra = warp_m + (lane & 7) + (lane & 8);
    int ca = ((lane >> 4) << 3);
    uint32_t a_lm = (uint32_t)(ra * ROWB + ca * 2);
    int rb = warp_n + (lane & 7) + ((lane >> 4) << 3);
    int cb = (((lane >> 3) & 1) << 3);
    uint32_t b_lm = (uint32_t)(rb * ROWB + cb * 2);

    float acc[4][8][4];
    #pragma unroll
    for (int mi = 0; mi < 4; mi++)
        #pragma unroll
        for (int ni = 0; ni < 8; ni++)
            #pragma unroll
            for (int q = 0; q < 4; q++) acc[mi][ni][q] = 0.f;

    float areg[16];

    // ---- prologue ----
    {
        #pragma unroll
        for (int q = 0; q < 4; q++) {
            float4 v = avalid ? *(const float4*)(aptr + q * 4) : make_float4(0.f, 0.f, 0.f, 0.f);
            areg[q * 4 + 0] = v.x; areg[q * 4 + 1] = v.y; areg[q * 4 + 2] = v.z; areg[q * 4 + 3] = v.w;
        }
        #pragma unroll
        for (int c = 0; c < 4; c++)
            CP_ASYNC16(b_sts + W_OFF_BH + c * 16, (const void*)(bhptr + c * 8));
        CP_COMMIT();
        uint4 H, L;
        split8h(areg, H, L);       STS128(a_sts + W_OFF_AH, H);      STS128(a_sts + W_OFF_AL, L);
        split8h(areg + 8, H, L);   STS128(a_sts + W_OFF_AH + 16, H); STS128(a_sts + W_OFF_AL + 16, L);
        CP_WAIT0();
        __syncthreads();
    }

    for (int kt = 0; kt < nk; kt++) {
        int cur = kt & 1;
        uint32_t bcur = sb + cur * WST_SZ;
        uint32_t bnxt_off = (uint32_t)((cur ^ 1) * WST_SZ);
        bool more = (kt + 1) < nk;

        if (more) {
            const float* ap = aptr + (kt + 1) * 32;
            #pragma unroll
            for (int q = 0; q < 4; q++) {
                float4 v = avalid ? *(const float4*)(ap + q * 4) : make_float4(0.f, 0.f, 0.f, 0.f);
                areg[q * 4 + 0] = v.x; areg[q * 4 + 1] = v.y; areg[q * 4 + 2] = v.z; areg[q * 4 + 3] = v.w;
            }
            const __half* bh = bhptr + (kt + 1) * 32;
            #pragma unroll
            for (int c = 0; c < 4; c++)
                CP_ASYNC16(b_sts + bnxt_off + W_OFF_BH + c * 16, (const void*)(bh + c * 8));
            CP_COMMIT();
        }

        #pragma unroll
        for (int ks = 0; ks < 2; ks++) {
            uint32_t koff = ks * 32;
            uint32_t ah[4][4], al[4][4], bh[8][2];
            #pragma unroll
            for (int mi = 0; mi < 4; mi++)
                LDMX4(ah[mi][0], ah[mi][1], ah[mi][2], ah[mi][3],
                      bcur + W_OFF_AH + a_lm + mi * (16 * ROWB) + koff);
            #pragma unroll
            for (int mi = 0; mi < 4; mi++)
                LDMX4(al[mi][0], al[mi][1], al[mi][2], al[mi][3],
                      bcur + W_OFF_AL + a_lm + mi * (16 * ROWB) + koff);
            #pragma unroll
            for (int bg = 0; bg < 4; bg++)
                LDMX4(bh[bg * 2][0], bh[bg * 2][1], bh[bg * 2 + 1][0], bh[bg * 2 + 1][1],
                      bcur + W_OFF_BH + b_lm + bg * (16 * ROWB) + koff);

            #pragma unroll
            for (int mi = 0; mi < 4; mi++)
                #pragma unroll
                for (int ni = 0; ni < 8; ni++)
                    MMA16816(acc[mi][ni], ah[mi], bh[ni]);
            #pragma unroll
            for (int mi = 0; mi < 4; mi++)
                #pragma unroll
                for (int ni = 0; ni < 8; ni++)
                    MMA16816(acc[mi][ni], al[mi], bh[ni]);
        }

        if (more) {
            uint4 H, L;
            split8h(areg, H, L);
            STS128(a_sts + bnxt_off + W_OFF_AH, H);      STS128(a_sts + bnxt_off + W_OFF_AL, L);
            split8h(areg + 8, H, L);
            STS128(a_sts + bnxt_off + W_OFF_AH + 16, H); STS128(a_sts + bnxt_off + W_OFF_AL + 16, L);
            CP_WAIT0();
        }
        __syncthreads();
    }

    int g = lane >> 2, t4 = lane & 3;
    #pragma unroll
    for (int mi = 0; mi < 4; mi++) {
        int r0 = mrow0 + warp_m + mi * 16 + g;
        #pragma unroll
        for (int ni = 0; ni < 8; ni++) {
            int col = ncol0 + warp_n + ni * 8 + t4 * 2;
            if (r0 < M)
                *(float2*)(C + (size_t)r0 * N + col) = make_float2(acc[mi][ni][0], acc[mi][ni][1]);
            if (r0 + 8 < M)
                *(float2*)(C + (size_t)(r0 + 8) * N + col) = make_float2(acc[mi][ni][2], acc[mi][ni][3]);
        }
    }
}

// ================= GEMM: block 128x128, 8 warps (2x4), warp tile 64x32 =================
#define ST_SZ  30720
#define OFF_AH 0
#define OFF_AL 10240
#define OFF_BH 20480
#define GEMM_SMEM (2 * ST_SZ)

__global__ __launch_bounds__(256, 1) void gemm_mma(
    const float* __restrict__ A,
    const __half* __restrict__ Bth,
    float* __restrict__ C, int M, int N, int K)
{
    extern __shared__ char smem[];
    uint32_t sb = smem_u32(smem);
    int tid = threadIdx.x;
    int lane = tid & 31, wid = tid >> 5;
    int warp_m = (wid & 1) * 64;
    int warp_n = (wid >> 1) * 32;
    int mrow0 = blockIdx.y * 128;
    int ncol0 = blockIdx.x * 128;
    int nk = K >> 5;

    int arow = tid >> 1;
    int aseg = (tid & 1) << 4;
    int agrow = mrow0 + arow;
    bool avalid = agrow < M;
    const float* aptr = A + (size_t)agrow * K + aseg;
    uint32_t a_sts = sb + arow * ROWB + aseg * 2;

    int brow = tid >> 1;
    int bcc  = (tid & 1) * 2;
    const __half* bhptr = Bth + (size_t)(ncol0 + brow) * K + bcc * 8;
    uint32_t b_sts = sb + brow * ROWB + bcc * 16;

    int ra = warp_m + (lane & 7) + (lane & 8);
    int ca = ((lane >> 4) << 3);
    uint32_t a_lm = (uint32_t)(ra * ROWB + ca * 2);
    int rb = warp_n + (lane & 7) + ((lane >> 4) << 3);
    int cb = (((lane >> 3) & 1) << 3);
    uint32_t b_lm = (uint32_t)(rb * ROWB + cb * 2);

    float acc[4][4][4];
    #pragma unroll
    for (int mi = 0; mi < 4; mi++)
        #pragma unroll
        for (int ni = 0; ni < 4; ni++)
            #pragma unroll
            for (int q = 0; q < 4; q++) acc[mi][ni][q] = 0.f;

    float areg[16];

    {
        #pragma unroll
        for (int q = 0; q < 4; q++) {
            float4 v = avalid ? *(const float4*)(aptr + q * 4) : make_float4(0.f, 0.f, 0.f, 0.f);
            areg[q * 4 + 0] = v.x; areg[q * 4 + 1] = v.y; areg[q * 4 + 2] = v.z; areg[q * 4 + 3] = v.w;
        }
        CP_ASYNC16(b_sts + OFF_BH, (const void*)bhptr);
        CP_ASYNC16(b_sts + OFF_BH + 16, (const void*)(bhptr + 8));
        CP_COMMIT();
        uint4 H, L;
        split8h(areg, H, L);       STS128(a_sts + OFF_AH, H);      STS128(a_sts + OFF_AL, L);
        split8h(areg + 8, H, L);   STS128(a_sts + OFF_AH + 16, H); STS128(a_sts + OFF_AL + 16, L);
        CP_WAIT0();
        __syncthreads();
    }

    for (int kt = 0; kt < nk; kt++) {
        int cur = kt & 1;
        uint32_t bcur = sb + cur * ST_SZ;
        uint32_t bnxt_off = (uint32_t)((cur ^ 1) * ST_SZ);
        bool more = (kt + 1) < nk;

        if (more) {
            const float* ap = aptr + (kt + 1) * 32;
            #pragma unroll
            for (int q = 0; q < 4; q++) {
                float4 v = avalid ? *(const float4*)(ap + q * 4) : make_float4(0.f, 0.f, 0.f, 0.f);
                areg[q * 4 + 0] = v.x; areg[q * 4 + 1] = v.y; areg[q * 4 + 2] = v.z; areg[q * 4 + 3] = v.w;
            }
            const __half* bh = bhptr + (kt + 1) * 32;
            CP_ASYNC16(b_sts + bnxt_off + OFF_BH, (const void*)bh);
            CP_ASYNC16(b_sts + bnxt_off + OFF_BH + 16, (const void*)(bh + 8));
            CP_COMMIT();
        }

        #pragma unroll
        for (int ks = 0; ks < 2; ks++) {
            uint32_t koff = ks * 32;
            uint32_t ah[4][4], al[4][4], bh[4][2];
            #pragma unroll
            for (int mi = 0; mi < 4; mi++)
                LDMX4(ah[mi][0], ah[mi][1], ah[mi][2], ah[mi][3],
                      bcur + OFF_AH + a_lm + mi * (16 * ROWB) + koff);
            #pragma unroll
            for (int mi = 0; mi < 4; mi++)
                LDMX4(al[mi][0], al[mi][1], al[mi][2], al[mi][3],
                      bcur + OFF_AL + a_lm + mi * (16 * ROWB) + koff);
            #pragma unroll
            for (int bg = 0; bg < 2; bg++)
                LDMX4(bh[bg * 2][0], bh[bg * 2][1], bh[bg * 2 + 1][0], bh[bg * 2 + 1][1],
                      bcur + OFF_BH + b_lm + bg * (16 * ROWB) + koff);
            #pragma unroll
            for (int mi = 0; mi < 4; mi++)
                #pragma unroll
                for (int ni = 0; ni < 4; ni++)
                    MMA16816(acc[mi][ni], ah[mi], bh[ni]);
            #pragma unroll
            for (int mi = 0; mi < 4; mi++)
                #pragma unroll
                for (int ni = 0; ni < 4; ni++)
                    MMA16816(acc[mi][ni], al[mi], bh[ni]);
        }

        if (more) {
            uint4 H, L;
            split8h(areg, H, L);
            STS128(a_sts + bnxt_off + OFF_AH, H);      STS128(a_sts + bnxt_off + OFF_AL, L);
            split8h(areg + 8, H, L);
            STS128(a_sts + bnxt_off + OFF_AH + 16, H); STS128(a_sts + bnxt_off + OFF_AL + 16, L);
            CP_WAIT0();
        }
        __syncthreads();
    }

    int g = lane >> 2, t4 = lane & 3;
    #pragma unroll
    for (int mi = 0; mi < 4; mi++) {
        int r0 = mrow0 + warp_m + mi * 16 + g;
        #pragma unroll
        for (int ni = 0; ni < 4; ni++) {
            int col = ncol0 + warp_n + ni * 8 + t4 * 2;
            if (r0 < M)
                *(float2*)(C + (size_t)r0 * N + col) = make_float2(acc[mi][ni][0], acc[mi][ni][1]);
            if (r0 + 8 < M)
                *(float2*)(C + (size_t)(r0 + 8) * N + col) = make_float2(acc[mi][ni][2], acc[mi][ni][3]);
        }
    }
}

// ---------------- zero accumulators + degree buffers ----------------
__global__ void zero_scratch() {
    size_t t = (size_t)blockIdx.x * blockDim.x + threadIdx.x;
    size_t stride = (size_t)gridDim.x * blockDim.x;
    float4 z = make_float4(0.f, 0.f, 0.f, 0.f);
    for (size_t i = t; i < (size_t)N_SENT * D_H / 4; i += stride) ((float4*)g_acc_s1)[i] = z;
    for (size_t i = t; i < (size_t)N_DOC  * D_H / 4; i += stride) ((float4*)g_acc_d1)[i] = z;
    for (size_t i = t; i < (size_t)N_SENT * D_O / 4; i += stride) ((float4*)g_acc_s2)[i] = z;
    for (size_t i = t; i < (size_t)N_DOC  * D_O / 4; i += stride) ((float4*)g_acc_d2)[i] = z;
    for (size_t i = t; i < N_SENT / 4; i += stride) ((float4*)g_inv_ss)[i] = z;
    for (size_t i = t; i < N_SENT / 4; i += stride) ((float4*)g_inv_ds)[i] = z;
    for (size_t i = t; i < N_DOC  / 4; i += stride) ((float4*)g_inv_sd)[i] = z;
}

// ---------------- degree count + invert ----------------
__global__ void count_deg(const int* __restrict__ dst, int E, float* __restrict__ deg) {
    int i = blockIdx.x * blockDim.x + threadIdx.x;
    if (i < E) atomicAdd(&deg[dst[i]], 1.0f);
}
__global__ void invert_deg(float* __restrict__ deg, int n) {
    int i = blockIdx.x * blockDim.x + threadIdx.x;
    if (i < n) deg[i] = 1.0f / fmaxf(deg[i], 1.0f);
}

// ---------------- weight build: transposed fp16 ----------------
__global__ void build_w3t(const float* __restrict__ coeff, const float* __restrict__ basis,
                          const float* __restrict__ loopw,
                          __half* __restrict__ outH,
                          int K, int D, int Npad, int r0, int r1) {
    int idx = blockIdx.x * blockDim.x + threadIdx.x;
    if (idx >= Npad * K) return;
    int o = idx / K;
    int k = idx % K;
    float v = 0.f;
    if (o < 3 * D) {
        int seg = o / D, od = o % D;
        if (seg == 2) v = loopw[k * D + od];
        else {
            int r = (seg == 0) ? r0 : r1;
            v = coeff[r * 2 + 0] * basis[(size_t)k * D + od]
              + coeff[r * 2 + 1] * basis[(size_t)K * D + (size_t)k * D + od];
        }
    }
    outH[idx] = __float2half(v);
}
__global__ void build_w2t(const float* __restrict__ coeff, const float* __restrict__ basis,
                          const float* __restrict__ loopw,
                          __half* __restrict__ outH,
                          int K, int D, int Npad, int r0) {
    int idx = blockIdx.x * blockDim.x + threadIdx.x;
    if (idx >= Npad * K) return;
    int o = idx / K;
    int k = idx % K;
    float v = 0.f;
    if (o < 2 * D) {
        int seg = o / D, od = o % D;
        if (seg == 1) v = loopw[k * D + od];
        else {
            v = coeff[r0 * 2 + 0] * basis[(size_t)k * D + od]
              + coeff[r0 * 2 + 1] * basis[(size_t)K * D + (size_t)k * D + od];
        }
    }
    outH[idx] = __float2half(v);
}

// ---------------- edge scatter: acc[dst] += P[src, colOff:colOff+D] * invdeg[dst] ----------------
__device__ __forceinline__ void redAdd4(float* addr, float4 v) {
    asm volatile("red.global.add.v4.f32 [%0], {%1, %2, %3, %4};"
                 :: "l"(addr), "f"(v.x), "f"(v.y), "f"(v.z), "f"(v.w) : "memory");
}
__global__ void scatter_scaled(const int* __restrict__ src, const int* __restrict__ dst, int E,
                               const float* __restrict__ P, int ldp, int colOff,
                               float* __restrict__ acc, int lda,
                               const float* __restrict__ invdeg, int D4) {
    long long t = (long long)blockIdx.x * blockDim.x + threadIdx.x;
    int e = (int)(t / D4);
    int j = (int)(t % D4);
    if (e >= E) return;
    int s = src[e];
    int d = dst[e];
    float sc = invdeg[d];
    float4 v = *(const float4*)(P + (size_t)s * ldp + colOff + 4 * j);
    redAdd4(acc + (size_t)d * lda + 4 * j, make_float4(v.x * sc, v.y * sc, v.z * sc, v.w * sc));
}

// ---------------- layer-1 combine ----------------
__global__ void combine_relu(const float* __restrict__ acc, const float* __restrict__ P,
                             int ldp, int colOff, const float* __restrict__ bias,
                             float* __restrict__ h, int N, int D4, int D) {
    int t = blockIdx.x * blockDim.x + threadIdx.x;
    if (t >= N * D4) return;
    int i = t / D4;
    int j = t % D4;
    float4 a = *(const float4*)(acc + (size_t)i * D + 4 * j);
    float4 p = *(const float4*)(P + (size_t)i * ldp + colOff + 4 * j);
    float4 b = *(const float4*)(bias + 4 * j);
    float4 r;
    r.x = fmaxf(a.x + p.x + b.x, 0.f);
    r.y = fmaxf(a.y + p.y + b.y, 0.f);
    r.z = fmaxf(a.z + p.z + b.z, 0.f);
    r.w = fmaxf(a.w + p.w + b.w, 0.f);
    *(float4*)(h + (size_t)i * D + 4 * j) = r;
}

// ---------------- out init ----------------
__global__ void init_out(float* __restrict__ out, const float* __restrict__ b_score) {
    int g = threadIdx.x;
    if (g < NGRAPH) out[g] = b_score[0];
}

// ---------------- layer-2 combine + relu + score + per-graph reduce ----------------
__global__ void combine2_readout(const float* __restrict__ acc, const float* __restrict__ P,
                                 int ldp, int colOff, const float* __restrict__ bias,
                                 const float* __restrict__ wscore,
                                 const int* __restrict__ gid,
                                 float* __restrict__ out, int N) {
    int warp = (blockIdx.x * blockDim.x + threadIdx.x) >> 5;
    int lane = threadIdx.x & 31;
    if (warp >= N) return;
    float4 a = *(const float4*)(acc + (size_t)warp * D_O + lane * 4);
    float4 p = *(const float4*)(P + (size_t)warp * ldp + colOff + lane * 4);
    float4 b = *(const float4*)(bias + lane * 4);
    float4 w = *(const float4*)(wscore + lane * 4);
    float s = fmaxf(a.x + p.x + b.x, 0.f) * w.x
            + fmaxf(a.y + p.y + b.y, 0.f) * w.y
            + fmaxf(a.z + p.z + b.z, 0.f) * w.z
            + fmaxf(a.w + p.w + b.w, 0.f) * w.w;
    #pragma unroll
    for (int off = 16; off; off >>= 1) s += __shfl_down_sync(0xffffffffu, s, off);
    if (lane == 0) atomicAdd(&out[gid[warp]], s);
}

// ---------------- host launcher ----------------
static void* symaddr(const void* sym) {
    void* p = nullptr;
    cudaGetSymbolAddress(&p, sym);
    return p;
}

extern "C" void kernel_launch(void* const* d_in, const int* in_sizes, int n_in,
                              void* d_out, int out_size) {
    const float* x_sent  = (const float*)d_in[0];
    const float* x_doc   = (const float*)d_in[1];
    const float* coeff1  = (const float*)d_in[2];
    const float* basis1  = (const float*)d_in[3];
    const float* loop_w1 = (const float*)d_in[4];
    const float* bias1   = (const float*)d_in[5];
    const float* coeff2  = (const float*)d_in[6];
    const float* basis2  = (const float*)d_in[7];
    const float* loop_w2 = (const float*)d_in[8];
    const float* bias2   = (const float*)d_in[9];
    const float* w_score = (const float*)d_in[10];
    const float* b_score = (const float*)d_in[11];
    const int*   src_ss  = (const int*)d_in[12];
    const int*   dst_ss  = (const int*)d_in[13];
    const int*   src_sd  = (const int*)d_in[14];
    const int*   dst_sd  = (const int*)d_in[15];
    const int*   src_ds  = (const int*)d_in[16];
    const int*   dst_ds  = (const int*)d_in[17];
    const int*   gid_sent= (const int*)d_in[18];
    const int*   gid_doc = (const int*)d_in[19];
    float* out = (float*)d_out;

    __half* pB1sh = (__half*)symaddr(g_B1s_h);
    __half* pB1dh = (__half*)symaddr(g_B1d_h);
    __half* pB2sh = (__half*)symaddr(g_B2s_h);
    __half* pB2dh = (__half*)symaddr(g_B2d_h);

    float* pPs  = (float*)symaddr(g_Ps);
    float* pPd  = (float*)symaddr(g_Pd);
    float* pA1s = (float*)symaddr(g_acc_s1);
    float* pA1d = (float*)symaddr(g_acc_d1);
    float* pHs  = (float*)symaddr(g_hs);
    float* pHd  = (float*)symaddr(g_hd);
    float* pPs2 = (float*)symaddr(g_Ps2);
    float* pPd2 = (float*)symaddr(g_Pd2);
    float* pA2s = (float*)symaddr(g_acc_s2);
    float* pA2d = (float*)symaddr(g_acc_d2);
    float* pIss = (float*)symaddr(g_inv_ss);
    float* pIds = (float*)symaddr(g_inv_ds);
    float* pIsd = (float*)symaddr(g_inv_sd);

    cudaFuncSetAttribute(gemm_mma, cudaFuncAttributeMaxDynamicSharedMemorySize, GEMM_SMEM);
    cudaFuncSetAttribute(gemm_mma_wide, cudaFuncAttributeMaxDynamicSharedMemorySize, WIDE_SMEM);

    cudaStream_t st = 0;

    // Launch order: #5 (0-based) is the big layer-1 sent GEMM so ncu (-s 5 -c 1) profiles it.
    zero_scratch<<<1184, 256, 0, st>>>();                                                     // 0
    count_deg<<<(E_SS + 255) / 256, 256, 0, st>>>(dst_ss, E_SS, pIss);                        // 1
    count_deg<<<(E_DS + 255) / 256, 256, 0, st>>>(dst_ds, E_DS, pIds);                        // 2
    count_deg<<<(E_SD + 255) / 256, 256, 0, st>>>(dst_sd, E_SD, pIsd);                        // 3
    build_w3t<<<(768 * 768 + 255) / 256, 256, 0, st>>>(coeff1, basis1, loop_w1, pB1sh, D_IN, D_H, 768, 0, 2); // 4
    {                                                                                          // 5 (profiled)
        dim3 g(768 / 256, (N_SENT + 127) / 128);
        gemm_mma_wide<<<g, 256, WIDE_SMEM, st>>>(x_sent, pB1sh, pPs, N_SENT, 3 * D_H, D_IN);
    }

    invert_deg<<<(N_SENT + 255) / 256, 256, 0, st>>>(pIss, N_SENT);
    invert_deg<<<(N_SENT + 255) / 256, 256, 0, st>>>(pIds, N_SENT);
    invert_deg<<<(N_DOC + 255) / 256, 256, 0, st>>>(pIsd, N_DOC);

    build_w2t<<<(512 * 768 + 255) / 256, 256, 0, st>>>(coeff1, basis1, loop_w1, pB1dh, D_IN, D_H, 512, 1);
    build_w3t<<<(384 * 256 + 255) / 256, 256, 0, st>>>(coeff2, basis2, loop_w2, pB2sh, D_H, D_O, 384, 0, 2);
    build_w2t<<<(256 * 256 + 255) / 256, 256, 0, st>>>(coeff2, basis2, loop_w2, pB2dh, D_H, D_O, 256, 1);

    {
        dim3 g(512 / 256, (N_DOC + 127) / 128);
        gemm_mma_wide<<<g, 256, WIDE_SMEM, st>>>(x_doc, pB1dh, pPd, N_DOC, 2 * D_H, D_IN);
    }

    // layer-1 aggregation
    {
        long long T = (long long)E_SS * (D_H / 4);
        scatter_scaled<<<(unsigned)((T + 255) / 256), 256, 0, st>>>(src_ss, dst_ss, E_SS, pPs, 3 * D_H, D_H, pA1s, D_H, pIss, D_H / 4);
    }
    {
        long long T = (long long)E_DS * (D_H / 4);
        scatter_scaled<<<(unsigned)((T + 255) / 256), 256, 0, st>>>(src_ds, dst_ds, E_DS, pPd, 2 * D_H, 0, pA1s, D_H, pIds, D_H / 4);
    }
    {
        long long T = (long long)E_SD * (D_H / 4);
        scatter_scaled<<<(unsigned)((T + 255) / 256), 256, 0, st>>>(src_sd, dst_sd, E_SD, pPs, 3 * D_H, 0, pA1d, D_H, pIsd, D_H / 4);
    }

    // layer-1 combine
    combine_relu<<<(N_SENT * (D_H / 4) + 255) / 256, 256, 0, st>>>(pA1s, pPs, 3 * D_H, 2 * D_H, bias1, pHs, N_SENT, D_H / 4, D_H);
    combine_relu<<<(N_DOC * (D_H / 4) + 255) / 256, 256, 0, st>>>(pA1d, pPd, 2 * D_H, D_H, bias1, pHd, N_DOC, D_H / 4, D_H);

    // layer-2 projections
    {
        dim3 g(384 / 128, (N_SENT + 127) / 128);
        gemm_mma<<<g, 256, GEMM_SMEM, st>>>(pHs, pB2sh, pPs2, N_SENT, 3 * D_O, D_H);
    }
    {
        dim3 g(256 / 256, (N_DOC + 127) / 128);
        gemm_mma_wide<<<g, 256, WIDE_SMEM, st>>>(pHd, pB2dh, pPd2, N_DOC, 2 * D_O, D_H);
    }

    // layer-2 aggregation
    {
        long long T = (long long)E_SS * (D_O / 4);
        scatter_scaled<<<(unsigned)((T + 255) / 256), 256, 0, st>>>(src_ss, dst_ss, E_SS, pPs2, 3 * D_O, D_O, pA2s, D_O, pIss, D_O / 4);
    }
    {
        long long T = (long long)E_DS * (D_O / 4);
        scatter_scaled<<<(unsigned)((T + 255) / 256), 256, 0, st>>>(src_ds, dst_ds, E_DS, pPd2, 2 * D_O, 0, pA2s, D_O, pIds, D_O / 4);
    }
    {
        long long T = (long long)E_SD * (D_O / 4);
        scatter_scaled<<<(unsigned)((T + 255) / 256), 256, 0, st>>>(src_sd, dst_sd, E_SD, pPs2, 3 * D_O, 0, pA2d, D_O, pIsd, D_O / 4);
    }

    // readout
    init_out<<<1, 32, 0, st>>>(out, b_score);
    combine2_readout<<<(N_SENT + 7) / 8, 256, 0, st>>>(pA2s, pPs2, 3 * D_O, 2 * D_O, bias2, w_score, gid_sent, out, N_SENT);
    combine2_readout<<<(N_DOC + 7) / 8, 256, 0, st>>>(pA2d, pPd2, 2 * D_O, D_O, bias2, w_score, gid_doc, out, N_DOC);
}

// round 6
// speedup vs baseline: 2.3997x; 1.0748x over previous
#include <cuda_runtime.h>
#include <cuda_fp16.h>
#include <cstdint>
#include <cstddef>

#define N_SENT 100000
#define N_DOC  10000
#define NGRAPH 32
#define D_IN   768
#define D_H    256
#define D_O    128
#define E_SS   400000
#define E_SD   100000
#define E_DS   100000

// ---------------- scratch (device globals: allocation-free) ----------------
__device__ __half g_B1s_h[768 * 768];   // layer1 sent: N=768,K=768
__device__ __half g_B1d_h[512 * 768];   // layer1 doc:  N=512,K=768
__device__ __half g_B2s_h[384 * 256];   // layer2 sent: N=384,K=256
__device__ __half g_B2d_h[256 * 256];   // layer2 doc:  N=256,K=256

__device__ float g_Ps [(size_t)N_SENT * (3 * D_H)];
__device__ float g_Pd [(size_t)N_DOC  * (2 * D_H)];
__device__ float g_acc_s1[(size_t)N_SENT * D_H];
__device__ float g_acc_d1[(size_t)N_DOC  * D_H];
__device__ float g_hs [(size_t)N_SENT * D_H];
__device__ float g_hd [(size_t)N_DOC  * D_H];
__device__ float g_Ps2[(size_t)N_SENT * (3 * D_O)];
__device__ float g_Pd2[(size_t)N_DOC  * (2 * D_O)];
__device__ float g_acc_s2[(size_t)N_SENT * D_O];
__device__ float g_acc_d2[(size_t)N_DOC  * D_O];
__device__ float g_inv_ss[N_SENT];
__device__ float g_inv_ds[N_SENT];
__device__ float g_inv_sd[N_DOC];

// ---------------- PTX helpers ----------------
__device__ __forceinline__ uint32_t smem_u32(const void* p) {
    uint32_t a;
    asm("{ .reg .u64 t; cvta.to.shared.u64 t, %1; cvt.u32.u64 %0, t; }" : "=r"(a) : "l"(p));
    return a;
}

#define CP_ASYNC16(saddr, gaddr) \
    asm volatile("cp.async.ca.shared.global [%0], [%1], 16;" :: "r"(saddr), "l"(gaddr) : "memory")
#define CP_COMMIT() asm volatile("cp.async.commit_group;" ::: "memory")
#define CP_WAIT0()  asm volatile("cp.async.wait_group 0;" ::: "memory")

#define LDMX4(r0, r1, r2, r3, addr) \
    asm volatile("ldmatrix.sync.aligned.m8n8.x4.shared.b16 {%0,%1,%2,%3}, [%4];" \
                 : "=r"(r0), "=r"(r1), "=r"(r2), "=r"(r3) : "r"(addr))

#define MMA16816(d, a, b) \
    asm volatile("mma.sync.aligned.m16n8k16.row.col.f32.f16.f16.f32 " \
                 "{%0,%1,%2,%3}, {%4,%5,%6,%7}, {%8,%9}, {%0,%1,%2,%3};" \
                 : "+f"((d)[0]), "+f"((d)[1]), "+f"((d)[2]), "+f"((d)[3]) \
                 : "r"((a)[0]), "r"((a)[1]), "r"((a)[2]), "r"((a)[3]), "r"((b)[0]), "r"((b)[1]))

#define STS128(addr, v) \
    asm volatile("st.shared.v4.b32 [%0], {%1, %2, %3, %4};" \
                 :: "r"((uint32_t)(addr)), "r"((v).x), "r"((v).y), "r"((v).z), "r"((v).w) : "memory")

// ---------------- fp16 split helper: a = hi + lo ----------------
__device__ __forceinline__ void split8h(const float* f, uint4& H, uint4& L) {
    uint32_t hs[8], ls[8];
    #pragma unroll
    for (int i = 0; i < 8; i++) {
        __half h = __float2half(f[i]);
        __half l = __float2half(f[i] - __half2float(h));
        hs[i] = (uint32_t)__half_as_ushort(h);
        ls[i] = (uint32_t)__half_as_ushort(l);
    }
    H = make_uint4(hs[0] | (hs[1] << 16), hs[2] | (hs[3] << 16), hs[4] | (hs[5] << 16), hs[6] | (hs[7] << 16));
    L = make_uint4(ls[0] | (ls[1] << 16), ls[2] | (ls[3] << 16), ls[4] | (ls[5] << 16), ls[6] | (ls[7] << 16));
}

#define ROWB   80

// ================= GEMM: block 128x128, 8 warps (2x4), warp tile 64x32, OCC 2 =============
// C[M,N] = A[M,K](fp32) @ Bt[N,K](fp16)^T, 2-term fp16 split: AhBh + AlBh. N % 128 == 0.
#define ST_SZ  30720                 // per stage: AH 10240 + AL 10240 + BH 10240
#define OFF_AH 0
#define OFF_AL 10240
#define OFF_BH 20480
#define GEMM_SMEM (2 * ST_SZ)

__global__ __launch_bounds__(256, 2) void gemm_mma(
    const float* __restrict__ A,
    const __half* __restrict__ Bth,
    float* __restrict__ C, int M, int N, int K)
{
    extern __shared__ char smem[];
    uint32_t sb = smem_u32(smem);
    int tid = threadIdx.x;
    int lane = tid & 31, wid = tid >> 5;
    int warp_m = (wid & 1) * 64;
    int warp_n = (wid >> 1) * 32;
    int mrow0 = blockIdx.y * 128;
    int ncol0 = blockIdx.x * 128;
    int nk = K >> 5;

    int arow = tid >> 1;
    int aseg = (tid & 1) << 4;
    int agrow = mrow0 + arow;
    bool avalid = agrow < M;
    const float* aptr = A + (size_t)agrow * K + aseg;
    uint32_t a_sts = sb + arow * ROWB + aseg * 2;

    int brow = tid >> 1;
    int bcc  = (tid & 1) * 2;
    const __half* bhptr = Bth + (size_t)(ncol0 + brow) * K + bcc * 8;
    uint32_t b_sts = sb + brow * ROWB + bcc * 16;

    int ra = warp_m + (lane & 7) + (lane & 8);
    int ca = ((lane >> 4) << 3);
    uint32_t a_lm = (uint32_t)(ra * ROWB + ca * 2);
    int rb = warp_n + (lane & 7) + ((lane >> 4) << 3);
    int cb = (((lane >> 3) & 1) << 3);
    uint32_t b_lm = (uint32_t)(rb * ROWB + cb * 2);

    float acc[4][4][4];
    #pragma unroll
    for (int mi = 0; mi < 4; mi++)
        #pragma unroll
        for (int ni = 0; ni < 4; ni++)
            #pragma unroll
            for (int q = 0; q < 4; q++) acc[mi][ni][q] = 0.f;

    float areg[16];

    {
        #pragma unroll
        for (int q = 0; q < 4; q++) {
            float4 v = avalid ? *(const float4*)(aptr + q * 4) : make_float4(0.f, 0.f, 0.f, 0.f);
            areg[q * 4 + 0] = v.x; areg[q * 4 + 1] = v.y; areg[q * 4 + 2] = v.z; areg[q * 4 + 3] = v.w;
        }
        CP_ASYNC16(b_sts + OFF_BH, (const void*)bhptr);
        CP_ASYNC16(b_sts + OFF_BH + 16, (const void*)(bhptr + 8));
        CP_COMMIT();
        uint4 H, L;
        split8h(areg, H, L);       STS128(a_sts + OFF_AH, H);      STS128(a_sts + OFF_AL, L);
        split8h(areg + 8, H, L);   STS128(a_sts + OFF_AH + 16, H); STS128(a_sts + OFF_AL + 16, L);
        CP_WAIT0();
        __syncthreads();
    }

    for (int kt = 0; kt < nk; kt++) {
        int cur = kt & 1;
        uint32_t bcur = sb + cur * ST_SZ;
        uint32_t bnxt_off = (uint32_t)((cur ^ 1) * ST_SZ);
        bool more = (kt + 1) < nk;

        if (more) {
            const float* ap = aptr + (kt + 1) * 32;
            #pragma unroll
            for (int q = 0; q < 4; q++) {
                float4 v = avalid ? *(const float4*)(ap + q * 4) : make_float4(0.f, 0.f, 0.f, 0.f);
                areg[q * 4 + 0] = v.x; areg[q * 4 + 1] = v.y; areg[q * 4 + 2] = v.z; areg[q * 4 + 3] = v.w;
            }
            const __half* bh = bhptr + (kt + 1) * 32;
            CP_ASYNC16(b_sts + bnxt_off + OFF_BH, (const void*)bh);
            CP_ASYNC16(b_sts + bnxt_off + OFF_BH + 16, (const void*)(bh + 8));
            CP_COMMIT();
        }

        #pragma unroll
        for (int ks = 0; ks < 2; ks++) {
            uint32_t koff = ks * 32;
            uint32_t ah[4][4], al[4][4], bh[4][2];
            #pragma unroll
            for (int mi = 0; mi < 4; mi++)
                LDMX4(ah[mi][0], ah[mi][1], ah[mi][2], ah[mi][3],
                      bcur + OFF_AH + a_lm + mi * (16 * ROWB) + koff);
            #pragma unroll
            for (int mi = 0; mi < 4; mi++)
                LDMX4(al[mi][0], al[mi][1], al[mi][2], al[mi][3],
                      bcur + OFF_AL + a_lm + mi * (16 * ROWB) + koff);
            #pragma unroll
            for (int bg = 0; bg < 2; bg++)
                LDMX4(bh[bg * 2][0], bh[bg * 2][1], bh[bg * 2 + 1][0], bh[bg * 2 + 1][1],
                      bcur + OFF_BH + b_lm + bg * (16 * ROWB) + koff);
            #pragma unroll
            for (int mi = 0; mi < 4; mi++)
                #pragma unroll
                for (int ni = 0; ni < 4; ni++)
                    MMA16816(acc[mi][ni], ah[mi], bh[ni]);
            #pragma unroll
            for (int mi = 0; mi < 4; mi++)
                #pragma unroll
                for (int ni = 0; ni < 4; ni++)
                    MMA16816(acc[mi][ni], al[mi], bh[ni]);
        }

        if (more) {
            uint4 H, L;
            split8h(areg, H, L);
            STS128(a_sts + bnxt_off + OFF_AH, H);      STS128(a_sts + bnxt_off + OFF_AL, L);
            split8h(areg + 8, H, L);
            STS128(a_sts + bnxt_off + OFF_AH + 16, H); STS128(a_sts + bnxt_off + OFF_AL + 16, L);
            CP_WAIT0();
        }
        __syncthreads();
    }

    int g = lane >> 2, t4 = lane & 3;
    #pragma unroll
    for (int mi = 0; mi < 4; mi++) {
        int r0 = mrow0 + warp_m + mi * 16 + g;
        #pragma unroll
        for (int ni = 0; ni < 4; ni++) {
            int col = ncol0 + warp_n + ni * 8 + t4 * 2;
            if (r0 < M)
                *(float2*)(C + (size_t)r0 * N + col) = make_float2(acc[mi][ni][0], acc[mi][ni][1]);
            if (r0 + 8 < M)
                *(float2*)(C + (size_t)(r0 + 8) * N + col) = make_float2(acc[mi][ni][2], acc[mi][ni][3]);
        }
    }
}

// ---------------- zero accumulators + degree buffers ----------------
__global__ void zero_scratch() {
    size_t t = (size_t)blockIdx.x * blockDim.x + threadIdx.x;
    size_t stride = (size_t)gridDim.x * blockDim.x;
    float4 z = make_float4(0.f, 0.f, 0.f, 0.f);
    for (size_t i = t; i < (size_t)N_SENT * D_H / 4; i += stride) ((float4*)g_acc_s1)[i] = z;
    for (size_t i = t; i < (size_t)N_DOC  * D_H / 4; i += stride) ((float4*)g_acc_d1)[i] = z;
    for (size_t i = t; i < (size_t)N_SENT * D_O / 4; i += stride) ((float4*)g_acc_s2)[i] = z;
    for (size_t i = t; i < (size_t)N_DOC  * D_O / 4; i += stride) ((float4*)g_acc_d2)[i] = z;
    for (size_t i = t; i < N_SENT / 4; i += stride) ((float4*)g_inv_ss)[i] = z;
    for (size_t i = t; i < N_SENT / 4; i += stride) ((float4*)g_inv_ds)[i] = z;
    for (size_t i = t; i < N_DOC  / 4; i += stride) ((float4*)g_inv_sd)[i] = z;
}

// ---------------- degree count + invert ----------------
__global__ void count_deg(const int* __restrict__ dst, int E, float* __restrict__ deg) {
    int i = blockIdx.x * blockDim.x + threadIdx.x;
    if (i < E) atomicAdd(&deg[dst[i]], 1.0f);
}
__global__ void invert_deg(float* __restrict__ deg, int n) {
    int i = blockIdx.x * blockDim.x + threadIdx.x;
    if (i < n) deg[i] = 1.0f / fmaxf(deg[i], 1.0f);
}

// ---------------- weight build: transposed fp16 ----------------
__global__ void build_w3t(const float* __restrict__ coeff, const float* __restrict__ basis,
                          const float* __restrict__ loopw,
                          __half* __restrict__ outH,
                          int K, int D, int Npad, int r0, int r1) {
    int idx = blockIdx.x * blockDim.x + threadIdx.x;
    if (idx >= Npad * K) return;
    int o = idx / K;
    int k = idx % K;
    float v = 0.f;
    if (o < 3 * D) {
        int seg = o / D, od = o % D;
        if (seg == 2) v = loopw[k * D + od];
        else {
            int r = (seg == 0) ? r0 : r1;
            v = coeff[r * 2 + 0] * basis[(size_t)k * D + od]
              + coeff[r * 2 + 1] * basis[(size_t)K * D + (size_t)k * D + od];
        }
    }
    outH[idx] = __float2half(v);
}
__global__ void build_w2t(const float* __restrict__ coeff, const float* __restrict__ basis,
                          const float* __restrict__ loopw,
                          __half* __restrict__ outH,
                          int K, int D, int Npad, int r0) {
    int idx = blockIdx.x * blockDim.x + threadIdx.x;
    if (idx >= Npad * K) return;
    int o = idx / K;
    int k = idx % K;
    float v = 0.f;
    if (o < 2 * D) {
        int seg = o / D, od = o % D;
        if (seg == 1) v = loopw[k * D + od];
        else {
            v = coeff[r0 * 2 + 0] * basis[(size_t)k * D + od]
              + coeff[r0 * 2 + 1] * basis[(size_t)K * D + (size_t)k * D + od];
        }
    }
    outH[idx] = __float2half(v);
}

// ---------------- edge scatter ----------------
__device__ __forceinline__ void redAdd4(float* addr, float4 v) {
    asm volatile("red.global.add.v4.f32 [%0], {%1, %2, %3, %4};"
                 :: "l"(addr), "f"(v.x), "f"(v.y), "f"(v.z), "f"(v.w) : "memory");
}
__global__ void scatter_scaled(const int* __restrict__ src, const int* __restrict__ dst, int E,
                               const float* __restrict__ P, int ldp, int colOff,
                               float* __restrict__ acc, int lda,
                               const float* __restrict__ invdeg, int D4) {
    long long t = (long long)blockIdx.x * blockDim.x + threadIdx.x;
    int e = (int)(t / D4);
    int j = (int)(t % D4);
    if (e >= E) return;
    int s = src[e];
    int d = dst[e];
    float sc = invdeg[d];
    float4 v = *(const float4*)(P + (size_t)s * ldp + colOff + 4 * j);
    redAdd4(acc + (size_t)d * lda + 4 * j, make_float4(v.x * sc, v.y * sc, v.z * sc, v.w * sc));
}

// ---------------- layer-1 combine ----------------
__global__ void combine_relu(const float* __restrict__ acc, const float* __restrict__ P,
                             int ldp, int colOff, const float* __restrict__ bias,
                             float* __restrict__ h, int N, int D4, int D) {
    int t = blockIdx.x * blockDim.x + threadIdx.x;
    if (t >= N * D4) return;
    int i = t / D4;
    int j = t % D4;
    float4 a = *(const float4*)(acc + (size_t)i * D + 4 * j);
    float4 p = *(const float4*)(P + (size_t)i * ldp + colOff + 4 * j);
    float4 b = *(const float4*)(bias + 4 * j);
    float4 r;
    r.x = fmaxf(a.x + p.x + b.x, 0.f);
    r.y = fmaxf(a.y + p.y + b.y, 0.f);
    r.z = fmaxf(a.z + p.z + b.z, 0.f);
    r.w = fmaxf(a.w + p.w + b.w, 0.f);
    *(float4*)(h + (size_t)i * D + 4 * j) = r;
}

// ---------------- out init ----------------
__global__ void init_out(float* __restrict__ out, const float* __restrict__ b_score) {
    int g = threadIdx.x;
    if (g < NGRAPH) out[g] = b_score[0];
}

// ---------------- layer-2 combine + relu + score + per-graph reduce ----------------
__global__ void combine2_readout(const float* __restrict__ acc, const float* __restrict__ P,
                                 int ldp, int colOff, const float* __restrict__ bias,
                                 const float* __restrict__ wscore,
                                 const int* __restrict__ gid,
                                 float* __restrict__ out, int N) {
    int warp = (blockIdx.x * blockDim.x + threadIdx.x) >> 5;
    int lane = threadIdx.x & 31;
    if (warp >= N) return;
    float4 a = *(const float4*)(acc + (size_t)warp * D_O + lane * 4);
    float4 p = *(const float4*)(P + (size_t)warp * ldp + colOff + lane * 4);
    float4 b = *(const float4*)(bias + lane * 4);
    float4 w = *(const float4*)(wscore + lane * 4);
    float s = fmaxf(a.x + p.x + b.x, 0.f) * w.x
            + fmaxf(a.y + p.y + b.y, 0.f) * w.y
            + fmaxf(a.z + p.z + b.z, 0.f) * w.z
            + fmaxf(a.w + p.w + b.w, 0.f) * w.w;
    #pragma unroll
    for (int off = 16; off; off >>= 1) s += __shfl_down_sync(0xffffffffu, s, off);
    if (lane == 0) atomicAdd(&out[gid[warp]], s);
}

// ---------------- host launcher ----------------
static void* symaddr(const void* sym) {
    void* p = nullptr;
    cudaGetSymbolAddress(&p, sym);
    return p;
}

extern "C" void kernel_launch(void* const* d_in, const int* in_sizes, int n_in,
                              void* d_out, int out_size) {
    const float* x_sent  = (const float*)d_in[0];
    const float* x_doc   = (const float*)d_in[1];
    const float* coeff1  = (const float*)d_in[2];
    const float* basis1  = (const float*)d_in[3];
    const float* loop_w1 = (const float*)d_in[4];
    const float* bias1   = (const float*)d_in[5];
    const float* coeff2  = (const float*)d_in[6];
    const float* basis2  = (const float*)d_in[7];
    const float* loop_w2 = (const float*)d_in[8];
    const float* bias2   = (const float*)d_in[9];
    const float* w_score = (const float*)d_in[10];
    const float* b_score = (const float*)d_in[11];
    const int*   src_ss  = (const int*)d_in[12];
    const int*   dst_ss  = (const int*)d_in[13];
    const int*   src_sd  = (const int*)d_in[14];
    const int*   dst_sd  = (const int*)d_in[15];
    const int*   src_ds  = (const int*)d_in[16];
    const int*   dst_ds  = (const int*)d_in[17];
    const int*   gid_sent= (const int*)d_in[18];
    const int*   gid_doc = (const int*)d_in[19];
    float* out = (float*)d_out;

    __half* pB1sh = (__half*)symaddr(g_B1s_h);
    __half* pB1dh = (__half*)symaddr(g_B1d_h);
    __half* pB2sh = (__half*)symaddr(g_B2s_h);
    __half* pB2dh = (__half*)symaddr(g_B2d_h);

    float* pPs  = (float*)symaddr(g_Ps);
    float* pPd  = (float*)symaddr(g_Pd);
    float* pA1s = (float*)symaddr(g_acc_s1);
    float* pA1d = (float*)symaddr(g_acc_d1);
    float* pHs  = (float*)symaddr(g_hs);
    float* pHd  = (float*)symaddr(g_hd);
    float* pPs2 = (float*)symaddr(g_Ps2);
    float* pPd2 = (float*)symaddr(g_Pd2);
    float* pA2s = (float*)symaddr(g_acc_s2);
    float* pA2d = (float*)symaddr(g_acc_d2);
    float* pIss = (float*)symaddr(g_inv_ss);
    float* pIds = (float*)symaddr(g_inv_ds);
    float* pIsd = (float*)symaddr(g_inv_sd);

    cudaFuncSetAttribute(gemm_mma, cudaFuncAttributeMaxDynamicSharedMemorySize, GEMM_SMEM);

    cudaStream_t st = 0;

    // Harness issues 2 launches before ours; global #5 = my index 3 → big GEMM profiled.
    zero_scratch<<<1184, 256, 0, st>>>();                                                     // idx 0
    count_deg<<<(E_SS + 255) / 256, 256, 0, st>>>(dst_ss, E_SS, pIss);                        // idx 1
    build_w3t<<<(768 * 768 + 255) / 256, 256, 0, st>>>(coeff1, basis1, loop_w1, pB1sh, D_IN, D_H, 768, 0, 2); // idx 2
    {                                                                                          // idx 3 (ncu -s 5)
        dim3 g(768 / 128, (N_SENT + 127) / 128);
        gemm_mma<<<g, 256, GEMM_SMEM, st>>>(x_sent, pB1sh, pPs, N_SENT, 3 * D_H, D_IN);
    }

    count_deg<<<(E_DS + 255) / 256, 256, 0, st>>>(dst_ds, E_DS, pIds);
    count_deg<<<(E_SD + 255) / 256, 256, 0, st>>>(dst_sd, E_SD, pIsd);
    invert_deg<<<(N_SENT + 255) / 256, 256, 0, st>>>(pIss, N_SENT);
    invert_deg<<<(N_SENT + 255) / 256, 256, 0, st>>>(pIds, N_SENT);
    invert_deg<<<(N_DOC + 255) / 256, 256, 0, st>>>(pIsd, N_DOC);

    build_w2t<<<(512 * 768 + 255) / 256, 256, 0, st>>>(coeff1, basis1, loop_w1, pB1dh, D_IN, D_H, 512, 1);
    build_w3t<<<(384 * 256 + 255) / 256, 256, 0, st>>>(coeff2, basis2, loop_w2, pB2sh, D_H, D_O, 384, 0, 2);
    build_w2t<<<(256 * 256 + 255) / 256, 256, 0, st>>>(coeff2, basis2, loop_w2, pB2dh, D_H, D_O, 256, 1);

    {
        dim3 g(512 / 128, (N_DOC + 127) / 128);
        gemm_mma<<<g, 256, GEMM_SMEM, st>>>(x_doc, pB1dh, pPd, N_DOC, 2 * D_H, D_IN);
    }

    // layer-1 aggregation
    {
        long long T = (long long)E_SS * (D_H / 4);
        scatter_scaled<<<(unsigned)((T + 255) / 256), 256, 0, st>>>(src_ss, dst_ss, E_SS, pPs, 3 * D_H, D_H, pA1s, D_H, pIss, D_H / 4);
    }
    {
        long long T = (long long)E_DS * (D_H / 4);
        scatter_scaled<<<(unsigned)((T + 255) / 256), 256, 0, st>>>(src_ds, dst_ds, E_DS, pPd, 2 * D_H, 0, pA1s, D_H, pIds, D_H / 4);
    }
    {
        long long T = (long long)E_SD * (D_H / 4);
        scatter_scaled<<<(unsigned)((T + 255) / 256), 256, 0, st>>>(src_sd, dst_sd, E_SD, pPs, 3 * D_H, 0, pA1d, D_H, pIsd, D_H / 4);
    }

    // layer-1 combine
    combine_relu<<<(N_SENT * (D_H / 4) + 255) / 256, 256, 0, st>>>(pA1s, pPs, 3 * D_H, 2 * D_H, bias1, pHs, N_SENT, D_H / 4, D_H);
    combine_relu<<<(N_DOC * (D_H / 4) + 255) / 256, 256, 0, st>>>(pA1d, pPd, 2 * D_H, D_H, bias1, pHd, N_DOC, D_H / 4, D_H);

    // layer-2 projections
    {
        dim3 g(384 / 128, (N_SENT + 127) / 128);
        gemm_mma<<<g, 256, GEMM_SMEM, st>>>(pHs, pB2sh, pPs2, N_SENT, 3 * D_O, D_H);
    }
    {
        dim3 g(256 / 128, (N_DOC + 127) / 128);
        gemm_mma<<<g, 256, GEMM_SMEM, st>>>(pHd, pB2dh, pPd2, N_DOC, 2 * D_O, D_H);
    }

    // layer-2 aggregation
    {
        long long T = (long long)E_SS * (D_O / 4);
        scatter_scaled<<<(unsigned)((T + 255) / 256), 256, 0, st>>>(src_ss, dst_ss, E_SS, pPs2, 3 * D_O, D_O, pA2s, D_O, pIss, D_O / 4);
    }
    {
        long long T = (long long)E_DS * (D_O / 4);
        scatter_scaled<<<(unsigned)((T + 255) / 256), 256, 0, st>>>(src_ds, dst_ds, E_DS, pPd2, 2 * D_O, 0, pA2s, D_O, pIds, D_O / 4);
    }
    {
        long long T = (long long)E_SD * (D_O / 4);
        scatter_scaled<<<(unsigned)((T + 255) / 256), 256, 0, st>>>(src_sd, dst_sd, E_SD, pPs2, 3 * D_O, 0, pA2d, D_O, pIsd, D_O / 4);
    }

    // readout
    init_out<<<1, 32, 0, st>>>(out, b_score);
    combine2_readout<<<(N_SENT + 7) / 8, 256, 0, st>>>(pA2s, pPs2, 3 * D_O, 2 * D_O, bias2, w_score, gid_sent, out, N_SENT);
    combine2_readout<<<(N_DOC + 7) / 8, 256, 0, st>>>(pA2d, pPd2, 2 * D_O, D_O, bias2, w_score, gid_doc, out, N_DOC);
}

// round 7
// speedup vs baseline: 2.4472x; 1.0198x over previous
#include <cuda_runtime.h>
#include <cuda_fp16.h>
#include <cstdint>
#include <cstddef>

#define N_SENT 100000
#define N_DOC  10000
#define SENT_PAD 100096
#define DOC_PAD  10112
#define NGRAPH 32
#define D_IN   768
#define D_H    256
#define D_O    128
#define E_SS   400000
#define E_SD   100000
#define E_DS   100000

// ---------------- scratch (device globals: allocation-free) ----------------
__device__ __align__(16) __half g_B1s_h[768 * 768];
__device__ __align__(16) __half g_B1d_h[512 * 768];
__device__ __align__(16) __half g_B2s_h[384 * 256];
__device__ __align__(16) __half g_B2d_h[256 * 256];

// split fp16 activations (padded rows, zero-filled)
__device__ __align__(16) __half g_xs_h[(size_t)SENT_PAD * D_IN];
__device__ __align__(16) __half g_xs_l[(size_t)SENT_PAD * D_IN];
__device__ __align__(16) __half g_xd_h[(size_t)DOC_PAD * D_IN];
__device__ __align__(16) __half g_xd_l[(size_t)DOC_PAD * D_IN];
__device__ __align__(16) __half g_hs_h[(size_t)SENT_PAD * D_H];
__device__ __align__(16) __half g_hs_l[(size_t)SENT_PAD * D_H];
__device__ __align__(16) __half g_hd_h[(size_t)DOC_PAD * D_H];
__device__ __align__(16) __half g_hd_l[(size_t)DOC_PAD * D_H];

__device__ float g_Ps [(size_t)N_SENT * (3 * D_H)];
__device__ float g_Pd [(size_t)N_DOC  * (2 * D_H)];
__device__ float g_acc_s1[(size_t)N_SENT * D_H];
__device__ float g_acc_d1[(size_t)N_DOC  * D_H];
__device__ float g_Ps2[(size_t)N_SENT * (3 * D_O)];
__device__ float g_Pd2[(size_t)N_DOC  * (2 * D_O)];
__device__ float g_acc_s2[(size_t)N_SENT * D_O];
__device__ float g_acc_d2[(size_t)N_DOC  * D_O];
__device__ float g_inv_ss[N_SENT];
__device__ float g_inv_ds[N_SENT];
__device__ float g_inv_sd[N_DOC];

// ---------------- PTX helpers ----------------
__device__ __forceinline__ uint32_t smem_u32(const void* p) {
    uint32_t a;
    asm("{ .reg .u64 t; cvta.to.shared.u64 t, %1; cvt.u32.u64 %0, t; }" : "=r"(a) : "l"(p));
    return a;
}

#define CP_ASYNC16(saddr, gaddr) \
    asm volatile("cp.async.cg.shared.global [%0], [%1], 16;" :: "r"(saddr), "l"(gaddr) : "memory")
#define CP_COMMIT() asm volatile("cp.async.commit_group;" ::: "memory")
#define CP_WAIT1()  asm volatile("cp.async.wait_group 1;" ::: "memory")

#define LDMX4(r0, r1, r2, r3, addr) \
    asm volatile("ldmatrix.sync.aligned.m8n8.x4.shared.b16 {%0,%1,%2,%3}, [%4];" \
                 : "=r"(r0), "=r"(r1), "=r"(r2), "=r"(r3) : "r"(addr))

#define MMA16816(d, a, b) \
    asm volatile("mma.sync.aligned.m16n8k16.row.col.f32.f16.f16.f32 " \
                 "{%0,%1,%2,%3}, {%4,%5,%6,%7}, {%8,%9}, {%0,%1,%2,%3};" \
                 : "+f"((d)[0]), "+f"((d)[1]), "+f"((d)[2]), "+f"((d)[3]) \
                 : "r"((a)[0]), "r"((a)[1]), "r"((a)[2]), "r"((a)[3]), "r"((b)[0]), "r"((b)[1]))

// ---------------- fp16 split helper: a = hi + lo ----------------
__device__ __forceinline__ void split8h(const float* f, uint4& H, uint4& L) {
    uint32_t hs[8], ls[8];
    #pragma unroll
    for (int i = 0; i < 8; i++) {
        __half h = __float2half(f[i]);
        __half l = __float2half(f[i] - __half2float(h));
        hs[i] = (uint32_t)__half_as_ushort(h);
        ls[i] = (uint32_t)__half_as_ushort(l);
    }
    H = make_uint4(hs[0] | (hs[1] << 16), hs[2] | (hs[3] << 16), hs[4] | (hs[5] << 16), hs[6] | (hs[7] << 16));
    L = make_uint4(ls[0] | (ls[1] << 16), ls[2] | (ls[3] << 16), ls[4] | (ls[5] << 16), ls[6] | (ls[7] << 16));
}

#define ROWB   80

// ================= GEMM v2: all-cp.async, 3-stage, block 128x128, warps 4m x 2n =========
// C[M,N] = (Ah+Al)[Mpad,K](fp16) @ Bt[N,K](fp16)^T, fp32 accum. N % 128 == 0.
#define ST_SZ  30720                 // per stage: AH 10240 + AL 10240 + BH 10240
#define OFF_AH 0
#define OFF_AL 10240
#define OFF_BH 20480
#define NSTAGE 3
#define GEMM_SMEM (NSTAGE * ST_SZ)

__global__ __launch_bounds__(256, 2) void gemm2(
    const __half* __restrict__ Ah,
    const __half* __restrict__ Al,
    const __half* __restrict__ Bt,
    float* __restrict__ C, int M, int N, int K)
{
    extern __shared__ char smem[];
    uint32_t sb = smem_u32(smem);
    int tid = threadIdx.x;
    int lane = tid & 31, wid = tid >> 5;
    int warp_m = (wid & 3) * 32;
    int warp_n = (wid >> 2) * 64;
    int mrow0 = blockIdx.y * 128;
    int ncol0 = blockIdx.x * 128;
    int nk = K >> 5;

    // producer: thread t -> row t>>1, 32-byte chunk (t&1)
    int prow = tid >> 1;
    int pch  = (tid & 1) * 16;     // halves offset
    const __half* aH = Ah + (size_t)(mrow0 + prow) * K + pch;
    const __half* aL = Al + (size_t)(mrow0 + prow) * K + pch;
    const __half* bP = Bt + (size_t)(ncol0 + prow) * K + pch;
    uint32_t sts = (uint32_t)(prow * ROWB + pch * 2);

    // ldmatrix lane addresses
    int ra = warp_m + (lane & 7) + (lane & 8);
    int ca = ((lane >> 4) << 3);
    uint32_t a_lm = (uint32_t)(ra * ROWB + ca * 2);
    int rb = warp_n + (lane & 7) + ((lane >> 4) << 3);
    int cb = (((lane >> 3) & 1) << 3);
    uint32_t b_lm = (uint32_t)(rb * ROWB + cb * 2);

    float acc[2][8][4];
    #pragma unroll
    for (int mi = 0; mi < 2; mi++)
        #pragma unroll
        for (int ni = 0; ni < 8; ni++)
            #pragma unroll
            for (int q = 0; q < 4; q++) acc[mi][ni][q] = 0.f;

    // prologue: prefetch stages 0,1
    #pragma unroll
    for (int s = 0; s < 2; s++) {
        if (s < nk) {
            uint32_t base = sb + s * ST_SZ;
            const __half* ah = aH + s * 32;
            const __half* al = aL + s * 32;
            const __half* bp = bP + s * 32;
            CP_ASYNC16(base + OFF_AH + sts, ah); CP_ASYNC16(base + OFF_AH + sts + 16, ah + 8);
            CP_ASYNC16(base + OFF_AL + sts, al); CP_ASYNC16(base + OFF_AL + sts + 16, al + 8);
            CP_ASYNC16(base + OFF_BH + sts, bp); CP_ASYNC16(base + OFF_BH + sts + 16, bp + 8);
        }
        CP_COMMIT();
    }

    for (int kt = 0; kt < nk; kt++) {
        CP_WAIT1();
        __syncthreads();

        // prefetch stage kt+2 into buffer (kt+2)%3
        int pf = kt + 2;
        if (pf < nk) {
            uint32_t base = sb + (pf % NSTAGE) * ST_SZ;
            const __half* ah = aH + pf * 32;
            const __half* al = aL + pf * 32;
            const __half* bp = bP + pf * 32;
            CP_ASYNC16(base + OFF_AH + sts, ah); CP_ASYNC16(base + OFF_AH + sts + 16, ah + 8);
            CP_ASYNC16(base + OFF_AL + sts, al); CP_ASYNC16(base + OFF_AL + sts + 16, al + 8);
            CP_ASYNC16(base + OFF_BH + sts, bp); CP_ASYNC16(base + OFF_BH + sts + 16, bp + 8);
        }
        CP_COMMIT();

        uint32_t bcur = sb + (kt % NSTAGE) * ST_SZ;
        #pragma unroll
        for (int ks = 0; ks < 2; ks++) {
            uint32_t koff = ks * 32;
            uint32_t ahf[2][4], alf[2][4], bh[8][2];
            #pragma unroll
            for (int mi = 0; mi < 2; mi++)
                LDMX4(ahf[mi][0], ahf[mi][1], ahf[mi][2], ahf[mi][3],
                      bcur + OFF_AH + a_lm + mi * (16 * ROWB) + koff);
            #pragma unroll
            for (int mi = 0; mi < 2; mi++)
                LDMX4(alf[mi][0], alf[mi][1], alf[mi][2], alf[mi][3],
                      bcur + OFF_AL + a_lm + mi * (16 * ROWB) + koff);
            #pragma unroll
            for (int bg = 0; bg < 4; bg++)
                LDMX4(bh[bg * 2][0], bh[bg * 2][1], bh[bg * 2 + 1][0], bh[bg * 2 + 1][1],
                      bcur + OFF_BH + b_lm + bg * (16 * ROWB) + koff);

            #pragma unroll
            for (int mi = 0; mi < 2; mi++)
                #pragma unroll
                for (int ni = 0; ni < 8; ni++)
                    MMA16816(acc[mi][ni], ahf[mi], bh[ni]);
            #pragma unroll
            for (int mi = 0; mi < 2; mi++)
                #pragma unroll
                for (int ni = 0; ni < 8; ni++)
                    MMA16816(acc[mi][ni], alf[mi], bh[ni]);
        }
        __syncthreads();
    }

    int g = lane >> 2, t4 = lane & 3;
    #pragma unroll
    for (int mi = 0; mi < 2; mi++) {
        int r0 = mrow0 + warp_m + mi * 16 + g;
        #pragma unroll
        for (int ni = 0; ni < 8; ni++) {
            int col = ncol0 + warp_n + ni * 8 + t4 * 2;
            if (r0 < M)
                *(float2*)(C + (size_t)r0 * N + col) = make_float2(acc[mi][ni][0], acc[mi][ni][1]);
            if (r0 + 8 < M)
                *(float2*)(C + (size_t)(r0 + 8) * N + col) = make_float2(acc[mi][ni][2], acc[mi][ni][3]);
        }
    }
}

// ---------------- fp32 -> fp16 hi/lo split (padded, zero-filled) ----------------
__global__ void split_f32(const float* __restrict__ x, __half* __restrict__ hi, __half* __restrict__ lo,
                          long long nreal, long long npad) {
    long long base = ((long long)blockIdx.x * blockDim.x + threadIdx.x) * 8;
    if (base >= npad) return;
    float f[8];
    if (base < nreal) {
        float4 v0 = *(const float4*)(x + base);
        float4 v1 = *(const float4*)(x + base + 4);
        f[0] = v0.x; f[1] = v0.y; f[2] = v0.z; f[3] = v0.w;
        f[4] = v1.x; f[5] = v1.y; f[6] = v1.z; f[7] = v1.w;
    } else {
        #pragma unroll
        for (int q = 0; q < 8; q++) f[q] = 0.f;
    }
    uint4 H, L;
    split8h(f, H, L);
    *(uint4*)(hi + base) = H;
    *(uint4*)(lo + base) = L;
}

// ---------------- zero accumulators + degree buffers ----------------
__global__ void zero_scratch() {
    size_t t = (size_t)blockIdx.x * blockDim.x + threadIdx.x;
    size_t stride = (size_t)gridDim.x * blockDim.x;
    float4 z = make_float4(0.f, 0.f, 0.f, 0.f);
    for (size_t i = t; i < (size_t)N_SENT * D_H / 4; i += stride) ((float4*)g_acc_s1)[i] = z;
    for (size_t i = t; i < (size_t)N_DOC  * D_H / 4; i += stride) ((float4*)g_acc_d1)[i] = z;
    for (size_t i = t; i < (size_t)N_SENT * D_O / 4; i += stride) ((float4*)g_acc_s2)[i] = z;
    for (size_t i = t; i < (size_t)N_DOC  * D_O / 4; i += stride) ((float4*)g_acc_d2)[i] = z;
    for (size_t i = t; i < N_SENT / 4; i += stride) ((float4*)g_inv_ss)[i] = z;
    for (size_t i = t; i < N_SENT / 4; i += stride) ((float4*)g_inv_ds)[i] = z;
    for (size_t i = t; i < N_DOC  / 4; i += stride) ((float4*)g_inv_sd)[i] = z;
}

// ---------------- degree count + invert ----------------
__global__ void count_deg(const int* __restrict__ dst, int E, float* __restrict__ deg) {
    int i = blockIdx.x * blockDim.x + threadIdx.x;
    if (i < E) atomicAdd(&deg[dst[i]], 1.0f);
}
__global__ void invert_deg(float* __restrict__ deg, int n) {
    int i = blockIdx.x * blockDim.x + threadIdx.x;
    if (i < n) deg[i] = 1.0f / fmaxf(deg[i], 1.0f);
}

// ---------------- weight build: transposed fp16 ----------------
__global__ void build_w3t(const float* __restrict__ coeff, const float* __restrict__ basis,
                          const float* __restrict__ loopw,
                          __half* __restrict__ outH,
                          int K, int D, int Npad, int r0, int r1) {
    int idx = blockIdx.x * blockDim.x + threadIdx.x;
    if (idx >= Npad * K) return;
    int o = idx / K;
    int k = idx % K;
    float v = 0.f;
    if (o < 3 * D) {
        int seg = o / D, od = o % D;
        if (seg == 2) v = loopw[k * D + od];
        else {
            int r = (seg == 0) ? r0 : r1;
            v = coeff[r * 2 + 0] * basis[(size_t)k * D + od]
              + coeff[r * 2 + 1] * basis[(size_t)K * D + (size_t)k * D + od];
        }
    }
    outH[idx] = __float2half(v);
}
__global__ void build_w2t(const float* __restrict__ coeff, const float* __restrict__ basis,
                          const float* __restrict__ loopw,
                          __half* __restrict__ outH,
                          int K, int D, int Npad, int r0) {
    int idx = blockIdx.x * blockDim.x + threadIdx.x;
    if (idx >= Npad * K) return;
    int o = idx / K;
    int k = idx % K;
    float v = 0.f;
    if (o < 2 * D) {
        int seg = o / D, od = o % D;
        if (seg == 1) v = loopw[k * D + od];
        else {
            v = coeff[r0 * 2 + 0] * basis[(size_t)k * D + od]
              + coeff[r0 * 2 + 1] * basis[(size_t)K * D + (size_t)k * D + od];
        }
    }
    outH[idx] = __float2half(v);
}

// ---------------- edge scatter ----------------
__device__ __forceinline__ void redAdd4(float* addr, float4 v) {
    asm volatile("red.global.add.v4.f32 [%0], {%1, %2, %3, %4};"
                 :: "l"(addr), "f"(v.x), "f"(v.y), "f"(v.z), "f"(v.w) : "memory");
}
__global__ void scatter_scaled(const int* __restrict__ src, const int* __restrict__ dst, int E,
                               const float* __restrict__ P, int ldp, int colOff,
                               float* __restrict__ acc, int lda,
                               const float* __restrict__ invdeg, int D4) {
    long long t = (long long)blockIdx.x * blockDim.x + threadIdx.x;
    int e = (int)(t / D4);
    int j = (int)(t % D4);
    if (e >= E) return;
    int s = src[e];
    int d = dst[e];
    float sc = invdeg[d];
    float4 v = *(const float4*)(P + (size_t)s * ldp + colOff + 4 * j);
    redAdd4(acc + (size_t)d * lda + 4 * j, make_float4(v.x * sc, v.y * sc, v.z * sc, v.w * sc));
}

// ---------------- layer-1 combine: h = relu(acc + P_loop + bias), emit split fp16 --------
__global__ void combine_relu_split(const float* __restrict__ acc, const float* __restrict__ P,
                                   int ldp, int colOff, const float* __restrict__ bias,
                                   __half* __restrict__ hhi, __half* __restrict__ hlo,
                                   int Nreal, int Npad, int D) {
    int D8 = D / 8;
    int t = blockIdx.x * blockDim.x + threadIdx.x;
    if (t >= Npad * D8) return;
    int i = t / D8;
    int j = t % D8;
    float f[8];
    if (i < Nreal) {
        float4 a0 = *(const float4*)(acc + (size_t)i * D + 8 * j);
        float4 a1 = *(const float4*)(acc + (size_t)i * D + 8 * j + 4);
        float4 p0 = *(const float4*)(P + (size_t)i * ldp + colOff + 8 * j);
        float4 p1 = *(const float4*)(P + (size_t)i * ldp + colOff + 8 * j + 4);
        float4 b0 = *(const float4*)(bias + 8 * j);
        float4 b1 = *(const float4*)(bias + 8 * j + 4);
        f[0] = fmaxf(a0.x + p0.x + b0.x, 0.f);
        f[1] = fmaxf(a0.y + p0.y + b0.y, 0.f);
        f[2] = fmaxf(a0.z + p0.z + b0.z, 0.f);
        f[3] = fmaxf(a0.w + p0.w + b0.w, 0.f);
        f[4] = fmaxf(a1.x + p1.x + b1.x, 0.f);
        f[5] = fmaxf(a1.y + p1.y + b1.y, 0.f);
        f[6] = fmaxf(a1.z + p1.z + b1.z, 0.f);
        f[7] = fmaxf(a1.w + p1.w + b1.w, 0.f);
    } else {
        #pragma unroll
        for (int q = 0; q < 8; q++) f[q] = 0.f;
    }
    uint4 H, L;
    split8h(f, H, L);
    *(uint4*)(hhi + (size_t)i * D + 8 * j) = H;
    *(uint4*)(hlo + (size_t)i * D + 8 * j) = L;
}

// ---------------- out init ----------------
__global__ void init_out(float* __restrict__ out, const float* __restrict__ b_score) {
    int g = threadIdx.x;
    if (g < NGRAPH) out[g] = b_score[0];
}

// ---------------- layer-2 combine + relu + score + per-graph reduce ----------------
__global__ void combine2_readout(const float* __restrict__ acc, const float* __restrict__ P,
                                 int ldp, int colOff, const float* __restrict__ bias,
                                 const float* __restrict__ wscore,
                                 const int* __restrict__ gid,
                                 float* __restrict__ out, int N) {
    int warp = (blockIdx.x * blockDim.x + threadIdx.x) >> 5;
    int lane = threadIdx.x & 31;
    if (warp >= N) return;
    float4 a = *(const float4*)(acc + (size_t)warp * D_O + lane * 4);
    float4 p = *(const float4*)(P + (size_t)warp * ldp + colOff + lane * 4);
    float4 b = *(const float4*)(bias + lane * 4);
    float4 w = *(const float4*)(wscore + lane * 4);
    float s = fmaxf(a.x + p.x + b.x, 0.f) * w.x
            + fmaxf(a.y + p.y + b.y, 0.f) * w.y
            + fmaxf(a.z + p.z + b.z, 0.f) * w.z
            + fmaxf(a.w + p.w + b.w, 0.f) * w.w;
    #pragma unroll
    for (int off = 16; off; off >>= 1) s += __shfl_down_sync(0xffffffffu, s, off);
    if (lane == 0) atomicAdd(&out[gid[warp]], s);
}

// ---------------- host launcher ----------------
static void* symaddr(const void* sym) {
    void* p = nullptr;
    cudaGetSymbolAddress(&p, sym);
    return p;
}

extern "C" void kernel_launch(void* const* d_in, const int* in_sizes, int n_in,
                              void* d_out, int out_size) {
    const float* x_sent  = (const float*)d_in[0];
    const float* x_doc   = (const float*)d_in[1];
    const float* coeff1  = (const float*)d_in[2];
    const float* basis1  = (const float*)d_in[3];
    const float* loop_w1 = (const float*)d_in[4];
    const float* bias1   = (const float*)d_in[5];
    const float* coeff2  = (const float*)d_in[6];
    const float* basis2  = (const float*)d_in[7];
    const float* loop_w2 = (const float*)d_in[8];
    const float* bias2   = (const float*)d_in[9];
    const float* w_score = (const float*)d_in[10];
    const float* b_score = (const float*)d_in[11];
    const int*   src_ss  = (const int*)d_in[12];
    const int*   dst_ss  = (const int*)d_in[13];
    const int*   src_sd  = (const int*)d_in[14];
    const int*   dst_sd  = (const int*)d_in[15];
    const int*   src_ds  = (const int*)d_in[16];
    const int*   dst_ds  = (const int*)d_in[17];
    const int*   gid_sent= (const int*)d_in[18];
    const int*   gid_doc = (const int*)d_in[19];
    float* out = (float*)d_out;

    __half* pB1sh = (__half*)symaddr(g_B1s_h);
    __half* pB1dh = (__half*)symaddr(g_B1d_h);
    __half* pB2sh = (__half*)symaddr(g_B2s_h);
    __half* pB2dh = (__half*)symaddr(g_B2d_h);

    __half* pXsh = (__half*)symaddr(g_xs_h);
    __half* pXsl = (__half*)symaddr(g_xs_l);
    __half* pXdh = (__half*)symaddr(g_xd_h);
    __half* pXdl = (__half*)symaddr(g_xd_l);
    __half* pHsh = (__half*)symaddr(g_hs_h);
    __half* pHsl = (__half*)symaddr(g_hs_l);
    __half* pHdh = (__half*)symaddr(g_hd_h);
    __half* pHdl = (__half*)symaddr(g_hd_l);

    float* pPs  = (float*)symaddr(g_Ps);
    float* pPd  = (float*)symaddr(g_Pd);
    float* pA1s = (float*)symaddr(g_acc_s1);
    float* pA1d = (float*)symaddr(g_acc_d1);
    float* pPs2 = (float*)symaddr(g_Ps2);
    float* pPd2 = (float*)symaddr(g_Pd2);
    float* pA2s = (float*)symaddr(g_acc_s2);
    float* pA2d = (float*)symaddr(g_acc_d2);
    float* pIss = (float*)symaddr(g_inv_ss);
    float* pIds = (float*)symaddr(g_inv_ds);
    float* pIsd = (float*)symaddr(g_inv_sd);

    cudaFuncSetAttribute(gemm2, cudaFuncAttributeMaxDynamicSharedMemorySize, GEMM_SMEM);

    cudaStream_t st = 0;

    // Harness issues 2 launches before ours; global #5 = my idx 3 → big GEMM profiled.
    zero_scratch<<<1184, 256, 0, st>>>();                                                    // idx 0
    {                                                                                        // idx 1
        long long nreal = (long long)N_SENT * D_IN, npad = (long long)SENT_PAD * D_IN;
        split_f32<<<(unsigned)((npad / 8 + 255) / 256), 256, 0, st>>>(x_sent, pXsh, pXsl, nreal, npad);
    }
    build_w3t<<<(768 * 768 + 255) / 256, 256, 0, st>>>(coeff1, basis1, loop_w1, pB1sh, D_IN, D_H, 768, 0, 2); // idx 2
    {                                                                                        // idx 3 (ncu -s 5)
        dim3 g(768 / 128, SENT_PAD / 128);
        gemm2<<<g, 256, GEMM_SMEM, st>>>(pXsh, pXsl, pB1sh, pPs, N_SENT, 3 * D_H, D_IN);
    }

    {
        long long nreal = (long long)N_DOC * D_IN, npad = (long long)DOC_PAD * D_IN;
        split_f32<<<(unsigned)((npad / 8 + 255) / 256), 256, 0, st>>>(x_doc, pXdh, pXdl, nreal, npad);
    }
    count_deg<<<(E_SS + 255) / 256, 256, 0, st>>>(dst_ss, E_SS, pIss);
    count_deg<<<(E_DS + 255) / 256, 256, 0, st>>>(dst_ds, E_DS, pIds);
    count_deg<<<(E_SD + 255) / 256, 256, 0, st>>>(dst_sd, E_SD, pIsd);
    invert_deg<<<(N_SENT + 255) / 256, 256, 0, st>>>(pIss, N_SENT);
    invert_deg<<<(N_SENT + 255) / 256, 256, 0, st>>>(pIds, N_SENT);
    invert_deg<<<(N_DOC + 255) / 256, 256, 0, st>>>(pIsd, N_DOC);

    build_w2t<<<(512 * 768 + 255) / 256, 256, 0, st>>>(coeff1, basis1, loop_w1, pB1dh, D_IN, D_H, 512, 1);
    build_w3t<<<(384 * 256 + 255) / 256, 256, 0, st>>>(coeff2, basis2, loop_w2, pB2sh, D_H, D_O, 384, 0, 2);
    build_w2t<<<(256 * 256 + 255) / 256, 256, 0, st>>>(coeff2, basis2, loop_w2, pB2dh, D_H, D_O, 256, 1);

    {
        dim3 g(512 / 128, DOC_PAD / 128);
        gemm2<<<g, 256, GEMM_SMEM, st>>>(pXdh, pXdl, pB1dh, pPd, N_DOC, 2 * D_H, D_IN);
    }

    // layer-1 aggregation
    {
        long long T = (long long)E_SS * (D_H / 4);
        scatter_scaled<<<(unsigned)((T + 255) / 256), 256, 0, st>>>(src_ss, dst_ss, E_SS, pPs, 3 * D_H, D_H, pA1s, D_H, pIss, D_H / 4);
    }
    {
        long long T = (long long)E_DS * (D_H / 4);
        scatter_scaled<<<(unsigned)((T + 255) / 256), 256, 0, st>>>(src_ds, dst_ds, E_DS, pPd, 2 * D_H, 0, pA1s, D_H, pIds, D_H / 4);
    }
    {
        long long T = (long long)E_SD * (D_H / 4);
        scatter_scaled<<<(unsigned)((T + 255) / 256), 256, 0, st>>>(src_sd, dst_sd, E_SD, pPs, 3 * D_H, 0, pA1d, D_H, pIsd, D_H / 4);
    }

    // layer-1 combine (emit split fp16)
    combine_relu_split<<<(SENT_PAD * (D_H / 8) + 255) / 256, 256, 0, st>>>(pA1s, pPs, 3 * D_H, 2 * D_H, bias1, pHsh, pHsl, N_SENT, SENT_PAD, D_H);
    combine_relu_split<<<(DOC_PAD * (D_H / 8) + 255) / 256, 256, 0, st>>>(pA1d, pPd, 2 * D_H, D_H, bias1, pHdh, pHdl, N_DOC, DOC_PAD, D_H);

    // layer-2 projections
    {
        dim3 g(384 / 128, SENT_PAD / 128);
        gemm2<<<g, 256, GEMM_SMEM, st>>>(pHsh, pHsl, pB2sh, pPs2, N_SENT, 3 * D_O, D_H);
    }
    {
        dim3 g(256 / 128, DOC_PAD / 128);
        gemm2<<<g, 256, GEMM_SMEM, st>>>(pHdh, pHdl, pB2dh, pPd2, N_DOC, 2 * D_O, D_H);
    }

    // layer-2 aggregation
    {
        long long T = (long long)E_SS * (D_O / 4);
        scatter_scaled<<<(unsigned)((T + 255) / 256), 256, 0, st>>>(src_ss, dst_ss, E_SS, pPs2, 3 * D_O, D_O, pA2s, D_O, pIss, D_O / 4);
    }
    {
        long long T = (long long)E_DS * (D_O / 4);
        scatter_scaled<<<(unsigned)((T + 255) / 256), 256, 0, st>>>(src_ds, dst_ds, E_DS, pPd2, 2 * D_O, 0, pA2s, D_O, pIds, D_O / 4);
    }
    {
        long long T = (long long)E_SD * (D_O / 4);
        scatter_scaled<<<(unsigned)((T + 255) / 256), 256, 0, st>>>(src_sd, dst_sd, E_SD, pPs2, 3 * D_O, 0, pA2d, D_O, pIsd, D_O / 4);
    }

    // readout
    init_out<<<1, 32, 0, st>>>(out, b_score);
    combine2_readout<<<(N_SENT + 7) / 8, 256, 0, st>>>(pA2s, pPs2, 3 * D_O, 2 * D_O, bias2, w_score, gid_sent, out, N_SENT);
    combine2_readout<<<(N_DOC + 7) / 8, 256, 0, st>>>(pA2d, pPd2, 2 * D_O, D_O, bias2, w_score, gid_doc, out, N_DOC);
}

// round 8
// speedup vs baseline: 3.1305x; 1.2792x over previous
#include <cuda_runtime.h>
#include <cuda_fp16.h>
#include <cstdint>
#include <cstddef>

#define N_SENT 100000
#define N_DOC  10000
#define SENT_PAD 100096
#define DOC_PAD  10112
#define NGRAPH 32
#define D_IN   768
#define D_H    256
#define D_O    128
#define E_SS   400000
#define E_SD   100000
#define E_DS   100000

// ---------------- scratch (device globals: allocation-free) ----------------
__device__ __align__(16) __half g_B1s_h[768 * 768];
__device__ __align__(16) __half g_B1d_h[512 * 768];
__device__ __align__(16) __half g_B2s_h[384 * 256];
__device__ __align__(16) __half g_B2d_h[256 * 256];

// fp16 activations (padded rows, zero-filled)
__device__ __align__(16) __half g_xs_h[(size_t)SENT_PAD * D_IN];
__device__ __align__(16) __half g_xd_h[(size_t)DOC_PAD * D_IN];
__device__ __align__(16) __half g_hs_h[(size_t)SENT_PAD * D_H];
__device__ __align__(16) __half g_hd_h[(size_t)DOC_PAD * D_H];

__device__ float g_Ps [(size_t)N_SENT * (3 * D_H)];
__device__ float g_Pd [(size_t)N_DOC  * (2 * D_H)];
__device__ float g_acc_s1[(size_t)N_SENT * D_H];
__device__ float g_acc_d1[(size_t)N_DOC  * D_H];
__device__ float g_Ps2[(size_t)N_SENT * (3 * D_O)];
__device__ float g_Pd2[(size_t)N_DOC  * (2 * D_O)];
__device__ float g_acc_s2[(size_t)N_SENT * D_O];
__device__ float g_acc_d2[(size_t)N_DOC  * D_O];
__device__ float g_inv_ss[N_SENT];
__device__ float g_inv_ds[N_SENT];
__device__ float g_inv_sd[N_DOC];

// ---------------- PTX helpers ----------------
__device__ __forceinline__ uint32_t smem_u32(const void* p) {
    uint32_t a;
    asm("{ .reg .u64 t; cvta.to.shared.u64 t, %1; cvt.u32.u64 %0, t; }" : "=r"(a) : "l"(p));
    return a;
}

#define CP_ASYNC16(saddr, gaddr) \
    asm volatile("cp.async.cg.shared.global [%0], [%1], 16;" :: "r"(saddr), "l"(gaddr) : "memory")
#define CP_COMMIT() asm volatile("cp.async.commit_group;" ::: "memory")
#define CP_WAIT1()  asm volatile("cp.async.wait_group 1;" ::: "memory")

#define LDMX4(r0, r1, r2, r3, addr) \
    asm volatile("ldmatrix.sync.aligned.m8n8.x4.shared.b16 {%0,%1,%2,%3}, [%4];" \
                 : "=r"(r0), "=r"(r1), "=r"(r2), "=r"(r3) : "r"(addr))

#define MMA16816(d, a, b) \
    asm volatile("mma.sync.aligned.m16n8k16.row.col.f32.f16.f16.f32 " \
                 "{%0,%1,%2,%3}, {%4,%5,%6,%7}, {%8,%9}, {%0,%1,%2,%3};" \
                 : "+f"((d)[0]), "+f"((d)[1]), "+f"((d)[2]), "+f"((d)[3]) \
                 : "r"((a)[0]), "r"((a)[1]), "r"((a)[2]), "r"((a)[3]), "r"((b)[0]), "r"((b)[1]))

// ---------------- fp32 -> fp16 pack8 ----------------
__device__ __forceinline__ uint4 pack8h(const float* f) {
    uint32_t hs[8];
    #pragma unroll
    for (int i = 0; i < 8; i++) hs[i] = (uint32_t)__half_as_ushort(__float2half(f[i]));
    return make_uint4(hs[0] | (hs[1] << 16), hs[2] | (hs[3] << 16), hs[4] | (hs[5] << 16), hs[6] | (hs[7] << 16));
}

#define ROWB   80

// ================= GEMM v3: fp16 x fp16, all-cp.async, 3-stage, 128x128, warps 4m x 2n ====
// C[M,N] = A[Mpad,K](fp16) @ Bt[N,K](fp16)^T, fp32 accum. N % 128 == 0.
#define ST_SZ  20480                 // per stage: A 10240 + B 10240
#define OFF_A  0
#define OFF_B  10240
#define NSTAGE 3
#define GEMM_SMEM (NSTAGE * ST_SZ)

__global__ __launch_bounds__(256, 2) void gemm3(
    const __half* __restrict__ A,
    const __half* __restrict__ Bt,
    float* __restrict__ C, int M, int N, int K)
{
    extern __shared__ char smem[];
    uint32_t sb = smem_u32(smem);
    int tid = threadIdx.x;
    int lane = tid & 31, wid = tid >> 5;
    int warp_m = (wid & 3) * 32;
    int warp_n = (wid >> 2) * 64;
    int mrow0 = blockIdx.y * 128;
    int ncol0 = blockIdx.x * 128;
    int nk = K >> 5;

    // producer: thread t -> row t>>1, 32-byte chunk (t&1)
    int prow = tid >> 1;
    int pch  = (tid & 1) * 16;
    const __half* aP = A + (size_t)(mrow0 + prow) * K + pch;
    const __half* bP = Bt + (size_t)(ncol0 + prow) * K + pch;
    uint32_t sts = (uint32_t)(prow * ROWB + pch * 2);

    // ldmatrix lane addresses
    int ra = warp_m + (lane & 7) + (lane & 8);
    int ca = ((lane >> 4) << 3);
    uint32_t a_lm = (uint32_t)(ra * ROWB + ca * 2);
    int rb = warp_n + (lane & 7) + ((lane >> 4) << 3);
    int cb = (((lane >> 3) & 1) << 3);
    uint32_t b_lm = (uint32_t)(rb * ROWB + cb * 2);

    float acc[2][8][4];
    #pragma unroll
    for (int mi = 0; mi < 2; mi++)
        #pragma unroll
        for (int ni = 0; ni < 8; ni++)
            #pragma unroll
            for (int q = 0; q < 4; q++) acc[mi][ni][q] = 0.f;

    // prologue: prefetch stages 0,1
    #pragma unroll
    for (int s = 0; s < 2; s++) {
        if (s < nk) {
            uint32_t base = sb + s * ST_SZ;
            const __half* ap = aP + s * 32;
            const __half* bp = bP + s * 32;
            CP_ASYNC16(base + OFF_A + sts, ap); CP_ASYNC16(base + OFF_A + sts + 16, ap + 8);
            CP_ASYNC16(base + OFF_B + sts, bp); CP_ASYNC16(base + OFF_B + sts + 16, bp + 8);
        }
        CP_COMMIT();
    }

    for (int kt = 0; kt < nk; kt++) {
        CP_WAIT1();
        __syncthreads();

        int pf = kt + 2;
        if (pf < nk) {
            uint32_t base = sb + (pf % NSTAGE) * ST_SZ;
            const __half* ap = aP + pf * 32;
            const __half* bp = bP + pf * 32;
            CP_ASYNC16(base + OFF_A + sts, ap); CP_ASYNC16(base + OFF_A + sts + 16, ap + 8);
            CP_ASYNC16(base + OFF_B + sts, bp); CP_ASYNC16(base + OFF_B + sts + 16, bp + 8);
        }
        CP_COMMIT();

        uint32_t bcur = sb + (kt % NSTAGE) * ST_SZ;
        #pragma unroll
        for (int ks = 0; ks < 2; ks++) {
            uint32_t koff = ks * 32;
            uint32_t af[2][4], bf[8][2];
            #pragma unroll
            for (int mi = 0; mi < 2; mi++)
                LDMX4(af[mi][0], af[mi][1], af[mi][2], af[mi][3],
                      bcur + OFF_A + a_lm + mi * (16 * ROWB) + koff);
            #pragma unroll
            for (int bg = 0; bg < 4; bg++)
                LDMX4(bf[bg * 2][0], bf[bg * 2][1], bf[bg * 2 + 1][0], bf[bg * 2 + 1][1],
                      bcur + OFF_B + b_lm + bg * (16 * ROWB) + koff);
            #pragma unroll
            for (int mi = 0; mi < 2; mi++)
                #pragma unroll
                for (int ni = 0; ni < 8; ni++)
                    MMA16816(acc[mi][ni], af[mi], bf[ni]);
        }
        __syncthreads();
    }

    int g = lane >> 2, t4 = lane & 3;
    #pragma unroll
    for (int mi = 0; mi < 2; mi++) {
        int r0 = mrow0 + warp_m + mi * 16 + g;
        #pragma unroll
        for (int ni = 0; ni < 8; ni++) {
            int col = ncol0 + warp_n + ni * 8 + t4 * 2;
            if (r0 < M)
                *(float2*)(C + (size_t)r0 * N + col) = make_float2(acc[mi][ni][0], acc[mi][ni][1]);
            if (r0 + 8 < M)
                *(float2*)(C + (size_t)(r0 + 8) * N + col) = make_float2(acc[mi][ni][2], acc[mi][ni][3]);
        }
    }
}

// ---------------- fp32 -> fp16 convert (padded, zero-filled) ----------------
__global__ void cvt_f16(const float* __restrict__ x, __half* __restrict__ hi,
                        long long nreal, long long npad) {
    long long base = ((long long)blockIdx.x * blockDim.x + threadIdx.x) * 8;
    if (base >= npad) return;
    float f[8];
    if (base < nreal) {
        float4 v0 = *(const float4*)(x + base);
        float4 v1 = *(const float4*)(x + base + 4);
        f[0] = v0.x; f[1] = v0.y; f[2] = v0.z; f[3] = v0.w;
        f[4] = v1.x; f[5] = v1.y; f[6] = v1.z; f[7] = v1.w;
    } else {
        #pragma unroll
        for (int q = 0; q < 8; q++) f[q] = 0.f;
    }
    *(uint4*)(hi + base) = pack8h(f);
}

// ---------------- zero accumulators + degree buffers ----------------
__global__ void zero_scratch() {
    size_t t = (size_t)blockIdx.x * blockDim.x + threadIdx.x;
    size_t stride = (size_t)gridDim.x * blockDim.x;
    float4 z = make_float4(0.f, 0.f, 0.f, 0.f);
    for (size_t i = t; i < (size_t)N_SENT * D_H / 4; i += stride) ((float4*)g_acc_s1)[i] = z;
    for (size_t i = t; i < (size_t)N_DOC  * D_H / 4; i += stride) ((float4*)g_acc_d1)[i] = z;
    for (size_t i = t; i < (size_t)N_SENT * D_O / 4; i += stride) ((float4*)g_acc_s2)[i] = z;
    for (size_t i = t; i < (size_t)N_DOC  * D_O / 4; i += stride) ((float4*)g_acc_d2)[i] = z;
    for (size_t i = t; i < N_SENT / 4; i += stride) ((float4*)g_inv_ss)[i] = z;
    for (size_t i = t; i < N_SENT / 4; i += stride) ((float4*)g_inv_ds)[i] = z;
    for (size_t i = t; i < N_DOC  / 4; i += stride) ((float4*)g_inv_sd)[i] = z;
}

// ---------------- degree count + invert ----------------
__global__ void count_deg(const int* __restrict__ dst, int E, float* __restrict__ deg) {
    int i = blockIdx.x * blockDim.x + threadIdx.x;
    if (i < E) atomicAdd(&deg[dst[i]], 1.0f);
}
__global__ void invert_deg(float* __restrict__ deg, int n) {
    int i = blockIdx.x * blockDim.x + threadIdx.x;
    if (i < n) deg[i] = 1.0f / fmaxf(deg[i], 1.0f);
}

// ---------------- weight build: transposed fp16 ----------------
__global__ void build_w3t(const float* __restrict__ coeff, const float* __restrict__ basis,
                          const float* __restrict__ loopw,
                          __half* __restrict__ outH,
                          int K, int D, int Npad, int r0, int r1) {
    int idx = blockIdx.x * blockDim.x + threadIdx.x;
    if (idx >= Npad * K) return;
    int o = idx / K;
    int k = idx % K;
    float v = 0.f;
    if (o < 3 * D) {
        int seg = o / D, od = o % D;
        if (seg == 2) v = loopw[k * D + od];
        else {
            int r = (seg == 0) ? r0 : r1;
            v = coeff[r * 2 + 0] * basis[(size_t)k * D + od]
              + coeff[r * 2 + 1] * basis[(size_t)K * D + (size_t)k * D + od];
        }
    }
    outH[idx] = __float2half(v);
}
__global__ void build_w2t(const float* __restrict__ coeff, const float* __restrict__ basis,
                          const float* __restrict__ loopw,
                          __half* __restrict__ outH,
                          int K, int D, int Npad, int r0) {
    int idx = blockIdx.x * blockDim.x + threadIdx.x;
    if (idx >= Npad * K) return;
    int o = idx / K;
    int k = idx % K;
    float v = 0.f;
    if (o < 2 * D) {
        int seg = o / D, od = o % D;
        if (seg == 1) v = loopw[k * D + od];
        else {
            v = coeff[r0 * 2 + 0] * basis[(size_t)k * D + od]
              + coeff[r0 * 2 + 1] * basis[(size_t)K * D + (size_t)k * D + od];
        }
    }
    outH[idx] = __float2half(v);
}

// ---------------- edge scatter ----------------
__device__ __forceinline__ void redAdd4(float* addr, float4 v) {
    asm volatile("red.global.add.v4.f32 [%0], {%1, %2, %3, %4};"
                 :: "l"(addr), "f"(v.x), "f"(v.y), "f"(v.z), "f"(v.w) : "memory");
}
__global__ void scatter_scaled(const int* __restrict__ src, const int* __restrict__ dst, int E,
                               const float* __restrict__ P, int ldp, int colOff,
                               float* __restrict__ acc, int lda,
                               const float* __restrict__ invdeg, int D4) {
    long long t = (long long)blockIdx.x * blockDim.x + threadIdx.x;
    int e = (int)(t / D4);
    int j = (int)(t % D4);
    if (e >= E) return;
    int s = src[e];
    int d = dst[e];
    float sc = invdeg[d];
    float4 v = *(const float4*)(P + (size_t)s * ldp + colOff + 4 * j);
    redAdd4(acc + (size_t)d * lda + 4 * j, make_float4(v.x * sc, v.y * sc, v.z * sc, v.w * sc));
}

// ---------------- layer-1 combine: h = relu(acc + P_loop + bias), emit fp16 ----------
__global__ void combine_relu_h(const float* __restrict__ acc, const float* __restrict__ P,
                               int ldp, int colOff, const float* __restrict__ bias,
                               __half* __restrict__ hout, int Nreal, int Npad, int D) {
    int D8 = D / 8;
    int t = blockIdx.x * blockDim.x + threadIdx.x;
    if (t >= Npad * D8) return;
    int i = t / D8;
    int j = t % D8;
    float f[8];
    if (i < Nreal) {
        float4 a0 = *(const float4*)(acc + (size_t)i * D + 8 * j);
        float4 a1 = *(const float4*)(acc + (size_t)i * D + 8 * j + 4);
        float4 p0 = *(const float4*)(P + (size_t)i * ldp + colOff + 8 * j);
        float4 p1 = *(const float4*)(P + (size_t)i * ldp + colOff + 8 * j + 4);
        float4 b0 = *(const float4*)(bias + 8 * j);
        float4 b1 = *(const float4*)(bias + 8 * j + 4);
        f[0] = fmaxf(a0.x + p0.x + b0.x, 0.f);
        f[1] = fmaxf(a0.y + p0.y + b0.y, 0.f);
        f[2] = fmaxf(a0.z + p0.z + b0.z, 0.f);
        f[3] = fmaxf(a0.w + p0.w + b0.w, 0.f);
        f[4] = fmaxf(a1.x + p1.x + b1.x, 0.f);
        f[5] = fmaxf(a1.y + p1.y + b1.y, 0.f);
        f[6] = fmaxf(a1.z + p1.z + b1.z, 0.f);
        f[7] = fmaxf(a1.w + p1.w + b1.w, 0.f);
    } else {
        #pragma unroll
        for (int q = 0; q < 8; q++) f[q] = 0.f;
    }
    *(uint4*)(hout + (size_t)i * D + 8 * j) = pack8h(f);
}

// ---------------- out init ----------------
__global__ void init_out(float* __restrict__ out, const float* __restrict__ b_score) {
    int g = threadIdx.x;
    if (g < NGRAPH) out[g] = b_score[0];
}

// ---------------- layer-2 combine + relu + score + per-graph reduce ----------------
__global__ void combine2_readout(const float* __restrict__ acc, const float* __restrict__ P,
                                 int ldp, int colOff, const float* __restrict__ bias,
                                 const float* __restrict__ wscore,
                                 const int* __restrict__ gid,
                                 float* __restrict__ out, int N) {
    int warp = (blockIdx.x * blockDim.x + threadIdx.x) >> 5;
    int lane = threadIdx.x & 31;
    if (warp >= N) return;
    float4 a = *(const float4*)(acc + (size_t)warp * D_O + lane * 4);
    float4 p = *(const float4*)(P + (size_t)warp * ldp + colOff + lane * 4);
    float4 b = *(const float4*)(bias + lane * 4);
    float4 w = *(const float4*)(wscore + lane * 4);
    float s = fmaxf(a.x + p.x + b.x, 0.f) * w.x
            + fmaxf(a.y + p.y + b.y, 0.f) * w.y
            + fmaxf(a.z + p.z + b.z, 0.f) * w.z
            + fmaxf(a.w + p.w + b.w, 0.f) * w.w;
    #pragma unroll
    for (int off = 16; off; off >>= 1) s += __shfl_down_sync(0xffffffffu, s, off);
    if (lane == 0) atomicAdd(&out[gid[warp]], s);
}

// ---------------- host launcher ----------------
static void* symaddr(const void* sym) {
    void* p = nullptr;
    cudaGetSymbolAddress(&p, sym);
    return p;
}

extern "C" void kernel_launch(void* const* d_in, const int* in_sizes, int n_in,
                              void* d_out, int out_size) {
    const float* x_sent  = (const float*)d_in[0];
    const float* x_doc   = (const float*)d_in[1];
    const float* coeff1  = (const float*)d_in[2];
    const float* basis1  = (const float*)d_in[3];
    const float* loop_w1 = (const float*)d_in[4];
    const float* bias1   = (const float*)d_in[5];
    const float* coeff2  = (const float*)d_in[6];
    const float* basis2  = (const float*)d_in[7];
    const float* loop_w2 = (const float*)d_in[8];
    const float* bias2   = (const float*)d_in[9];
    const float* w_score = (const float*)d_in[10];
    const float* b_score = (const float*)d_in[11];
    const int*   src_ss  = (const int*)d_in[12];
    const int*   dst_ss  = (const int*)d_in[13];
    const int*   src_sd  = (const int*)d_in[14];
    const int*   dst_sd  = (const int*)d_in[15];
    const int*   src_ds  = (const int*)d_in[16];
    const int*   dst_ds  = (const int*)d_in[17];
    const int*   gid_sent= (const int*)d_in[18];
    const int*   gid_doc = (const int*)d_in[19];
    float* out = (float*)d_out;

    __half* pB1sh = (__half*)symaddr(g_B1s_h);
    __half* pB1dh = (__half*)symaddr(g_B1d_h);
    __half* pB2sh = (__half*)symaddr(g_B2s_h);
    __half* pB2dh = (__half*)symaddr(g_B2d_h);

    __half* pXsh = (__half*)symaddr(g_xs_h);
    __half* pXdh = (__half*)symaddr(g_xd_h);
    __half* pHsh = (__half*)symaddr(g_hs_h);
    __half* pHdh = (__half*)symaddr(g_hd_h);

    float* pPs  = (float*)symaddr(g_Ps);
    float* pPd  = (float*)symaddr(g_Pd);
    float* pA1s = (float*)symaddr(g_acc_s1);
    float* pA1d = (float*)symaddr(g_acc_d1);
    float* pPs2 = (float*)symaddr(g_Ps2);
    float* pPd2 = (float*)symaddr(g_Pd2);
    float* pA2s = (float*)symaddr(g_acc_s2);
    float* pA2d = (float*)symaddr(g_acc_d2);
    float* pIss = (float*)symaddr(g_inv_ss);
    float* pIds = (float*)symaddr(g_inv_ds);
    float* pIsd = (float*)symaddr(g_inv_sd);

    cudaFuncSetAttribute(gemm3, cudaFuncAttributeMaxDynamicSharedMemorySize, GEMM_SMEM);

    cudaStream_t st = 0;

    // Harness issues 2 launches before ours; global #5 = my idx 3 → big GEMM profiled.
    zero_scratch<<<1184, 256, 0, st>>>();                                                    // idx 0
    {                                                                                        // idx 1
        long long nreal = (long long)N_SENT * D_IN, npad = (long long)SENT_PAD * D_IN;
        cvt_f16<<<(unsigned)((npad / 8 + 255) / 256), 256, 0, st>>>(x_sent, pXsh, nreal, npad);
    }
    build_w3t<<<(768 * 768 + 255) / 256, 256, 0, st>>>(coeff1, basis1, loop_w1, pB1sh, D_IN, D_H, 768, 0, 2); // idx 2
    {                                                                                        // idx 3 (ncu -s 5)
        dim3 g(768 / 128, SENT_PAD / 128);
        gemm3<<<g, 256, GEMM_SMEM, st>>>(pXsh, pB1sh, pPs, N_SENT, 3 * D_H, D_IN);
    }

    {
        long long nreal = (long long)N_DOC * D_IN, npad = (long long)DOC_PAD * D_IN;
        cvt_f16<<<(unsigned)((npad / 8 + 255) / 256), 256, 0, st>>>(x_doc, pXdh, nreal, npad);
    }
    count_deg<<<(E_SS + 255) / 256, 256, 0, st>>>(dst_ss, E_SS, pIss);
    count_deg<<<(E_DS + 255) / 256, 256, 0, st>>>(dst_ds, E_DS, pIds);
    count_deg<<<(E_SD + 255) / 256, 256, 0, st>>>(dst_sd, E_SD, pIsd);
    invert_deg<<<(N_SENT + 255) / 256, 256, 0, st>>>(pIss, N_SENT);
    invert_deg<<<(N_SENT + 255) / 256, 256, 0, st>>>(pIds, N_SENT);
    invert_deg<<<(N_DOC + 255) / 256, 256, 0, st>>>(pIsd, N_DOC);

    build_w2t<<<(512 * 768 + 255) / 256, 256, 0, st>>>(coeff1, basis1, loop_w1, pB1dh, D_IN, D_H, 512, 1);
    build_w3t<<<(384 * 256 + 255) / 256, 256, 0, st>>>(coeff2, basis2, loop_w2, pB2sh, D_H, D_O, 384, 0, 2);
    build_w2t<<<(256 * 256 + 255) / 256, 256, 0, st>>>(coeff2, basis2, loop_w2, pB2dh, D_H, D_O, 256, 1);

    {
        dim3 g(512 / 128, DOC_PAD / 128);
        gemm3<<<g, 256, GEMM_SMEM, st>>>(pXdh, pB1dh, pPd, N_DOC, 2 * D_H, D_IN);
    }

    // layer-1 aggregation
    {
        long long T = (long long)E_SS * (D_H / 4);
        scatter_scaled<<<(unsigned)((T + 255) / 256), 256, 0, st>>>(src_ss, dst_ss, E_SS, pPs, 3 * D_H, D_H, pA1s, D_H, pIss, D_H / 4);
    }
    {
        long long T = (long long)E_DS * (D_H / 4);
        scatter_scaled<<<(unsigned)((T + 255) / 256), 256, 0, st>>>(src_ds, dst_ds, E_DS, pPd, 2 * D_H, 0, pA1s, D_H, pIds, D_H / 4);
    }
    {
        long long T = (long long)E_SD * (D_H / 4);
        scatter_scaled<<<(unsigned)((T + 255) / 256), 256, 0, st>>>(src_sd, dst_sd, E_SD, pPs, 3 * D_H, 0, pA1d, D_H, pIsd, D_H / 4);
    }

    // layer-1 combine (emit fp16)
    combine_relu_h<<<(SENT_PAD * (D_H / 8) + 255) / 256, 256, 0, st>>>(pA1s, pPs, 3 * D_H, 2 * D_H, bias1, pHsh, N_SENT, SENT_PAD, D_H);
    combine_relu_h<<<(DOC_PAD * (D_H / 8) + 255) / 256, 256, 0, st>>>(pA1d, pPd, 2 * D_H, D_H, bias1, pHdh, N_DOC, DOC_PAD, D_H);

    // layer-2 projections
    {
        dim3 g(384 / 128, SENT_PAD / 128);
        gemm3<<<g, 256, GEMM_SMEM, st>>>(pHsh, pB2sh, pPs2, N_SENT, 3 * D_O, D_H);
    }
    {
        dim3 g(256 / 128, DOC_PAD / 128);
        gemm3<<<g, 256, GEMM_SMEM, st>>>(pHdh, pB2dh, pPd2, N_DOC, 2 * D_O, D_H);
    }

    // layer-2 aggregation
    {
        long long T = (long long)E_SS * (D_O / 4);
        scatter_scaled<<<(unsigned)((T + 255) / 256), 256, 0, st>>>(src_ss, dst_ss, E_SS, pPs2, 3 * D_O, D_O, pA2s, D_O, pIss, D_O / 4);
    }
    {
        long long T = (long long)E_DS * (D_O / 4);
        scatter_scaled<<<(unsigned)((T + 255) / 256), 256, 0, st>>>(src_ds, dst_ds, E_DS, pPd2, 2 * D_O, 0, pA2s, D_O, pIds, D_O / 4);
    }
    {
        long long T = (long long)E_SD * (D_O / 4);
        scatter_scaled<<<(unsigned)((T + 255) / 256), 256, 0, st>>>(src_sd, dst_sd, E_SD, pPs2, 3 * D_O, 0, pA2d, D_O, pIsd, D_O / 4);
    }

    // readout
    init_out<<<1, 32, 0, st>>>(out, b_score);
    combine2_readout<<<(N_SENT + 7) / 8, 256, 0, st>>>(pA2s, pPs2, 3 * D_O, 2 * D_O, bias2, w_score, gid_sent, out, N_SENT);
    combine2_readout<<<(N_DOC + 7) / 8, 256, 0, st>>>(pA2d, pPd2, 2 * D_O, D_O, bias2, w_score, gid_doc, out, N_DOC);
}

// round 9
// speedup vs baseline: 3.8207x; 1.2205x over previous
#include <cuda_runtime.h>
#include <cuda_fp16.h>
#include <cstdint>
#include <cstddef>

#define N_SENT 100000
#define N_DOC  10000
#define SENT_PAD 100096
#define DOC_PAD  10112
#define NGRAPH 32
#define D_IN   768
#define D_H    256
#define D_O    128
#define E_SS   400000
#define E_SD   100000
#define E_DS   100000

// ---------------- scratch (device globals: allocation-free) ----------------
__device__ __align__(16) __half g_B1s_h[768 * 768];
__device__ __align__(16) __half g_B1d_h[512 * 768];
__device__ __align__(16) __half g_B2s_h[384 * 256];
__device__ __align__(16) __half g_B2d_h[256 * 256];

__device__ __align__(16) __half g_xs_h[(size_t)SENT_PAD * D_IN];
__device__ __align__(16) __half g_xd_h[(size_t)DOC_PAD * D_IN];
__device__ __align__(16) __half g_hs_h[(size_t)SENT_PAD * D_H];
__device__ __align__(16) __half g_hd_h[(size_t)DOC_PAD * D_H];

__device__ float g_Ps [(size_t)N_SENT * (3 * D_H)];
__device__ float g_Pd [(size_t)N_DOC  * (2 * D_H)];
__device__ float g_Ps2[(size_t)N_SENT * (3 * D_O)];
__device__ float g_Pd2[(size_t)N_DOC  * (2 * D_O)];

// CSR structures (incoming edges per destination)
__device__ int   g_deg_ss[N_SENT], g_deg_ds[N_SENT], g_deg_sd[N_DOC];
__device__ int   g_ptr_ss[N_SENT], g_ptr_ds[N_SENT], g_ptr_sd[N_DOC];
__device__ int   g_cur_ss[N_SENT], g_cur_ds[N_SENT], g_cur_sd[N_DOC];
__device__ int   g_adj_ss[E_SS], g_adj_ds[E_DS], g_adj_sd[E_SD];
__device__ float g_inv_ss[N_SENT], g_inv_ds[N_SENT], g_inv_sd[N_DOC];
__device__ int   g_bsum_a[128], g_bsum_b[128], g_bsum_c[128];
__device__ int   g_part_ss[N_SENT], g_part_ds[N_SENT], g_part_sd[N_DOC];

// ---------------- PTX helpers ----------------
__device__ __forceinline__ uint32_t smem_u32(const void* p) {
    uint32_t a;
    asm("{ .reg .u64 t; cvta.to.shared.u64 t, %1; cvt.u32.u64 %0, t; }" : "=r"(a) : "l"(p));
    return a;
}

#define CP_ASYNC16(saddr, gaddr) \
    asm volatile("cp.async.cg.shared.global [%0], [%1], 16;" :: "r"(saddr), "l"(gaddr) : "memory")
#define CP_COMMIT() asm volatile("cp.async.commit_group;" ::: "memory")
#define CP_WAIT1()  asm volatile("cp.async.wait_group 1;" ::: "memory")

#define LDMX4(r0, r1, r2, r3, addr) \
    asm volatile("ldmatrix.sync.aligned.m8n8.x4.shared.b16 {%0,%1,%2,%3}, [%4];" \
                 : "=r"(r0), "=r"(r1), "=r"(r2), "=r"(r3) : "r"(addr))

#define MMA16816(d, a, b) \
    asm volatile("mma.sync.aligned.m16n8k16.row.col.f32.f16.f16.f32 " \
                 "{%0,%1,%2,%3}, {%4,%5,%6,%7}, {%8,%9}, {%0,%1,%2,%3};" \
                 : "+f"((d)[0]), "+f"((d)[1]), "+f"((d)[2]), "+f"((d)[3]) \
                 : "r"((a)[0]), "r"((a)[1]), "r"((a)[2]), "r"((a)[3]), "r"((b)[0]), "r"((b)[1]))

__device__ __forceinline__ uint4 pack8h(const float* f) {
    uint32_t hs[8];
    #pragma unroll
    for (int i = 0; i < 8; i++) hs[i] = (uint32_t)__half_as_ushort(__float2half(f[i]));
    return make_uint4(hs[0] | (hs[1] << 16), hs[2] | (hs[3] << 16), hs[4] | (hs[5] << 16), hs[6] | (hs[7] << 16));
}
__device__ __forceinline__ uint2 pack4h(float4 v) {
    uint32_t h0 = (uint32_t)__half_as_ushort(__float2half(v.x));
    uint32_t h1 = (uint32_t)__half_as_ushort(__float2half(v.y));
    uint32_t h2 = (uint32_t)__half_as_ushort(__float2half(v.z));
    uint32_t h3 = (uint32_t)__half_as_ushort(__float2half(v.w));
    return make_uint2(h0 | (h1 << 16), h2 | (h3 << 16));
}

#define ROWB   80

// ================= GEMM v3: fp16 x fp16, all-cp.async, 3-stage, 128x128 =================
#define ST_SZ  20480
#define OFF_A  0
#define OFF_B  10240
#define NSTAGE 3
#define GEMM_SMEM (NSTAGE * ST_SZ)

__global__ __launch_bounds__(256, 2) void gemm3(
    const __half* __restrict__ A,
    const __half* __restrict__ Bt,
    float* __restrict__ C, int M, int N, int K)
{
    extern __shared__ char smem[];
    uint32_t sb = smem_u32(smem);
    int tid = threadIdx.x;
    int lane = tid & 31, wid = tid >> 5;
    int warp_m = (wid & 3) * 32;
    int warp_n = (wid >> 2) * 64;
    int mrow0 = blockIdx.y * 128;
    int ncol0 = blockIdx.x * 128;
    int nk = K >> 5;

    int prow = tid >> 1;
    int pch  = (tid & 1) * 16;
    const __half* aP = A + (size_t)(mrow0 + prow) * K + pch;
    const __half* bP = Bt + (size_t)(ncol0 + prow) * K + pch;
    uint32_t sts = (uint32_t)(prow * ROWB + pch * 2);

    int ra = warp_m + (lane & 7) + (lane & 8);
    int ca = ((lane >> 4) << 3);
    uint32_t a_lm = (uint32_t)(ra * ROWB + ca * 2);
    int rb = warp_n + (lane & 7) + ((lane >> 4) << 3);
    int cb = (((lane >> 3) & 1) << 3);
    uint32_t b_lm = (uint32_t)(rb * ROWB + cb * 2);

    float acc[2][8][4];
    #pragma unroll
    for (int mi = 0; mi < 2; mi++)
        #pragma unroll
        for (int ni = 0; ni < 8; ni++)
            #pragma unroll
            for (int q = 0; q < 4; q++) acc[mi][ni][q] = 0.f;

    #pragma unroll
    for (int s = 0; s < 2; s++) {
        if (s < nk) {
            uint32_t base = sb + s * ST_SZ;
            const __half* ap = aP + s * 32;
            const __half* bp = bP + s * 32;
            CP_ASYNC16(base + OFF_A + sts, ap); CP_ASYNC16(base + OFF_A + sts + 16, ap + 8);
            CP_ASYNC16(base + OFF_B + sts, bp); CP_ASYNC16(base + OFF_B + sts + 16, bp + 8);
        }
        CP_COMMIT();
    }

    for (int kt = 0; kt < nk; kt++) {
        CP_WAIT1();
        __syncthreads();

        int pf = kt + 2;
        if (pf < nk) {
            uint32_t base = sb + (pf % NSTAGE) * ST_SZ;
            const __half* ap = aP + pf * 32;
            const __half* bp = bP + pf * 32;
            CP_ASYNC16(base + OFF_A + sts, ap); CP_ASYNC16(base + OFF_A + sts + 16, ap + 8);
            CP_ASYNC16(base + OFF_B + sts, bp); CP_ASYNC16(base + OFF_B + sts + 16, bp + 8);
        }
        CP_COMMIT();

        uint32_t bcur = sb + (kt % NSTAGE) * ST_SZ;
        #pragma unroll
        for (int ks = 0; ks < 2; ks++) {
            uint32_t koff = ks * 32;
            uint32_t af[2][4], bf[8][2];
            #pragma unroll
            for (int mi = 0; mi < 2; mi++)
                LDMX4(af[mi][0], af[mi][1], af[mi][2], af[mi][3],
                      bcur + OFF_A + a_lm + mi * (16 * ROWB) + koff);
            #pragma unroll
            for (int bg = 0; bg < 4; bg++)
                LDMX4(bf[bg * 2][0], bf[bg * 2][1], bf[bg * 2 + 1][0], bf[bg * 2 + 1][1],
                      bcur + OFF_B + b_lm + bg * (16 * ROWB) + koff);
            #pragma unroll
            for (int mi = 0; mi < 2; mi++)
                #pragma unroll
                for (int ni = 0; ni < 8; ni++)
                    MMA16816(acc[mi][ni], af[mi], bf[ni]);
        }
        __syncthreads();
    }

    int g = lane >> 2, t4 = lane & 3;
    #pragma unroll
    for (int mi = 0; mi < 2; mi++) {
        int r0 = mrow0 + warp_m + mi * 16 + g;
        #pragma unroll
        for (int ni = 0; ni < 8; ni++) {
            int col = ncol0 + warp_n + ni * 8 + t4 * 2;
            if (r0 < M)
                *(float2*)(C + (size_t)r0 * N + col) = make_float2(acc[mi][ni][0], acc[mi][ni][1]);
            if (r0 + 8 < M)
                *(float2*)(C + (size_t)(r0 + 8) * N + col) = make_float2(acc[mi][ni][2], acc[mi][ni][3]);
        }
    }
}

// ---------------- fp32 -> fp16 convert (padded, zero-filled) ----------------
__global__ void cvt_f16(const float* __restrict__ x, __half* __restrict__ hi,
                        long long nreal, long long npad) {
    long long base = ((long long)blockIdx.x * blockDim.x + threadIdx.x) * 8;
    if (base >= npad) return;
    float f[8];
    if (base < nreal) {
        float4 v0 = *(const float4*)(x + base);
        float4 v1 = *(const float4*)(x + base + 4);
        f[0] = v0.x; f[1] = v0.y; f[2] = v0.z; f[3] = v0.w;
        f[4] = v1.x; f[5] = v1.y; f[6] = v1.z; f[7] = v1.w;
    } else {
        #pragma unroll
        for (int q = 0; q < 8; q++) f[q] = 0.f;
    }
    *(uint4*)(hi + base) = pack8h(f);
}

// ---------------- CSR construction ----------------
__global__ void zero_deg() {
    int i = blockIdx.x * blockDim.x + threadIdx.x;
    if (i < N_SENT) { g_deg_ss[i] = 0; g_deg_ds[i] = 0; }
    if (i < N_DOC)  { g_deg_sd[i] = 0; }
}
__global__ void count_deg_i(const int* __restrict__ dst, int E, int* __restrict__ deg) {
    int i = blockIdx.x * blockDim.x + threadIdx.x;
    if (i < E) atomicAdd(&deg[dst[i]], 1);
}
__global__ void invert_deg_i(const int* __restrict__ deg, float* __restrict__ inv, int n) {
    int i = blockIdx.x * blockDim.x + threadIdx.x;
    if (i < n) inv[i] = 1.0f / (float)max(deg[i], 1);
}
// block-local exclusive scan (1024/block), emits block totals
__global__ void scan_local(const int* __restrict__ deg, int* __restrict__ part,
                           int* __restrict__ bsum, int n) {
    __shared__ int sm[1024];
    int i = blockIdx.x * 1024 + threadIdx.x;
    int v = (i < n) ? deg[i] : 0;
    sm[threadIdx.x] = v;
    __syncthreads();
    #pragma unroll
    for (int off = 1; off < 1024; off <<= 1) {
        int t = (threadIdx.x >= off) ? sm[threadIdx.x - off] : 0;
        __syncthreads();
        sm[threadIdx.x] += t;
        __syncthreads();
    }
    if (i < n) part[i] = sm[threadIdx.x] - v;
    if (threadIdx.x == 1023) bsum[blockIdx.x] = sm[1023];
}
// single-block exclusive scan of block sums (nb <= 128)
__global__ void scan_block(int* __restrict__ bsum, int nb) {
    __shared__ int sm[128];
    int v = (threadIdx.x < nb) ? bsum[threadIdx.x] : 0;
    sm[threadIdx.x] = v;
    __syncthreads();
    #pragma unroll
    for (int off = 1; off < 128; off <<= 1) {
        int t = (threadIdx.x >= off) ? sm[threadIdx.x - off] : 0;
        __syncthreads();
        sm[threadIdx.x] += t;
        __syncthreads();
    }
    if (threadIdx.x < nb) bsum[threadIdx.x] = sm[threadIdx.x] - v;
}
__global__ void scan_final(const int* __restrict__ part, const int* __restrict__ bsum,
                           int* __restrict__ ptr, int* __restrict__ cur, int n) {
    int i = blockIdx.x * blockDim.x + threadIdx.x;
    if (i < n) {
        int p = part[i] + bsum[i >> 10];
        ptr[i] = p;
        cur[i] = p;
    }
}
__global__ void fill_csr(const int* __restrict__ src, const int* __restrict__ dst, int E,
                         int* __restrict__ cur, int* __restrict__ adj) {
    int e = blockIdx.x * blockDim.x + threadIdx.x;
    if (e < E) {
        int p = atomicAdd(&cur[dst[e]], 1);
        adj[p] = src[e];
    }
}

// ---------------- weight build: transposed fp16 ----------------
__global__ void build_w3t(const float* __restrict__ coeff, const float* __restrict__ basis,
                          const float* __restrict__ loopw,
                          __half* __restrict__ outH,
                          int K, int D, int Npad, int r0, int r1) {
    int idx = blockIdx.x * blockDim.x + threadIdx.x;
    if (idx >= Npad * K) return;
    int o = idx / K;
    int k = idx % K;
    float v = 0.f;
    if (o < 3 * D) {
        int seg = o / D, od = o % D;
        if (seg == 2) v = loopw[k * D + od];
        else {
            int r = (seg == 0) ? r0 : r1;
            v = coeff[r * 2 + 0] * basis[(size_t)k * D + od]
              + coeff[r * 2 + 1] * basis[(size_t)K * D + (size_t)k * D + od];
        }
    }
    outH[idx] = __float2half(v);
}
__global__ void build_w2t(const float* __restrict__ coeff, const float* __restrict__ basis,
                          const float* __restrict__ loopw,
                          __half* __restrict__ outH,
                          int K, int D, int Npad, int r0) {
    int idx = blockIdx.x * blockDim.x + threadIdx.x;
    if (idx >= Npad * K) return;
    int o = idx / K;
    int k = idx % K;
    float v = 0.f;
    if (o < 2 * D) {
        int seg = o / D, od = o % D;
        if (seg == 1) v = loopw[k * D + od];
        else {
            v = coeff[r0 * 2 + 0] * basis[(size_t)k * D + od]
              + coeff[r0 * 2 + 1] * basis[(size_t)K * D + (size_t)k * D + od];
        }
    }
    outH[idx] = __float2half(v);
}

// ---------------- float4 ops ----------------
__device__ __forceinline__ float4 f4add(float4 a, float4 b) {
    return make_float4(a.x + b.x, a.y + b.y, a.z + b.z, a.w + b.w);
}
__device__ __forceinline__ float4 f4fma(float4 a, float s, float4 b) {
    return make_float4(fmaf(a.x, s, b.x), fmaf(a.y, s, b.y), fmaf(a.z, s, b.z), fmaf(a.w, s, b.w));
}
__device__ __forceinline__ float4 f4scale(float4 a, float s) {
    return make_float4(a.x * s, a.y * s, a.z * s, a.w * s);
}
__device__ __forceinline__ float4 f4relu(float4 a) {
    return make_float4(fmaxf(a.x, 0.f), fmaxf(a.y, 0.f), fmaxf(a.z, 0.f), fmaxf(a.w, 0.f));
}

// ---------------- layer-1 gather (warp per dst node) + combine + fp16 emit ----------------
// sent: h = relu( inv_ss*sum_ss Ps[src,256:512] + inv_ds*sum_ds Pd[src,0:256] + Ps[i,512:768] + bias )
__global__ void gather1_sent(const float* __restrict__ Ps, const float* __restrict__ Pd,
                             const float* __restrict__ bias, __half* __restrict__ hout) {
    int w = (blockIdx.x * blockDim.x + threadIdx.x) >> 5;
    int lane = threadIdx.x & 31;
    if (w >= SENT_PAD) return;
    __half* orow = hout + (size_t)w * D_H;
    if (w >= N_SENT) {
        *(uint2*)((char*)orow + lane * 8) = make_uint2(0u, 0u);
        *(uint2*)((char*)orow + 256 + lane * 8) = make_uint2(0u, 0u);
        return;
    }
    float4 A0 = make_float4(0.f, 0.f, 0.f, 0.f), A1 = A0;
    int p = g_ptr_ss[w], d = g_deg_ss[w];
    for (int k = 0; k < d; k++) {
        int s = g_adj_ss[p + k];
        const float4* r = (const float4*)(Ps + (size_t)s * 768 + 256);
        A0 = f4add(A0, r[lane]);
        A1 = f4add(A1, r[lane + 32]);
    }
    float sc = g_inv_ss[w];
    A0 = f4scale(A0, sc); A1 = f4scale(A1, sc);
    p = g_ptr_ds[w]; d = g_deg_ds[w];
    float sc2 = g_inv_ds[w];
    for (int k = 0; k < d; k++) {
        int s = g_adj_ds[p + k];
        const float4* r = (const float4*)(Pd + (size_t)s * 512);
        A0 = f4fma(r[lane], sc2, A0);
        A1 = f4fma(r[lane + 32], sc2, A1);
    }
    const float4* L = (const float4*)(Ps + (size_t)w * 768 + 512);
    const float4* B = (const float4*)bias;
    A0 = f4relu(f4add(f4add(A0, L[lane]), B[lane]));
    A1 = f4relu(f4add(f4add(A1, L[lane + 32]), B[lane + 32]));
    *(uint2*)((char*)orow + lane * 8) = pack4h(A0);
    *(uint2*)((char*)orow + 256 + lane * 8) = pack4h(A1);
}
// doc: h = relu( inv_sd*sum_sd Ps[src,0:256] + Pd[i,256:512] + bias )
__global__ void gather1_doc(const float* __restrict__ Ps, const float* __restrict__ Pd,
                            const float* __restrict__ bias, __half* __restrict__ hout) {
    int w = (blockIdx.x * blockDim.x + threadIdx.x) >> 5;
    int lane = threadIdx.x & 31;
    if (w >= DOC_PAD) return;
    __half* orow = hout + (size_t)w * D_H;
    if (w >= N_DOC) {
        *(uint2*)((char*)orow + lane * 8) = make_uint2(0u, 0u);
        *(uint2*)((char*)orow + 256 + lane * 8) = make_uint2(0u, 0u);
        return;
    }
    float4 A0 = make_float4(0.f, 0.f, 0.f, 0.f), A1 = A0;
    int p = g_ptr_sd[w], d = g_deg_sd[w];
    for (int k = 0; k < d; k++) {
        int s = g_adj_sd[p + k];
        const float4* r = (const float4*)(Ps + (size_t)s * 768);
        A0 = f4add(A0, r[lane]);
        A1 = f4add(A1, r[lane + 32]);
    }
    float sc = g_inv_sd[w];
    A0 = f4scale(A0, sc); A1 = f4scale(A1, sc);
    const float4* L = (const float4*)(Pd + (size_t)w * 512 + 256);
    const float4* B = (const float4*)bias;
    A0 = f4relu(f4add(f4add(A0, L[lane]), B[lane]));
    A1 = f4relu(f4add(f4add(A1, L[lane + 32]), B[lane + 32]));
    *(uint2*)((char*)orow + lane * 8) = pack4h(A0);
    *(uint2*)((char*)orow + 256 + lane * 8) = pack4h(A1);
}

// ---------------- layer-2 gather + combine + relu + score + per-graph reduce -------------
__global__ void init_out(float* __restrict__ out, const float* __restrict__ b_score) {
    int g = threadIdx.x;
    if (g < NGRAPH) out[g] = b_score[0];
}
// sent: v = relu( inv_ss*sum_ss Ps2[src,128:256] + inv_ds*sum_ds Pd2[src,0:128] + Ps2[i,256:384] + bias )
__global__ void gather2_sent(const float* __restrict__ Ps2, const float* __restrict__ Pd2,
                             const float* __restrict__ bias, const float* __restrict__ wscore,
                             const int* __restrict__ gid, float* __restrict__ out) {
    int w = (blockIdx.x * blockDim.x + threadIdx.x) >> 5;
    int lane = threadIdx.x & 31;
    if (w >= N_SENT) return;
    float4 A = make_float4(0.f, 0.f, 0.f, 0.f);
    int p = g_ptr_ss[w], d = g_deg_ss[w];
    for (int k = 0; k < d; k++) {
        int s = g_adj_ss[p + k];
        A = f4add(A, ((const float4*)(Ps2 + (size_t)s * 384 + 128))[lane]);
    }
    A = f4scale(A, g_inv_ss[w]);
    p = g_ptr_ds[w]; d = g_deg_ds[w];
    float sc2 = g_inv_ds[w];
    for (int k = 0; k < d; k++) {
        int s = g_adj_ds[p + k];
        A = f4fma(((const float4*)(Pd2 + (size_t)s * 256))[lane], sc2, A);
    }
    float4 L = ((const float4*)(Ps2 + (size_t)w * 384 + 256))[lane];
    float4 B = ((const float4*)bias)[lane];
    float4 W = ((const float4*)wscore)[lane];
    A = f4relu(f4add(f4add(A, L), B));
    float s = A.x * W.x + A.y * W.y + A.z * W.z + A.w * W.w;
    #pragma unroll
    for (int off = 16; off; off >>= 1) s += __shfl_down_sync(0xffffffffu, s, off);
    if (lane == 0) atomicAdd(&out[gid[w]], s);
}
// doc: v = relu( inv_sd*sum_sd Ps2[src,0:128] + Pd2[i,128:256] + bias )
__global__ void gather2_doc(const float* __restrict__ Ps2, const float* __restrict__ Pd2,
                            const float* __restrict__ bias, const float* __restrict__ wscore,
                            const int* __restrict__ gid, float* __restrict__ out) {
    int w = (blockIdx.x * blockDim.x + threadIdx.x) >> 5;
    int lane = threadIdx.x & 31;
    if (w >= N_DOC) return;
    float4 A = make_float4(0.f, 0.f, 0.f, 0.f);
    int p = g_ptr_sd[w], d = g_deg_sd[w];
    for (int k = 0; k < d; k++) {
        int s = g_adj_sd[p + k];
        A = f4add(A, ((const float4*)(Ps2 + (size_t)s * 384))[lane]);
    }
    A = f4scale(A, g_inv_sd[w]);
    float4 L = ((const float4*)(Pd2 + (size_t)w * 256 + 128))[lane];
    float4 B = ((const float4*)bias)[lane];
    float4 W = ((const float4*)wscore)[lane];
    A = f4relu(f4add(f4add(A, L), B));
    float s = A.x * W.x + A.y * W.y + A.z * W.z + A.w * W.w;
    #pragma unroll
    for (int off = 16; off; off >>= 1) s += __shfl_down_sync(0xffffffffu, s, off);
    if (lane == 0) atomicAdd(&out[gid[w]], s);
}

// ---------------- host launcher ----------------
static void* symaddr(const void* sym) {
    void* p = nullptr;
    cudaGetSymbolAddress(&p, sym);
    return p;
}

extern "C" void kernel_launch(void* const* d_in, const int* in_sizes, int n_in,
                              void* d_out, int out_size) {
    const float* x_sent  = (const float*)d_in[0];
    const float* x_doc   = (const float*)d_in[1];
    const float* coeff1  = (const float*)d_in[2];
    const float* basis1  = (const float*)d_in[3];
    const float* loop_w1 = (const float*)d_in[4];
    const float* bias1   = (const float*)d_in[5];
    const float* coeff2  = (const float*)d_in[6];
    const float* basis2  = (const float*)d_in[7];
    const float* loop_w2 = (const float*)d_in[8];
    const float* bias2   = (const float*)d_in[9];
    const float* w_score = (const float*)d_in[10];
    const float* b_score = (const float*)d_in[11];
    const int*   src_ss  = (const int*)d_in[12];
    const int*   dst_ss  = (const int*)d_in[13];
    const int*   src_sd  = (const int*)d_in[14];
    const int*   dst_sd  = (const int*)d_in[15];
    const int*   src_ds  = (const int*)d_in[16];
    const int*   dst_ds  = (const int*)d_in[17];
    const int*   gid_sent= (const int*)d_in[18];
    const int*   gid_doc = (const int*)d_in[19];
    float* out = (float*)d_out;

    __half* pB1sh = (__half*)symaddr(g_B1s_h);
    __half* pB1dh = (__half*)symaddr(g_B1d_h);
    __half* pB2sh = (__half*)symaddr(g_B2s_h);
    __half* pB2dh = (__half*)symaddr(g_B2d_h);
    __half* pXsh = (__half*)symaddr(g_xs_h);
    __half* pXdh = (__half*)symaddr(g_xd_h);
    __half* pHsh = (__half*)symaddr(g_hs_h);
    __half* pHdh = (__half*)symaddr(g_hd_h);
    float* pPs  = (float*)symaddr(g_Ps);
    float* pPd  = (float*)symaddr(g_Pd);
    float* pPs2 = (float*)symaddr(g_Ps2);
    float* pPd2 = (float*)symaddr(g_Pd2);

    int* pDegSS = (int*)symaddr(g_deg_ss);
    int* pDegDS = (int*)symaddr(g_deg_ds);
    int* pDegSD = (int*)symaddr(g_deg_sd);
    int* pPtrSS = (int*)symaddr(g_ptr_ss);
    int* pPtrDS = (int*)symaddr(g_ptr_ds);
    int* pPtrSD = (int*)symaddr(g_ptr_sd);
    int* pCurSS = (int*)symaddr(g_cur_ss);
    int* pCurDS = (int*)symaddr(g_cur_ds);
    int* pCurSD = (int*)symaddr(g_cur_sd);
    int* pAdjSS = (int*)symaddr(g_adj_ss);
    int* pAdjDS = (int*)symaddr(g_adj_ds);
    int* pAdjSD = (int*)symaddr(g_adj_sd);
    float* pInvSS = (float*)symaddr(g_inv_ss);
    float* pInvDS = (float*)symaddr(g_inv_ds);
    float* pInvSD = (float*)symaddr(g_inv_sd);
    int* pBa = (int*)symaddr(g_bsum_a);
    int* pBb = (int*)symaddr(g_bsum_b);
    int* pBc = (int*)symaddr(g_bsum_c);
    int* pPartSS = (int*)symaddr(g_part_ss);
    int* pPartDS = (int*)symaddr(g_part_ds);
    int* pPartSD = (int*)symaddr(g_part_sd);

    cudaFuncSetAttribute(gemm3, cudaFuncAttributeMaxDynamicSharedMemorySize, GEMM_SMEM);

    cudaStream_t st = 0;

    // Harness issues 2 launches before ours; global #5 = my idx 3 → big GEMM profiled.
    zero_deg<<<(N_SENT + 255) / 256, 256, 0, st>>>();                                        // idx 0
    {                                                                                        // idx 1
        long long nreal = (long long)N_SENT * D_IN, npad = (long long)SENT_PAD * D_IN;
        cvt_f16<<<(unsigned)((npad / 8 + 255) / 256), 256, 0, st>>>(x_sent, pXsh, nreal, npad);
    }
    build_w3t<<<(768 * 768 + 255) / 256, 256, 0, st>>>(coeff1, basis1, loop_w1, pB1sh, D_IN, D_H, 768, 0, 2); // idx 2
    {                                                                                        // idx 3 (ncu -s 5)
        dim3 g(768 / 128, SENT_PAD / 128);
        gemm3<<<g, 256, GEMM_SMEM, st>>>(pXsh, pB1sh, pPs, N_SENT, 3 * D_H, D_IN);
    }

    // ---- CSR build ----
    count_deg_i<<<(E_SS + 255) / 256, 256, 0, st>>>(dst_ss, E_SS, pDegSS);
    count_deg_i<<<(E_DS + 255) / 256, 256, 0, st>>>(dst_ds, E_DS, pDegDS);
    count_deg_i<<<(E_SD + 255) / 256, 256, 0, st>>>(dst_sd, E_SD, pDegSD);
    invert_deg_i<<<(N_SENT + 255) / 256, 256, 0, st>>>(pDegSS, pInvSS, N_SENT);
    invert_deg_i<<<(N_SENT + 255) / 256, 256, 0, st>>>(pDegDS, pInvDS, N_SENT);
    invert_deg_i<<<(N_DOC + 255) / 256, 256, 0, st>>>(pDegSD, pInvSD, N_DOC);
    {
        int nbS = (N_SENT + 1023) / 1024;   // 98
        int nbD = (N_DOC + 1023) / 1024;    // 10
        scan_local<<<nbS, 1024, 0, st>>>(pDegSS, pPartSS, pBa, N_SENT);
        scan_local<<<nbS, 1024, 0, st>>>(pDegDS, pPartDS, pBb, N_SENT);
        scan_local<<<nbD, 1024, 0, st>>>(pDegSD, pPartSD, pBc, N_DOC);
        scan_block<<<1, 128, 0, st>>>(pBa, nbS);
        scan_block<<<1, 128, 0, st>>>(pBb, nbS);
        scan_block<<<1, 128, 0, st>>>(pBc, nbD);
        scan_final<<<(N_SENT + 255) / 256, 256, 0, st>>>(pPartSS, pBa, pPtrSS, pCurSS, N_SENT);
        scan_final<<<(N_SENT + 255) / 256, 256, 0, st>>>(pPartDS, pBb, pPtrDS, pCurDS, N_SENT);
        scan_final<<<(N_DOC + 255) / 256, 256, 0, st>>>(pPartSD, pBc, pPtrSD, pCurSD, N_DOC);
        fill_csr<<<(E_SS + 255) / 256, 256, 0, st>>>(src_ss, dst_ss, E_SS, pCurSS, pAdjSS);
        fill_csr<<<(E_DS + 255) / 256, 256, 0, st>>>(src_ds, dst_ds, E_DS, pCurDS, pAdjDS);
        fill_csr<<<(E_SD + 255) / 256, 256, 0, st>>>(src_sd, dst_sd, E_SD, pCurSD, pAdjSD);
    }

    // remaining inputs + weights + doc GEMM
    {
        long long nreal = (long long)N_DOC * D_IN, npad = (long long)DOC_PAD * D_IN;
        cvt_f16<<<(unsigned)((npad / 8 + 255) / 256), 256, 0, st>>>(x_doc, pXdh, nreal, npad);
    }
    build_w2t<<<(512 * 768 + 255) / 256, 256, 0, st>>>(coeff1, basis1, loop_w1, pB1dh, D_IN, D_H, 512, 1);
    build_w3t<<<(384 * 256 + 255) / 256, 256, 0, st>>>(coeff2, basis2, loop_w2, pB2sh, D_H, D_O, 384, 0, 2);
    build_w2t<<<(256 * 256 + 255) / 256, 256, 0, st>>>(coeff2, basis2, loop_w2, pB2dh, D_H, D_O, 256, 1);
    {
        dim3 g(512 / 128, DOC_PAD / 128);
        gemm3<<<g, 256, GEMM_SMEM, st>>>(pXdh, pB1dh, pPd, N_DOC, 2 * D_H, D_IN);
    }

    // layer-1 gather + combine -> fp16 h
    gather1_sent<<<(SENT_PAD * 32 + 255) / 256, 256, 0, st>>>(pPs, pPd, bias1, pHsh);
    gather1_doc<<<(DOC_PAD * 32 + 255) / 256, 256, 0, st>>>(pPs, pPd, bias1, pHdh);

    // layer-2 projections
    {
        dim3 g(384 / 128, SENT_PAD / 128);
        gemm3<<<g, 256, GEMM_SMEM, st>>>(pHsh, pB2sh, pPs2, N_SENT, 3 * D_O, D_H);
    }
    {
        dim3 g(256 / 128, DOC_PAD / 128);
        gemm3<<<g, 256, GEMM_SMEM, st>>>(pHdh, pB2dh, pPd2, N_DOC, 2 * D_O, D_H);
    }

    // layer-2 gather + combine + readout
    init_out<<<1, 32, 0, st>>>(out, b_score);
    gather2_sent<<<(N_SENT * 32 + 255) / 256, 256, 0, st>>>(pPs2, pPd2, bias2, w_score, gid_sent, out);
    gather2_doc<<<(N_DOC * 32 + 255) / 256, 256, 0, st>>>(pPs2, pPd2, bias2, w_score, gid_doc, out);
}

// round 10
// speedup vs baseline: 3.9609x; 1.0367x over previous
#include <cuda_runtime.h>
#include <cuda_fp16.h>
#include <cstdint>
#include <cstddef>

#define N_SENT 100000
#define N_DOC  10000
#define SENT_PAD 100096
#define DOC_PAD  10112
#define NGRAPH 32
#define D_IN   768
#define D_H    256
#define D_O    128
#define E_SS   400000
#define E_SD   100000
#define E_DS   100000

// ---------------- scratch (device globals: allocation-free) ----------------
__device__ __align__(16) __half g_B1s_h[768 * 768];
__device__ __align__(16) __half g_B1d_h[512 * 768];
__device__ __align__(16) __half g_B2s_h[384 * 256];
__device__ __align__(16) __half g_B2d_h[256 * 256];

__device__ __align__(16) __half g_xs_h[(size_t)SENT_PAD * D_IN];
__device__ __align__(16) __half g_xd_h[(size_t)DOC_PAD * D_IN];
__device__ __align__(16) __half g_hs_h[(size_t)SENT_PAD * D_H];
__device__ __align__(16) __half g_hd_h[(size_t)DOC_PAD * D_H];

// fp16 projection outputs
__device__ __align__(16) __half g_Ps [(size_t)N_SENT * (3 * D_H)];
__device__ __align__(16) __half g_Pd [(size_t)N_DOC  * (2 * D_H)];
__device__ __align__(16) __half g_Ps2[(size_t)N_SENT * (3 * D_O)];
__device__ __align__(16) __half g_Pd2[(size_t)N_DOC  * (2 * D_O)];

// CSR structures (incoming edges per destination)
__device__ int   g_deg_ss[N_SENT], g_deg_ds[N_SENT], g_deg_sd[N_DOC];
__device__ int   g_ptr_ss[N_SENT], g_ptr_ds[N_SENT], g_ptr_sd[N_DOC];
__device__ int   g_cur_ss[N_SENT], g_cur_ds[N_SENT], g_cur_sd[N_DOC];
__device__ int   g_adj_ss[E_SS], g_adj_ds[E_DS], g_adj_sd[E_SD];
__device__ float g_inv_ss[N_SENT], g_inv_ds[N_SENT], g_inv_sd[N_DOC];
__device__ int   g_bsum_a[128], g_bsum_b[128], g_bsum_c[128];
__device__ int   g_part_ss[N_SENT], g_part_ds[N_SENT], g_part_sd[N_DOC];

// ---------------- PTX helpers ----------------
__device__ __forceinline__ uint32_t smem_u32(const void* p) {
    uint32_t a;
    asm("{ .reg .u64 t; cvta.to.shared.u64 t, %1; cvt.u32.u64 %0, t; }" : "=r"(a) : "l"(p));
    return a;
}

#define CP_ASYNC16(saddr, gaddr) \
    asm volatile("cp.async.cg.shared.global [%0], [%1], 16;" :: "r"(saddr), "l"(gaddr) : "memory")
#define CP_COMMIT() asm volatile("cp.async.commit_group;" ::: "memory")
#define CP_WAIT1()  asm volatile("cp.async.wait_group 1;" ::: "memory")

#define LDMX4(r0, r1, r2, r3, addr) \
    asm volatile("ldmatrix.sync.aligned.m8n8.x4.shared.b16 {%0,%1,%2,%3}, [%4];" \
                 : "=r"(r0), "=r"(r1), "=r"(r2), "=r"(r3) : "r"(addr))

#define MMA16816(d, a, b) \
    asm volatile("mma.sync.aligned.m16n8k16.row.col.f32.f16.f16.f32 " \
                 "{%0,%1,%2,%3}, {%4,%5,%6,%7}, {%8,%9}, {%0,%1,%2,%3};" \
                 : "+f"((d)[0]), "+f"((d)[1]), "+f"((d)[2]), "+f"((d)[3]) \
                 : "r"((a)[0]), "r"((a)[1]), "r"((a)[2]), "r"((a)[3]), "r"((b)[0]), "r"((b)[1]))

__device__ __forceinline__ uint4 pack8h(const float* f) {
    uint32_t hs[8];
    #pragma unroll
    for (int i = 0; i < 8; i++) hs[i] = (uint32_t)__half_as_ushort(__float2half(f[i]));
    return make_uint4(hs[0] | (hs[1] << 16), hs[2] | (hs[3] << 16), hs[4] | (hs[5] << 16), hs[6] | (hs[7] << 16));
}
__device__ __forceinline__ void add8h(float* A, uint4 v) {
    const __half2* h = (const __half2*)&v;
    #pragma unroll
    for (int i = 0; i < 4; i++) {
        float2 f = __half22float2(h[i]);
        A[2 * i] += f.x; A[2 * i + 1] += f.y;
    }
}
__device__ __forceinline__ void unpack8h(float* A, uint4 v) {
    const __half2* h = (const __half2*)&v;
    #pragma unroll
    for (int i = 0; i < 4; i++) {
        float2 f = __half22float2(h[i]);
        A[2 * i] = f.x; A[2 * i + 1] = f.y;
    }
}
__device__ __forceinline__ void add4h(float* A, uint2 v) {
    const __half2* h = (const __half2*)&v;
    #pragma unroll
    for (int i = 0; i < 2; i++) {
        float2 f = __half22float2(h[i]);
        A[2 * i] += f.x; A[2 * i + 1] += f.y;
    }
}

#define ROWB   80

// ================= GEMM v4: fp16 x fp16 -> fp16, 3-stage single-sync, 128x128 =============
#define ST_SZ  20480
#define OFF_A  0
#define OFF_B  10240
#define NSTAGE 3
#define GEMM_SMEM (NSTAGE * ST_SZ)

__global__ __launch_bounds__(256, 2) void gemm4(
    const __half* __restrict__ A,
    const __half* __restrict__ Bt,
    __half* __restrict__ C, int M, int N, int K)
{
    extern __shared__ char smem[];
    uint32_t sb = smem_u32(smem);
    int tid = threadIdx.x;
    int lane = tid & 31, wid = tid >> 5;
    int warp_m = (wid & 3) * 32;
    int warp_n = (wid >> 2) * 64;
    int mrow0 = blockIdx.y * 128;
    int ncol0 = blockIdx.x * 128;
    int nk = K >> 5;

    int prow = tid >> 1;
    int pch  = (tid & 1) * 16;
    const __half* aP = A + (size_t)(mrow0 + prow) * K + pch;
    const __half* bP = Bt + (size_t)(ncol0 + prow) * K + pch;
    uint32_t sts = (uint32_t)(prow * ROWB + pch * 2);

    int ra = warp_m + (lane & 7) + (lane & 8);
    int ca = ((lane >> 4) << 3);
    uint32_t a_lm = (uint32_t)(ra * ROWB + ca * 2);
    int rb = warp_n + (lane & 7) + ((lane >> 4) << 3);
    int cb = (((lane >> 3) & 1) << 3);
    uint32_t b_lm = (uint32_t)(rb * ROWB + cb * 2);

    float acc[2][8][4];
    #pragma unroll
    for (int mi = 0; mi < 2; mi++)
        #pragma unroll
        for (int ni = 0; ni < 8; ni++)
            #pragma unroll
            for (int q = 0; q < 4; q++) acc[mi][ni][q] = 0.f;

    #pragma unroll
    for (int s = 0; s < 2; s++) {
        if (s < nk) {
            uint32_t base = sb + s * ST_SZ;
            const __half* ap = aP + s * 32;
            const __half* bp = bP + s * 32;
            CP_ASYNC16(base + OFF_A + sts, ap); CP_ASYNC16(base + OFF_A + sts + 16, ap + 8);
            CP_ASYNC16(base + OFF_B + sts, bp); CP_ASYNC16(base + OFF_B + sts + 16, bp + 8);
        }
        CP_COMMIT();
    }

    for (int kt = 0; kt < nk; kt++) {
        CP_WAIT1();
        __syncthreads();            // single barrier per iteration: all stage-kt data visible,
                                    // and all warps finished reading buffer (kt+2)%3 in iter kt-1
        int pf = kt + 2;
        if (pf < nk) {
            uint32_t base = sb + (pf % NSTAGE) * ST_SZ;
            const __half* ap = aP + pf * 32;
            const __half* bp = bP + pf * 32;
            CP_ASYNC16(base + OFF_A + sts, ap); CP_ASYNC16(base + OFF_A + sts + 16, ap + 8);
            CP_ASYNC16(base + OFF_B + sts, bp); CP_ASYNC16(base + OFF_B + sts + 16, bp + 8);
        }
        CP_COMMIT();

        uint32_t bcur = sb + (kt % NSTAGE) * ST_SZ;
        #pragma unroll
        for (int ks = 0; ks < 2; ks++) {
            uint32_t koff = ks * 32;
            uint32_t af[2][4], bf[8][2];
            #pragma unroll
            for (int mi = 0; mi < 2; mi++)
                LDMX4(af[mi][0], af[mi][1], af[mi][2], af[mi][3],
                      bcur + OFF_A + a_lm + mi * (16 * ROWB) + koff);
            #pragma unroll
            for (int bg = 0; bg < 4; bg++)
                LDMX4(bf[bg * 2][0], bf[bg * 2][1], bf[bg * 2 + 1][0], bf[bg * 2 + 1][1],
                      bcur + OFF_B + b_lm + bg * (16 * ROWB) + koff);
            #pragma unroll
            for (int mi = 0; mi < 2; mi++)
                #pragma unroll
                for (int ni = 0; ni < 8; ni++)
                    MMA16816(acc[mi][ni], af[mi], bf[ni]);
        }
    }

    int g = lane >> 2, t4 = lane & 3;
    #pragma unroll
    for (int mi = 0; mi < 2; mi++) {
        int r0 = mrow0 + warp_m + mi * 16 + g;
        #pragma unroll
        for (int ni = 0; ni < 8; ni++) {
            int col = ncol0 + warp_n + ni * 8 + t4 * 2;
            if (r0 < M)
                *(__half2*)(C + (size_t)r0 * N + col) = __floats2half2_rn(acc[mi][ni][0], acc[mi][ni][1]);
            if (r0 + 8 < M)
                *(__half2*)(C + (size_t)(r0 + 8) * N + col) = __floats2half2_rn(acc[mi][ni][2], acc[mi][ni][3]);
        }
    }
}

// ---------------- fp32 -> fp16 convert (padded, zero-filled) ----------------
__global__ void cvt_f16(const float* __restrict__ x, __half* __restrict__ hi,
                        long long nreal, long long npad) {
    long long base = ((long long)blockIdx.x * blockDim.x + threadIdx.x) * 8;
    if (base >= npad) return;
    float f[8];
    if (base < nreal) {
        float4 v0 = *(const float4*)(x + base);
        float4 v1 = *(const float4*)(x + base + 4);
        f[0] = v0.x; f[1] = v0.y; f[2] = v0.z; f[3] = v0.w;
        f[4] = v1.x; f[5] = v1.y; f[6] = v1.z; f[7] = v1.w;
    } else {
        #pragma unroll
        for (int q = 0; q < 8; q++) f[q] = 0.f;
    }
    *(uint4*)(hi + base) = pack8h(f);
}

// ---------------- CSR construction ----------------
__global__ void zero_deg() {
    int i = blockIdx.x * blockDim.x + threadIdx.x;
    if (i < N_SENT) { g_deg_ss[i] = 0; g_deg_ds[i] = 0; }
    if (i < N_DOC)  { g_deg_sd[i] = 0; }
}
__global__ void count_deg_i(const int* __restrict__ dst, int E, int* __restrict__ deg) {
    int i = blockIdx.x * blockDim.x + threadIdx.x;
    if (i < E) atomicAdd(&deg[dst[i]], 1);
}
__global__ void invert_deg_i(const int* __restrict__ deg, float* __restrict__ inv, int n) {
    int i = blockIdx.x * blockDim.x + threadIdx.x;
    if (i < n) inv[i] = 1.0f / (float)max(deg[i], 1);
}
__global__ void scan_local(const int* __restrict__ deg, int* __restrict__ part,
                           int* __restrict__ bsum, int n) {
    __shared__ int sm[1024];
    int i = blockIdx.x * 1024 + threadIdx.x;
    int v = (i < n) ? deg[i] : 0;
    sm[threadIdx.x] = v;
    __syncthreads();
    #pragma unroll
    for (int off = 1; off < 1024; off <<= 1) {
        int t = (threadIdx.x >= off) ? sm[threadIdx.x - off] : 0;
        __syncthreads();
        sm[threadIdx.x] += t;
        __syncthreads();
    }
    if (i < n) part[i] = sm[threadIdx.x] - v;
    if (threadIdx.x == 1023) bsum[blockIdx.x] = sm[1023];
}
__global__ void scan_block(int* __restrict__ bsum, int nb) {
    __shared__ int sm[128];
    int v = (threadIdx.x < nb) ? bsum[threadIdx.x] : 0;
    sm[threadIdx.x] = v;
    __syncthreads();
    #pragma unroll
    for (int off = 1; off < 128; off <<= 1) {
        int t = (threadIdx.x >= off) ? sm[threadIdx.x - off] : 0;
        __syncthreads();
        sm[threadIdx.x] += t;
        __syncthreads();
    }
    if (threadIdx.x < nb) bsum[threadIdx.x] = sm[threadIdx.x] - v;
}
__global__ void scan_final(const int* __restrict__ part, const int* __restrict__ bsum,
                           int* __restrict__ ptr, int* __restrict__ cur, int n) {
    int i = blockIdx.x * blockDim.x + threadIdx.x;
    if (i < n) {
        int p = part[i] + bsum[i >> 10];
        ptr[i] = p;
        cur[i] = p;
    }
}
__global__ void fill_csr(const int* __restrict__ src, const int* __restrict__ dst, int E,
                         int* __restrict__ cur, int* __restrict__ adj) {
    int e = blockIdx.x * blockDim.x + threadIdx.x;
    if (e < E) {
        int p = atomicAdd(&cur[dst[e]], 1);
        adj[p] = src[e];
    }
}

// ---------------- weight build: transposed fp16 ----------------
__global__ void build_w3t(const float* __restrict__ coeff, const float* __restrict__ basis,
                          const float* __restrict__ loopw,
                          __half* __restrict__ outH,
                          int K, int D, int Npad, int r0, int r1) {
    int idx = blockIdx.x * blockDim.x + threadIdx.x;
    if (idx >= Npad * K) return;
    int o = idx / K;
    int k = idx % K;
    float v = 0.f;
    if (o < 3 * D) {
        int seg = o / D, od = o % D;
        if (seg == 2) v = loopw[k * D + od];
        else {
            int r = (seg == 0) ? r0 : r1;
            v = coeff[r * 2 + 0] * basis[(size_t)k * D + od]
              + coeff[r * 2 + 1] * basis[(size_t)K * D + (size_t)k * D + od];
        }
    }
    outH[idx] = __float2half(v);
}
__global__ void build_w2t(const float* __restrict__ coeff, const float* __restrict__ basis,
                          const float* __restrict__ loopw,
                          __half* __restrict__ outH,
                          int K, int D, int Npad, int r0) {
    int idx = blockIdx.x * blockDim.x + threadIdx.x;
    if (idx >= Npad * K) return;
    int o = idx / K;
    int k = idx % K;
    float v = 0.f;
    if (o < 2 * D) {
        int seg = o / D, od = o % D;
        if (seg == 1) v = loopw[k * D + od];
        else {
            v = coeff[r0 * 2 + 0] * basis[(size_t)k * D + od]
              + coeff[r0 * 2 + 1] * basis[(size_t)K * D + (size_t)k * D + od];
        }
    }
    outH[idx] = __float2half(v);
}

// ---------------- layer-1 gather (warp per dst node) + combine + fp16 emit ----------------
__global__ void gather1_sent(const __half* __restrict__ Ps, const __half* __restrict__ Pd,
                             const float* __restrict__ bias, __half* __restrict__ hout) {
    int w = (blockIdx.x * blockDim.x + threadIdx.x) >> 5;
    int lane = threadIdx.x & 31;
    if (w >= SENT_PAD) return;
    __half* orow = hout + (size_t)w * D_H;
    if (w >= N_SENT) {
        *(uint4*)(orow + lane * 8) = make_uint4(0u, 0u, 0u, 0u);
        return;
    }
    float A[8] = {0.f}, Bv[8] = {0.f};
    int p = g_ptr_ss[w], d = g_deg_ss[w];
    for (int k = 0; k < d; k++) {
        int s = g_adj_ss[p + k];
        add8h(A, *(const uint4*)(Ps + (size_t)s * 768 + 256 + lane * 8));
    }
    float sc = g_inv_ss[w];
    p = g_ptr_ds[w]; d = g_deg_ds[w];
    for (int k = 0; k < d; k++) {
        int s = g_adj_ds[p + k];
        add4h(Bv,     *(const uint2*)(Pd + (size_t)s * 512 + lane * 8));
        add4h(Bv + 4, *(const uint2*)(Pd + (size_t)s * 512 + lane * 8 + 4));
    }
    float sc2 = g_inv_ds[w];
    float L[8];
    unpack8h(L, *(const uint4*)(Ps + (size_t)w * 768 + 512 + lane * 8));
    float f[8];
    #pragma unroll
    for (int i = 0; i < 8; i++)
        f[i] = fmaxf(fmaf(A[i], sc, fmaf(Bv[i], sc2, L[i] + bias[lane * 8 + i])), 0.f);
    *(uint4*)(orow + lane * 8) = pack8h(f);
}
__global__ void gather1_doc(const __half* __restrict__ Ps, const __half* __restrict__ Pd,
                            const float* __restrict__ bias, __half* __restrict__ hout) {
    int w = (blockIdx.x * blockDim.x + threadIdx.x) >> 5;
    int lane = threadIdx.x & 31;
    if (w >= DOC_PAD) return;
    __half* orow = hout + (size_t)w * D_H;
    if (w >= N_DOC) {
        *(uint4*)(orow + lane * 8) = make_uint4(0u, 0u, 0u, 0u);
        return;
    }
    float A[8] = {0.f};
    int p = g_ptr_sd[w], d = g_deg_sd[w];
    for (int k = 0; k < d; k++) {
        int s = g_adj_sd[p + k];
        add8h(A, *(const uint4*)(Ps + (size_t)s * 768 + lane * 8));
    }
    float sc = g_inv_sd[w];
    float L[8];
    unpack8h(L, *(const uint4*)(Pd + (size_t)w * 512 + 256 + lane * 8));
    float f[8];
    #pragma unroll
    for (int i = 0; i < 8; i++)
        f[i] = fmaxf(fmaf(A[i], sc, L[i] + bias[lane * 8 + i]), 0.f);
    *(uint4*)(orow + lane * 8) = pack8h(f);
}

// ---------------- layer-2 gather + combine + relu + score + per-graph reduce -------------
__global__ void init_out(float* __restrict__ out, const float* __restrict__ b_score) {
    int g = threadIdx.x;
    if (g < NGRAPH) out[g] = b_score[0];
}
__global__ void gather2_sent(const __half* __restrict__ Ps2, const __half* __restrict__ Pd2,
                             const float* __restrict__ bias, const float* __restrict__ wscore,
                             const int* __restrict__ gid, float* __restrict__ out) {
    int w = (blockIdx.x * blockDim.x + threadIdx.x) >> 5;
    int lane = threadIdx.x & 31;
    if (w >= N_SENT) return;
    float A[4] = {0.f}, Bv[4] = {0.f};
    int p = g_ptr_ss[w], d = g_deg_ss[w];
    for (int k = 0; k < d; k++) {
        int s = g_adj_ss[p + k];
        add4h(A, *(const uint2*)(Ps2 + (size_t)s * 384 + 128 + lane * 4));
    }
    float sc = g_inv_ss[w];
    p = g_ptr_ds[w]; d = g_deg_ds[w];
    for (int k = 0; k < d; k++) {
        int s = g_adj_ds[p + k];
        add4h(Bv, *(const uint2*)(Pd2 + (size_t)s * 256 + lane * 4));
    }
    float sc2 = g_inv_ds[w];
    float L[4] = {0.f};
    add4h(L, *(const uint2*)(Ps2 + (size_t)w * 384 + 256 + lane * 4));
    float4 B = ((const float4*)bias)[lane];
    float4 W = ((const float4*)wscore)[lane];
    float bb[4] = {B.x, B.y, B.z, B.w};
    float ww[4] = {W.x, W.y, W.z, W.w};
    float s = 0.f;
    #pragma unroll
    for (int i = 0; i < 4; i++)
        s += fmaxf(fmaf(A[i], sc, fmaf(Bv[i], sc2, L[i] + bb[i])), 0.f) * ww[i];
    #pragma unroll
    for (int off = 16; off; off >>= 1) s += __shfl_down_sync(0xffffffffu, s, off);
    if (lane == 0) atomicAdd(&out[gid[w]], s);
}
__global__ void gather2_doc(const __half* __restrict__ Ps2, const __half* __restrict__ Pd2,
                            const float* __restrict__ bias, const float* __restrict__ wscore,
                            const int* __restrict__ gid, float* __restrict__ out) {
    int w = (blockIdx.x * blockDim.x + threadIdx.x) >> 5;
    int lane = threadIdx.x & 31;
    if (w >= N_DOC) return;
    float A[4] = {0.f};
    int p = g_ptr_sd[w], d = g_deg_sd[w];
    for (int k = 0; k < d; k++) {
        int s = g_adj_sd[p + k];
        add4h(A, *(const uint2*)(Ps2 + (size_t)s * 384 + lane * 4));
    }
    float sc = g_inv_sd[w];
    float L[4] = {0.f};
    add4h(L, *(const uint2*)(Pd2 + (size_t)w * 256 + 128 + lane * 4));
    float4 B = ((const float4*)bias)[lane];
    float4 W = ((const float4*)wscore)[lane];
    float bb[4] = {B.x, B.y, B.z, B.w};
    float ww[4] = {W.x, W.y, W.z, W.w};
    float s = 0.f;
    #pragma unroll
    for (int i = 0; i < 4; i++)
        s += fmaxf(fmaf(A[i], sc, L[i] + bb[i]), 0.f) * ww[i];
    #pragma unroll
    for (int off = 16; off; off >>= 1) s += __shfl_down_sync(0xffffffffu, s, off);
    if (lane == 0) atomicAdd(&out[gid[w]], s);
}

// ---------------- host launcher ----------------
static void* symaddr(const void* sym) {
    void* p = nullptr;
    cudaGetSymbolAddress(&p, sym);
    return p;
}

extern "C" void kernel_launch(void* const* d_in, const int* in_sizes, int n_in,
                              void* d_out, int out_size) {
    const float* x_sent  = (const float*)d_in[0];
    const float* x_doc   = (const float*)d_in[1];
    const float* coeff1  = (const float*)d_in[2];
    const float* basis1  = (const float*)d_in[3];
    const float* loop_w1 = (const float*)d_in[4];
    const float* bias1   = (const float*)d_in[5];
    const float* coeff2  = (const float*)d_in[6];
    const float* basis2  = (const float*)d_in[7];
    const float* loop_w2 = (const float*)d_in[8];
    const float* bias2   = (const float*)d_in[9];
    const float* w_score = (const float*)d_in[10];
    const float* b_score = (const float*)d_in[11];
    const int*   src_ss  = (const int*)d_in[12];
    const int*   dst_ss  = (const int*)d_in[13];
    const int*   src_sd  = (const int*)d_in[14];
    const int*   dst_sd  = (const int*)d_in[15];
    const int*   src_ds  = (const int*)d_in[16];
    const int*   dst_ds  = (const int*)d_in[17];
    const int*   gid_sent= (const int*)d_in[18];
    const int*   gid_doc = (const int*)d_in[19];
    float* out = (float*)d_out;

    __half* pB1sh = (__half*)symaddr(g_B1s_h);
    __half* pB1dh = (__half*)symaddr(g_B1d_h);
    __half* pB2sh = (__half*)symaddr(g_B2s_h);
    __half* pB2dh = (__half*)symaddr(g_B2d_h);
    __half* pXsh = (__half*)symaddr(g_xs_h);
    __half* pXdh = (__half*)symaddr(g_xd_h);
    __half* pHsh = (__half*)symaddr(g_hs_h);
    __half* pHdh = (__half*)symaddr(g_hd_h);
    __half* pPs  = (__half*)symaddr(g_Ps);
    __half* pPd  = (__half*)symaddr(g_Pd);
    __half* pPs2 = (__half*)symaddr(g_Ps2);
    __half* pPd2 = (__half*)symaddr(g_Pd2);

    int* pDegSS = (int*)symaddr(g_deg_ss);
    int* pDegDS = (int*)symaddr(g_deg_ds);
    int* pDegSD = (int*)symaddr(g_deg_sd);
    int* pPtrSS = (int*)symaddr(g_ptr_ss);
    int* pPtrDS = (int*)symaddr(g_ptr_ds);
    int* pPtrSD = (int*)symaddr(g_ptr_sd);
    int* pCurSS = (int*)symaddr(g_cur_ss);
    int* pCurDS = (int*)symaddr(g_cur_ds);
    int* pCurSD = (int*)symaddr(g_cur_sd);
    int* pAdjSS = (int*)symaddr(g_adj_ss);
    int* pAdjDS = (int*)symaddr(g_adj_ds);
    int* pAdjSD = (int*)symaddr(g_adj_sd);
    float* pInvSS = (float*)symaddr(g_inv_ss);
    float* pInvDS = (float*)symaddr(g_inv_ds);
    float* pInvSD = (float*)symaddr(g_inv_sd);
    int* pBa = (int*)symaddr(g_bsum_a);
    int* pBb = (int*)symaddr(g_bsum_b);
    int* pBc = (int*)symaddr(g_bsum_c);
    int* pPartSS = (int*)symaddr(g_part_ss);
    int* pPartDS = (int*)symaddr(g_part_ds);
    int* pPartSD = (int*)symaddr(g_part_sd);

    cudaFuncSetAttribute(gemm4, cudaFuncAttributeMaxDynamicSharedMemorySize, GEMM_SMEM);

    cudaStream_t st = 0;

    // Harness issues 2 launches before ours; global #5 = my idx 3 → big GEMM profiled.
    zero_deg<<<(N_SENT + 255) / 256, 256, 0, st>>>();                                        // idx 0
    {                                                                                        // idx 1
        long long nreal = (long long)N_SENT * D_IN, npad = (long long)SENT_PAD * D_IN;
        cvt_f16<<<(unsigned)((npad / 8 + 255) / 256), 256, 0, st>>>(x_sent, pXsh, nreal, npad);
    }
    build_w3t<<<(768 * 768 + 255) / 256, 256, 0, st>>>(coeff1, basis1, loop_w1, pB1sh, D_IN, D_H, 768, 0, 2); // idx 2
    {                                                                                        // idx 3 (ncu -s 5)
        dim3 g(768 / 128, SENT_PAD / 128);
        gemm4<<<g, 256, GEMM_SMEM, st>>>(pXsh, pB1sh, pPs, N_SENT, 3 * D_H, D_IN);
    }

    // ---- CSR build ----
    count_deg_i<<<(E_SS + 255) / 256, 256, 0, st>>>(dst_ss, E_SS, pDegSS);
    count_deg_i<<<(E_DS + 255) / 256, 256, 0, st>>>(dst_ds, E_DS, pDegDS);
    count_deg_i<<<(E_SD + 255) / 256, 256, 0, st>>>(dst_sd, E_SD, pDegSD);
    invert_deg_i<<<(N_SENT + 255) / 256, 256, 0, st>>>(pDegSS, pInvSS, N_SENT);
    invert_deg_i<<<(N_SENT + 255) / 256, 256, 0, st>>>(pDegDS, pInvDS, N_SENT);
    invert_deg_i<<<(N_DOC + 255) / 256, 256, 0, st>>>(pDegSD, pInvSD, N_DOC);
    {
        int nbS = (N_SENT + 1023) / 1024;
        int nbD = (N_DOC + 1023) / 1024;
        scan_local<<<nbS, 1024, 0, st>>>(pDegSS, pPartSS, pBa, N_SENT);
        scan_local<<<nbS, 1024, 0, st>>>(pDegDS, pPartDS, pBb, N_SENT);
        scan_local<<<nbD, 1024, 0, st>>>(pDegSD, pPartSD, pBc, N_DOC);
        scan_block<<<1, 128, 0, st>>>(pBa, nbS);
        scan_block<<<1, 128, 0, st>>>(pBb, nbS);
        scan_block<<<1, 128, 0, st>>>(pBc, nbD);
        scan_final<<<(N_SENT + 255) / 256, 256, 0, st>>>(pPartSS, pBa, pPtrSS, pCurSS, N_SENT);
        scan_final<<<(N_SENT + 255) / 256, 256, 0, st>>>(pPartDS, pBb, pPtrDS, pCurDS, N_SENT);
        scan_final<<<(N_DOC + 255) / 256, 256, 0, st>>>(pPartSD, pBc, pPtrSD, pCurSD, N_DOC);
        fill_csr<<<(E_SS + 255) / 256, 256, 0, st>>>(src_ss, dst_ss, E_SS, pCurSS, pAdjSS);
        fill_csr<<<(E_DS + 255) / 256, 256, 0, st>>>(src_ds, dst_ds, E_DS, pCurDS, pAdjDS);
        fill_csr<<<(E_SD + 255) / 256, 256, 0, st>>>(src_sd, dst_sd, E_SD, pCurSD, pAdjSD);
    }

    {
        long long nreal = (long long)N_DOC * D_IN, npad = (long long)DOC_PAD * D_IN;
        cvt_f16<<<(unsigned)((npad / 8 + 255) / 256), 256, 0, st>>>(x_doc, pXdh, nreal, npad);
    }
    build_w2t<<<(512 * 768 + 255) / 256, 256, 0, st>>>(coeff1, basis1, loop_w1, pB1dh, D_IN, D_H, 512, 1);
    build_w3t<<<(384 * 256 + 255) / 256, 256, 0, st>>>(coeff2, basis2, loop_w2, pB2sh, D_H, D_O, 384, 0, 2);
    build_w2t<<<(256 * 256 + 255) / 256, 256, 0, st>>>(coeff2, basis2, loop_w2, pB2dh, D_H, D_O, 256, 1);
    {
        dim3 g(512 / 128, DOC_PAD / 128);
        gemm4<<<g, 256, GEMM_SMEM, st>>>(pXdh, pB1dh, pPd, N_DOC, 2 * D_H, D_IN);
    }

    // layer-1 gather + combine -> fp16 h
    gather1_sent<<<(SENT_PAD * 32 + 255) / 256, 256, 0, st>>>(pPs, pPd, bias1, pHsh);
    gather1_doc<<<(DOC_PAD * 32 + 255) / 256, 256, 0, st>>>(pPs, pPd, bias1, pHdh);

    // layer-2 projections
    {
        dim3 g(384 / 128, SENT_PAD / 128);
        gemm4<<<g, 256, GEMM_SMEM, st>>>(pHsh, pB2sh, pPs2, N_SENT, 3 * D_O, D_H);
    }
    {
        dim3 g(256 / 128, DOC_PAD / 128);
        gemm4<<<g, 256, GEMM_SMEM, st>>>(pHdh, pB2dh, pPd2, N_DOC, 2 * D_O, D_H);
    }

    // layer-2 gather + combine + readout
    init_out<<<1, 32, 0, st>>>(out, b_score);
    gather2_sent<<<(N_SENT * 32 + 255) / 256, 256, 0, st>>>(pPs2, pPd2, bias2, w_score, gid_sent, out);
    gather2_doc<<<(N_DOC * 32 + 255) / 256, 256, 0, st>>>(pPs2, pPd2, bias2, w_score, gid_doc, out);
}

// round 11
// speedup vs baseline: 4.1446x; 1.0464x over previous
#include <cuda_runtime.h>
#include <cuda_fp16.h>
#include <cstdint>
#include <cstddef>

#define N_SENT 100000
#define N_DOC  10000
#define SENT_PAD 100096
#define DOC_PAD  10112
#define NGRAPH 32
#define D_IN   768
#define D_H    256
#define D_O    128
#define E_SS   400000
#define E_SD   100000
#define E_DS   100000

// ---------------- scratch (device globals: allocation-free) ----------------
__device__ __align__(16) __half g_B1s_h[768 * 768];
__device__ __align__(16) __half g_B1d_h[512 * 768];
__device__ __align__(16) __half g_B2s_h[384 * 256];
__device__ __align__(16) __half g_B2d_h[256 * 256];

__device__ __align__(16) __half g_xs_h[(size_t)SENT_PAD * D_IN];
__device__ __align__(16) __half g_xd_h[(size_t)DOC_PAD * D_IN];
__device__ __align__(16) __half g_hs_h[(size_t)SENT_PAD * D_H];
__device__ __align__(16) __half g_hd_h[(size_t)DOC_PAD * D_H];

__device__ __align__(16) __half g_Ps [(size_t)N_SENT * (3 * D_H)];
__device__ __align__(16) __half g_Pd [(size_t)N_DOC  * (2 * D_H)];
__device__ __align__(16) __half g_Ps2[(size_t)N_SENT * (3 * D_O)];
__device__ __align__(16) __half g_Pd2[(size_t)N_DOC  * (2 * D_O)];

// CSR structures (incoming edges per destination)
__device__ int   g_deg_ss[N_SENT], g_deg_ds[N_SENT], g_deg_sd[N_DOC];
__device__ int   g_ptr_ss[N_SENT], g_ptr_ds[N_SENT], g_ptr_sd[N_DOC];
__device__ int   g_cur_ss[N_SENT], g_cur_ds[N_SENT], g_cur_sd[N_DOC];
__device__ int   g_adj_ss[E_SS], g_adj_ds[E_DS], g_adj_sd[E_SD];
__device__ float g_inv_ss[N_SENT], g_inv_ds[N_SENT], g_inv_sd[N_DOC];
__device__ int   g_bsum_a[128], g_bsum_b[128], g_bsum_c[128];
__device__ int   g_part_ss[N_SENT], g_part_ds[N_SENT], g_part_sd[N_DOC];

// ---------------- PTX helpers ----------------
__device__ __forceinline__ uint32_t smem_u32(const void* p) {
    uint32_t a;
    asm("{ .reg .u64 t; cvta.to.shared.u64 t, %1; cvt.u32.u64 %0, t; }" : "=r"(a) : "l"(p));
    return a;
}

#define CP_ASYNC16(saddr, gaddr) \
    asm volatile("cp.async.cg.shared.global [%0], [%1], 16;" :: "r"(saddr), "l"(gaddr) : "memory")
#define CP_COMMIT() asm volatile("cp.async.commit_group;" ::: "memory")
#define CP_WAIT1()  asm volatile("cp.async.wait_group 1;" ::: "memory")

#define LDMX4(r0, r1, r2, r3, addr) \
    asm volatile("ldmatrix.sync.aligned.m8n8.x4.shared.b16 {%0,%1,%2,%3}, [%4];" \
                 : "=r"(r0), "=r"(r1), "=r"(r2), "=r"(r3) : "r"(addr))

#define MMA16816(d, a, b) \
    asm volatile("mma.sync.aligned.m16n8k16.row.col.f32.f16.f16.f32 " \
                 "{%0,%1,%2,%3}, {%4,%5,%6,%7}, {%8,%9}, {%0,%1,%2,%3};" \
                 : "+f"((d)[0]), "+f"((d)[1]), "+f"((d)[2]), "+f"((d)[3]) \
                 : "r"((a)[0]), "r"((a)[1]), "r"((a)[2]), "r"((a)[3]), "r"((b)[0]), "r"((b)[1]))

__device__ __forceinline__ uint4 pack8h(const float* f) {
    uint32_t hs[8];
    #pragma unroll
    for (int i = 0; i < 8; i++) hs[i] = (uint32_t)__half_as_ushort(__float2half(f[i]));
    return make_uint4(hs[0] | (hs[1] << 16), hs[2] | (hs[3] << 16), hs[4] | (hs[5] << 16), hs[6] | (hs[7] << 16));
}
__device__ __forceinline__ void add8h(float* A, uint4 v) {
    const __half2* h = (const __half2*)&v;
    #pragma unroll
    for (int i = 0; i < 4; i++) {
        float2 f = __half22float2(h[i]);
        A[2 * i] += f.x; A[2 * i + 1] += f.y;
    }
}
__device__ __forceinline__ void unpack8h(float* A, uint4 v) {
    const __half2* h = (const __half2*)&v;
    #pragma unroll
    for (int i = 0; i < 4; i++) {
        float2 f = __half22float2(h[i]);
        A[2 * i] = f.x; A[2 * i + 1] = f.y;
    }
}
__device__ __forceinline__ void add4h(float* A, uint2 v) {
    const __half2* h = (const __half2*)&v;
    #pragma unroll
    for (int i = 0; i < 2; i++) {
        float2 f = __half22float2(h[i]);
        A[2 * i] += f.x; A[2 * i + 1] += f.y;
    }
}

#define ROWB   80

// ================= GEMM: fp16 x fp16 -> fp16, 3-stage single-sync, 128x128 =============
#define ST_SZ  20480
#define OFF_A  0
#define OFF_B  10240
#define NSTAGE 3
#define GEMM_SMEM (NSTAGE * ST_SZ)

__global__ __launch_bounds__(256, 2) void gemm4(
    const __half* __restrict__ A,
    const __half* __restrict__ Bt,
    __half* __restrict__ C, int M, int N, int K)
{
    extern __shared__ char smem[];
    uint32_t sb = smem_u32(smem);
    int tid = threadIdx.x;
    int lane = tid & 31, wid = tid >> 5;
    int warp_m = (wid & 3) * 32;
    int warp_n = (wid >> 2) * 64;
    int mrow0 = blockIdx.y * 128;
    int ncol0 = blockIdx.x * 128;
    int nk = K >> 5;

    int prow = tid >> 1;
    int pch  = (tid & 1) * 16;
    const __half* aP = A + (size_t)(mrow0 + prow) * K + pch;
    const __half* bP = Bt + (size_t)(ncol0 + prow) * K + pch;
    uint32_t sts = (uint32_t)(prow * ROWB + pch * 2);

    int ra = warp_m + (lane & 7) + (lane & 8);
    int ca = ((lane >> 4) << 3);
    uint32_t a_lm = (uint32_t)(ra * ROWB + ca * 2);
    int rb = warp_n + (lane & 7) + ((lane >> 4) << 3);
    int cb = (((lane >> 3) & 1) << 3);
    uint32_t b_lm = (uint32_t)(rb * ROWB + cb * 2);

    float acc[2][8][4];
    #pragma unroll
    for (int mi = 0; mi < 2; mi++)
        #pragma unroll
        for (int ni = 0; ni < 8; ni++)
            #pragma unroll
            for (int q = 0; q < 4; q++) acc[mi][ni][q] = 0.f;

    #pragma unroll
    for (int s = 0; s < 2; s++) {
        if (s < nk) {
            uint32_t base = sb + s * ST_SZ;
            const __half* ap = aP + s * 32;
            const __half* bp = bP + s * 32;
            CP_ASYNC16(base + OFF_A + sts, ap); CP_ASYNC16(base + OFF_A + sts + 16, ap + 8);
            CP_ASYNC16(base + OFF_B + sts, bp); CP_ASYNC16(base + OFF_B + sts + 16, bp + 8);
        }
        CP_COMMIT();
    }

    for (int kt = 0; kt < nk; kt++) {
        CP_WAIT1();
        __syncthreads();

        int pf = kt + 2;
        if (pf < nk) {
            uint32_t base = sb + (pf % NSTAGE) * ST_SZ;
            const __half* ap = aP + pf * 32;
            const __half* bp = bP + pf * 32;
            CP_ASYNC16(base + OFF_A + sts, ap); CP_ASYNC16(base + OFF_A + sts + 16, ap + 8);
            CP_ASYNC16(base + OFF_B + sts, bp); CP_ASYNC16(base + OFF_B + sts + 16, bp + 8);
        }
        CP_COMMIT();

        uint32_t bcur = sb + (kt % NSTAGE) * ST_SZ;
        #pragma unroll
        for (int ks = 0; ks < 2; ks++) {
            uint32_t koff = ks * 32;
            uint32_t af[2][4], bf[8][2];
            #pragma unroll
            for (int mi = 0; mi < 2; mi++)
                LDMX4(af[mi][0], af[mi][1], af[mi][2], af[mi][3],
                      bcur + OFF_A + a_lm + mi * (16 * ROWB) + koff);
            #pragma unroll
            for (int bg = 0; bg < 4; bg++)
                LDMX4(bf[bg * 2][0], bf[bg * 2][1], bf[bg * 2 + 1][0], bf[bg * 2 + 1][1],
                      bcur + OFF_B + b_lm + bg * (16 * ROWB) + koff);
            #pragma unroll
            for (int mi = 0; mi < 2; mi++)
                #pragma unroll
                for (int ni = 0; ni < 8; ni++)
                    MMA16816(acc[mi][ni], af[mi], bf[ni]);
        }
    }

    int g = lane >> 2, t4 = lane & 3;
    #pragma unroll
    for (int mi = 0; mi < 2; mi++) {
        int r0 = mrow0 + warp_m + mi * 16 + g;
        #pragma unroll
        for (int ni = 0; ni < 8; ni++) {
            int col = ncol0 + warp_n + ni * 8 + t4 * 2;
            if (r0 < M)
                *(__half2*)(C + (size_t)r0 * N + col) = __floats2half2_rn(acc[mi][ni][0], acc[mi][ni][1]);
            if (r0 + 8 < M)
                *(__half2*)(C + (size_t)(r0 + 8) * N + col) = __floats2half2_rn(acc[mi][ni][2], acc[mi][ni][3]);
        }
    }
}

// ---------------- fp32 -> fp16 convert (padded, zero-filled) ----------------
__global__ void cvt_f16(const float* __restrict__ x, __half* __restrict__ hi,
                        long long nreal, long long npad) {
    long long base = ((long long)blockIdx.x * blockDim.x + threadIdx.x) * 8;
    if (base >= npad) return;
    float f[8];
    if (base < nreal) {
        float4 v0 = *(const float4*)(x + base);
        float4 v1 = *(const float4*)(x + base + 4);
        f[0] = v0.x; f[1] = v0.y; f[2] = v0.z; f[3] = v0.w;
        f[4] = v1.x; f[5] = v1.y; f[6] = v1.z; f[7] = v1.w;
    } else {
        #pragma unroll
        for (int q = 0; q < 8; q++) f[q] = 0.f;
    }
    *(uint4*)(hi + base) = pack8h(f);
}

// ---------------- CSR construction (fused across the 3 relations) ----------------
__global__ void zero_deg() {
    int i = blockIdx.x * blockDim.x + threadIdx.x;
    if (i < N_SENT) { g_deg_ss[i] = 0; g_deg_ds[i] = 0; }
    if (i < N_DOC)  { g_deg_sd[i] = 0; }
}
__global__ void count_all(const int* __restrict__ dss, const int* __restrict__ dds,
                          const int* __restrict__ dsd) {
    int i = blockIdx.x * blockDim.x + threadIdx.x;
    if (i < E_SS) atomicAdd(&g_deg_ss[dss[i]], 1);
    else if (i < E_SS + E_DS) atomicAdd(&g_deg_ds[dds[i - E_SS]], 1);
    else if (i < E_SS + E_DS + E_SD) atomicAdd(&g_deg_sd[dsd[i - E_SS - E_DS]], 1);
}
#define NB_S 98
#define NB_D 10
__global__ void scan_local_all() {
    __shared__ int sm[1024];
    const int* deg; int* part; int* bsum; int n; int blk;
    if (blockIdx.x < NB_S) { deg = g_deg_ss; part = g_part_ss; bsum = g_bsum_a; n = N_SENT; blk = blockIdx.x; }
    else if (blockIdx.x < 2 * NB_S) { deg = g_deg_ds; part = g_part_ds; bsum = g_bsum_b; n = N_SENT; blk = blockIdx.x - NB_S; }
    else { deg = g_deg_sd; part = g_part_sd; bsum = g_bsum_c; n = N_DOC; blk = blockIdx.x - 2 * NB_S; }
    int i = blk * 1024 + threadIdx.x;
    int v = (i < n) ? deg[i] : 0;
    sm[threadIdx.x] = v;
    __syncthreads();
    #pragma unroll
    for (int off = 1; off < 1024; off <<= 1) {
        int t = (threadIdx.x >= off) ? sm[threadIdx.x - off] : 0;
        __syncthreads();
        sm[threadIdx.x] += t;
        __syncthreads();
    }
    if (i < n) part[i] = sm[threadIdx.x] - v;
    if (threadIdx.x == 1023) bsum[blk] = sm[1023];
}
__global__ void scan_block_all() {
    __shared__ int sm[128];
    int* bsum; int nb;
    if (blockIdx.x == 0) { bsum = g_bsum_a; nb = NB_S; }
    else if (blockIdx.x == 1) { bsum = g_bsum_b; nb = NB_S; }
    else { bsum = g_bsum_c; nb = NB_D; }
    int v = (threadIdx.x < nb) ? bsum[threadIdx.x] : 0;
    sm[threadIdx.x] = v;
    __syncthreads();
    #pragma unroll
    for (int off = 1; off < 128; off <<= 1) {
        int t = (threadIdx.x >= off) ? sm[threadIdx.x - off] : 0;
        __syncthreads();
        sm[threadIdx.x] += t;
        __syncthreads();
    }
    if (threadIdx.x < nb) bsum[threadIdx.x] = sm[threadIdx.x] - v;
}
__global__ void scan_final_all() {
    int i = blockIdx.x * blockDim.x + threadIdx.x;
    if (i < N_SENT) {
        int p = g_part_ss[i] + g_bsum_a[i >> 10];
        g_ptr_ss[i] = p; g_cur_ss[i] = p;
        g_inv_ss[i] = 1.0f / (float)max(g_deg_ss[i], 1);
    } else if (i < 2 * N_SENT) {
        int j = i - N_SENT;
        int p = g_part_ds[j] + g_bsum_b[j >> 10];
        g_ptr_ds[j] = p; g_cur_ds[j] = p;
        g_inv_ds[j] = 1.0f / (float)max(g_deg_ds[j], 1);
    } else if (i < 2 * N_SENT + N_DOC) {
        int j = i - 2 * N_SENT;
        int p = g_part_sd[j] + g_bsum_c[j >> 10];
        g_ptr_sd[j] = p; g_cur_sd[j] = p;
        g_inv_sd[j] = 1.0f / (float)max(g_deg_sd[j], 1);
    }
}
__global__ void fill_all(const int* __restrict__ sss, const int* __restrict__ dss,
                         const int* __restrict__ sds, const int* __restrict__ dds,
                         const int* __restrict__ ssd, const int* __restrict__ dsd) {
    int i = blockIdx.x * blockDim.x + threadIdx.x;
    if (i < E_SS) {
        int p = atomicAdd(&g_cur_ss[dss[i]], 1);
        g_adj_ss[p] = sss[i];
    } else if (i < E_SS + E_DS) {
        int e = i - E_SS;
        int p = atomicAdd(&g_cur_ds[dds[e]], 1);
        g_adj_ds[p] = sds[e];
    } else if (i < E_SS + E_DS + E_SD) {
        int e = i - E_SS - E_DS;
        int p = atomicAdd(&g_cur_sd[dsd[e]], 1);
        g_adj_sd[p] = ssd[e];
    }
}

// ---------------- weight build: transposed fp16 ----------------
__global__ void build_w3t(const float* __restrict__ coeff, const float* __restrict__ basis,
                          const float* __restrict__ loopw,
                          __half* __restrict__ outH,
                          int K, int D, int Npad, int r0, int r1) {
    int idx = blockIdx.x * blockDim.x + threadIdx.x;
    if (idx >= Npad * K) return;
    int o = idx / K;
    int k = idx % K;
    float v = 0.f;
    if (o < 3 * D) {
        int seg = o / D, od = o % D;
        if (seg == 2) v = loopw[k * D + od];
        else {
            int r = (seg == 0) ? r0 : r1;
            v = coeff[r * 2 + 0] * basis[(size_t)k * D + od]
              + coeff[r * 2 + 1] * basis[(size_t)K * D + (size_t)k * D + od];
        }
    }
    outH[idx] = __float2half(v);
}
__global__ void build_w2t(const float* __restrict__ coeff, const float* __restrict__ basis,
                          const float* __restrict__ loopw,
                          __half* __restrict__ outH,
                          int K, int D, int Npad, int r0) {
    int idx = blockIdx.x * blockDim.x + threadIdx.x;
    if (idx >= Npad * K) return;
    int o = idx / K;
    int k = idx % K;
    float v = 0.f;
    if (o < 2 * D) {
        int seg = o / D, od = o % D;
        if (seg == 1) v = loopw[k * D + od];
        else {
            v = coeff[r0 * 2 + 0] * basis[(size_t)k * D + od]
              + coeff[r0 * 2 + 1] * basis[(size_t)K * D + (size_t)k * D + od];
        }
    }
    outH[idx] = __float2half(v);
}

// ---------------- layer-1 gather (warp per dst node) + combine + fp16 emit ----------------
__global__ void gather1_sent(const __half* __restrict__ Ps, const __half* __restrict__ Pd,
                             const float* __restrict__ bias, __half* __restrict__ hout) {
    int w = (blockIdx.x * blockDim.x + threadIdx.x) >> 5;
    int lane = threadIdx.x & 31;
    if (w >= SENT_PAD) return;
    __half* orow = hout + (size_t)w * D_H;
    if (w >= N_SENT) {
        *(uint4*)(orow + lane * 8) = make_uint4(0u, 0u, 0u, 0u);
        return;
    }
    float A[8] = {0.f}, Bv[8] = {0.f};
    int p = g_ptr_ss[w], d = g_deg_ss[w];
    for (int k = 0; k < d; k++) {
        int s = g_adj_ss[p + k];
        add8h(A, *(const uint4*)(Ps + (size_t)s * 768 + 256 + lane * 8));
    }
    float sc = g_inv_ss[w];
    p = g_ptr_ds[w]; d = g_deg_ds[w];
    for (int k = 0; k < d; k++) {
        int s = g_adj_ds[p + k];
        add4h(Bv,     *(const uint2*)(Pd + (size_t)s * 512 + lane * 8));
        add4h(Bv + 4, *(const uint2*)(Pd + (size_t)s * 512 + lane * 8 + 4));
    }
    float sc2 = g_inv_ds[w];
    float L[8];
    unpack8h(L, *(const uint4*)(Ps + (size_t)w * 768 + 512 + lane * 8));
    float f[8];
    #pragma unroll
    for (int i = 0; i < 8; i++)
        f[i] = fmaxf(fmaf(A[i], sc, fmaf(Bv[i], sc2, L[i] + bias[lane * 8 + i])), 0.f);
    *(uint4*)(orow + lane * 8) = pack8h(f);
}
__global__ void gather1_doc(const __half* __restrict__ Ps, const __half* __restrict__ Pd,
                            const float* __restrict__ bias, __half* __restrict__ hout) {
    int w = (blockIdx.x * blockDim.x + threadIdx.x) >> 5;
    int lane = threadIdx.x & 31;
    if (w >= DOC_PAD) return;
    __half* orow = hout + (size_t)w * D_H;
    if (w >= N_DOC) {
        *(uint4*)(orow + lane * 8) = make_uint4(0u, 0u, 0u, 0u);
        return;
    }
    float A[8] = {0.f};
    int p = g_ptr_sd[w], d = g_deg_sd[w];
    for (int k = 0; k < d; k++) {
        int s = g_adj_sd[p + k];
        add8h(A, *(const uint4*)(Ps + (size_t)s * 768 + lane * 8));
    }
    float sc = g_inv_sd[w];
    float L[8];
    unpack8h(L, *(const uint4*)(Pd + (size_t)w * 512 + 256 + lane * 8));
    float f[8];
    #pragma unroll
    for (int i = 0; i < 8; i++)
        f[i] = fmaxf(fmaf(A[i], sc, L[i] + bias[lane * 8 + i]), 0.f);
    *(uint4*)(orow + lane * 8) = pack8h(f);
}

// ---------------- layer-2 gather + combine + relu + score + per-graph reduce -------------
__global__ void init_out(float* __restrict__ out, const float* __restrict__ b_score) {
    int g = threadIdx.x;
    if (g < NGRAPH) out[g] = b_score[0];
}
__global__ void gather2_sent(const __half* __restrict__ Ps2, const __half* __restrict__ Pd2,
                             const float* __restrict__ bias, const float* __restrict__ wscore,
                             const int* __restrict__ gid, float* __restrict__ out) {
    int w = (blockIdx.x * blockDim.x + threadIdx.x) >> 5;
    int lane = threadIdx.x & 31;
    if (w >= N_SENT) return;
    float A[4] = {0.f}, Bv[4] = {0.f};
    int p = g_ptr_ss[w], d = g_deg_ss[w];
    for (int k = 0; k < d; k++) {
        int s = g_adj_ss[p + k];
        add4h(A, *(const uint2*)(Ps2 + (size_t)s * 384 + 128 + lane * 4));
    }
    float sc = g_inv_ss[w];
    p = g_ptr_ds[w]; d = g_deg_ds[w];
    for (int k = 0; k < d; k++) {
        int s = g_adj_ds[p + k];
        add4h(Bv, *(const uint2*)(Pd2 + (size_t)s * 256 + lane * 4));
    }
    float sc2 = g_inv_ds[w];
    float L[4] = {0.f};
    add4h(L, *(const uint2*)(Ps2 + (size_t)w * 384 + 256 + lane * 4));
    float4 B = ((const float4*)bias)[lane];
    float4 W = ((const float4*)wscore)[lane];
    float bb[4] = {B.x, B.y, B.z, B.w};
    float ww[4] = {W.x, W.y, W.z, W.w};
    float s = 0.f;
    #pragma unroll
    for (int i = 0; i < 4; i++)
        s += fmaxf(fmaf(A[i], sc, fmaf(Bv[i], sc2, L[i] + bb[i])), 0.f) * ww[i];
    #pragma unroll
    for (int off = 16; off; off >>= 1) s += __shfl_down_sync(0xffffffffu, s, off);
    if (lane == 0) atomicAdd(&out[gid[w]], s);
}
__global__ void gather2_doc(const __half* __restrict__ Ps2, const __half* __restrict__ Pd2,
                            const float* __restrict__ bias, const float* __restrict__ wscore,
                            const int* __restrict__ gid, float* __restrict__ out) {
    int w = (blockIdx.x * blockDim.x + threadIdx.x) >> 5;
    int lane = threadIdx.x & 31;
    if (w >= N_DOC) return;
    float A[4] = {0.f};
    int p = g_ptr_sd[w], d = g_deg_sd[w];
    for (int k = 0; k < d; k++) {
        int s = g_adj_sd[p + k];
        add4h(A, *(const uint2*)(Ps2 + (size_t)s * 384 + lane * 4));
    }
    float sc = g_inv_sd[w];
    float L[4] = {0.f};
    add4h(L, *(const uint2*)(Pd2 + (size_t)w * 256 + 128 + lane * 4));
    float4 B = ((const float4*)bias)[lane];
    float4 W = ((const float4*)wscore)[lane];
    float bb[4] = {B.x, B.y, B.z, B.w};
    float ww[4] = {W.x, W.y, W.z, W.w};
    float s = 0.f;
    #pragma unroll
    for (int i = 0; i < 4; i++)
        s += fmaxf(fmaf(A[i], sc, L[i] + bb[i]), 0.f) * ww[i];
    #pragma unroll
    for (int off = 16; off; off >>= 1) s += __shfl_down_sync(0xffffffffu, s, off);
    if (lane == 0) atomicAdd(&out[gid[w]], s);
}

// ---------------- host launcher ----------------
static void* symaddr(const void* sym) {
    void* p = nullptr;
    cudaGetSymbolAddress(&p, sym);
    return p;
}

extern "C" void kernel_launch(void* const* d_in, const int* in_sizes, int n_in,
                              void* d_out, int out_size) {
    const float* x_sent  = (const float*)d_in[0];
    const float* x_doc   = (const float*)d_in[1];
    const float* coeff1  = (const float*)d_in[2];
    const float* basis1  = (const float*)d_in[3];
    const float* loop_w1 = (const float*)d_in[4];
    const float* bias1   = (const float*)d_in[5];
    const float* coeff2  = (const float*)d_in[6];
    const float* basis2  = (const float*)d_in[7];
    const float* loop_w2 = (const float*)d_in[8];
    const float* bias2   = (const float*)d_in[9];
    const float* w_score = (const float*)d_in[10];
    const float* b_score = (const float*)d_in[11];
    const int*   src_ss  = (const int*)d_in[12];
    const int*   dst_ss  = (const int*)d_in[13];
    const int*   src_sd  = (const int*)d_in[14];
    const int*   dst_sd  = (const int*)d_in[15];
    const int*   src_ds  = (const int*)d_in[16];
    const int*   dst_ds  = (const int*)d_in[17];
    const int*   gid_sent= (const int*)d_in[18];
    const int*   gid_doc = (const int*)d_in[19];
    float* out = (float*)d_out;

    __half* pB1sh = (__half*)symaddr(g_B1s_h);
    __half* pB1dh = (__half*)symaddr(g_B1d_h);
    __half* pB2sh = (__half*)symaddr(g_B2s_h);
    __half* pB2dh = (__half*)symaddr(g_B2d_h);
    __half* pXsh = (__half*)symaddr(g_xs_h);
    __half* pXdh = (__half*)symaddr(g_xd_h);
    __half* pHsh = (__half*)symaddr(g_hs_h);
    __half* pHdh = (__half*)symaddr(g_hd_h);
    __half* pPs  = (__half*)symaddr(g_Ps);
    __half* pPd  = (__half*)symaddr(g_Pd);
    __half* pPs2 = (__half*)symaddr(g_Ps2);
    __half* pPd2 = (__half*)symaddr(g_Pd2);

    cudaFuncSetAttribute(gemm4, cudaFuncAttributeMaxDynamicSharedMemorySize, GEMM_SMEM);

    // one-time side stream + events (created on the uncaptured correctness call;
    // no device memory involved)
    static cudaStream_t s2 = nullptr;
    static cudaEvent_t eFork = nullptr, eSide = nullptr;
    if (s2 == nullptr) {
        cudaStreamCreateWithFlags(&s2, cudaStreamNonBlocking);
        cudaEventCreateWithFlags(&eFork, cudaEventDisableTiming);
        cudaEventCreateWithFlags(&eSide, cudaEventDisableTiming);
    }

    cudaStream_t st = 0;

    // ---- main stream head (harness has 2 launches before ours; global #5 = idx 3) ----
    zero_deg<<<(N_SENT + 255) / 256, 256, 0, st>>>();                                        // idx 0
    cudaEventRecord(eFork, st);
    {                                                                                        // idx 1
        long long nreal = (long long)N_SENT * D_IN, npad = (long long)SENT_PAD * D_IN;
        cvt_f16<<<(unsigned)((npad / 8 + 255) / 256), 256, 0, st>>>(x_sent, pXsh, nreal, npad);
    }
    build_w3t<<<(768 * 768 + 255) / 256, 256, 0, st>>>(coeff1, basis1, loop_w1, pB1sh, D_IN, D_H, 768, 0, 2); // idx 2
    {                                                                                        // idx 3 (ncu -s 5)
        dim3 g(768 / 128, SENT_PAD / 128);
        gemm4<<<g, 256, GEMM_SMEM, st>>>(pXsh, pB1sh, pPs, N_SENT, 3 * D_H, D_IN);
    }

    // ---- side stream: CSR build + doc-side prep, overlapped under the big GEMM ----
    cudaStreamWaitEvent(s2, eFork, 0);
    {
        int Etot = E_SS + E_DS + E_SD;
        count_all<<<(Etot + 255) / 256, 256, 0, s2>>>(dst_ss, dst_ds, dst_sd);
        scan_local_all<<<2 * NB_S + NB_D, 1024, 0, s2>>>();
        scan_block_all<<<3, 128, 0, s2>>>();
        scan_final_all<<<(2 * N_SENT + N_DOC + 255) / 256, 256, 0, s2>>>();
        fill_all<<<(Etot + 255) / 256, 256, 0, s2>>>(src_ss, dst_ss, src_ds, dst_ds, src_sd, dst_sd);
    }
    {
        long long nreal = (long long)N_DOC * D_IN, npad = (long long)DOC_PAD * D_IN;
        cvt_f16<<<(unsigned)((npad / 8 + 255) / 256), 256, 0, s2>>>(x_doc, pXdh, nreal, npad);
    }
    build_w2t<<<(512 * 768 + 255) / 256, 256, 0, s2>>>(coeff1, basis1, loop_w1, pB1dh, D_IN, D_H, 512, 1);
    build_w3t<<<(384 * 256 + 255) / 256, 256, 0, s2>>>(coeff2, basis2, loop_w2, pB2sh, D_H, D_O, 384, 0, 2);
    build_w2t<<<(256 * 256 + 255) / 256, 256, 0, s2>>>(coeff2, basis2, loop_w2, pB2dh, D_H, D_O, 256, 1);
    cudaEventRecord(eSide, s2);

    // ---- join back to main stream ----
    cudaStreamWaitEvent(st, eSide, 0);

    {
        dim3 g(512 / 128, DOC_PAD / 128);
        gemm4<<<g, 256, GEMM_SMEM, st>>>(pXdh, pB1dh, pPd, N_DOC, 2 * D_H, D_IN);
    }

    // layer-1 gather + combine -> fp16 h
    gather1_sent<<<(SENT_PAD * 32 + 255) / 256, 256, 0, st>>>(pPs, pPd, bias1, pHsh);
    gather1_doc<<<(DOC_PAD * 32 + 255) / 256, 256, 0, st>>>(pPs, pPd, bias1, pHdh);

    // layer-2 projections
    {
        dim3 g(384 / 128, SENT_PAD / 128);
        gemm4<<<g, 256, GEMM_SMEM, st>>>(pHsh, pB2sh, pPs2, N_SENT, 3 * D_O, D_H);
    }
    {
        dim3 g(256 / 128, DOC_PAD / 128);
        gemm4<<<g, 256, GEMM_SMEM, st>>>(pHdh, pB2dh, pPd2, N_DOC, 2 * D_O, D_H);
    }

    // layer-2 gather + combine + readout
    init_out<<<1, 32, 0, st>>>(out, b_score);
    gather2_sent<<<(N_SENT * 32 + 255) / 256, 256, 0, st>>>(pPs2, pPd2, bias2, w_score, gid_sent, out);
    gather2_doc<<<(N_DOC * 32 + 255) / 256, 256, 0, st>>>(pPs2, pPd2, bias2, w_score, gid_doc, out);
}

// round 12
// speedup vs baseline: 4.2118x; 1.0162x over previous
#include <cuda_runtime.h>
#include <cuda_fp16.h>
#include <cstdint>
#include <cstddef>

#define N_SENT 100000
#define N_DOC  10000
#define SENT_PAD 100096
#define DOC_PAD  10112
#define NGRAPH 32
#define D_IN   768
#define D_H    256
#define D_O    128
#define E_SS   400000
#define E_SD   100000
#define E_DS   100000

// ---------------- scratch (device globals: allocation-free) ----------------
__device__ __align__(16) __half g_B1s_h[768 * 768];
__device__ __align__(16) __half g_B1d_h[512 * 768];
__device__ __align__(16) __half g_B2s_h[384 * 256];
__device__ __align__(16) __half g_B2d_h[256 * 256];

__device__ __align__(16) __half g_xs_h[(size_t)SENT_PAD * D_IN];
__device__ __align__(16) __half g_xd_h[(size_t)DOC_PAD * D_IN];
__device__ __align__(16) __half g_hs_h[(size_t)SENT_PAD * D_H];
__device__ __align__(16) __half g_hd_h[(size_t)DOC_PAD * D_H];

__device__ __align__(16) __half g_Ps [(size_t)N_SENT * (3 * D_H)];
__device__ __align__(16) __half g_Pd [(size_t)N_DOC  * (2 * D_H)];
__device__ __align__(16) __half g_Ps2[(size_t)N_SENT * (3 * D_O)];
__device__ __align__(16) __half g_Pd2[(size_t)N_DOC  * (2 * D_O)];

// CSR structures (incoming edges per destination)
__device__ int   g_deg_ss[N_SENT], g_deg_ds[N_SENT], g_deg_sd[N_DOC];
__device__ int   g_ptr_ss[N_SENT], g_ptr_ds[N_SENT], g_ptr_sd[N_DOC];
__device__ int   g_cur_ss[N_SENT], g_cur_ds[N_SENT], g_cur_sd[N_DOC];
__device__ int   g_adj_ss[E_SS], g_adj_ds[E_DS], g_adj_sd[E_SD];
__device__ float g_inv_ss[N_SENT], g_inv_ds[N_SENT], g_inv_sd[N_DOC];
__device__ int   g_bsum_a[128], g_bsum_b[128], g_bsum_c[128];
__device__ int   g_part_ss[N_SENT], g_part_ds[N_SENT], g_part_sd[N_DOC];

// ---------------- PTX helpers ----------------
__device__ __forceinline__ uint32_t smem_u32(const void* p) {
    uint32_t a;
    asm("{ .reg .u64 t; cvta.to.shared.u64 t, %1; cvt.u32.u64 %0, t; }" : "=r"(a) : "l"(p));
    return a;
}

#define CP_ASYNC16(saddr, gaddr) \
    asm volatile("cp.async.cg.shared.global [%0], [%1], 16;" :: "r"(saddr), "l"(gaddr) : "memory")
#define CP_COMMIT() asm volatile("cp.async.commit_group;" ::: "memory")
#define CP_WAIT1()  asm volatile("cp.async.wait_group 1;" ::: "memory")

#define LDMX4(r0, r1, r2, r3, addr) \
    asm volatile("ldmatrix.sync.aligned.m8n8.x4.shared.b16 {%0,%1,%2,%3}, [%4];" \
                 : "=r"(r0), "=r"(r1), "=r"(r2), "=r"(r3) : "r"(addr))

#define MMA16816(d, a, b) \
    asm volatile("mma.sync.aligned.m16n8k16.row.col.f32.f16.f16.f32 " \
                 "{%0,%1,%2,%3}, {%4,%5,%6,%7}, {%8,%9}, {%0,%1,%2,%3};" \
                 : "+f"((d)[0]), "+f"((d)[1]), "+f"((d)[2]), "+f"((d)[3]) \
                 : "r"((a)[0]), "r"((a)[1]), "r"((a)[2]), "r"((a)[3]), "r"((b)[0]), "r"((b)[1]))

__device__ __forceinline__ uint4 pack8h(const float* f) {
    uint32_t hs[8];
    #pragma unroll
    for (int i = 0; i < 8; i++) hs[i] = (uint32_t)__half_as_ushort(__float2half(f[i]));
    return make_uint4(hs[0] | (hs[1] << 16), hs[2] | (hs[3] << 16), hs[4] | (hs[5] << 16), hs[6] | (hs[7] << 16));
}
__device__ __forceinline__ void add8h(float* A, uint4 v) {
    const __half2* h = (const __half2*)&v;
    #pragma unroll
    for (int i = 0; i < 4; i++) {
        float2 f = __half22float2(h[i]);
        A[2 * i] += f.x; A[2 * i + 1] += f.y;
    }
}
__device__ __forceinline__ void unpack8h(float* A, uint4 v) {
    const __half2* h = (const __half2*)&v;
    #pragma unroll
    for (int i = 0; i < 4; i++) {
        float2 f = __half22float2(h[i]);
        A[2 * i] = f.x; A[2 * i + 1] = f.y;
    }
}
__device__ __forceinline__ void add4h(float* A, uint2 v) {
    const __half2* h = (const __half2*)&v;
    #pragma unroll
    for (int i = 0; i < 2; i++) {
        float2 f = __half22float2(h[i]);
        A[2 * i] += f.x; A[2 * i + 1] += f.y;
    }
}

#define ROWB   80

// ================= GEMM: fp16 x fp16 -> fp16, 3-stage single-sync, 128x128 =============
#define ST_SZ  20480
#define OFF_A  0
#define OFF_B  10240
#define NSTAGE 3
#define GEMM_SMEM (NSTAGE * ST_SZ)

__global__ __launch_bounds__(256, 2) void gemm4(
    const __half* __restrict__ A,
    const __half* __restrict__ Bt,
    __half* __restrict__ C, int M, int N, int K)
{
    extern __shared__ char smem[];
    uint32_t sb = smem_u32(smem);
    int tid = threadIdx.x;
    int lane = tid & 31, wid = tid >> 5;
    int warp_m = (wid & 3) * 32;
    int warp_n = (wid >> 2) * 64;
    int mrow0 = blockIdx.y * 128;
    int ncol0 = blockIdx.x * 128;
    int nk = K >> 5;

    int prow = tid >> 1;
    int pch  = (tid & 1) * 16;
    const __half* aP = A + (size_t)(mrow0 + prow) * K + pch;
    const __half* bP = Bt + (size_t)(ncol0 + prow) * K + pch;
    uint32_t sts = (uint32_t)(prow * ROWB + pch * 2);

    int ra = warp_m + (lane & 7) + (lane & 8);
    int ca = ((lane >> 4) << 3);
    uint32_t a_lm = (uint32_t)(ra * ROWB + ca * 2);
    int rb = warp_n + (lane & 7) + ((lane >> 4) << 3);
    int cb = (((lane >> 3) & 1) << 3);
    uint32_t b_lm = (uint32_t)(rb * ROWB + cb * 2);

    float acc[2][8][4];
    #pragma unroll
    for (int mi = 0; mi < 2; mi++)
        #pragma unroll
        for (int ni = 0; ni < 8; ni++)
            #pragma unroll
            for (int q = 0; q < 4; q++) acc[mi][ni][q] = 0.f;

    #pragma unroll
    for (int s = 0; s < 2; s++) {
        if (s < nk) {
            uint32_t base = sb + s * ST_SZ;
            const __half* ap = aP + s * 32;
            const __half* bp = bP + s * 32;
            CP_ASYNC16(base + OFF_A + sts, ap); CP_ASYNC16(base + OFF_A + sts + 16, ap + 8);
            CP_ASYNC16(base + OFF_B + sts, bp); CP_ASYNC16(base + OFF_B + sts + 16, bp + 8);
        }
        CP_COMMIT();
    }

    for (int kt = 0; kt < nk; kt++) {
        CP_WAIT1();
        __syncthreads();

        int pf = kt + 2;
        if (pf < nk) {
            uint32_t base = sb + (pf % NSTAGE) * ST_SZ;
            const __half* ap = aP + pf * 32;
            const __half* bp = bP + pf * 32;
            CP_ASYNC16(base + OFF_A + sts, ap); CP_ASYNC16(base + OFF_A + sts + 16, ap + 8);
            CP_ASYNC16(base + OFF_B + sts, bp); CP_ASYNC16(base + OFF_B + sts + 16, bp + 8);
        }
        CP_COMMIT();

        uint32_t bcur = sb + (kt % NSTAGE) * ST_SZ;
        #pragma unroll
        for (int ks = 0; ks < 2; ks++) {
            uint32_t koff = ks * 32;
            uint32_t af[2][4], bf[8][2];
            #pragma unroll
            for (int mi = 0; mi < 2; mi++)
                LDMX4(af[mi][0], af[mi][1], af[mi][2], af[mi][3],
                      bcur + OFF_A + a_lm + mi * (16 * ROWB) + koff);
            #pragma unroll
            for (int bg = 0; bg < 4; bg++)
                LDMX4(bf[bg * 2][0], bf[bg * 2][1], bf[bg * 2 + 1][0], bf[bg * 2 + 1][1],
                      bcur + OFF_B + b_lm + bg * (16 * ROWB) + koff);
            #pragma unroll
            for (int mi = 0; mi < 2; mi++)
                #pragma unroll
                for (int ni = 0; ni < 8; ni++)
                    MMA16816(acc[mi][ni], af[mi], bf[ni]);
        }
    }

    int g = lane >> 2, t4 = lane & 3;
    #pragma unroll
    for (int mi = 0; mi < 2; mi++) {
        int r0 = mrow0 + warp_m + mi * 16 + g;
        #pragma unroll
        for (int ni = 0; ni < 8; ni++) {
            int col = ncol0 + warp_n + ni * 8 + t4 * 2;
            if (r0 < M)
                *(__half2*)(C + (size_t)r0 * N + col) = __floats2half2_rn(acc[mi][ni][0], acc[mi][ni][1]);
            if (r0 + 8 < M)
                *(__half2*)(C + (size_t)(r0 + 8) * N + col) = __floats2half2_rn(acc[mi][ni][2], acc[mi][ni][3]);
        }
    }
}

// ---------------- fp32 -> fp16 convert (padded, zero-filled) ----------------
__global__ void cvt_f16(const float* __restrict__ x, __half* __restrict__ hi,
                        long long nreal, long long npad) {
    long long base = ((long long)blockIdx.x * blockDim.x + threadIdx.x) * 8;
    if (base >= npad) return;
    float f[8];
    if (base < nreal) {
        float4 v0 = *(const float4*)(x + base);
        float4 v1 = *(const float4*)(x + base + 4);
        f[0] = v0.x; f[1] = v0.y; f[2] = v0.z; f[3] = v0.w;
        f[4] = v1.x; f[5] = v1.y; f[6] = v1.z; f[7] = v1.w;
    } else {
        #pragma unroll
        for (int q = 0; q < 8; q++) f[q] = 0.f;
    }
    *(uint4*)(hi + base) = pack8h(f);
}

// ---------------- CSR construction (fused across the 3 relations) ----------------
__global__ void zero_deg() {
    int i = blockIdx.x * blockDim.x + threadIdx.x;
    if (i < N_SENT) { g_deg_ss[i] = 0; g_deg_ds[i] = 0; }
    if (i < N_DOC)  { g_deg_sd[i] = 0; }
}
__global__ void count_all(const int* __restrict__ dss, const int* __restrict__ dds,
                          const int* __restrict__ dsd) {
    int i = blockIdx.x * blockDim.x + threadIdx.x;
    if (i < E_SS) atomicAdd(&g_deg_ss[dss[i]], 1);
    else if (i < E_SS + E_DS) atomicAdd(&g_deg_ds[dds[i - E_SS]], 1);
    else if (i < E_SS + E_DS + E_SD) atomicAdd(&g_deg_sd[dsd[i - E_SS - E_DS]], 1);
}
#define NB_S 98
#define NB_D 10
__global__ void scan_local_all() {
    __shared__ int sm[1024];
    const int* deg; int* part; int* bsum; int n; int blk;
    if (blockIdx.x < NB_S) { deg = g_deg_ss; part = g_part_ss; bsum = g_bsum_a; n = N_SENT; blk = blockIdx.x; }
    else if (blockIdx.x < 2 * NB_S) { deg = g_deg_ds; part = g_part_ds; bsum = g_bsum_b; n = N_SENT; blk = blockIdx.x - NB_S; }
    else { deg = g_deg_sd; part = g_part_sd; bsum = g_bsum_c; n = N_DOC; blk = blockIdx.x - 2 * NB_S; }
    int i = blk * 1024 + threadIdx.x;
    int v = (i < n) ? deg[i] : 0;
    sm[threadIdx.x] = v;
    __syncthreads();
    #pragma unroll
    for (int off = 1; off < 1024; off <<= 1) {
        int t = (threadIdx.x >= off) ? sm[threadIdx.x - off] : 0;
        __syncthreads();
        sm[threadIdx.x] += t;
        __syncthreads();
    }
    if (i < n) part[i] = sm[threadIdx.x] - v;
    if (threadIdx.x == 1023) bsum[blk] = sm[1023];
}
__global__ void scan_block_all() {
    __shared__ int sm[128];
    int* bsum; int nb;
    if (blockIdx.x == 0) { bsum = g_bsum_a; nb = NB_S; }
    else if (blockIdx.x == 1) { bsum = g_bsum_b; nb = NB_S; }
    else { bsum = g_bsum_c; nb = NB_D; }
    int v = (threadIdx.x < nb) ? bsum[threadIdx.x] : 0;
    sm[threadIdx.x] = v;
    __syncthreads();
    #pragma unroll
    for (int off = 1; off < 128; off <<= 1) {
        int t = (threadIdx.x >= off) ? sm[threadIdx.x - off] : 0;
        __syncthreads();
        sm[threadIdx.x] += t;
        __syncthreads();
    }
    if (threadIdx.x < nb) bsum[threadIdx.x] = sm[threadIdx.x] - v;
}
__global__ void scan_final_all() {
    int i = blockIdx.x * blockDim.x + threadIdx.x;
    if (i < N_SENT) {
        int p = g_part_ss[i] + g_bsum_a[i >> 10];
        g_ptr_ss[i] = p; g_cur_ss[i] = p;
        g_inv_ss[i] = 1.0f / (float)max(g_deg_ss[i], 1);
    } else if (i < 2 * N_SENT) {
        int j = i - N_SENT;
        int p = g_part_ds[j] + g_bsum_b[j >> 10];
        g_ptr_ds[j] = p; g_cur_ds[j] = p;
        g_inv_ds[j] = 1.0f / (float)max(g_deg_ds[j], 1);
    } else if (i < 2 * N_SENT + N_DOC) {
        int j = i - 2 * N_SENT;
        int p = g_part_sd[j] + g_bsum_c[j >> 10];
        g_ptr_sd[j] = p; g_cur_sd[j] = p;
        g_inv_sd[j] = 1.0f / (float)max(g_deg_sd[j], 1);
    }
}
__global__ void fill_all(const int* __restrict__ sss, const int* __restrict__ dss,
                         const int* __restrict__ sds, const int* __restrict__ dds,
                         const int* __restrict__ ssd, const int* __restrict__ dsd) {
    int i = blockIdx.x * blockDim.x + threadIdx.x;
    if (i < E_SS) {
        int p = atomicAdd(&g_cur_ss[dss[i]], 1);
        g_adj_ss[p] = sss[i];
    } else if (i < E_SS + E_DS) {
        int e = i - E_SS;
        int p = atomicAdd(&g_cur_ds[dds[e]], 1);
        g_adj_ds[p] = sds[e];
    } else if (i < E_SS + E_DS + E_SD) {
        int e = i - E_SS - E_DS;
        int p = atomicAdd(&g_cur_sd[dsd[e]], 1);
        g_adj_sd[p] = ssd[e];
    }
}

// ---------------- weight build: transposed fp16 ----------------
__global__ void build_w3t(const float* __restrict__ coeff, const float* __restrict__ basis,
                          const float* __restrict__ loopw,
                          __half* __restrict__ outH,
                          int K, int D, int Npad, int r0, int r1) {
    int idx = blockIdx.x * blockDim.x + threadIdx.x;
    if (idx >= Npad * K) return;
    int o = idx / K;
    int k = idx % K;
    float v = 0.f;
    if (o < 3 * D) {
        int seg = o / D, od = o % D;
        if (seg == 2) v = loopw[k * D + od];
        else {
            int r = (seg == 0) ? r0 : r1;
            v = coeff[r * 2 + 0] * basis[(size_t)k * D + od]
              + coeff[r * 2 + 1] * basis[(size_t)K * D + (size_t)k * D + od];
        }
    }
    outH[idx] = __float2half(v);
}
__global__ void build_w2t(const float* __restrict__ coeff, const float* __restrict__ basis,
                          const float* __restrict__ loopw,
                          __half* __restrict__ outH,
                          int K, int D, int Npad, int r0) {
    int idx = blockIdx.x * blockDim.x + threadIdx.x;
    if (idx >= Npad * K) return;
    int o = idx / K;
    int k = idx % K;
    float v = 0.f;
    if (o < 2 * D) {
        int seg = o / D, od = o % D;
        if (seg == 1) v = loopw[k * D + od];
        else {
            v = coeff[r0 * 2 + 0] * basis[(size_t)k * D + od]
              + coeff[r0 * 2 + 1] * basis[(size_t)K * D + (size_t)k * D + od];
        }
    }
    outH[idx] = __float2half(v);
}

// ---------------- layer-1 gather (warp per dst node) + combine + fp16 emit ----------------
__global__ void gather1_sent(const __half* __restrict__ Ps, const __half* __restrict__ Pd,
                             const float* __restrict__ bias, __half* __restrict__ hout) {
    int w = (blockIdx.x * blockDim.x + threadIdx.x) >> 5;
    int lane = threadIdx.x & 31;
    if (w >= SENT_PAD) return;
    __half* orow = hout + (size_t)w * D_H;
    if (w >= N_SENT) {
        *(uint4*)(orow + lane * 8) = make_uint4(0u, 0u, 0u, 0u);
        return;
    }
    float A[8] = {0.f}, Bv[8] = {0.f};
    int p = g_ptr_ss[w], d = g_deg_ss[w];
    int k = 0;
    for (; k + 1 < d; k += 2) {
        int s0 = g_adj_ss[p + k], s1 = g_adj_ss[p + k + 1];
        uint4 v0 = *(const uint4*)(Ps + (size_t)s0 * 768 + 256 + lane * 8);
        uint4 v1 = *(const uint4*)(Ps + (size_t)s1 * 768 + 256 + lane * 8);
        add8h(A, v0); add8h(A, v1);
    }
    if (k < d) {
        int s0 = g_adj_ss[p + k];
        add8h(A, *(const uint4*)(Ps + (size_t)s0 * 768 + 256 + lane * 8));
    }
    float sc = g_inv_ss[w];
    p = g_ptr_ds[w]; d = g_deg_ds[w];
    k = 0;
    for (; k + 1 < d; k += 2) {
        int s0 = g_adj_ds[p + k], s1 = g_adj_ds[p + k + 1];
        uint4 v0 = *(const uint4*)(Pd + (size_t)s0 * 512 + lane * 8);
        uint4 v1 = *(const uint4*)(Pd + (size_t)s1 * 512 + lane * 8);
        add8h(Bv, v0); add8h(Bv, v1);
    }
    if (k < d) {
        int s0 = g_adj_ds[p + k];
        add8h(Bv, *(const uint4*)(Pd + (size_t)s0 * 512 + lane * 8));
    }
    float sc2 = g_inv_ds[w];
    float L[8];
    unpack8h(L, *(const uint4*)(Ps + (size_t)w * 768 + 512 + lane * 8));
    float f[8];
    #pragma unroll
    for (int i = 0; i < 8; i++)
        f[i] = fmaxf(fmaf(A[i], sc, fmaf(Bv[i], sc2, L[i] + bias[lane * 8 + i])), 0.f);
    *(uint4*)(orow + lane * 8) = pack8h(f);
}
__global__ void gather1_doc(const __half* __restrict__ Ps, const __half* __restrict__ Pd,
                            const float* __restrict__ bias, __half* __restrict__ hout) {
    int w = (blockIdx.x * blockDim.x + threadIdx.x) >> 5;
    int lane = threadIdx.x & 31;
    if (w >= DOC_PAD) return;
    __half* orow = hout + (size_t)w * D_H;
    if (w >= N_DOC) {
        *(uint4*)(orow + lane * 8) = make_uint4(0u, 0u, 0u, 0u);
        return;
    }
    float A[8] = {0.f};
    int p = g_ptr_sd[w], d = g_deg_sd[w];
    int k = 0;
    for (; k + 1 < d; k += 2) {
        int s0 = g_adj_sd[p + k], s1 = g_adj_sd[p + k + 1];
        uint4 v0 = *(const uint4*)(Ps + (size_t)s0 * 768 + lane * 8);
        uint4 v1 = *(const uint4*)(Ps + (size_t)s1 * 768 + lane * 8);
        add8h(A, v0); add8h(A, v1);
    }
    if (k < d) {
        int s0 = g_adj_sd[p + k];
        add8h(A, *(const uint4*)(Ps + (size_t)s0 * 768 + lane * 8));
    }
    float sc = g_inv_sd[w];
    float L[8];
    unpack8h(L, *(const uint4*)(Pd + (size_t)w * 512 + 256 + lane * 8));
    float f[8];
    #pragma unroll
    for (int i = 0; i < 8; i++)
        f[i] = fmaxf(fmaf(A[i], sc, L[i] + bias[lane * 8 + i]), 0.f);
    *(uint4*)(orow + lane * 8) = pack8h(f);
}

// ---------------- layer-2 gather + combine + relu + score + per-graph reduce -------------
__global__ void init_out(float* __restrict__ out, const float* __restrict__ b_score) {
    int g = threadIdx.x;
    if (g < NGRAPH) out[g] = b_score[0];
}
__global__ void gather2_sent(const __half* __restrict__ Ps2, const __half* __restrict__ Pd2,
                             const float* __restrict__ bias, const float* __restrict__ wscore,
                             const int* __restrict__ gid, float* __restrict__ out) {
    int w = (blockIdx.x * blockDim.x + threadIdx.x) >> 5;
    int lane = threadIdx.x & 31;
    if (w >= N_SENT) return;
    float A[4] = {0.f}, Bv[4] = {0.f};
    int p = g_ptr_ss[w], d = g_deg_ss[w];
    int k = 0;
    for (; k + 1 < d; k += 2) {
        int s0 = g_adj_ss[p + k], s1 = g_adj_ss[p + k + 1];
        uint2 v0 = *(const uint2*)(Ps2 + (size_t)s0 * 384 + 128 + lane * 4);
        uint2 v1 = *(const uint2*)(Ps2 + (size_t)s1 * 384 + 128 + lane * 4);
        add4h(A, v0); add4h(A, v1);
    }
    if (k < d) {
        int s0 = g_adj_ss[p + k];
        add4h(A, *(const uint2*)(Ps2 + (size_t)s0 * 384 + 128 + lane * 4));
    }
    float sc = g_inv_ss[w];
    p = g_ptr_ds[w]; d = g_deg_ds[w];
    k = 0;
    for (; k + 1 < d; k += 2) {
        int s0 = g_adj_ds[p + k], s1 = g_adj_ds[p + k + 1];
        uint2 v0 = *(const uint2*)(Pd2 + (size_t)s0 * 256 + lane * 4);
        uint2 v1 = *(const uint2*)(Pd2 + (size_t)s1 * 256 + lane * 4);
        add4h(Bv, v0); add4h(Bv, v1);
    }
    if (k < d) {
        int s0 = g_adj_ds[p + k];
        add4h(Bv, *(const uint2*)(Pd2 + (size_t)s0 * 256 + lane * 4));
    }
    float sc2 = g_inv_ds[w];
    float L[4] = {0.f};
    add4h(L, *(const uint2*)(Ps2 + (size_t)w * 384 + 256 + lane * 4));
    float4 B = ((const float4*)bias)[lane];
    float4 W = ((const float4*)wscore)[lane];
    float bb[4] = {B.x, B.y, B.z, B.w};
    float ww[4] = {W.x, W.y, W.z, W.w};
    float s = 0.f;
    #pragma unroll
    for (int i = 0; i < 4; i++)
        s += fmaxf(fmaf(A[i], sc, fmaf(Bv[i], sc2, L[i] + bb[i])), 0.f) * ww[i];
    #pragma unroll
    for (int off = 16; off; off >>= 1) s += __shfl_down_sync(0xffffffffu, s, off);
    if (lane == 0) atomicAdd(&out[gid[w]], s);
}
__global__ void gather2_doc(const __half* __restrict__ Ps2, const __half* __restrict__ Pd2,
                            const float* __restrict__ bias, const float* __restrict__ wscore,
                            const int* __restrict__ gid, float* __restrict__ out) {
    int w = (blockIdx.x * blockDim.x + threadIdx.x) >> 5;
    int lane = threadIdx.x & 31;
    if (w >= N_DOC) return;
    float A[4] = {0.f};
    int p = g_ptr_sd[w], d = g_deg_sd[w];
    int k = 0;
    for (; k + 1 < d; k += 2) {
        int s0 = g_adj_sd[p + k], s1 = g_adj_sd[p + k + 1];
        uint2 v0 = *(const uint2*)(Ps2 + (size_t)s0 * 384 + lane * 4);
        uint2 v1 = *(const uint2*)(Ps2 + (size_t)s1 * 384 + lane * 4);
        add4h(A, v0); add4h(A, v1);
    }
    if (k < d) {
        int s0 = g_adj_sd[p + k];
        add4h(A, *(const uint2*)(Ps2 + (size_t)s0 * 384 + lane * 4));
    }
    float sc = g_inv_sd[w];
    float L[4] = {0.f};
    add4h(L, *(const uint2*)(Pd2 + (size_t)w * 256 + 128 + lane * 4));
    float4 B = ((const float4*)bias)[lane];
    float4 W = ((const float4*)wscore)[lane];
    float bb[4] = {B.x, B.y, B.z, B.w};
    float ww[4] = {W.x, W.y, W.z, W.w};
    float s = 0.f;
    #pragma unroll
    for (int i = 0; i < 4; i++)
        s += fmaxf(fmaf(A[i], sc, L[i] + bb[i]), 0.f) * ww[i];
    #pragma unroll
    for (int off = 16; off; off >>= 1) s += __shfl_down_sync(0xffffffffu, s, off);
    if (lane == 0) atomicAdd(&out[gid[w]], s);
}

// ---------------- host launcher ----------------
static void* symaddr(const void* sym) {
    void* p = nullptr;
    cudaGetSymbolAddress(&p, sym);
    return p;
}

extern "C" void kernel_launch(void* const* d_in, const int* in_sizes, int n_in,
                              void* d_out, int out_size) {
    const float* x_sent  = (const float*)d_in[0];
    const float* x_doc   = (const float*)d_in[1];
    const float* coeff1  = (const float*)d_in[2];
    const float* basis1  = (const float*)d_in[3];
    const float* loop_w1 = (const float*)d_in[4];
    const float* bias1   = (const float*)d_in[5];
    const float* coeff2  = (const float*)d_in[6];
    const float* basis2  = (const float*)d_in[7];
    const float* loop_w2 = (const float*)d_in[8];
    const float* bias2   = (const float*)d_in[9];
    const float* w_score = (const float*)d_in[10];
    const float* b_score = (const float*)d_in[11];
    const int*   src_ss  = (const int*)d_in[12];
    const int*   dst_ss  = (const int*)d_in[13];
    const int*   src_sd  = (const int*)d_in[14];
    const int*   dst_sd  = (const int*)d_in[15];
    const int*   src_ds  = (const int*)d_in[16];
    const int*   dst_ds  = (const int*)d_in[17];
    const int*   gid_sent= (const int*)d_in[18];
    const int*   gid_doc = (const int*)d_in[19];
    float* out = (float*)d_out;

    __half* pB1sh = (__half*)symaddr(g_B1s_h);
    __half* pB1dh = (__half*)symaddr(g_B1d_h);
    __half* pB2sh = (__half*)symaddr(g_B2s_h);
    __half* pB2dh = (__half*)symaddr(g_B2d_h);
    __half* pXsh = (__half*)symaddr(g_xs_h);
    __half* pXdh = (__half*)symaddr(g_xd_h);
    __half* pHsh = (__half*)symaddr(g_hs_h);
    __half* pHdh = (__half*)symaddr(g_hd_h);
    __half* pPs  = (__half*)symaddr(g_Ps);
    __half* pPd  = (__half*)symaddr(g_Pd);
    __half* pPs2 = (__half*)symaddr(g_Ps2);
    __half* pPd2 = (__half*)symaddr(g_Pd2);

    cudaFuncSetAttribute(gemm4, cudaFuncAttributeMaxDynamicSharedMemorySize, GEMM_SMEM);

    static cudaStream_t s2 = nullptr;
    static cudaEvent_t eFork = nullptr, eSide = nullptr, eG1d = nullptr, eD2 = nullptr;
    if (s2 == nullptr) {
        cudaStreamCreateWithFlags(&s2, cudaStreamNonBlocking);
        cudaEventCreateWithFlags(&eFork, cudaEventDisableTiming);
        cudaEventCreateWithFlags(&eSide, cudaEventDisableTiming);
        cudaEventCreateWithFlags(&eG1d, cudaEventDisableTiming);
        cudaEventCreateWithFlags(&eD2, cudaEventDisableTiming);
    }

    cudaStream_t st = 0;

    // ---- main stream head (harness has 2 launches before ours; global #5 = idx 3) ----
    zero_deg<<<(N_SENT + 255) / 256, 256, 0, st>>>();                                        // idx 0
    cudaEventRecord(eFork, st);
    {                                                                                        // idx 1
        long long nreal = (long long)N_SENT * D_IN, npad = (long long)SENT_PAD * D_IN;
        cvt_f16<<<(unsigned)((npad / 8 + 255) / 256), 256, 0, st>>>(x_sent, pXsh, nreal, npad);
    }
    build_w3t<<<(768 * 768 + 255) / 256, 256, 0, st>>>(coeff1, basis1, loop_w1, pB1sh, D_IN, D_H, 768, 0, 2); // idx 2
    {                                                                                        // idx 3 (ncu -s 5)
        dim3 g(768 / 128, SENT_PAD / 128);
        gemm4<<<g, 256, GEMM_SMEM, st>>>(pXsh, pB1sh, pPs, N_SENT, 3 * D_H, D_IN);
    }

    // ---- side stream: CSR + doc prep + doc layer-1 GEMM under the big GEMM ----
    cudaStreamWaitEvent(s2, eFork, 0);
    {
        int Etot = E_SS + E_DS + E_SD;
        count_all<<<(Etot + 255) / 256, 256, 0, s2>>>(dst_ss, dst_ds, dst_sd);
        scan_local_all<<<2 * NB_S + NB_D, 1024, 0, s2>>>();
        scan_block_all<<<3, 128, 0, s2>>>();
        scan_final_all<<<(2 * N_SENT + N_DOC + 255) / 256, 256, 0, s2>>>();
        fill_all<<<(Etot + 255) / 256, 256, 0, s2>>>(src_ss, dst_ss, src_ds, dst_ds, src_sd, dst_sd);
    }
    {
        long long nreal = (long long)N_DOC * D_IN, npad = (long long)DOC_PAD * D_IN;
        cvt_f16<<<(unsigned)((npad / 8 + 255) / 256), 256, 0, s2>>>(x_doc, pXdh, nreal, npad);
    }
    build_w2t<<<(512 * 768 + 255) / 256, 256, 0, s2>>>(coeff1, basis1, loop_w1, pB1dh, D_IN, D_H, 512, 1);
    build_w3t<<<(384 * 256 + 255) / 256, 256, 0, s2>>>(coeff2, basis2, loop_w2, pB2sh, D_H, D_O, 384, 0, 2);
    build_w2t<<<(256 * 256 + 255) / 256, 256, 0, s2>>>(coeff2, basis2, loop_w2, pB2dh, D_H, D_O, 256, 1);
    {
        dim3 g(512 / 128, DOC_PAD / 128);
        gemm4<<<g, 256, GEMM_SMEM, s2>>>(pXdh, pB1dh, pPd, N_DOC, 2 * D_H, D_IN);
    }
    cudaEventRecord(eSide, s2);

    // ---- join: gather layer 1 ----
    cudaStreamWaitEvent(st, eSide, 0);
    gather1_doc<<<(DOC_PAD * 32 + 255) / 256, 256, 0, st>>>(pPs, pPd, bias1, pHdh);
    cudaEventRecord(eG1d, st);
    gather1_sent<<<(SENT_PAD * 32 + 255) / 256, 256, 0, st>>>(pPs, pPd, bias1, pHsh);

    // side: doc layer-2 GEMM concurrent with main's sent layer-2 GEMM
    cudaStreamWaitEvent(s2, eG1d, 0);
    {
        dim3 g(256 / 128, DOC_PAD / 128);
        gemm4<<<g, 256, GEMM_SMEM, s2>>>(pHdh, pB2dh, pPd2, N_DOC, 2 * D_O, D_H);
    }
    cudaEventRecord(eD2, s2);

    // main: sent layer-2 GEMM
    {
        dim3 g(384 / 128, SENT_PAD / 128);
        gemm4<<<g, 256, GEMM_SMEM, st>>>(pHsh, pB2sh, pPs2, N_SENT, 3 * D_O, D_H);
    }

    // join + readout
    cudaStreamWaitEvent(st, eD2, 0);
    init_out<<<1, 32, 0, st>>>(out, b_score);
    gather2_sent<<<(N_SENT * 32 + 255) / 256, 256, 0, st>>>(pPs2, pPd2, bias2, w_score, gid_sent, out);
    gather2_doc<<<(N_DOC * 32 + 255) / 256, 256, 0, st>>>(pPs2, pPd2, bias2, w_score, gid_doc, out);
}

// round 13
// speedup vs baseline: 4.2709x; 1.0140x over previous
#include <cuda_runtime.h>
#include <cuda_fp16.h>
#include <cstdint>
#include <cstddef>

#define N_SENT 100000
#define N_DOC  10000
#define SENT_PAD 100096
#define DOC_PAD  10112
#define NGRAPH 32
#define D_IN   768
#define D_H    256
#define D_O    128
#define E_SS   400000
#define E_SD   100000
#define E_DS   100000

// ---------------- scratch (device globals: allocation-free) ----------------
__device__ __align__(16) __half g_B1s_h[768 * 768];
__device__ __align__(16) __half g_B1d_h[512 * 768];
__device__ __align__(16) __half g_B2s_h[384 * 256];
__device__ __align__(16) __half g_B2d_h[256 * 256];

__device__ __align__(16) __half g_xs_h[(size_t)SENT_PAD * D_IN];
__device__ __align__(16) __half g_xd_h[(size_t)DOC_PAD * D_IN];
__device__ __align__(16) __half g_hs_h[(size_t)SENT_PAD * D_H];
__device__ __align__(16) __half g_hd_h[(size_t)DOC_PAD * D_H];

__device__ __align__(16) __half g_Ps [(size_t)SENT_PAD * (3 * D_H)];
__device__ __align__(16) __half g_Pd [(size_t)N_DOC  * (2 * D_H)];
__device__ __align__(16) __half g_Ps2[(size_t)N_SENT * (3 * D_O)];
__device__ __align__(16) __half g_Pd2[(size_t)N_DOC  * (2 * D_O)];

// CSR structures (incoming edges per destination)
__device__ int   g_deg_ss[N_SENT], g_deg_ds[N_SENT], g_deg_sd[N_DOC];
__device__ int   g_ptr_ss[N_SENT], g_ptr_ds[N_SENT], g_ptr_sd[N_DOC];
__device__ int   g_cur_ss[N_SENT], g_cur_ds[N_SENT], g_cur_sd[N_DOC];
__device__ int   g_adj_ss[E_SS], g_adj_ds[E_DS], g_adj_sd[E_SD];
__device__ float g_inv_ss[N_SENT], g_inv_ds[N_SENT], g_inv_sd[N_DOC];
__device__ int   g_bsum_a[128], g_bsum_b[128], g_bsum_c[128];
__device__ int   g_part_ss[N_SENT], g_part_ds[N_SENT], g_part_sd[N_DOC];

// ---------------- PTX helpers ----------------
__device__ __forceinline__ uint32_t smem_u32(const void* p) {
    uint32_t a;
    asm("{ .reg .u64 t; cvta.to.shared.u64 t, %1; cvt.u32.u64 %0, t; }" : "=r"(a) : "l"(p));
    return a;
}

#define CP_ASYNC16(saddr, gaddr) \
    asm volatile("cp.async.cg.shared.global [%0], [%1], 16;" :: "r"(saddr), "l"(gaddr) : "memory")
#define CP_COMMIT() asm volatile("cp.async.commit_group;" ::: "memory")
#define CP_WAIT1()  asm volatile("cp.async.wait_group 1;" ::: "memory")

#define LDMX4(r0, r1, r2, r3, addr) \
    asm volatile("ldmatrix.sync.aligned.m8n8.x4.shared.b16 {%0,%1,%2,%3}, [%4];" \
                 : "=r"(r0), "=r"(r1), "=r"(r2), "=r"(r3) : "r"(addr))

#define MMA16816(d, a, b) \
    asm volatile("mma.sync.aligned.m16n8k16.row.col.f32.f16.f16.f32 " \
                 "{%0,%1,%2,%3}, {%4,%5,%6,%7}, {%8,%9}, {%0,%1,%2,%3};" \
                 : "+f"((d)[0]), "+f"((d)[1]), "+f"((d)[2]), "+f"((d)[3]) \
                 : "r"((a)[0]), "r"((a)[1]), "r"((a)[2]), "r"((a)[3]), "r"((b)[0]), "r"((b)[1]))

__device__ __forceinline__ uint4 pack8h(const float* f) {
    uint32_t hs[8];
    #pragma unroll
    for (int i = 0; i < 8; i++) hs[i] = (uint32_t)__half_as_ushort(__float2half(f[i]));
    return make_uint4(hs[0] | (hs[1] << 16), hs[2] | (hs[3] << 16), hs[4] | (hs[5] << 16), hs[6] | (hs[7] << 16));
}
__device__ __forceinline__ void add8h(float* A, uint4 v) {
    const __half2* h = (const __half2*)&v;
    #pragma unroll
    for (int i = 0; i < 4; i++) {
        float2 f = __half22float2(h[i]);
        A[2 * i] += f.x; A[2 * i + 1] += f.y;
    }
}
__device__ __forceinline__ void unpack8h(float* A, uint4 v) {
    const __half2* h = (const __half2*)&v;
    #pragma unroll
    for (int i = 0; i < 4; i++) {
        float2 f = __half22float2(h[i]);
        A[2 * i] = f.x; A[2 * i + 1] = f.y;
    }
}
__device__ __forceinline__ void add4h(float* A, uint2 v) {
    const __half2* h = (const __half2*)&v;
    #pragma unroll
    for (int i = 0; i < 2; i++) {
        float2 f = __half22float2(h[i]);
        A[2 * i] += f.x; A[2 * i + 1] += f.y;
    }
}

#define ROWB   80

// ================= GEMM: fp16 x fp16 -> fp16, 3-stage single-sync, 128x128 =============
// N is the row stride (ld) of C; grid.x covers the column strip; Bt/C may be pre-offset.
#define ST_SZ  20480
#define OFF_A  0
#define OFF_B  10240
#define NSTAGE 3
#define GEMM_SMEM (NSTAGE * ST_SZ)

__global__ __launch_bounds__(256, 2) void gemm4(
    const __half* __restrict__ A,
    const __half* __restrict__ Bt,
    __half* __restrict__ C, int M, int N, int K)
{
    extern __shared__ char smem[];
    uint32_t sb = smem_u32(smem);
    int tid = threadIdx.x;
    int lane = tid & 31, wid = tid >> 5;
    int warp_m = (wid & 3) * 32;
    int warp_n = (wid >> 2) * 64;
    int mrow0 = blockIdx.y * 128;
    int ncol0 = blockIdx.x * 128;
    int nk = K >> 5;

    int prow = tid >> 1;
    int pch  = (tid & 1) * 16;
    const __half* aP = A + (size_t)(mrow0 + prow) * K + pch;
    const __half* bP = Bt + (size_t)(ncol0 + prow) * K + pch;
    uint32_t sts = (uint32_t)(prow * ROWB + pch * 2);

    int ra = warp_m + (lane & 7) + (lane & 8);
    int ca = ((lane >> 4) << 3);
    uint32_t a_lm = (uint32_t)(ra * ROWB + ca * 2);
    int rb = warp_n + (lane & 7) + ((lane >> 4) << 3);
    int cb = (((lane >> 3) & 1) << 3);
    uint32_t b_lm = (uint32_t)(rb * ROWB + cb * 2);

    float acc[2][8][4];
    #pragma unroll
    for (int mi = 0; mi < 2; mi++)
        #pragma unroll
        for (int ni = 0; ni < 8; ni++)
            #pragma unroll
            for (int q = 0; q < 4; q++) acc[mi][ni][q] = 0.f;

    #pragma unroll
    for (int s = 0; s < 2; s++) {
        if (s < nk) {
            uint32_t base = sb + s * ST_SZ;
            const __half* ap = aP + s * 32;
            const __half* bp = bP + s * 32;
            CP_ASYNC16(base + OFF_A + sts, ap); CP_ASYNC16(base + OFF_A + sts + 16, ap + 8);
            CP_ASYNC16(base + OFF_B + sts, bp); CP_ASYNC16(base + OFF_B + sts + 16, bp + 8);
        }
        CP_COMMIT();
    }

    for (int kt = 0; kt < nk; kt++) {
        CP_WAIT1();
        __syncthreads();

        int pf = kt + 2;
        if (pf < nk) {
            uint32_t base = sb + (pf % NSTAGE) * ST_SZ;
            const __half* ap = aP + pf * 32;
            const __half* bp = bP + pf * 32;
            CP_ASYNC16(base + OFF_A + sts, ap); CP_ASYNC16(base + OFF_A + sts + 16, ap + 8);
            CP_ASYNC16(base + OFF_B + sts, bp); CP_ASYNC16(base + OFF_B + sts + 16, bp + 8);
        }
        CP_COMMIT();

        uint32_t bcur = sb + (kt % NSTAGE) * ST_SZ;
        #pragma unroll
        for (int ks = 0; ks < 2; ks++) {
            uint32_t koff = ks * 32;
            uint32_t af[2][4], bf[8][2];
            #pragma unroll
            for (int mi = 0; mi < 2; mi++)
                LDMX4(af[mi][0], af[mi][1], af[mi][2], af[mi][3],
                      bcur + OFF_A + a_lm + mi * (16 * ROWB) + koff);
            #pragma unroll
            for (int bg = 0; bg < 4; bg++)
                LDMX4(bf[bg * 2][0], bf[bg * 2][1], bf[bg * 2 + 1][0], bf[bg * 2 + 1][1],
                      bcur + OFF_B + b_lm + bg * (16 * ROWB) + koff);
            #pragma unroll
            for (int mi = 0; mi < 2; mi++)
                #pragma unroll
                for (int ni = 0; ni < 8; ni++)
                    MMA16816(acc[mi][ni], af[mi], bf[ni]);
        }
    }

    int g = lane >> 2, t4 = lane & 3;
    #pragma unroll
    for (int mi = 0; mi < 2; mi++) {
        int r0 = mrow0 + warp_m + mi * 16 + g;
        #pragma unroll
        for (int ni = 0; ni < 8; ni++) {
            int col = ncol0 + warp_n + ni * 8 + t4 * 2;
            if (r0 < M)
                *(__half2*)(C + (size_t)r0 * N + col) = __floats2half2_rn(acc[mi][ni][0], acc[mi][ni][1]);
            if (r0 + 8 < M)
                *(__half2*)(C + (size_t)(r0 + 8) * N + col) = __floats2half2_rn(acc[mi][ni][2], acc[mi][ni][3]);
        }
    }
}

// ---------------- fp32 -> fp16 convert (padded, zero-filled) ----------------
__global__ void cvt_f16(const float* __restrict__ x, __half* __restrict__ hi,
                        long long nreal, long long npad) {
    long long base = ((long long)blockIdx.x * blockDim.x + threadIdx.x) * 8;
    if (base >= npad) return;
    float f[8];
    if (base < nreal) {
        float4 v0 = *(const float4*)(x + base);
        float4 v1 = *(const float4*)(x + base + 4);
        f[0] = v0.x; f[1] = v0.y; f[2] = v0.z; f[3] = v0.w;
        f[4] = v1.x; f[5] = v1.y; f[6] = v1.z; f[7] = v1.w;
    } else {
        #pragma unroll
        for (int q = 0; q < 8; q++) f[q] = 0.f;
    }
    *(uint4*)(hi + base) = pack8h(f);
}

// ---------------- CSR construction (fused across the 3 relations) ----------------
__global__ void zero_deg() {
    int i = blockIdx.x * blockDim.x + threadIdx.x;
    if (i < N_SENT) { g_deg_ss[i] = 0; g_deg_ds[i] = 0; }
    if (i < N_DOC)  { g_deg_sd[i] = 0; }
}
__global__ void count_all(const int* __restrict__ dss, const int* __restrict__ dds,
                          const int* __restrict__ dsd) {
    int i = blockIdx.x * blockDim.x + threadIdx.x;
    if (i < E_SS) atomicAdd(&g_deg_ss[dss[i]], 1);
    else if (i < E_SS + E_DS) atomicAdd(&g_deg_ds[dds[i - E_SS]], 1);
    else if (i < E_SS + E_DS + E_SD) atomicAdd(&g_deg_sd[dsd[i - E_SS - E_DS]], 1);
}
#define NB_S 98
#define NB_D 10
__global__ void scan_local_all() {
    __shared__ int sm[1024];
    const int* deg; int* part; int* bsum; int n; int blk;
    if (blockIdx.x < NB_S) { deg = g_deg_ss; part = g_part_ss; bsum = g_bsum_a; n = N_SENT; blk = blockIdx.x; }
    else if (blockIdx.x < 2 * NB_S) { deg = g_deg_ds; part = g_part_ds; bsum = g_bsum_b; n = N_SENT; blk = blockIdx.x - NB_S; }
    else { deg = g_deg_sd; part = g_part_sd; bsum = g_bsum_c; n = N_DOC; blk = blockIdx.x - 2 * NB_S; }
    int i = blk * 1024 + threadIdx.x;
    int v = (i < n) ? deg[i] : 0;
    sm[threadIdx.x] = v;
    __syncthreads();
    #pragma unroll
    for (int off = 1; off < 1024; off <<= 1) {
        int t = (threadIdx.x >= off) ? sm[threadIdx.x - off] : 0;
        __syncthreads();
        sm[threadIdx.x] += t;
        __syncthreads();
    }
    if (i < n) part[i] = sm[threadIdx.x] - v;
    if (threadIdx.x == 1023) bsum[blk] = sm[1023];
}
__global__ void scan_block_all() {
    __shared__ int sm[128];
    int* bsum; int nb;
    if (blockIdx.x == 0) { bsum = g_bsum_a; nb = NB_S; }
    else if (blockIdx.x == 1) { bsum = g_bsum_b; nb = NB_S; }
    else { bsum = g_bsum_c; nb = NB_D; }
    int v = (threadIdx.x < nb) ? bsum[threadIdx.x] : 0;
    sm[threadIdx.x] = v;
    __syncthreads();
    #pragma unroll
    for (int off = 1; off < 128; off <<= 1) {
        int t = (threadIdx.x >= off) ? sm[threadIdx.x - off] : 0;
        __syncthreads();
        sm[threadIdx.x] += t;
        __syncthreads();
    }
    if (threadIdx.x < nb) bsum[threadIdx.x] = sm[threadIdx.x] - v;
}
__global__ void scan_final_all() {
    int i = blockIdx.x * blockDim.x + threadIdx.x;
    if (i < N_SENT) {
        int p = g_part_ss[i] + g_bsum_a[i >> 10];
        g_ptr_ss[i] = p; g_cur_ss[i] = p;
        g_inv_ss[i] = 1.0f / (float)max(g_deg_ss[i], 1);
    } else if (i < 2 * N_SENT) {
        int j = i - N_SENT;
        int p = g_part_ds[j] + g_bsum_b[j >> 10];
        g_ptr_ds[j] = p; g_cur_ds[j] = p;
        g_inv_ds[j] = 1.0f / (float)max(g_deg_ds[j], 1);
    } else if (i < 2 * N_SENT + N_DOC) {
        int j = i - 2 * N_SENT;
        int p = g_part_sd[j] + g_bsum_c[j >> 10];
        g_ptr_sd[j] = p; g_cur_sd[j] = p;
        g_inv_sd[j] = 1.0f / (float)max(g_deg_sd[j], 1);
    }
}
__global__ void fill_all(const int* __restrict__ sss, const int* __restrict__ dss,
                         const int* __restrict__ sds, const int* __restrict__ dds,
                         const int* __restrict__ ssd, const int* __restrict__ dsd) {
    int i = blockIdx.x * blockDim.x + threadIdx.x;
    if (i < E_SS) {
        int p = atomicAdd(&g_cur_ss[dss[i]], 1);
        g_adj_ss[p] = sss[i];
    } else if (i < E_SS + E_DS) {
        int e = i - E_SS;
        int p = atomicAdd(&g_cur_ds[dds[e]], 1);
        g_adj_ds[p] = sds[e];
    } else if (i < E_SS + E_DS + E_SD) {
        int e = i - E_SS - E_DS;
        int p = atomicAdd(&g_cur_sd[dsd[e]], 1);
        g_adj_sd[p] = ssd[e];
    }
}

// ---------------- weight build: transposed fp16 ----------------
__global__ void build_w3t(const float* __restrict__ coeff, const float* __restrict__ basis,
                          const float* __restrict__ loopw,
                          __half* __restrict__ outH,
                          int K, int D, int Npad, int r0, int r1) {
    int idx = blockIdx.x * blockDim.x + threadIdx.x;
    if (idx >= Npad * K) return;
    int o = idx / K;
    int k = idx % K;
    float v = 0.f;
    if (o < 3 * D) {
        int seg = o / D, od = o % D;
        if (seg == 2) v = loopw[k * D + od];
        else {
            int r = (seg == 0) ? r0 : r1;
            v = coeff[r * 2 + 0] * basis[(size_t)k * D + od]
              + coeff[r * 2 + 1] * basis[(size_t)K * D + (size_t)k * D + od];
        }
    }
    outH[idx] = __float2half(v);
}
__global__ void build_w2t(const float* __restrict__ coeff, const float* __restrict__ basis,
                          const float* __restrict__ loopw,
                          __half* __restrict__ outH,
                          int K, int D, int Npad, int r0) {
    int idx = blockIdx.x * blockDim.x + threadIdx.x;
    if (idx >= Npad * K) return;
    int o = idx / K;
    int k = idx % K;
    float v = 0.f;
    if (o < 2 * D) {
        int seg = o / D, od = o % D;
        if (seg == 1) v = loopw[k * D + od];
        else {
            v = coeff[r0 * 2 + 0] * basis[(size_t)k * D + od]
              + coeff[r0 * 2 + 1] * basis[(size_t)K * D + (size_t)k * D + od];
        }
    }
    outH[idx] = __float2half(v);
}

// ---------------- layer-1 gather (warp per dst node) + combine + fp16 emit ----------------
__global__ void gather1_sent(const __half* __restrict__ Ps, const __half* __restrict__ Pd,
                             const float* __restrict__ bias, __half* __restrict__ hout) {
    int w = (blockIdx.x * blockDim.x + threadIdx.x) >> 5;
    int lane = threadIdx.x & 31;
    if (w >= SENT_PAD) return;
    __half* orow = hout + (size_t)w * D_H;
    if (w >= N_SENT) {
        *(uint4*)(orow + lane * 8) = make_uint4(0u, 0u, 0u, 0u);
        return;
    }
    float A[8] = {0.f}, Bv[8] = {0.f};
    int p = g_ptr_ss[w], d = g_deg_ss[w];
    int k = 0;
    for (; k + 1 < d; k += 2) {
        int s0 = g_adj_ss[p + k], s1 = g_adj_ss[p + k + 1];
        uint4 v0 = *(const uint4*)(Ps + (size_t)s0 * 768 + 256 + lane * 8);
        uint4 v1 = *(const uint4*)(Ps + (size_t)s1 * 768 + 256 + lane * 8);
        add8h(A, v0); add8h(A, v1);
    }
    if (k < d) {
        int s0 = g_adj_ss[p + k];
        add8h(A, *(const uint4*)(Ps + (size_t)s0 * 768 + 256 + lane * 8));
    }
    float sc = g_inv_ss[w];
    p = g_ptr_ds[w]; d = g_deg_ds[w];
    k = 0;
    for (; k + 1 < d; k += 2) {
        int s0 = g_adj_ds[p + k], s1 = g_adj_ds[p + k + 1];
        uint4 v0 = *(const uint4*)(Pd + (size_t)s0 * 512 + lane * 8);
        uint4 v1 = *(const uint4*)(Pd + (size_t)s1 * 512 + lane * 8);
        add8h(Bv, v0); add8h(Bv, v1);
    }
    if (k < d) {
        int s0 = g_adj_ds[p + k];
        add8h(Bv, *(const uint4*)(Pd + (size_t)s0 * 512 + lane * 8));
    }
    float sc2 = g_inv_ds[w];
    float L[8];
    unpack8h(L, *(const uint4*)(Ps + (size_t)w * 768 + 512 + lane * 8));
    float f[8];
    #pragma unroll
    for (int i = 0; i < 8; i++)
        f[i] = fmaxf(fmaf(A[i], sc, fmaf(Bv[i], sc2, L[i] + bias[lane * 8 + i])), 0.f);
    *(uint4*)(orow + lane * 8) = pack8h(f);
}
__global__ void gather1_doc(const __half* __restrict__ Ps, const __half* __restrict__ Pd,
                            const float* __restrict__ bias, __half* __restrict__ hout) {
    int w = (blockIdx.x * blockDim.x + threadIdx.x) >> 5;
    int lane = threadIdx.x & 31;
    if (w >= DOC_PAD) return;
    __half* orow = hout + (size_t)w * D_H;
    if (w >= N_DOC) {
        *(uint4*)(orow + lane * 8) = make_uint4(0u, 0u, 0u, 0u);
        return;
    }
    float A[8] = {0.f};
    int p = g_ptr_sd[w], d = g_deg_sd[w];
    int k = 0;
    for (; k + 1 < d; k += 2) {
        int s0 = g_adj_sd[p + k], s1 = g_adj_sd[p + k + 1];
        uint4 v0 = *(const uint4*)(Ps + (size_t)s0 * 768 + lane * 8);
        uint4 v1 = *(const uint4*)(Ps + (size_t)s1 * 768 + lane * 8);
        add8h(A, v0); add8h(A, v1);
    }
    if (k < d) {
        int s0 = g_adj_sd[p + k];
        add8h(A, *(const uint4*)(Ps + (size_t)s0 * 768 + lane * 8));
    }
    float sc = g_inv_sd[w];
    float L[8];
    unpack8h(L, *(const uint4*)(Pd + (size_t)w * 512 + 256 + lane * 8));
    float f[8];
    #pragma unroll
    for (int i = 0; i < 8; i++)
        f[i] = fmaxf(fmaf(A[i], sc, L[i] + bias[lane * 8 + i]), 0.f);
    *(uint4*)(orow + lane * 8) = pack8h(f);
}

// ---------------- layer-2 gather + combine + relu + score + per-graph reduce -------------
__global__ void init_out(float* __restrict__ out, const float* __restrict__ b_score) {
    int g = threadIdx.x;
    if (g < NGRAPH) out[g] = b_score[0];
}
__global__ void gather2_sent(const __half* __restrict__ Ps2, const __half* __restrict__ Pd2,
                             const float* __restrict__ bias, const float* __restrict__ wscore,
                             const int* __restrict__ gid, float* __restrict__ out) {
    int w = (blockIdx.x * blockDim.x + threadIdx.x) >> 5;
    int lane = threadIdx.x & 31;
    if (w >= N_SENT) return;
    float A[4] = {0.f}, Bv[4] = {0.f};
    int p = g_ptr_ss[w], d = g_deg_ss[w];
    int k = 0;
    for (; k + 1 < d; k += 2) {
        int s0 = g_adj_ss[p + k], s1 = g_adj_ss[p + k + 1];
        uint2 v0 = *(const uint2*)(Ps2 + (size_t)s0 * 384 + 128 + lane * 4);
        uint2 v1 = *(const uint2*)(Ps2 + (size_t)s1 * 384 + 128 + lane * 4);
        add4h(A, v0); add4h(A, v1);
    }
    if (k < d) {
        int s0 = g_adj_ss[p + k];
        add4h(A, *(const uint2*)(Ps2 + (size_t)s0 * 384 + 128 + lane * 4));
    }
    float sc = g_inv_ss[w];
    p = g_ptr_ds[w]; d = g_deg_ds[w];
    k = 0;
    for (; k + 1 < d; k += 2) {
        int s0 = g_adj_ds[p + k], s1 = g_adj_ds[p + k + 1];
        uint2 v0 = *(const uint2*)(Pd2 + (size_t)s0 * 256 + lane * 4);
        uint2 v1 = *(const uint2*)(Pd2 + (size_t)s1 * 256 + lane * 4);
        add4h(Bv, v0); add4h(Bv, v1);
    }
    if (k < d) {
        int s0 = g_adj_ds[p + k];
        add4h(Bv, *(const uint2*)(Pd2 + (size_t)s0 * 256 + lane * 4));
    }
    float sc2 = g_inv_ds[w];
    float L[4] = {0.f};
    add4h(L, *(const uint2*)(Ps2 + (size_t)w * 384 + 256 + lane * 4));
    float4 B = ((const float4*)bias)[lane];
    float4 W = ((const float4*)wscore)[lane];
    float bb[4] = {B.x, B.y, B.z, B.w};
    float ww[4] = {W.x, W.y, W.z, W.w};
    float s = 0.f;
    #pragma unroll
    for (int i = 0; i < 4; i++)
        s += fmaxf(fmaf(A[i], sc, fmaf(Bv[i], sc2, L[i] + bb[i])), 0.f) * ww[i];
    #pragma unroll
    for (int off = 16; off; off >>= 1) s += __shfl_down_sync(0xffffffffu, s, off);
    if (lane == 0) atomicAdd(&out[gid[w]], s);
}
__global__ void gather2_doc(const __half* __restrict__ Ps2, const __half* __restrict__ Pd2,
                            const float* __restrict__ bias, const float* __restrict__ wscore,
                            const int* __restrict__ gid, float* __restrict__ out) {
    int w = (blockIdx.x * blockDim.x + threadIdx.x) >> 5;
    int lane = threadIdx.x & 31;
    if (w >= N_DOC) return;
    float A[4] = {0.f};
    int p = g_ptr_sd[w], d = g_deg_sd[w];
    int k = 0;
    for (; k + 1 < d; k += 2) {
        int s0 = g_adj_sd[p + k], s1 = g_adj_sd[p + k + 1];
        uint2 v0 = *(const uint2*)(Ps2 + (size_t)s0 * 384 + lane * 4);
        uint2 v1 = *(const uint2*)(Ps2 + (size_t)s1 * 384 + lane * 4);
        add4h(A, v0); add4h(A, v1);
    }
    if (k < d) {
        int s0 = g_adj_sd[p + k];
        add4h(A, *(const uint2*)(Ps2 + (size_t)s0 * 384 + lane * 4));
    }
    float sc = g_inv_sd[w];
    float L[4] = {0.f};
    add4h(L, *(const uint2*)(Pd2 + (size_t)w * 256 + 128 + lane * 4));
    float4 B = ((const float4*)bias)[lane];
    float4 W = ((const float4*)wscore)[lane];
    float bb[4] = {B.x, B.y, B.z, B.w};
    float ww[4] = {W.x, W.y, W.z, W.w};
    float s = 0.f;
    #pragma unroll
    for (int i = 0; i < 4; i++)
        s += fmaxf(fmaf(A[i], sc, L[i] + bb[i]), 0.f) * ww[i];
    #pragma unroll
    for (int off = 16; off; off >>= 1) s += __shfl_down_sync(0xffffffffu, s, off);
    if (lane == 0) atomicAdd(&out[gid[w]], s);
}

// ---------------- host launcher ----------------
static void* symaddr(const void* sym) {
    void* p = nullptr;
    cudaGetSymbolAddress(&p, sym);
    return p;
}

extern "C" void kernel_launch(void* const* d_in, const int* in_sizes, int n_in,
                              void* d_out, int out_size) {
    const float* x_sent  = (const float*)d_in[0];
    const float* x_doc   = (const float*)d_in[1];
    const float* coeff1  = (const float*)d_in[2];
    const float* basis1  = (const float*)d_in[3];
    const float* loop_w1 = (const float*)d_in[4];
    const float* bias1   = (const float*)d_in[5];
    const float* coeff2  = (const float*)d_in[6];
    const float* basis2  = (const float*)d_in[7];
    const float* loop_w2 = (const float*)d_in[8];
    const float* bias2   = (const float*)d_in[9];
    const float* w_score = (const float*)d_in[10];
    const float* b_score = (const float*)d_in[11];
    const int*   src_ss  = (const int*)d_in[12];
    const int*   dst_ss  = (const int*)d_in[13];
    const int*   src_sd  = (const int*)d_in[14];
    const int*   dst_sd  = (const int*)d_in[15];
    const int*   src_ds  = (const int*)d_in[16];
    const int*   dst_ds  = (const int*)d_in[17];
    const int*   gid_sent= (const int*)d_in[18];
    const int*   gid_doc = (const int*)d_in[19];
    float* out = (float*)d_out;

    __half* pB1sh = (__half*)symaddr(g_B1s_h);
    __half* pB1dh = (__half*)symaddr(g_B1d_h);
    __half* pB2sh = (__half*)symaddr(g_B2s_h);
    __half* pB2dh = (__half*)symaddr(g_B2d_h);
    __half* pXsh = (__half*)symaddr(g_xs_h);
    __half* pXdh = (__half*)symaddr(g_xd_h);
    __half* pHsh = (__half*)symaddr(g_hs_h);
    __half* pHdh = (__half*)symaddr(g_hd_h);
    __half* pPs  = (__half*)symaddr(g_Ps);
    __half* pPd  = (__half*)symaddr(g_Pd);
    __half* pPs2 = (__half*)symaddr(g_Ps2);
    __half* pPd2 = (__half*)symaddr(g_Pd2);

    cudaFuncSetAttribute(gemm4, cudaFuncAttributeMaxDynamicSharedMemorySize, GEMM_SMEM);

    static cudaStream_t s2 = nullptr;
    static cudaEvent_t eFork = nullptr, eSide = nullptr, eStripA = nullptr,
                       eHd = nullptr, eD2 = nullptr;
    if (s2 == nullptr) {
        cudaStreamCreateWithFlags(&s2, cudaStreamNonBlocking);
        cudaEventCreateWithFlags(&eFork, cudaEventDisableTiming);
        cudaEventCreateWithFlags(&eSide, cudaEventDisableTiming);
        cudaEventCreateWithFlags(&eStripA, cudaEventDisableTiming);
        cudaEventCreateWithFlags(&eHd, cudaEventDisableTiming);
        cudaEventCreateWithFlags(&eD2, cudaEventDisableTiming);
    }

    cudaStream_t st = 0;

    // ---- main stream head (harness has 2 launches before ours; global #5 = idx 3) ----
    zero_deg<<<(N_SENT + 255) / 256, 256, 0, st>>>();                                        // idx 0
    cudaEventRecord(eFork, st);
    {                                                                                        // idx 1
        long long nreal = (long long)N_SENT * D_IN, npad = (long long)SENT_PAD * D_IN;
        cvt_f16<<<(unsigned)((npad / 8 + 255) / 256), 256, 0, st>>>(x_sent, pXsh, nreal, npad);
    }
    build_w3t<<<(768 * 768 + 255) / 256, 256, 0, st>>>(coeff1, basis1, loop_w1, pB1sh, D_IN, D_H, 768, 0, 2); // idx 2
    // idx 3 (ncu -s 5): strip A of layer-1 sent GEMM -> Ps cols 256:768 (ss + loop segments)
    {
        dim3 g(512 / 128, SENT_PAD / 128);
        gemm4<<<g, 256, GEMM_SMEM, st>>>(pXsh, pB1sh + (size_t)256 * D_IN, pPs + 256,
                                         N_SENT, 3 * D_H, D_IN);
    }
    cudaEventRecord(eStripA, st);

    // ---- side stream: CSR + doc prep + doc layer-1 GEMM under strip A ----
    cudaStreamWaitEvent(s2, eFork, 0);
    {
        int Etot = E_SS + E_DS + E_SD;
        count_all<<<(Etot + 255) / 256, 256, 0, s2>>>(dst_ss, dst_ds, dst_sd);
        scan_local_all<<<2 * NB_S + NB_D, 1024, 0, s2>>>();
        scan_block_all<<<3, 128, 0, s2>>>();
        scan_final_all<<<(2 * N_SENT + N_DOC + 255) / 256, 256, 0, s2>>>();
        fill_all<<<(Etot + 255) / 256, 256, 0, s2>>>(src_ss, dst_ss, src_ds, dst_ds, src_sd, dst_sd);
    }
    {
        long long nreal = (long long)N_DOC * D_IN, npad = (long long)DOC_PAD * D_IN;
        cvt_f16<<<(unsigned)((npad / 8 + 255) / 256), 256, 0, s2>>>(x_doc, pXdh, nreal, npad);
    }
    build_w2t<<<(512 * 768 + 255) / 256, 256, 0, s2>>>(coeff1, basis1, loop_w1, pB1dh, D_IN, D_H, 512, 1);
    build_w3t<<<(384 * 256 + 255) / 256, 256, 0, s2>>>(coeff2, basis2, loop_w2, pB2sh, D_H, D_O, 384, 0, 2);
    build_w2t<<<(256 * 256 + 255) / 256, 256, 0, s2>>>(coeff2, basis2, loop_w2, pB2dh, D_H, D_O, 256, 1);
    {
        dim3 g(512 / 128, DOC_PAD / 128);
        gemm4<<<g, 256, GEMM_SMEM, s2>>>(pXdh, pB1dh, pPd, N_DOC, 2 * D_H, D_IN);
    }
    cudaEventRecord(eSide, s2);

    // ---- side (after strip A): strip B of sent GEMM (Ps cols 0:256) -> doc path ----
    cudaStreamWaitEvent(s2, eStripA, 0);
    {
        dim3 g(256 / 128, SENT_PAD / 128);
        gemm4<<<g, 256, GEMM_SMEM, s2>>>(pXsh, pB1sh, pPs, N_SENT, 3 * D_H, D_IN);
    }
    gather1_doc<<<(DOC_PAD * 32 + 255) / 256, 256, 0, s2>>>(pPs, pPd, bias1, pHdh);
    cudaEventRecord(eHd, s2);
    {
        dim3 g(256 / 128, DOC_PAD / 128);
        gemm4<<<g, 256, GEMM_SMEM, s2>>>(pHdh, pB2dh, pPd2, N_DOC, 2 * D_O, D_H);
    }
    cudaEventRecord(eD2, s2);

    // ---- main: gather1_sent (needs strip A cols 256:768 + Pd + CSR), concurrent with strip B ----
    cudaStreamWaitEvent(st, eSide, 0);
    gather1_sent<<<(SENT_PAD * 32 + 255) / 256, 256, 0, st>>>(pPs, pPd, bias1, pHsh);

    // main: sent layer-2 GEMM (concurrent with side's gather1_doc + doc layer-2 GEMM)
    {
        dim3 g(384 / 128, SENT_PAD / 128);
        gemm4<<<g, 256, GEMM_SMEM, st>>>(pHsh, pB2sh, pPs2, N_SENT, 3 * D_O, D_H);
    }

    // join + readout
    cudaStreamWaitEvent(st, eD2, 0);
    init_out<<<1, 32, 0, st>>>(out, b_score);
    gather2_sent<<<(N_SENT * 32 + 255) / 256, 256, 0, st>>>(pPs2, pPd2, bias2, w_score, gid_sent, out);
    gather2_doc<<<(N_DOC * 32 + 255) / 256, 256, 0, st>>>(pPs2, pPd2, bias2, w_score, gid_doc, out);
}

// round 14
// speedup vs baseline: 4.2777x; 1.0016x over previous
#include <cuda_runtime.h>
#include <cuda_fp16.h>
#include <cstdint>
#include <cstddef>

#define N_SENT 100000
#define N_DOC  10000
#define SENT_PAD 100096
#define DOC_PAD  10112
#define HALF_S   50048
#define NGRAPH 32
#define D_IN   768
#define D_H    256
#define D_O    128
#define E_SS   400000
#define E_SD   100000
#define E_DS   100000

// ---------------- scratch (device globals: allocation-free) ----------------
__device__ __align__(16) __half g_B1s_h[768 * 768];
__device__ __align__(16) __half g_B1d_h[512 * 768];
__device__ __align__(16) __half g_B2s_h[384 * 256];
__device__ __align__(16) __half g_B2d_h[256 * 256];

__device__ __align__(16) __half g_xs_h[(size_t)SENT_PAD * D_IN];
__device__ __align__(16) __half g_xd_h[(size_t)DOC_PAD * D_IN];
__device__ __align__(16) __half g_hs_h[(size_t)SENT_PAD * D_H];
__device__ __align__(16) __half g_hd_h[(size_t)DOC_PAD * D_H];

__device__ __align__(16) __half g_Ps [(size_t)SENT_PAD * (3 * D_H)];
__device__ __align__(16) __half g_Pd [(size_t)N_DOC  * (2 * D_H)];
__device__ __align__(16) __half g_Ps2[(size_t)SENT_PAD * (3 * D_O)];
__device__ __align__(16) __half g_Pd2[(size_t)N_DOC  * (2 * D_O)];

// CSR structures (incoming edges per destination)
__device__ int   g_deg_ss[N_SENT], g_deg_ds[N_SENT], g_deg_sd[N_DOC];
__device__ int   g_ptr_ss[N_SENT], g_ptr_ds[N_SENT], g_ptr_sd[N_DOC];
__device__ int   g_cur_ss[N_SENT], g_cur_ds[N_SENT], g_cur_sd[N_DOC];
__device__ int   g_adj_ss[E_SS], g_adj_ds[E_DS], g_adj_sd[E_SD];
__device__ float g_inv_ss[N_SENT], g_inv_ds[N_SENT], g_inv_sd[N_DOC];
__device__ int   g_bsum_a[128], g_bsum_b[128], g_bsum_c[128];
__device__ int   g_part_ss[N_SENT], g_part_ds[N_SENT], g_part_sd[N_DOC];

// ---------------- PTX helpers ----------------
__device__ __forceinline__ uint32_t smem_u32(const void* p) {
    uint32_t a;
    asm("{ .reg .u64 t; cvta.to.shared.u64 t, %1; cvt.u32.u64 %0, t; }" : "=r"(a) : "l"(p));
    return a;
}

#define CP_ASYNC16(saddr, gaddr) \
    asm volatile("cp.async.cg.shared.global [%0], [%1], 16;" :: "r"(saddr), "l"(gaddr) : "memory")
#define CP_COMMIT() asm volatile("cp.async.commit_group;" ::: "memory")
#define CP_WAIT1()  asm volatile("cp.async.wait_group 1;" ::: "memory")

#define LDMX4(r0, r1, r2, r3, addr) \
    asm volatile("ldmatrix.sync.aligned.m8n8.x4.shared.b16 {%0,%1,%2,%3}, [%4];" \
                 : "=r"(r0), "=r"(r1), "=r"(r2), "=r"(r3) : "r"(addr))

#define MMA16816(d, a, b) \
    asm volatile("mma.sync.aligned.m16n8k16.row.col.f32.f16.f16.f32 " \
                 "{%0,%1,%2,%3}, {%4,%5,%6,%7}, {%8,%9}, {%0,%1,%2,%3};" \
                 : "+f"((d)[0]), "+f"((d)[1]), "+f"((d)[2]), "+f"((d)[3]) \
                 : "r"((a)[0]), "r"((a)[1]), "r"((a)[2]), "r"((a)[3]), "r"((b)[0]), "r"((b)[1]))

__device__ __forceinline__ uint4 pack8h(const float* f) {
    uint32_t hs[8];
    #pragma unroll
    for (int i = 0; i < 8; i++) hs[i] = (uint32_t)__half_as_ushort(__float2half(f[i]));
    return make_uint4(hs[0] | (hs[1] << 16), hs[2] | (hs[3] << 16), hs[4] | (hs[5] << 16), hs[6] | (hs[7] << 16));
}
__device__ __forceinline__ void add8h(float* A, uint4 v) {
    const __half2* h = (const __half2*)&v;
    #pragma unroll
    for (int i = 0; i < 4; i++) {
        float2 f = __half22float2(h[i]);
        A[2 * i] += f.x; A[2 * i + 1] += f.y;
    }
}
__device__ __forceinline__ void unpack8h(float* A, uint4 v) {
    const __half2* h = (const __half2*)&v;
    #pragma unroll
    for (int i = 0; i < 4; i++) {
        float2 f = __half22float2(h[i]);
        A[2 * i] = f.x; A[2 * i + 1] = f.y;
    }
}
__device__ __forceinline__ void add4h(float* A, uint2 v) {
    const __half2* h = (const __half2*)&v;
    #pragma unroll
    for (int i = 0; i < 2; i++) {
        float2 f = __half22float2(h[i]);
        A[2 * i] += f.x; A[2 * i + 1] += f.y;
    }
}

#define ROWB   80

// ================= GEMM: fp16 x fp16 -> fp16, 3-stage single-sync, 128x128 =============
// N = row stride of C. Bt/C may be pre-offset (column strips); A/C may be row-offset (row chunks).
#define ST_SZ  20480
#define OFF_A  0
#define OFF_B  10240
#define NSTAGE 3
#define GEMM_SMEM (NSTAGE * ST_SZ)

__global__ __launch_bounds__(256, 2) void gemm4(
    const __half* __restrict__ A,
    const __half* __restrict__ Bt,
    __half* __restrict__ C, int M, int N, int K)
{
    extern __shared__ char smem[];
    uint32_t sb = smem_u32(smem);
    int tid = threadIdx.x;
    int lane = tid & 31, wid = tid >> 5;
    int warp_m = (wid & 3) * 32;
    int warp_n = (wid >> 2) * 64;
    int mrow0 = blockIdx.y * 128;
    int ncol0 = blockIdx.x * 128;
    int nk = K >> 5;

    int prow = tid >> 1;
    int pch  = (tid & 1) * 16;
    const __half* aP = A + (size_t)(mrow0 + prow) * K + pch;
    const __half* bP = Bt + (size_t)(ncol0 + prow) * K + pch;
    uint32_t sts = (uint32_t)(prow * ROWB + pch * 2);

    int ra = warp_m + (lane & 7) + (lane & 8);
    int ca = ((lane >> 4) << 3);
    uint32_t a_lm = (uint32_t)(ra * ROWB + ca * 2);
    int rb = warp_n + (lane & 7) + ((lane >> 4) << 3);
    int cb = (((lane >> 3) & 1) << 3);
    uint32_t b_lm = (uint32_t)(rb * ROWB + cb * 2);

    float acc[2][8][4];
    #pragma unroll
    for (int mi = 0; mi < 2; mi++)
        #pragma unroll
        for (int ni = 0; ni < 8; ni++)
            #pragma unroll
            for (int q = 0; q < 4; q++) acc[mi][ni][q] = 0.f;

    #pragma unroll
    for (int s = 0; s < 2; s++) {
        if (s < nk) {
            uint32_t base = sb + s * ST_SZ;
            const __half* ap = aP + s * 32;
            const __half* bp = bP + s * 32;
            CP_ASYNC16(base + OFF_A + sts, ap); CP_ASYNC16(base + OFF_A + sts + 16, ap + 8);
            CP_ASYNC16(base + OFF_B + sts, bp); CP_ASYNC16(base + OFF_B + sts + 16, bp + 8);
        }
        CP_COMMIT();
    }

    for (int kt = 0; kt < nk; kt++) {
        CP_WAIT1();
        __syncthreads();

        int pf = kt + 2;
        if (pf < nk) {
            uint32_t base = sb + (pf % NSTAGE) * ST_SZ;
            const __half* ap = aP + pf * 32;
            const __half* bp = bP + pf * 32;
            CP_ASYNC16(base + OFF_A + sts, ap); CP_ASYNC16(base + OFF_A + sts + 16, ap + 8);
            CP_ASYNC16(base + OFF_B + sts, bp); CP_ASYNC16(base + OFF_B + sts + 16, bp + 8);
        }
        CP_COMMIT();

        uint32_t bcur = sb + (kt % NSTAGE) * ST_SZ;
        #pragma unroll
        for (int ks = 0; ks < 2; ks++) {
            uint32_t koff = ks * 32;
            uint32_t af[2][4], bf[8][2];
            #pragma unroll
            for (int mi = 0; mi < 2; mi++)
                LDMX4(af[mi][0], af[mi][1], af[mi][2], af[mi][3],
                      bcur + OFF_A + a_lm + mi * (16 * ROWB) + koff);
            #pragma unroll
            for (int bg = 0; bg < 4; bg++)
                LDMX4(bf[bg * 2][0], bf[bg * 2][1], bf[bg * 2 + 1][0], bf[bg * 2 + 1][1],
                      bcur + OFF_B + b_lm + bg * (16 * ROWB) + koff);
            #pragma unroll
            for (int mi = 0; mi < 2; mi++)
                #pragma unroll
                for (int ni = 0; ni < 8; ni++)
                    MMA16816(acc[mi][ni], af[mi], bf[ni]);
        }
    }

    int g = lane >> 2, t4 = lane & 3;
    #pragma unroll
    for (int mi = 0; mi < 2; mi++) {
        int r0 = mrow0 + warp_m + mi * 16 + g;
        #pragma unroll
        for (int ni = 0; ni < 8; ni++) {
            int col = ncol0 + warp_n + ni * 8 + t4 * 2;
            if (r0 < M)
                *(__half2*)(C + (size_t)r0 * N + col) = __floats2half2_rn(acc[mi][ni][0], acc[mi][ni][1]);
            if (r0 + 8 < M)
                *(__half2*)(C + (size_t)(r0 + 8) * N + col) = __floats2half2_rn(acc[mi][ni][2], acc[mi][ni][3]);
        }
    }
}

// ---------------- fp32 -> fp16 convert (padded, zero-filled) ----------------
__global__ void cvt_f16(const float* __restrict__ x, __half* __restrict__ hi,
                        long long nreal, long long npad) {
    long long base = ((long long)blockIdx.x * blockDim.x + threadIdx.x) * 8;
    if (base >= npad) return;
    float f[8];
    if (base < nreal) {
        float4 v0 = *(const float4*)(x + base);
        float4 v1 = *(const float4*)(x + base + 4);
        f[0] = v0.x; f[1] = v0.y; f[2] = v0.z; f[3] = v0.w;
        f[4] = v1.x; f[5] = v1.y; f[6] = v1.z; f[7] = v1.w;
    } else {
        #pragma unroll
        for (int q = 0; q < 8; q++) f[q] = 0.f;
    }
    *(uint4*)(hi + base) = pack8h(f);
}

// ---------------- CSR construction (fused across the 3 relations) ----------------
__global__ void zero_deg() {
    int i = blockIdx.x * blockDim.x + threadIdx.x;
    if (i < N_SENT) { g_deg_ss[i] = 0; g_deg_ds[i] = 0; }
    if (i < N_DOC)  { g_deg_sd[i] = 0; }
}
__global__ void count_all(const int* __restrict__ dss, const int* __restrict__ dds,
                          const int* __restrict__ dsd) {
    int i = blockIdx.x * blockDim.x + threadIdx.x;
    if (i < E_SS) atomicAdd(&g_deg_ss[dss[i]], 1);
    else if (i < E_SS + E_DS) atomicAdd(&g_deg_ds[dds[i - E_SS]], 1);
    else if (i < E_SS + E_DS + E_SD) atomicAdd(&g_deg_sd[dsd[i - E_SS - E_DS]], 1);
}
#define NB_S 98
#define NB_D 10
__global__ void scan_local_all() {
    __shared__ int sm[1024];
    const int* deg; int* part; int* bsum; int n; int blk;
    if (blockIdx.x < NB_S) { deg = g_deg_ss; part = g_part_ss; bsum = g_bsum_a; n = N_SENT; blk = blockIdx.x; }
    else if (blockIdx.x < 2 * NB_S) { deg = g_deg_ds; part = g_part_ds; bsum = g_bsum_b; n = N_SENT; blk = blockIdx.x - NB_S; }
    else { deg = g_deg_sd; part = g_part_sd; bsum = g_bsum_c; n = N_DOC; blk = blockIdx.x - 2 * NB_S; }
    int i = blk * 1024 + threadIdx.x;
    int v = (i < n) ? deg[i] : 0;
    sm[threadIdx.x] = v;
    __syncthreads();
    #pragma unroll
    for (int off = 1; off < 1024; off <<= 1) {
        int t = (threadIdx.x >= off) ? sm[threadIdx.x - off] : 0;
        __syncthreads();
        sm[threadIdx.x] += t;
        __syncthreads();
    }
    if (i < n) part[i] = sm[threadIdx.x] - v;
    if (threadIdx.x == 1023) bsum[blk] = sm[1023];
}
__global__ void scan_block_all() {
    __shared__ int sm[128];
    int* bsum; int nb;
    if (blockIdx.x == 0) { bsum = g_bsum_a; nb = NB_S; }
    else if (blockIdx.x == 1) { bsum = g_bsum_b; nb = NB_S; }
    else { bsum = g_bsum_c; nb = NB_D; }
    int v = (threadIdx.x < nb) ? bsum[threadIdx.x] : 0;
    sm[threadIdx.x] = v;
    __syncthreads();
    #pragma unroll
    for (int off = 1; off < 128; off <<= 1) {
        int t = (threadIdx.x >= off) ? sm[threadIdx.x - off] : 0;
        __syncthreads();
        sm[threadIdx.x] += t;
        __syncthreads();
    }
    if (threadIdx.x < nb) bsum[threadIdx.x] = sm[threadIdx.x] - v;
}
__global__ void scan_final_all() {
    int i = blockIdx.x * blockDim.x + threadIdx.x;
    if (i < N_SENT) {
        int p = g_part_ss[i] + g_bsum_a[i >> 10];
        g_ptr_ss[i] = p; g_cur_ss[i] = p;
        g_inv_ss[i] = 1.0f / (float)max(g_deg_ss[i], 1);
    } else if (i < 2 * N_SENT) {
        int j = i - N_SENT;
        int p = g_part_ds[j] + g_bsum_b[j >> 10];
        g_ptr_ds[j] = p; g_cur_ds[j] = p;
        g_inv_ds[j] = 1.0f / (float)max(g_deg_ds[j], 1);
    } else if (i < 2 * N_SENT + N_DOC) {
        int j = i - 2 * N_SENT;
        int p = g_part_sd[j] + g_bsum_c[j >> 10];
        g_ptr_sd[j] = p; g_cur_sd[j] = p;
        g_inv_sd[j] = 1.0f / (float)max(g_deg_sd[j], 1);
    }
}
__global__ void fill_all(const int* __restrict__ sss, const int* __restrict__ dss,
                         const int* __restrict__ sds, const int* __restrict__ dds,
                         const int* __restrict__ ssd, const int* __restrict__ dsd) {
    int i = blockIdx.x * blockDim.x + threadIdx.x;
    if (i < E_SS) {
        int p = atomicAdd(&g_cur_ss[dss[i]], 1);
        g_adj_ss[p] = sss[i];
    } else if (i < E_SS + E_DS) {
        int e = i - E_SS;
        int p = atomicAdd(&g_cur_ds[dds[e]], 1);
        g_adj_ds[p] = sds[e];
    } else if (i < E_SS + E_DS + E_SD) {
        int e = i - E_SS - E_DS;
        int p = atomicAdd(&g_cur_sd[dsd[e]], 1);
        g_adj_sd[p] = ssd[e];
    }
}

// ---------------- weight build: transposed fp16 ----------------
__global__ void build_w3t(const float* __restrict__ coeff, const float* __restrict__ basis,
                          const float* __restrict__ loopw,
                          __half* __restrict__ outH,
                          int K, int D, int Npad, int r0, int r1) {
    int idx = blockIdx.x * blockDim.x + threadIdx.x;
    if (idx >= Npad * K) return;
    int o = idx / K;
    int k = idx % K;
    float v = 0.f;
    if (o < 3 * D) {
        int seg = o / D, od = o % D;
        if (seg == 2) v = loopw[k * D + od];
        else {
            int r = (seg == 0) ? r0 : r1;
            v = coeff[r * 2 + 0] * basis[(size_t)k * D + od]
              + coeff[r * 2 + 1] * basis[(size_t)K * D + (size_t)k * D + od];
        }
    }
    outH[idx] = __float2half(v);
}
__global__ void build_w2t(const float* __restrict__ coeff, const float* __restrict__ basis,
                          const float* __restrict__ loopw,
                          __half* __restrict__ outH,
                          int K, int D, int Npad, int r0) {
    int idx = blockIdx.x * blockDim.x + threadIdx.x;
    if (idx >= Npad * K) return;
    int o = idx / K;
    int k = idx % K;
    float v = 0.f;
    if (o < 2 * D) {
        int seg = o / D, od = o % D;
        if (seg == 1) v = loopw[k * D + od];
        else {
            v = coeff[r0 * 2 + 0] * basis[(size_t)k * D + od]
              + coeff[r0 * 2 + 1] * basis[(size_t)K * D + (size_t)k * D + od];
        }
    }
    outH[idx] = __float2half(v);
}

// ---------------- layer-1 gather (warp per dst node) + combine + fp16 emit ----------------
// rows [w0, w1)
__global__ void gather1_sent(const __half* __restrict__ Ps, const __half* __restrict__ Pd,
                             const float* __restrict__ bias, __half* __restrict__ hout,
                             int w0, int w1) {
    int w = w0 + ((blockIdx.x * blockDim.x + threadIdx.x) >> 5);
    int lane = threadIdx.x & 31;
    if (w >= w1) return;
    __half* orow = hout + (size_t)w * D_H;
    if (w >= N_SENT) {
        *(uint4*)(orow + lane * 8) = make_uint4(0u, 0u, 0u, 0u);
        return;
    }
    float A[8] = {0.f}, Bv[8] = {0.f};
    int p = g_ptr_ss[w], d = g_deg_ss[w];
    int k = 0;
    for (; k + 1 < d; k += 2) {
        int s0 = g_adj_ss[p + k], s1 = g_adj_ss[p + k + 1];
        uint4 v0 = *(const uint4*)(Ps + (size_t)s0 * 768 + 256 + lane * 8);
        uint4 v1 = *(const uint4*)(Ps + (size_t)s1 * 768 + 256 + lane * 8);
        add8h(A, v0); add8h(A, v1);
    }
    if (k < d) {
        int s0 = g_adj_ss[p + k];
        add8h(A, *(const uint4*)(Ps + (size_t)s0 * 768 + 256 + lane * 8));
    }
    float sc = g_inv_ss[w];
    p = g_ptr_ds[w]; d = g_deg_ds[w];
    k = 0;
    for (; k + 1 < d; k += 2) {
        int s0 = g_adj_ds[p + k], s1 = g_adj_ds[p + k + 1];
        uint4 v0 = *(const uint4*)(Pd + (size_t)s0 * 512 + lane * 8);
        uint4 v1 = *(const uint4*)(Pd + (size_t)s1 * 512 + lane * 8);
        add8h(Bv, v0); add8h(Bv, v1);
    }
    if (k < d) {
        int s0 = g_adj_ds[p + k];
        add8h(Bv, *(const uint4*)(Pd + (size_t)s0 * 512 + lane * 8));
    }
    float sc2 = g_inv_ds[w];
    float L[8];
    unpack8h(L, *(const uint4*)(Ps + (size_t)w * 768 + 512 + lane * 8));
    float f[8];
    #pragma unroll
    for (int i = 0; i < 8; i++)
        f[i] = fmaxf(fmaf(A[i], sc, fmaf(Bv[i], sc2, L[i] + bias[lane * 8 + i])), 0.f);
    *(uint4*)(orow + lane * 8) = pack8h(f);
}
__global__ void gather1_doc(const __half* __restrict__ Ps, const __half* __restrict__ Pd,
                            const float* __restrict__ bias, __half* __restrict__ hout) {
    int w = (blockIdx.x * blockDim.x + threadIdx.x) >> 5;
    int lane = threadIdx.x & 31;
    if (w >= DOC_PAD) return;
    __half* orow = hout + (size_t)w * D_H;
    if (w >= N_DOC) {
        *(uint4*)(orow + lane * 8) = make_uint4(0u, 0u, 0u, 0u);
        return;
    }
    float A[8] = {0.f};
    int p = g_ptr_sd[w], d = g_deg_sd[w];
    int k = 0;
    for (; k + 1 < d; k += 2) {
        int s0 = g_adj_sd[p + k], s1 = g_adj_sd[p + k + 1];
        uint4 v0 = *(const uint4*)(Ps + (size_t)s0 * 768 + lane * 8);
        uint4 v1 = *(const uint4*)(Ps + (size_t)s1 * 768 + lane * 8);
        add8h(A, v0); add8h(A, v1);
    }
    if (k < d) {
        int s0 = g_adj_sd[p + k];
        add8h(A, *(const uint4*)(Ps + (size_t)s0 * 768 + lane * 8));
    }
    float sc = g_inv_sd[w];
    float L[8];
    unpack8h(L, *(const uint4*)(Pd + (size_t)w * 512 + 256 + lane * 8));
    float f[8];
    #pragma unroll
    for (int i = 0; i < 8; i++)
        f[i] = fmaxf(fmaf(A[i], sc, L[i] + bias[lane * 8 + i]), 0.f);
    *(uint4*)(orow + lane * 8) = pack8h(f);
}

// ---------------- layer-2 gather + combine + relu + score + per-graph reduce -------------
__global__ void init_out(float* __restrict__ out, const float* __restrict__ b_score) {
    int g = threadIdx.x;
    if (g < NGRAPH) out[g] = b_score[0];
}
__global__ void gather2_sent(const __half* __restrict__ Ps2, const __half* __restrict__ Pd2,
                             const float* __restrict__ bias, const float* __restrict__ wscore,
                             const int* __restrict__ gid, float* __restrict__ out) {
    int w = (blockIdx.x * blockDim.x + threadIdx.x) >> 5;
    int lane = threadIdx.x & 31;
    if (w >= N_SENT) return;
    float A[4] = {0.f}, Bv[4] = {0.f};
    int p = g_ptr_ss[w], d = g_deg_ss[w];
    int k = 0;
    for (; k + 1 < d; k += 2) {
        int s0 = g_adj_ss[p + k], s1 = g_adj_ss[p + k + 1];
        uint2 v0 = *(const uint2*)(Ps2 + (size_t)s0 * 384 + 128 + lane * 4);
        uint2 v1 = *(const uint2*)(Ps2 + (size_t)s1 * 384 + 128 + lane * 4);
        add4h(A, v0); add4h(A, v1);
    }
    if (k < d) {
        int s0 = g_adj_ss[p + k];
        add4h(A, *(const uint2*)(Ps2 + (size_t)s0 * 384 + 128 + lane * 4));
    }
    float sc = g_inv_ss[w];
    p = g_ptr_ds[w]; d = g_deg_ds[w];
    k = 0;
    for (; k + 1 < d; k += 2) {
        int s0 = g_adj_ds[p + k], s1 = g_adj_ds[p + k + 1];
        uint2 v0 = *(const uint2*)(Pd2 + (size_t)s0 * 256 + lane * 4);
        uint2 v1 = *(const uint2*)(Pd2 + (size_t)s1 * 256 + lane * 4);
        add4h(Bv, v0); add4h(Bv, v1);
    }
    if (k < d) {
        int s0 = g_adj_ds[p + k];
        add4h(Bv, *(const uint2*)(Pd2 + (size_t)s0 * 256 + lane * 4));
    }
    float sc2 = g_inv_ds[w];
    float L[4] = {0.f};
    add4h(L, *(const uint2*)(Ps2 + (size_t)w * 384 + 256 + lane * 4));
    float4 B = ((const float4*)bias)[lane];
    float4 W = ((const float4*)wscore)[lane];
    float bb[4] = {B.x, B.y, B.z, B.w};
    float ww[4] = {W.x, W.y, W.z, W.w};
    float s = 0.f;
    #pragma unroll
    for (int i = 0; i < 4; i++)
        s += fmaxf(fmaf(A[i], sc, fmaf(Bv[i], sc2, L[i] + bb[i])), 0.f) * ww[i];
    #pragma unroll
    for (int off = 16; off; off >>= 1) s += __shfl_down_sync(0xffffffffu, s, off);
    if (lane == 0) atomicAdd(&out[gid[w]], s);
}
__global__ void gather2_doc(const __half* __restrict__ Ps2, const __half* __restrict__ Pd2,
                            const float* __restrict__ bias, const float* __restrict__ wscore,
                            const int* __restrict__ gid, float* __restrict__ out) {
    int w = (blockIdx.x * blockDim.x + threadIdx.x) >> 5;
    int lane = threadIdx.x & 31;
    if (w >= N_DOC) return;
    float A[4] = {0.f};
    int p = g_ptr_sd[w], d = g_deg_sd[w];
    int k = 0;
    for (; k + 1 < d; k += 2) {
        int s0 = g_adj_sd[p + k], s1 = g_adj_sd[p + k + 1];
        uint2 v0 = *(const uint2*)(Ps2 + (size_t)s0 * 384 + lane * 4);
        uint2 v1 = *(const uint2*)(Ps2 + (size_t)s1 * 384 + lane * 4);
        add4h(A, v0); add4h(A, v1);
    }
    if (k < d) {
        int s0 = g_adj_sd[p + k];
        add4h(A, *(const uint2*)(Ps2 + (size_t)s0 * 384 + lane * 4));
    }
    float sc = g_inv_sd[w];
    float L[4] = {0.f};
    add4h(L, *(const uint2*)(Pd2 + (size_t)w * 256 + 128 + lane * 4));
    float4 B = ((const float4*)bias)[lane];
    float4 W = ((const float4*)wscore)[lane];
    float bb[4] = {B.x, B.y, B.z, B.w};
    float ww[4] = {W.x, W.y, W.z, W.w};
    float s = 0.f;
    #pragma unroll
    for (int i = 0; i < 4; i++)
        s += fmaxf(fmaf(A[i], sc, L[i] + bb[i]), 0.f) * ww[i];
    #pragma unroll
    for (int off = 16; off; off >>= 1) s += __shfl_down_sync(0xffffffffu, s, off);
    if (lane == 0) atomicAdd(&out[gid[w]], s);
}

// ---------------- host launcher ----------------
static void* symaddr(const void* sym) {
    void* p = nullptr;
    cudaGetSymbolAddress(&p, sym);
    return p;
}

extern "C" void kernel_launch(void* const* d_in, const int* in_sizes, int n_in,
                              void* d_out, int out_size) {
    const float* x_sent  = (const float*)d_in[0];
    const float* x_doc   = (const float*)d_in[1];
    const float* coeff1  = (const float*)d_in[2];
    const float* basis1  = (const float*)d_in[3];
    const float* loop_w1 = (const float*)d_in[4];
    const float* bias1   = (const float*)d_in[5];
    const float* coeff2  = (const float*)d_in[6];
    const float* basis2  = (const float*)d_in[7];
    const float* loop_w2 = (const float*)d_in[8];
    const float* bias2   = (const float*)d_in[9];
    const float* w_score = (const float*)d_in[10];
    const float* b_score = (const float*)d_in[11];
    const int*   src_ss  = (const int*)d_in[12];
    const int*   dst_ss  = (const int*)d_in[13];
    const int*   src_sd  = (const int*)d_in[14];
    const int*   dst_sd  = (const int*)d_in[15];
    const int*   src_ds  = (const int*)d_in[16];
    const int*   dst_ds  = (const int*)d_in[17];
    const int*   gid_sent= (const int*)d_in[18];
    const int*   gid_doc = (const int*)d_in[19];
    float* out = (float*)d_out;

    __half* pB1sh = (__half*)symaddr(g_B1s_h);
    __half* pB1dh = (__half*)symaddr(g_B1d_h);
    __half* pB2sh = (__half*)symaddr(g_B2s_h);
    __half* pB2dh = (__half*)symaddr(g_B2d_h);
    __half* pXsh = (__half*)symaddr(g_xs_h);
    __half* pXdh = (__half*)symaddr(g_xd_h);
    __half* pHsh = (__half*)symaddr(g_hs_h);
    __half* pHdh = (__half*)symaddr(g_hd_h);
    __half* pPs  = (__half*)symaddr(g_Ps);
    __half* pPd  = (__half*)symaddr(g_Pd);
    __half* pPs2 = (__half*)symaddr(g_Ps2);
    __half* pPd2 = (__half*)symaddr(g_Pd2);

    cudaFuncSetAttribute(gemm4, cudaFuncAttributeMaxDynamicSharedMemorySize, GEMM_SMEM);

    static cudaStream_t s2 = nullptr, s3 = nullptr;
    static cudaEvent_t eFork = nullptr, eSide = nullptr, eStripA = nullptr,
                       eD2 = nullptr, eCvt0 = nullptr, eCvt1 = nullptr,
                       eH0 = nullptr, eS2a = nullptr;
    if (s2 == nullptr) {
        cudaStreamCreateWithFlags(&s2, cudaStreamNonBlocking);
        cudaStreamCreateWithFlags(&s3, cudaStreamNonBlocking);
        cudaEventCreateWithFlags(&eFork, cudaEventDisableTiming);
        cudaEventCreateWithFlags(&eSide, cudaEventDisableTiming);
        cudaEventCreateWithFlags(&eStripA, cudaEventDisableTiming);
        cudaEventCreateWithFlags(&eD2, cudaEventDisableTiming);
        cudaEventCreateWithFlags(&eCvt0, cudaEventDisableTiming);
        cudaEventCreateWithFlags(&eCvt1, cudaEventDisableTiming);
        cudaEventCreateWithFlags(&eH0, cudaEventDisableTiming);
        cudaEventCreateWithFlags(&eS2a, cudaEventDisableTiming);
    }

    cudaStream_t st = 0;

    // ---- head ----
    zero_deg<<<(N_SENT + 255) / 256, 256, 0, st>>>();
    cudaEventRecord(eFork, st);

    // s3: x_sent convert, row-chunked
    cudaStreamWaitEvent(s3, eFork, 0);
    {
        long long npadc = (long long)HALF_S * D_IN;
        long long nrealc = (long long)HALF_S * D_IN;          // rows 0..HALF_S-1 all real
        cvt_f16<<<(unsigned)((npadc / 8 + 255) / 256), 256, 0, s3>>>(x_sent, pXsh, nrealc, npadc);
        cudaEventRecord(eCvt0, s3);
        long long npadc2 = (long long)(SENT_PAD - HALF_S) * D_IN;
        long long nrealc2 = (long long)(N_SENT - HALF_S) * D_IN;
        cvt_f16<<<(unsigned)((npadc2 / 8 + 255) / 256), 256, 0, s3>>>(
            x_sent + (size_t)HALF_S * D_IN, pXsh + (size_t)HALF_S * D_IN, nrealc2, npadc2);
        cudaEventRecord(eCvt1, s3);
    }

    // main: weights for strip A, then strip A row-chunks as converts land
    build_w3t<<<(768 * 768 + 255) / 256, 256, 0, st>>>(coeff1, basis1, loop_w1, pB1sh, D_IN, D_H, 768, 0, 2);
    cudaStreamWaitEvent(st, eCvt0, 0);
    {   // strip A (Ps cols 256:768), rows [0, HALF_S)
        dim3 g(512 / 128, HALF_S / 128);
        gemm4<<<g, 256, GEMM_SMEM, st>>>(pXsh, pB1sh + (size_t)256 * D_IN, pPs + 256,
                                         N_SENT, 3 * D_H, D_IN);
    }
    cudaStreamWaitEvent(st, eCvt1, 0);
    {   // strip A rows [HALF_S, SENT_PAD)
        dim3 g(512 / 128, (SENT_PAD - HALF_S) / 128);
        gemm4<<<g, 256, GEMM_SMEM, st>>>(pXsh + (size_t)HALF_S * D_IN,
                                         pB1sh + (size_t)256 * D_IN,
                                         pPs + (size_t)HALF_S * 768 + 256,
                                         N_SENT - HALF_S, 3 * D_H, D_IN);
    }
    cudaEventRecord(eStripA, st);

    // ---- s2: CSR + doc prep + doc layer-1 GEMM under strip A ----
    cudaStreamWaitEvent(s2, eFork, 0);
    {
        int Etot = E_SS + E_DS + E_SD;
        count_all<<<(Etot + 255) / 256, 256, 0, s2>>>(dst_ss, dst_ds, dst_sd);
        scan_local_all<<<2 * NB_S + NB_D, 1024, 0, s2>>>();
        scan_block_all<<<3, 128, 0, s2>>>();
        scan_final_all<<<(2 * N_SENT + N_DOC + 255) / 256, 256, 0, s2>>>();
        fill_all<<<(Etot + 255) / 256, 256, 0, s2>>>(src_ss, dst_ss, src_ds, dst_ds, src_sd, dst_sd);
    }
    {
        long long nreal = (long long)N_DOC * D_IN, npad = (long long)DOC_PAD * D_IN;
        cvt_f16<<<(unsigned)((npad / 8 + 255) / 256), 256, 0, s2>>>(x_doc, pXdh, nreal, npad);
    }
    build_w2t<<<(512 * 768 + 255) / 256, 256, 0, s2>>>(coeff1, basis1, loop_w1, pB1dh, D_IN, D_H, 512, 1);
    build_w3t<<<(384 * 256 + 255) / 256, 256, 0, s2>>>(coeff2, basis2, loop_w2, pB2sh, D_H, D_O, 384, 0, 2);
    build_w2t<<<(256 * 256 + 255) / 256, 256, 0, s2>>>(coeff2, basis2, loop_w2, pB2dh, D_H, D_O, 256, 1);
    {
        dim3 g(512 / 128, DOC_PAD / 128);
        gemm4<<<g, 256, GEMM_SMEM, s2>>>(pXdh, pB1dh, pPd, N_DOC, 2 * D_H, D_IN);
    }
    cudaEventRecord(eSide, s2);

    // ---- s2 (after strip A): strip B (Ps cols 0:256) -> doc path ----
    cudaStreamWaitEvent(s2, eStripA, 0);
    {
        dim3 g(256 / 128, SENT_PAD / 128);
        gemm4<<<g, 256, GEMM_SMEM, s2>>>(pXsh, pB1sh, pPs, N_SENT, 3 * D_H, D_IN);
    }
    gather1_doc<<<(DOC_PAD * 32 + 255) / 256, 256, 0, s2>>>(pPs, pPd, bias1, pHdh);
    {
        dim3 g(256 / 128, DOC_PAD / 128);
        gemm4<<<g, 256, GEMM_SMEM, s2>>>(pHdh, pB2dh, pPd2, N_DOC, 2 * D_O, D_H);
    }
    cudaEventRecord(eD2, s2);

    // ---- main: gather1_sent chunk0, then chunk1 while s3 runs GEMM_s2 chunk0 ----
    cudaStreamWaitEvent(st, eSide, 0);   // Pd + CSR ready (strip A done on this stream)
    gather1_sent<<<(HALF_S * 32 + 255) / 256, 256, 0, st>>>(pPs, pPd, bias1, pHsh, 0, HALF_S);
    cudaEventRecord(eH0, st);
    gather1_sent<<<((SENT_PAD - HALF_S) * 32 + 255) / 256, 256, 0, st>>>(pPs, pPd, bias1, pHsh, HALF_S, SENT_PAD);

    // s3: layer-2 sent GEMM chunk0 (rows [0, HALF_S)), overlapped with gather chunk1
    cudaStreamWaitEvent(s3, eH0, 0);
    cudaStreamWaitEvent(s3, eSide, 0);   // B2s built on s2
    {
        dim3 g(384 / 128, HALF_S / 128);
        gemm4<<<g, 256, GEMM_SMEM, s3>>>(pHsh, pB2sh, pPs2, N_SENT, 3 * D_O, D_H);
    }
    cudaEventRecord(eS2a, s3);

    // main: layer-2 sent GEMM chunk1
    {
        dim3 g(384 / 128, (SENT_PAD - HALF_S) / 128);
        gemm4<<<g, 256, GEMM_SMEM, st>>>(pHsh + (size_t)HALF_S * D_H, pB2sh,
                                         pPs2 + (size_t)HALF_S * 384,
                                         N_SENT - HALF_S, 3 * D_O, D_H);
    }

    // join + readout
    cudaStreamWaitEvent(st, eS2a, 0);
    cudaStreamWaitEvent(st, eD2, 0);
    init_out<<<1, 32, 0, st>>>(out, b_score);
    gather2_sent<<<(N_SENT * 32 + 255) / 256, 256, 0, st>>>(pPs2, pPd2, bias2, w_score, gid_sent, out);
    gather2_doc<<<(N_DOC * 32 + 255) / 256, 256, 0, st>>>(pPs2, pPd2, bias2, w_score, gid_doc, out);
}

// round 15
// speedup vs baseline: 4.2889x; 1.0026x over previous
#include <cuda_runtime.h>
#include <cuda_fp16.h>
#include <cstdint>
#include <cstddef>

#define N_SENT 100000
#define N_DOC  10000
#define SENT_PAD 100096
#define DOC_PAD  10112
#define HALF_S   50048
#define NGRAPH 32
#define D_IN   768
#define D_H    256
#define D_O    128
#define E_SS   400000
#define E_SD   100000
#define E_DS   100000

// ---------------- scratch (device globals: allocation-free) ----------------
__device__ __align__(16) __half g_B1s_h[768 * 768];
__device__ __align__(16) __half g_B1d_h[512 * 768];
__device__ __align__(16) __half g_B2s_h[384 * 256];
__device__ __align__(16) __half g_B2d_h[256 * 256];

__device__ __align__(16) __half g_xs_h[(size_t)SENT_PAD * D_IN];
__device__ __align__(16) __half g_xd_h[(size_t)DOC_PAD * D_IN];
__device__ __align__(16) __half g_hs_h[(size_t)SENT_PAD * D_H];
__device__ __align__(16) __half g_hd_h[(size_t)DOC_PAD * D_H];

__device__ __align__(16) __half g_Ps [(size_t)SENT_PAD * (3 * D_H)];
__device__ __align__(16) __half g_Pd [(size_t)N_DOC  * (2 * D_H)];
__device__ __align__(16) __half g_Ps2[(size_t)SENT_PAD * (3 * D_O)];
__device__ __align__(16) __half g_Pd2[(size_t)N_DOC  * (2 * D_O)];

// CSR structures (incoming edges per destination)
__device__ int   g_deg_ss[N_SENT], g_deg_ds[N_SENT], g_deg_sd[N_DOC];
__device__ int   g_ptr_ss[N_SENT], g_ptr_ds[N_SENT], g_ptr_sd[N_DOC];
__device__ int   g_cur_ss[N_SENT], g_cur_ds[N_SENT], g_cur_sd[N_DOC];
__device__ int   g_adj_ss[E_SS], g_adj_ds[E_DS], g_adj_sd[E_SD];
__device__ float g_inv_ss[N_SENT], g_inv_ds[N_SENT], g_inv_sd[N_DOC];
__device__ int   g_bsum_a[128], g_bsum_b[128], g_bsum_c[128];
__device__ int   g_part_ss[N_SENT], g_part_ds[N_SENT], g_part_sd[N_DOC];

// ---------------- PTX helpers ----------------
__device__ __forceinline__ uint32_t smem_u32(const void* p) {
    uint32_t a;
    asm("{ .reg .u64 t; cvta.to.shared.u64 t, %1; cvt.u32.u64 %0, t; }" : "=r"(a) : "l"(p));
    return a;
}

#define CP_ASYNC16(saddr, gaddr) \
    asm volatile("cp.async.cg.shared.global [%0], [%1], 16;" :: "r"(saddr), "l"(gaddr) : "memory")
#define CP_COMMIT() asm volatile("cp.async.commit_group;" ::: "memory")
#define CP_WAIT1()  asm volatile("cp.async.wait_group 1;" ::: "memory")

#define LDMX4(r0, r1, r2, r3, addr) \
    asm volatile("ldmatrix.sync.aligned.m8n8.x4.shared.b16 {%0,%1,%2,%3}, [%4];" \
                 : "=r"(r0), "=r"(r1), "=r"(r2), "=r"(r3) : "r"(addr))

#define MMA16816(d, a, b) \
    asm volatile("mma.sync.aligned.m16n8k16.row.col.f32.f16.f16.f32 " \
                 "{%0,%1,%2,%3}, {%4,%5,%6,%7}, {%8,%9}, {%0,%1,%2,%3};" \
                 : "+f"((d)[0]), "+f"((d)[1]), "+f"((d)[2]), "+f"((d)[3]) \
                 : "r"((a)[0]), "r"((a)[1]), "r"((a)[2]), "r"((a)[3]), "r"((b)[0]), "r"((b)[1]))

__device__ __forceinline__ uint4 pack8h(const float* f) {
    uint32_t hs[8];
    #pragma unroll
    for (int i = 0; i < 8; i++) hs[i] = (uint32_t)__half_as_ushort(__float2half(f[i]));
    return make_uint4(hs[0] | (hs[1] << 16), hs[2] | (hs[3] << 16), hs[4] | (hs[5] << 16), hs[6] | (hs[7] << 16));
}
__device__ __forceinline__ void add8h(float* A, uint4 v) {
    const __half2* h = (const __half2*)&v;
    #pragma unroll
    for (int i = 0; i < 4; i++) {
        float2 f = __half22float2(h[i]);
        A[2 * i] += f.x; A[2 * i + 1] += f.y;
    }
}
__device__ __forceinline__ void unpack8h(float* A, uint4 v) {
    const __half2* h = (const __half2*)&v;
    #pragma unroll
    for (int i = 0; i < 4; i++) {
        float2 f = __half22float2(h[i]);
        A[2 * i] = f.x; A[2 * i + 1] = f.y;
    }
}
__device__ __forceinline__ void add4h(float* A, uint2 v) {
    const __half2* h = (const __half2*)&v;
    #pragma unroll
    for (int i = 0; i < 2; i++) {
        float2 f = __half22float2(h[i]);
        A[2 * i] += f.x; A[2 * i + 1] += f.y;
    }
}

#define ROWB   80

// ================= GEMM: fp16 x fp16 -> fp16, 3-stage single-sync, 128x128 =============
// N = row stride of C. Bt/C may be pre-offset (column strips); A/C may be row-offset.
#define ST_SZ  20480
#define OFF_A  0
#define OFF_B  10240
#define NSTAGE 3
#define GEMM_SMEM (NSTAGE * ST_SZ)

__global__ __launch_bounds__(256, 2) void gemm4(
    const __half* __restrict__ A,
    const __half* __restrict__ Bt,
    __half* __restrict__ C, int M, int N, int K)
{
    extern __shared__ char smem[];
    uint32_t sb = smem_u32(smem);
    int tid = threadIdx.x;
    int lane = tid & 31, wid = tid >> 5;
    int warp_m = (wid & 3) * 32;
    int warp_n = (wid >> 2) * 64;
    int mrow0 = blockIdx.y * 128;
    int ncol0 = blockIdx.x * 128;
    int nk = K >> 5;

    int prow = tid >> 1;
    int pch  = (tid & 1) * 16;
    const __half* aP = A + (size_t)(mrow0 + prow) * K + pch;
    const __half* bP = Bt + (size_t)(ncol0 + prow) * K + pch;
    uint32_t sts = (uint32_t)(prow * ROWB + pch * 2);

    int ra = warp_m + (lane & 7) + (lane & 8);
    int ca = ((lane >> 4) << 3);
    uint32_t a_lm = (uint32_t)(ra * ROWB + ca * 2);
    int rb = warp_n + (lane & 7) + ((lane >> 4) << 3);
    int cb = (((lane >> 3) & 1) << 3);
    uint32_t b_lm = (uint32_t)(rb * ROWB + cb * 2);

    float acc[2][8][4];
    #pragma unroll
    for (int mi = 0; mi < 2; mi++)
        #pragma unroll
        for (int ni = 0; ni < 8; ni++)
            #pragma unroll
            for (int q = 0; q < 4; q++) acc[mi][ni][q] = 0.f;

    #pragma unroll
    for (int s = 0; s < 2; s++) {
        if (s < nk) {
            uint32_t base = sb + s * ST_SZ;
            const __half* ap = aP + s * 32;
            const __half* bp = bP + s * 32;
            CP_ASYNC16(base + OFF_A + sts, ap); CP_ASYNC16(base + OFF_A + sts + 16, ap + 8);
            CP_ASYNC16(base + OFF_B + sts, bp); CP_ASYNC16(base + OFF_B + sts + 16, bp + 8);
        }
        CP_COMMIT();
    }

    for (int kt = 0; kt < nk; kt++) {
        CP_WAIT1();
        __syncthreads();

        int pf = kt + 2;
        if (pf < nk) {
            uint32_t base = sb + (pf % NSTAGE) * ST_SZ;
            const __half* ap = aP + pf * 32;
            const __half* bp = bP + pf * 32;
            CP_ASYNC16(base + OFF_A + sts, ap); CP_ASYNC16(base + OFF_A + sts + 16, ap + 8);
            CP_ASYNC16(base + OFF_B + sts, bp); CP_ASYNC16(base + OFF_B + sts + 16, bp + 8);
        }
        CP_COMMIT();

        uint32_t bcur = sb + (kt % NSTAGE) * ST_SZ;
        #pragma unroll
        for (int ks = 0; ks < 2; ks++) {
            uint32_t koff = ks * 32;
            uint32_t af[2][4], bf[8][2];
            #pragma unroll
            for (int mi = 0; mi < 2; mi++)
                LDMX4(af[mi][0], af[mi][1], af[mi][2], af[mi][3],
                      bcur + OFF_A + a_lm + mi * (16 * ROWB) + koff);
            #pragma unroll
            for (int bg = 0; bg < 4; bg++)
                LDMX4(bf[bg * 2][0], bf[bg * 2][1], bf[bg * 2 + 1][0], bf[bg * 2 + 1][1],
                      bcur + OFF_B + b_lm + bg * (16 * ROWB) + koff);
            #pragma unroll
            for (int mi = 0; mi < 2; mi++)
                #pragma unroll
                for (int ni = 0; ni < 8; ni++)
                    MMA16816(acc[mi][ni], af[mi], bf[ni]);
        }
    }

    int g = lane >> 2, t4 = lane & 3;
    #pragma unroll
    for (int mi = 0; mi < 2; mi++) {
        int r0 = mrow0 + warp_m + mi * 16 + g;
        #pragma unroll
        for (int ni = 0; ni < 8; ni++) {
            int col = ncol0 + warp_n + ni * 8 + t4 * 2;
            if (r0 < M)
                *(__half2*)(C + (size_t)r0 * N + col) = __floats2half2_rn(acc[mi][ni][0], acc[mi][ni][1]);
            if (r0 + 8 < M)
                *(__half2*)(C + (size_t)(r0 + 8) * N + col) = __floats2half2_rn(acc[mi][ni][2], acc[mi][ni][3]);
        }
    }
}

// ---------------- fp32 -> fp16 convert (padded, zero-filled) ----------------
__global__ void cvt_f16(const float* __restrict__ x, __half* __restrict__ hi,
                        long long nreal, long long npad) {
    long long base = ((long long)blockIdx.x * blockDim.x + threadIdx.x) * 8;
    if (base >= npad) return;
    float f[8];
    if (base < nreal) {
        float4 v0 = *(const float4*)(x + base);
        float4 v1 = *(const float4*)(x + base + 4);
        f[0] = v0.x; f[1] = v0.y; f[2] = v0.z; f[3] = v0.w;
        f[4] = v1.x; f[5] = v1.y; f[6] = v1.z; f[7] = v1.w;
    } else {
        #pragma unroll
        for (int q = 0; q < 8; q++) f[q] = 0.f;
    }
    *(uint4*)(hi + base) = pack8h(f);
}

// ---------------- CSR construction (fused across the 3 relations) ----------------
__global__ void zero_deg() {
    int i = blockIdx.x * blockDim.x + threadIdx.x;
    if (i < N_SENT) { g_deg_ss[i] = 0; g_deg_ds[i] = 0; }
    if (i < N_DOC)  { g_deg_sd[i] = 0; }
}
__global__ void count_all(const int* __restrict__ dss, const int* __restrict__ dds,
                          const int* __restrict__ dsd) {
    int i = blockIdx.x * blockDim.x + threadIdx.x;
    if (i < E_SS) atomicAdd(&g_deg_ss[dss[i]], 1);
    else if (i < E_SS + E_DS) atomicAdd(&g_deg_ds[dds[i - E_SS]], 1);
    else if (i < E_SS + E_DS + E_SD) atomicAdd(&g_deg_sd[dsd[i - E_SS - E_DS]], 1);
}
#define NB_S 98
#define NB_D 10
__global__ void scan_local_all() {
    __shared__ int sm[1024];
    const int* deg; int* part; int* bsum; int n; int blk;
    if (blockIdx.x < NB_S) { deg = g_deg_ss; part = g_part_ss; bsum = g_bsum_a; n = N_SENT; blk = blockIdx.x; }
    else if (blockIdx.x < 2 * NB_S) { deg = g_deg_ds; part = g_part_ds; bsum = g_bsum_b; n = N_SENT; blk = blockIdx.x - NB_S; }
    else { deg = g_deg_sd; part = g_part_sd; bsum = g_bsum_c; n = N_DOC; blk = blockIdx.x - 2 * NB_S; }
    int i = blk * 1024 + threadIdx.x;
    int v = (i < n) ? deg[i] : 0;
    sm[threadIdx.x] = v;
    __syncthreads();
    #pragma unroll
    for (int off = 1; off < 1024; off <<= 1) {
        int t = (threadIdx.x >= off) ? sm[threadIdx.x - off] : 0;
        __syncthreads();
        sm[threadIdx.x] += t;
        __syncthreads();
    }
    if (i < n) part[i] = sm[threadIdx.x] - v;
    if (threadIdx.x == 1023) bsum[blk] = sm[1023];
}
__global__ void scan_block_all() {
    __shared__ int sm[128];
    int* bsum; int nb;
    if (blockIdx.x == 0) { bsum = g_bsum_a; nb = NB_S; }
    else if (blockIdx.x == 1) { bsum = g_bsum_b; nb = NB_S; }
    else { bsum = g_bsum_c; nb = NB_D; }
    int v = (threadIdx.x < nb) ? bsum[threadIdx.x] : 0;
    sm[threadIdx.x] = v;
    __syncthreads();
    #pragma unroll
    for (int off = 1; off < 128; off <<= 1) {
        int t = (threadIdx.x >= off) ? sm[threadIdx.x - off] : 0;
        __syncthreads();
        sm[threadIdx.x] += t;
        __syncthreads();
    }
    if (threadIdx.x < nb) bsum[threadIdx.x] = sm[threadIdx.x] - v;
}
__global__ void scan_final_all() {
    int i = blockIdx.x * blockDim.x + threadIdx.x;
    if (i < N_SENT) {
        int p = g_part_ss[i] + g_bsum_a[i >> 10];
        g_ptr_ss[i] = p; g_cur_ss[i] = p;
        g_inv_ss[i] = 1.0f / (float)max(g_deg_ss[i], 1);
    } else if (i < 2 * N_SENT) {
        int j = i - N_SENT;
        int p = g_part_ds[j] + g_bsum_b[j >> 10];
        g_ptr_ds[j] = p; g_cur_ds[j] = p;
        g_inv_ds[j] = 1.0f / (float)max(g_deg_ds[j], 1);
    } else if (i < 2 * N_SENT + N_DOC) {
        int j = i - 2 * N_SENT;
        int p = g_part_sd[j] + g_bsum_c[j >> 10];
        g_ptr_sd[j] = p; g_cur_sd[j] = p;
        g_inv_sd[j] = 1.0f / (float)max(g_deg_sd[j], 1);
    }
}
__global__ void fill_all(const int* __restrict__ sss, const int* __restrict__ dss,
                         const int* __restrict__ sds, const int* __restrict__ dds,
                         const int* __restrict__ ssd, const int* __restrict__ dsd) {
    int i = blockIdx.x * blockDim.x + threadIdx.x;
    if (i < E_SS) {
        int p = atomicAdd(&g_cur_ss[dss[i]], 1);
        g_adj_ss[p] = sss[i];
    } else if (i < E_SS + E_DS) {
        int e = i - E_SS;
        int p = atomicAdd(&g_cur_ds[dds[e]], 1);
        g_adj_ds[p] = sds[e];
    } else if (i < E_SS + E_DS + E_SD) {
        int e = i - E_SS - E_DS;
        int p = atomicAdd(&g_cur_sd[dsd[e]], 1);
        g_adj_sd[p] = ssd[e];
    }
}

// ---------------- weight build: transposed fp16 ----------------
__global__ void build_w3t(const float* __restrict__ coeff, const float* __restrict__ basis,
                          const float* __restrict__ loopw,
                          __half* __restrict__ outH,
                          int K, int D, int Npad, int r0, int r1) {
    int idx = blockIdx.x * blockDim.x + threadIdx.x;
    if (idx >= Npad * K) return;
    int o = idx / K;
    int k = idx % K;
    float v = 0.f;
    if (o < 3 * D) {
        int seg = o / D, od = o % D;
        if (seg == 2) v = loopw[k * D + od];
        else {
            int r = (seg == 0) ? r0 : r1;
            v = coeff[r * 2 + 0] * basis[(size_t)k * D + od]
              + coeff[r * 2 + 1] * basis[(size_t)K * D + (size_t)k * D + od];
        }
    }
    outH[idx] = __float2half(v);
}
__global__ void build_w2t(const float* __restrict__ coeff, const float* __restrict__ basis,
                          const float* __restrict__ loopw,
                          __half* __restrict__ outH,
                          int K, int D, int Npad, int r0) {
    int idx = blockIdx.x * blockDim.x + threadIdx.x;
    if (idx >= Npad * K) return;
    int o = idx / K;
    int k = idx % K;
    float v = 0.f;
    if (o < 2 * D) {
        int seg = o / D, od = o % D;
        if (seg == 1) v = loopw[k * D + od];
        else {
            v = coeff[r0 * 2 + 0] * basis[(size_t)k * D + od]
              + coeff[r0 * 2 + 1] * basis[(size_t)K * D + (size_t)k * D + od];
        }
    }
    outH[idx] = __float2half(v);
}

// ---------------- layer-1 gather (warp per dst node) + combine + fp16 emit ----------------
__global__ void gather1_sent(const __half* __restrict__ Ps, const __half* __restrict__ Pd,
                             const float* __restrict__ bias, __half* __restrict__ hout,
                             int w0, int w1) {
    int w = w0 + ((blockIdx.x * blockDim.x + threadIdx.x) >> 5);
    int lane = threadIdx.x & 31;
    if (w >= w1) return;
    __half* orow = hout + (size_t)w * D_H;
    if (w >= N_SENT) {
        *(uint4*)(orow + lane * 8) = make_uint4(0u, 0u, 0u, 0u);
        return;
    }
    float A[8] = {0.f}, Bv[8] = {0.f};
    int p = g_ptr_ss[w], d = g_deg_ss[w];
    int k = 0;
    for (; k + 1 < d; k += 2) {
        int s0 = g_adj_ss[p + k], s1 = g_adj_ss[p + k + 1];
        uint4 v0 = *(const uint4*)(Ps + (size_t)s0 * 768 + 256 + lane * 8);
        uint4 v1 = *(const uint4*)(Ps + (size_t)s1 * 768 + 256 + lane * 8);
        add8h(A, v0); add8h(A, v1);
    }
    if (k < d) {
        int s0 = g_adj_ss[p + k];
        add8h(A, *(const uint4*)(Ps + (size_t)s0 * 768 + 256 + lane * 8));
    }
    float sc = g_inv_ss[w];
    p = g_ptr_ds[w]; d = g_deg_ds[w];
    k = 0;
    for (; k + 1 < d; k += 2) {
        int s0 = g_adj_ds[p + k], s1 = g_adj_ds[p + k + 1];
        uint4 v0 = *(const uint4*)(Pd + (size_t)s0 * 512 + lane * 8);
        uint4 v1 = *(const uint4*)(Pd + (size_t)s1 * 512 + lane * 8);
        add8h(Bv, v0); add8h(Bv, v1);
    }
    if (k < d) {
        int s0 = g_adj_ds[p + k];
        add8h(Bv, *(const uint4*)(Pd + (size_t)s0 * 512 + lane * 8));
    }
    float sc2 = g_inv_ds[w];
    float L[8];
    unpack8h(L, *(const uint4*)(Ps + (size_t)w * 768 + 512 + lane * 8));
    float f[8];
    #pragma unroll
    for (int i = 0; i < 8; i++)
        f[i] = fmaxf(fmaf(A[i], sc, fmaf(Bv[i], sc2, L[i] + bias[lane * 8 + i])), 0.f);
    *(uint4*)(orow + lane * 8) = pack8h(f);
}
__global__ void gather1_doc(const __half* __restrict__ Ps, const __half* __restrict__ Pd,
                            const float* __restrict__ bias, __half* __restrict__ hout) {
    int w = (blockIdx.x * blockDim.x + threadIdx.x) >> 5;
    int lane = threadIdx.x & 31;
    if (w >= DOC_PAD) return;
    __half* orow = hout + (size_t)w * D_H;
    if (w >= N_DOC) {
        *(uint4*)(orow + lane * 8) = make_uint4(0u, 0u, 0u, 0u);
        return;
    }
    float A[8] = {0.f};
    int p = g_ptr_sd[w], d = g_deg_sd[w];
    int k = 0;
    for (; k + 1 < d; k += 2) {
        int s0 = g_adj_sd[p + k], s1 = g_adj_sd[p + k + 1];
        uint4 v0 = *(const uint4*)(Ps + (size_t)s0 * 768 + lane * 8);
        uint4 v1 = *(const uint4*)(Ps + (size_t)s1 * 768 + lane * 8);
        add8h(A, v0); add8h(A, v1);
    }
    if (k < d) {
        int s0 = g_adj_sd[p + k];
        add8h(A, *(const uint4*)(Ps + (size_t)s0 * 768 + lane * 8));
    }
    float sc = g_inv_sd[w];
    float L[8];
    unpack8h(L, *(const uint4*)(Pd + (size_t)w * 512 + 256 + lane * 8));
    float f[8];
    #pragma unroll
    for (int i = 0; i < 8; i++)
        f[i] = fmaxf(fmaf(A[i], sc, L[i] + bias[lane * 8 + i]), 0.f);
    *(uint4*)(orow + lane * 8) = pack8h(f);
}

// ---------------- layer-2 gather + combine + relu + score + per-graph reduce -------------
__global__ void init_out(float* __restrict__ out, const float* __restrict__ b_score) {
    int g = threadIdx.x;
    if (g < NGRAPH) out[g] = b_score[0];
}
__global__ void gather2_sent(const __half* __restrict__ Ps2, const __half* __restrict__ Pd2,
                             const float* __restrict__ bias, const float* __restrict__ wscore,
                             const int* __restrict__ gid, float* __restrict__ out) {
    int w = (blockIdx.x * blockDim.x + threadIdx.x) >> 5;
    int lane = threadIdx.x & 31;
    if (w >= N_SENT) return;
    float A[4] = {0.f}, Bv[4] = {0.f};
    int p = g_ptr_ss[w], d = g_deg_ss[w];
    int k = 0;
    for (; k + 1 < d; k += 2) {
        int s0 = g_adj_ss[p + k], s1 = g_adj_ss[p + k + 1];
        uint2 v0 = *(const uint2*)(Ps2 + (size_t)s0 * 384 + 128 + lane * 4);
        uint2 v1 = *(const uint2*)(Ps2 + (size_t)s1 * 384 + 128 + lane * 4);
        add4h(A, v0); add4h(A, v1);
    }
    if (k < d) {
        int s0 = g_adj_ss[p + k];
        add4h(A, *(const uint2*)(Ps2 + (size_t)s0 * 384 + 128 + lane * 4));
    }
    float sc = g_inv_ss[w];
    p = g_ptr_ds[w]; d = g_deg_ds[w];
    k = 0;
    for (; k + 1 < d; k += 2) {
        int s0 = g_adj_ds[p + k], s1 = g_adj_ds[p + k + 1];
        uint2 v0 = *(const uint2*)(Pd2 + (size_t)s0 * 256 + lane * 4);
        uint2 v1 = *(const uint2*)(Pd2 + (size_t)s1 * 256 + lane * 4);
        add4h(Bv, v0); add4h(Bv, v1);
    }
    if (k < d) {
        int s0 = g_adj_ds[p + k];
        add4h(Bv, *(const uint2*)(Pd2 + (size_t)s0 * 256 + lane * 4));
    }
    float sc2 = g_inv_ds[w];
    float L[4] = {0.f};
    add4h(L, *(const uint2*)(Ps2 + (size_t)w * 384 + 256 + lane * 4));
    float4 B = ((const float4*)bias)[lane];
    float4 W = ((const float4*)wscore)[lane];
    float bb[4] = {B.x, B.y, B.z, B.w};
    float ww[4] = {W.x, W.y, W.z, W.w};
    float s = 0.f;
    #pragma unroll
    for (int i = 0; i < 4; i++)
        s += fmaxf(fmaf(A[i], sc, fmaf(Bv[i], sc2, L[i] + bb[i])), 0.f) * ww[i];
    #pragma unroll
    for (int off = 16; off; off >>= 1) s += __shfl_down_sync(0xffffffffu, s, off);
    if (lane == 0) atomicAdd(&out[gid[w]], s);
}
__global__ void gather2_doc(const __half* __restrict__ Ps2, const __half* __restrict__ Pd2,
                            const float* __restrict__ bias, const float* __restrict__ wscore,
                            const int* __restrict__ gid, float* __restrict__ out) {
    int w = (blockIdx.x * blockDim.x + threadIdx.x) >> 5;
    int lane = threadIdx.x & 31;
    if (w >= N_DOC) return;
    float A[4] = {0.f};
    int p = g_ptr_sd[w], d = g_deg_sd[w];
    int k = 0;
    for (; k + 1 < d; k += 2) {
        int s0 = g_adj_sd[p + k], s1 = g_adj_sd[p + k + 1];
        uint2 v0 = *(const uint2*)(Ps2 + (size_t)s0 * 384 + lane * 4);
        uint2 v1 = *(const uint2*)(Ps2 + (size_t)s1 * 384 + lane * 4);
        add4h(A, v0); add4h(A, v1);
    }
    if (k < d) {
        int s0 = g_adj_sd[p + k];
        add4h(A, *(const uint2*)(Ps2 + (size_t)s0 * 384 + lane * 4));
    }
    float sc = g_inv_sd[w];
    float L[4] = {0.f};
    add4h(L, *(const uint2*)(Pd2 + (size_t)w * 256 + 128 + lane * 4));
    float4 B = ((const float4*)bias)[lane];
    float4 W = ((const float4*)wscore)[lane];
    float bb[4] = {B.x, B.y, B.z, B.w};
    float ww[4] = {W.x, W.y, W.z, W.w};
    float s = 0.f;
    #pragma unroll
    for (int i = 0; i < 4; i++)
        s += fmaxf(fmaf(A[i], sc, L[i] + bb[i]), 0.f) * ww[i];
    #pragma unroll
    for (int off = 16; off; off >>= 1) s += __shfl_down_sync(0xffffffffu, s, off);
    if (lane == 0) atomicAdd(&out[gid[w]], s);
}

// ---------------- host launcher ----------------
static void* symaddr(const void* sym) {
    void* p = nullptr;
    cudaGetSymbolAddress(&p, sym);
    return p;
}

extern "C" void kernel_launch(void* const* d_in, const int* in_sizes, int n_in,
                              void* d_out, int out_size) {
    const float* x_sent  = (const float*)d_in[0];
    const float* x_doc   = (const float*)d_in[1];
    const float* coeff1  = (const float*)d_in[2];
    const float* basis1  = (const float*)d_in[3];
    const float* loop_w1 = (const float*)d_in[4];
    const float* bias1   = (const float*)d_in[5];
    const float* coeff2  = (const float*)d_in[6];
    const float* basis2  = (const float*)d_in[7];
    const float* loop_w2 = (const float*)d_in[8];
    const float* bias2   = (const float*)d_in[9];
    const float* w_score = (const float*)d_in[10];
    const float* b_score = (const float*)d_in[11];
    const int*   src_ss  = (const int*)d_in[12];
    const int*   dst_ss  = (const int*)d_in[13];
    const int*   src_sd  = (const int*)d_in[14];
    const int*   dst_sd  = (const int*)d_in[15];
    const int*   src_ds  = (const int*)d_in[16];
    const int*   dst_ds  = (const int*)d_in[17];
    const int*   gid_sent= (const int*)d_in[18];
    const int*   gid_doc = (const int*)d_in[19];
    float* out = (float*)d_out;

    __half* pB1sh = (__half*)symaddr(g_B1s_h);
    __half* pB1dh = (__half*)symaddr(g_B1d_h);
    __half* pB2sh = (__half*)symaddr(g_B2s_h);
    __half* pB2dh = (__half*)symaddr(g_B2d_h);
    __half* pXsh = (__half*)symaddr(g_xs_h);
    __half* pXdh = (__half*)symaddr(g_xd_h);
    __half* pHsh = (__half*)symaddr(g_hs_h);
    __half* pHdh = (__half*)symaddr(g_hd_h);
    __half* pPs  = (__half*)symaddr(g_Ps);
    __half* pPd  = (__half*)symaddr(g_Pd);
    __half* pPs2 = (__half*)symaddr(g_Ps2);
    __half* pPd2 = (__half*)symaddr(g_Pd2);

    cudaFuncSetAttribute(gemm4, cudaFuncAttributeMaxDynamicSharedMemorySize, GEMM_SMEM);

    static cudaStream_t s2 = nullptr, s3 = nullptr;
    static cudaEvent_t eFork = nullptr, eSide = nullptr, eStripA = nullptr,
                       eD2 = nullptr, eCvt0 = nullptr, eCvt1 = nullptr,
                       eH1 = nullptr, eB2 = nullptr;
    if (s2 == nullptr) {
        cudaStreamCreateWithFlags(&s2, cudaStreamNonBlocking);
        cudaStreamCreateWithFlags(&s3, cudaStreamNonBlocking);
        cudaEventCreateWithFlags(&eFork, cudaEventDisableTiming);
        cudaEventCreateWithFlags(&eSide, cudaEventDisableTiming);
        cudaEventCreateWithFlags(&eStripA, cudaEventDisableTiming);
        cudaEventCreateWithFlags(&eD2, cudaEventDisableTiming);
        cudaEventCreateWithFlags(&eCvt0, cudaEventDisableTiming);
        cudaEventCreateWithFlags(&eCvt1, cudaEventDisableTiming);
        cudaEventCreateWithFlags(&eH1, cudaEventDisableTiming);
        cudaEventCreateWithFlags(&eB2, cudaEventDisableTiming);
    }

    cudaStream_t st = 0;

    // ---- head ----
    zero_deg<<<(N_SENT + 255) / 256, 256, 0, st>>>();
    cudaEventRecord(eFork, st);

    // s3: x_sent convert, row-chunked so strip A starts at half-convert
    cudaStreamWaitEvent(s3, eFork, 0);
    {
        long long npadc = (long long)HALF_S * D_IN;
        cvt_f16<<<(unsigned)((npadc / 8 + 255) / 256), 256, 0, s3>>>(x_sent, pXsh, npadc, npadc);
        cudaEventRecord(eCvt0, s3);
        long long npadc2 = (long long)(SENT_PAD - HALF_S) * D_IN;
        long long nrealc2 = (long long)(N_SENT - HALF_S) * D_IN;
        cvt_f16<<<(unsigned)((npadc2 / 8 + 255) / 256), 256, 0, s3>>>(
            x_sent + (size_t)HALF_S * D_IN, pXsh + (size_t)HALF_S * D_IN, nrealc2, npadc2);
        cudaEventRecord(eCvt1, s3);
    }

    // main: weights for strip A, strip A row-chunks as converts land
    build_w3t<<<(768 * 768 + 255) / 256, 256, 0, st>>>(coeff1, basis1, loop_w1, pB1sh, D_IN, D_H, 768, 0, 2);
    cudaStreamWaitEvent(st, eCvt0, 0);
    {
        dim3 g(512 / 128, HALF_S / 128);
        gemm4<<<g, 256, GEMM_SMEM, st>>>(pXsh, pB1sh + (size_t)256 * D_IN, pPs + 256,
                                         N_SENT, 3 * D_H, D_IN);
    }
    cudaStreamWaitEvent(st, eCvt1, 0);
    {
        dim3 g(512 / 128, (SENT_PAD - HALF_S) / 128);
        gemm4<<<g, 256, GEMM_SMEM, st>>>(pXsh + (size_t)HALF_S * D_IN,
                                         pB1sh + (size_t)256 * D_IN,
                                         pPs + (size_t)HALF_S * 768 + 256,
                                         N_SENT - HALF_S, 3 * D_H, D_IN);
    }
    cudaEventRecord(eStripA, st);

    // ---- s2: CSR + doc prep + doc layer-1 GEMM under strip A ----
    cudaStreamWaitEvent(s2, eFork, 0);
    {
        int Etot = E_SS + E_DS + E_SD;
        count_all<<<(Etot + 255) / 256, 256, 0, s2>>>(dst_ss, dst_ds, dst_sd);
        scan_local_all<<<2 * NB_S + NB_D, 1024, 0, s2>>>();
        scan_block_all<<<3, 128, 0, s2>>>();
        scan_final_all<<<(2 * N_SENT + N_DOC + 255) / 256, 256, 0, s2>>>();
        fill_all<<<(Etot + 255) / 256, 256, 0, s2>>>(src_ss, dst_ss, src_ds, dst_ds, src_sd, dst_sd);
    }
    {
        long long nreal = (long long)N_DOC * D_IN, npad = (long long)DOC_PAD * D_IN;
        cvt_f16<<<(unsigned)((npad / 8 + 255) / 256), 256, 0, s2>>>(x_doc, pXdh, nreal, npad);
    }
    build_w2t<<<(512 * 768 + 255) / 256, 256, 0, s2>>>(coeff1, basis1, loop_w1, pB1dh, D_IN, D_H, 512, 1);
    build_w3t<<<(384 * 256 + 255) / 256, 256, 0, s2>>>(coeff2, basis2, loop_w2, pB2sh, D_H, D_O, 384, 0, 2);
    build_w2t<<<(256 * 256 + 255) / 256, 256, 0, s2>>>(coeff2, basis2, loop_w2, pB2dh, D_H, D_O, 256, 1);
    {
        dim3 g(512 / 128, DOC_PAD / 128);
        gemm4<<<g, 256, GEMM_SMEM, s2>>>(pXdh, pB1dh, pPd, N_DOC, 2 * D_H, D_IN);
    }
    cudaEventRecord(eSide, s2);

    // ---- s2 (after strip A): strip B of layer-1 sent GEMM (Ps cols 0:256) -> doc path ----
    cudaStreamWaitEvent(s2, eStripA, 0);
    {
        dim3 g(256 / 128, SENT_PAD / 128);
        gemm4<<<g, 256, GEMM_SMEM, s2>>>(pXsh, pB1sh, pPs, N_SENT, 3 * D_H, D_IN);
    }
    gather1_doc<<<(DOC_PAD * 32 + 255) / 256, 256, 0, s2>>>(pPs, pPd, bias1, pHdh);
    {
        dim3 g(256 / 128, DOC_PAD / 128);
        gemm4<<<g, 256, GEMM_SMEM, s2>>>(pHdh, pB2dh, pPd2, N_DOC, 2 * D_O, D_H);
    }
    cudaEventRecord(eD2, s2);

    // ---- main: gather1_sent (concurrent with strip B), then layer-2 strips ----
    cudaStreamWaitEvent(st, eSide, 0);   // Pd + CSR ready (strip A already done on this stream)
    gather1_sent<<<(SENT_PAD * 32 + 255) / 256, 256, 0, st>>>(pPs, pPd, bias1, pHsh, 0, SENT_PAD);
    cudaEventRecord(eH1, st);

    // main: layer-2 sent GEMM strip A (Ps2 cols 128:384 — everything gather2_sent reads)
    {
        dim3 g(256 / 128, SENT_PAD / 128);
        gemm4<<<g, 256, GEMM_SMEM, st>>>(pHsh, pB2sh + (size_t)128 * D_H, pPs2 + 128,
                                         N_SENT, 3 * D_O, D_H);
    }

    // s2: layer-2 sent GEMM strip B (Ps2 cols 0:128 — only gather2_doc reads it),
    // concurrent with main's gather2_sent
    cudaStreamWaitEvent(s2, eH1, 0);
    {
        dim3 g(128 / 128, SENT_PAD / 128);
        gemm4<<<g, 256, GEMM_SMEM, s2>>>(pHsh, pB2sh, pPs2, N_SENT, 3 * D_O, D_H);
    }
    cudaEventRecord(eB2, s2);

    // main: readout — gather2_sent right after strip A; gather2_doc after strip B joins
    cudaStreamWaitEvent(st, eD2, 0);     // Pd2 ready
    init_out<<<1, 32, 0, st>>>(out, b_score);
    gather2_sent<<<(N_SENT * 32 + 255) / 256, 256, 0, st>>>(pPs2, pPd2, bias2, w_score, gid_sent, out);
    cudaStreamWaitEvent(st, eB2, 0);     // Ps2 cols 0:128 ready
    gather2_doc<<<(N_DOC * 32 + 255) / 256, 256, 0, st>>>(pPs2, pPd2, bias2, w_score, gid_doc, out);
}

// round 16
// speedup vs baseline: 4.9562x; 1.1556x over previous
#include <cuda_runtime.h>
#include <cuda_fp16.h>
#include <cstdint>
#include <cstddef>

#define N_SENT 100000
#define N_DOC  10000
#define SENT_PAD 100096
#define DOC_PAD  10112
#define HALF_S   50048
#define NGRAPH 32
#define D_IN   768
#define D_H    256
#define D_O    128
#define E_SS   400000
#define E_SD   100000
#define E_DS   100000

// ---------------- scratch (device globals: allocation-free) ----------------
__device__ __align__(16) __half g_B1s_h[768 * 768];
__device__ __align__(16) __half g_B1d_h[512 * 768];
__device__ __align__(16) __half g_B2s_h[384 * 256];
__device__ __align__(16) __half g_B2d_h[256 * 256];

__device__ __align__(16) __half g_xs_h[(size_t)SENT_PAD * D_IN];
__device__ __align__(16) __half g_xd_h[(size_t)DOC_PAD * D_IN];
__device__ __align__(16) __half g_hs_h[(size_t)SENT_PAD * D_H];
__device__ __align__(16) __half g_hd_h[(size_t)DOC_PAD * D_H];

__device__ __align__(16) __half g_Ps [(size_t)SENT_PAD * (3 * D_H)];
__device__ __align__(16) __half g_Pd [(size_t)N_DOC  * (2 * D_H)];
__device__ __align__(16) __half g_Ps2[(size_t)SENT_PAD * (3 * D_O)];
__device__ __align__(16) __half g_Pd2[(size_t)N_DOC  * (2 * D_O)];

// doc-side aggregate-first buffers (mean commutes with projection)
__device__ __align__(16) __half g_aggx[(size_t)DOC_PAD * D_IN];
__device__ __align__(16) __half g_msg1[(size_t)DOC_PAD * D_H];
__device__ __align__(16) __half g_aggh[(size_t)DOC_PAD * D_H];
__device__ __align__(16) __half g_msg2[(size_t)DOC_PAD * D_O];

// CSR structures (incoming edges per destination)
__device__ int   g_deg_ss[N_SENT], g_deg_ds[N_SENT], g_deg_sd[N_DOC];
__device__ int   g_ptr_ss[N_SENT], g_ptr_ds[N_SENT], g_ptr_sd[N_DOC];
__device__ int   g_cur_ss[N_SENT], g_cur_ds[N_SENT], g_cur_sd[N_DOC];
__device__ int   g_adj_ss[E_SS], g_adj_ds[E_DS], g_adj_sd[E_SD];
__device__ float g_inv_ss[N_SENT], g_inv_ds[N_SENT], g_inv_sd[N_DOC];
__device__ int   g_bsum_a[128], g_bsum_b[128], g_bsum_c[128];
__device__ int   g_part_ss[N_SENT], g_part_ds[N_SENT], g_part_sd[N_DOC];

// ---------------- PTX helpers ----------------
__device__ __forceinline__ uint32_t smem_u32(const void* p) {
    uint32_t a;
    asm("{ .reg .u64 t; cvta.to.shared.u64 t, %1; cvt.u32.u64 %0, t; }" : "=r"(a) : "l"(p));
    return a;
}

#define CP_ASYNC16(saddr, gaddr) \
    asm volatile("cp.async.cg.shared.global [%0], [%1], 16;" :: "r"(saddr), "l"(gaddr) : "memory")
#define CP_COMMIT() asm volatile("cp.async.commit_group;" ::: "memory")
#define CP_WAIT1()  asm volatile("cp.async.wait_group 1;" ::: "memory")

#define LDMX4(r0, r1, r2, r3, addr) \
    asm volatile("ldmatrix.sync.aligned.m8n8.x4.shared.b16 {%0,%1,%2,%3}, [%4];" \
                 : "=r"(r0), "=r"(r1), "=r"(r2), "=r"(r3) : "r"(addr))

#define MMA16816(d, a, b) \
    asm volatile("mma.sync.aligned.m16n8k16.row.col.f32.f16.f16.f32 " \
                 "{%0,%1,%2,%3}, {%4,%5,%6,%7}, {%8,%9}, {%0,%1,%2,%3};" \
                 : "+f"((d)[0]), "+f"((d)[1]), "+f"((d)[2]), "+f"((d)[3]) \
                 : "r"((a)[0]), "r"((a)[1]), "r"((a)[2]), "r"((a)[3]), "r"((b)[0]), "r"((b)[1]))

__device__ __forceinline__ uint4 pack8h(const float* f) {
    uint32_t hs[8];
    #pragma unroll
    for (int i = 0; i < 8; i++) hs[i] = (uint32_t)__half_as_ushort(__float2half(f[i]));
    return make_uint4(hs[0] | (hs[1] << 16), hs[2] | (hs[3] << 16), hs[4] | (hs[5] << 16), hs[6] | (hs[7] << 16));
}
__device__ __forceinline__ void add8h(float* A, uint4 v) {
    const __half2* h = (const __half2*)&v;
    #pragma unroll
    for (int i = 0; i < 4; i++) {
        float2 f = __half22float2(h[i]);
        A[2 * i] += f.x; A[2 * i + 1] += f.y;
    }
}
__device__ __forceinline__ void unpack8h(float* A, uint4 v) {
    const __half2* h = (const __half2*)&v;
    #pragma unroll
    for (int i = 0; i < 4; i++) {
        float2 f = __half22float2(h[i]);
        A[2 * i] = f.x; A[2 * i + 1] = f.y;
    }
}
__device__ __forceinline__ void add4h(float* A, uint2 v) {
    const __half2* h = (const __half2*)&v;
    #pragma unroll
    for (int i = 0; i < 2; i++) {
        float2 f = __half22float2(h[i]);
        A[2 * i] += f.x; A[2 * i + 1] += f.y;
    }
}
__device__ __forceinline__ void unpack4h(float* A, uint2 v) {
    const __half2* h = (const __half2*)&v;
    #pragma unroll
    for (int i = 0; i < 2; i++) {
        float2 f = __half22float2(h[i]);
        A[2 * i] = f.x; A[2 * i + 1] = f.y;
    }
}

#define ROWB   80

// ================= GEMM: fp16 x fp16 -> fp16, 3-stage single-sync, 128x128 =============
#define ST_SZ  20480
#define OFF_A  0
#define OFF_B  10240
#define NSTAGE 3
#define GEMM_SMEM (NSTAGE * ST_SZ)

__global__ __launch_bounds__(256, 2) void gemm4(
    const __half* __restrict__ A,
    const __half* __restrict__ Bt,
    __half* __restrict__ C, int M, int N, int K)
{
    extern __shared__ char smem[];
    uint32_t sb = smem_u32(smem);
    int tid = threadIdx.x;
    int lane = tid & 31, wid = tid >> 5;
    int warp_m = (wid & 3) * 32;
    int warp_n = (wid >> 2) * 64;
    int mrow0 = blockIdx.y * 128;
    int ncol0 = blockIdx.x * 128;
    int nk = K >> 5;

    int prow = tid >> 1;
    int pch  = (tid & 1) * 16;
    const __half* aP = A + (size_t)(mrow0 + prow) * K + pch;
    const __half* bP = Bt + (size_t)(ncol0 + prow) * K + pch;
    uint32_t sts = (uint32_t)(prow * ROWB + pch * 2);

    int ra = warp_m + (lane & 7) + (lane & 8);
    int ca = ((lane >> 4) << 3);
    uint32_t a_lm = (uint32_t)(ra * ROWB + ca * 2);
    int rb = warp_n + (lane & 7) + ((lane >> 4) << 3);
    int cb = (((lane >> 3) & 1) << 3);
    uint32_t b_lm = (uint32_t)(rb * ROWB + cb * 2);

    float acc[2][8][4];
    #pragma unroll
    for (int mi = 0; mi < 2; mi++)
        #pragma unroll
        for (int ni = 0; ni < 8; ni++)
            #pragma unroll
            for (int q = 0; q < 4; q++) acc[mi][ni][q] = 0.f;

    #pragma unroll
    for (int s = 0; s < 2; s++) {
        if (s < nk) {
            uint32_t base = sb + s * ST_SZ;
            const __half* ap = aP + s * 32;
            const __half* bp = bP + s * 32;
            CP_ASYNC16(base + OFF_A + sts, ap); CP_ASYNC16(base + OFF_A + sts + 16, ap + 8);
            CP_ASYNC16(base + OFF_B + sts, bp); CP_ASYNC16(base + OFF_B + sts + 16, bp + 8);
        }
        CP_COMMIT();
    }

    for (int kt = 0; kt < nk; kt++) {
        CP_WAIT1();
        __syncthreads();

        int pf = kt + 2;
        if (pf < nk) {
            uint32_t base = sb + (pf % NSTAGE) * ST_SZ;
            const __half* ap = aP + pf * 32;
            const __half* bp = bP + pf * 32;
            CP_ASYNC16(base + OFF_A + sts, ap); CP_ASYNC16(base + OFF_A + sts + 16, ap + 8);
            CP_ASYNC16(base + OFF_B + sts, bp); CP_ASYNC16(base + OFF_B + sts + 16, bp + 8);
        }
        CP_COMMIT();

        uint32_t bcur = sb + (kt % NSTAGE) * ST_SZ;
        #pragma unroll
        for (int ks = 0; ks < 2; ks++) {
            uint32_t koff = ks * 32;
            uint32_t af[2][4], bf[8][2];
            #pragma unroll
            for (int mi = 0; mi < 2; mi++)
                LDMX4(af[mi][0], af[mi][1], af[mi][2], af[mi][3],
                      bcur + OFF_A + a_lm + mi * (16 * ROWB) + koff);
            #pragma unroll
            for (int bg = 0; bg < 4; bg++)
                LDMX4(bf[bg * 2][0], bf[bg * 2][1], bf[bg * 2 + 1][0], bf[bg * 2 + 1][1],
                      bcur + OFF_B + b_lm + bg * (16 * ROWB) + koff);
            #pragma unroll
            for (int mi = 0; mi < 2; mi++)
                #pragma unroll
                for (int ni = 0; ni < 8; ni++)
                    MMA16816(acc[mi][ni], af[mi], bf[ni]);
        }
    }

    int g = lane >> 2, t4 = lane & 3;
    #pragma unroll
    for (int mi = 0; mi < 2; mi++) {
        int r0 = mrow0 + warp_m + mi * 16 + g;
        #pragma unroll
        for (int ni = 0; ni < 8; ni++) {
            int col = ncol0 + warp_n + ni * 8 + t4 * 2;
            if (r0 < M)
                *(__half2*)(C + (size_t)r0 * N + col) = __floats2half2_rn(acc[mi][ni][0], acc[mi][ni][1]);
            if (r0 + 8 < M)
                *(__half2*)(C + (size_t)(r0 + 8) * N + col) = __floats2half2_rn(acc[mi][ni][2], acc[mi][ni][3]);
        }
    }
}

// ---------------- fp32 -> fp16 convert (padded, zero-filled) ----------------
__global__ void cvt_f16(const float* __restrict__ x, __half* __restrict__ hi,
                        long long nreal, long long npad) {
    long long base = ((long long)blockIdx.x * blockDim.x + threadIdx.x) * 8;
    if (base >= npad) return;
    float f[8];
    if (base < nreal) {
        float4 v0 = *(const float4*)(x + base);
        float4 v1 = *(const float4*)(x + base + 4);
        f[0] = v0.x; f[1] = v0.y; f[2] = v0.z; f[3] = v0.w;
        f[4] = v1.x; f[5] = v1.y; f[6] = v1.z; f[7] = v1.w;
    } else {
        #pragma unroll
        for (int q = 0; q < 8; q++) f[q] = 0.f;
    }
    *(uint4*)(hi + base) = pack8h(f);
}

// ---------------- CSR construction (fused across the 3 relations) ----------------
__global__ void zero_deg() {
    int i = blockIdx.x * blockDim.x + threadIdx.x;
    if (i < N_SENT) { g_deg_ss[i] = 0; g_deg_ds[i] = 0; }
    if (i < N_DOC)  { g_deg_sd[i] = 0; }
}
__global__ void count_all(const int* __restrict__ dss, const int* __restrict__ dds,
                          const int* __restrict__ dsd) {
    int i = blockIdx.x * blockDim.x + threadIdx.x;
    if (i < E_SS) atomicAdd(&g_deg_ss[dss[i]], 1);
    else if (i < E_SS + E_DS) atomicAdd(&g_deg_ds[dds[i - E_SS]], 1);
    else if (i < E_SS + E_DS + E_SD) atomicAdd(&g_deg_sd[dsd[i - E_SS - E_DS]], 1);
}
#define NB_S 98
#define NB_D 10
__global__ void scan_local_all() {
    __shared__ int sm[1024];
    const int* deg; int* part; int* bsum; int n; int blk;
    if (blockIdx.x < NB_S) { deg = g_deg_ss; part = g_part_ss; bsum = g_bsum_a; n = N_SENT; blk = blockIdx.x; }
    else if (blockIdx.x < 2 * NB_S) { deg = g_deg_ds; part = g_part_ds; bsum = g_bsum_b; n = N_SENT; blk = blockIdx.x - NB_S; }
    else { deg = g_deg_sd; part = g_part_sd; bsum = g_bsum_c; n = N_DOC; blk = blockIdx.x - 2 * NB_S; }
    int i = blk * 1024 + threadIdx.x;
    int v = (i < n) ? deg[i] : 0;
    sm[threadIdx.x] = v;
    __syncthreads();
    #pragma unroll
    for (int off = 1; off < 1024; off <<= 1) {
        int t = (threadIdx.x >= off) ? sm[threadIdx.x - off] : 0;
        __syncthreads();
        sm[threadIdx.x] += t;
        __syncthreads();
    }
    if (i < n) part[i] = sm[threadIdx.x] - v;
    if (threadIdx.x == 1023) bsum[blk] = sm[1023];
}
__global__ void scan_block_all() {
    __shared__ int sm[128];
    int* bsum; int nb;
    if (blockIdx.x == 0) { bsum = g_bsum_a; nb = NB_S; }
    else if (blockIdx.x == 1) { bsum = g_bsum_b; nb = NB_S; }
    else { bsum = g_bsum_c; nb = NB_D; }
    int v = (threadIdx.x < nb) ? bsum[threadIdx.x] : 0;
    sm[threadIdx.x] = v;
    __syncthreads();
    #pragma unroll
    for (int off = 1; off < 128; off <<= 1) {
        int t = (threadIdx.x >= off) ? sm[threadIdx.x - off] : 0;
        __syncthreads();
        sm[threadIdx.x] += t;
        __syncthreads();
    }
    if (threadIdx.x < nb) bsum[threadIdx.x] = sm[threadIdx.x] - v;
}
__global__ void scan_final_all() {
    int i = blockIdx.x * blockDim.x + threadIdx.x;
    if (i < N_SENT) {
        int p = g_part_ss[i] + g_bsum_a[i >> 10];
        g_ptr_ss[i] = p; g_cur_ss[i] = p;
        g_inv_ss[i] = 1.0f / (float)max(g_deg_ss[i], 1);
    } else if (i < 2 * N_SENT) {
        int j = i - N_SENT;
        int p = g_part_ds[j] + g_bsum_b[j >> 10];
        g_ptr_ds[j] = p; g_cur_ds[j] = p;
        g_inv_ds[j] = 1.0f / (float)max(g_deg_ds[j], 1);
    } else if (i < 2 * N_SENT + N_DOC) {
        int j = i - 2 * N_SENT;
        int p = g_part_sd[j] + g_bsum_c[j >> 10];
        g_ptr_sd[j] = p; g_cur_sd[j] = p;
        g_inv_sd[j] = 1.0f / (float)max(g_deg_sd[j], 1);
    }
}
__global__ void fill_all(const int* __restrict__ sss, const int* __restrict__ dss,
                         const int* __restrict__ sds, const int* __restrict__ dds,
                         const int* __restrict__ ssd, const int* __restrict__ dsd) {
    int i = blockIdx.x * blockDim.x + threadIdx.x;
    if (i < E_SS) {
        int p = atomicAdd(&g_cur_ss[dss[i]], 1);
        g_adj_ss[p] = sss[i];
    } else if (i < E_SS + E_DS) {
        int e = i - E_SS;
        int p = atomicAdd(&g_cur_ds[dds[e]], 1);
        g_adj_ds[p] = sds[e];
    } else if (i < E_SS + E_DS + E_SD) {
        int e = i - E_SS - E_DS;
        int p = atomicAdd(&g_cur_sd[dsd[e]], 1);
        g_adj_sd[p] = ssd[e];
    }
}

// ---------------- weight build: transposed fp16 ----------------
__global__ void build_w3t(const float* __restrict__ coeff, const float* __restrict__ basis,
                          const float* __restrict__ loopw,
                          __half* __restrict__ outH,
                          int K, int D, int Npad, int r0, int r1) {
    int idx = blockIdx.x * blockDim.x + threadIdx.x;
    if (idx >= Npad * K) return;
    int o = idx / K;
    int k = idx % K;
    float v = 0.f;
    if (o < 3 * D) {
        int seg = o / D, od = o % D;
        if (seg == 2) v = loopw[k * D + od];
        else {
            int r = (seg == 0) ? r0 : r1;
            v = coeff[r * 2 + 0] * basis[(size_t)k * D + od]
              + coeff[r * 2 + 1] * basis[(size_t)K * D + (size_t)k * D + od];
        }
    }
    outH[idx] = __float2half(v);
}
__global__ void build_w2t(const float* __restrict__ coeff, const float* __restrict__ basis,
                          const float* __restrict__ loopw,
                          __half* __restrict__ outH,
                          int K, int D, int Npad, int r0) {
    int idx = blockIdx.x * blockDim.x + threadIdx.x;
    if (idx >= Npad * K) return;
    int o = idx / K;
    int k = idx % K;
    float v = 0.f;
    if (o < 2 * D) {
        int seg = o / D, od = o % D;
        if (seg == 1) v = loopw[k * D + od];
        else {
            v = coeff[r0 * 2 + 0] * basis[(size_t)k * D + od]
              + coeff[r0 * 2 + 1] * basis[(size_t)K * D + (size_t)k * D + od];
        }
    }
    outH[idx] = __float2half(v);
}

// ---------------- doc-side aggregate-first gathers ----------------
// aggx[doc] = inv_sd * sum_{sd edges} x_sent_fp16[src]  (768 dims, warp per doc)
__global__ void gather_x_sd(const __half* __restrict__ xs, __half* __restrict__ aggx) {
    int w = (blockIdx.x * blockDim.x + threadIdx.x) >> 5;
    int lane = threadIdx.x & 31;
    if (w >= DOC_PAD) return;
    __half* orow = aggx + (size_t)w * D_IN;
    if (w >= N_DOC) {
        #pragma unroll
        for (int c = 0; c < 3; c++)
            *(uint4*)(orow + c * 256 + lane * 8) = make_uint4(0u, 0u, 0u, 0u);
        return;
    }
    float A[24];
    #pragma unroll
    for (int i = 0; i < 24; i++) A[i] = 0.f;
    int p = g_ptr_sd[w], d = g_deg_sd[w];
    for (int k = 0; k < d; k++) {
        int s = g_adj_sd[p + k];
        const __half* r = xs + (size_t)s * D_IN;
        add8h(A,      *(const uint4*)(r + lane * 8));
        add8h(A + 8,  *(const uint4*)(r + 256 + lane * 8));
        add8h(A + 16, *(const uint4*)(r + 512 + lane * 8));
    }
    float sc = g_inv_sd[w];
    #pragma unroll
    for (int c = 0; c < 3; c++) {
        float f[8];
        #pragma unroll
        for (int i = 0; i < 8; i++) f[i] = A[c * 8 + i] * sc;
        *(uint4*)(orow + c * 256 + lane * 8) = pack8h(f);
    }
}
// aggh[doc] = inv_sd * sum h_sent[src]  (256 dims)
__global__ void gather_h_sd(const __half* __restrict__ hs, __half* __restrict__ aggh) {
    int w = (blockIdx.x * blockDim.x + threadIdx.x) >> 5;
    int lane = threadIdx.x & 31;
    if (w >= DOC_PAD) return;
    __half* orow = aggh + (size_t)w * D_H;
    if (w >= N_DOC) {
        *(uint4*)(orow + lane * 8) = make_uint4(0u, 0u, 0u, 0u);
        return;
    }
    float A[8] = {0.f};
    int p = g_ptr_sd[w], d = g_deg_sd[w];
    for (int k = 0; k < d; k++) {
        int s = g_adj_sd[p + k];
        add8h(A, *(const uint4*)(hs + (size_t)s * D_H + lane * 8));
    }
    float sc = g_inv_sd[w];
    float f[8];
    #pragma unroll
    for (int i = 0; i < 8; i++) f[i] = A[i] * sc;
    *(uint4*)(orow + lane * 8) = pack8h(f);
}

// ---------------- doc combines (no edge loops) ----------------
__global__ void combine1_doc(const __half* __restrict__ msg, const __half* __restrict__ Pd,
                             const float* __restrict__ bias, __half* __restrict__ hout) {
    int w = (blockIdx.x * blockDim.x + threadIdx.x) >> 5;
    int lane = threadIdx.x & 31;
    if (w >= DOC_PAD) return;
    __half* orow = hout + (size_t)w * D_H;
    if (w >= N_DOC) {
        *(uint4*)(orow + lane * 8) = make_uint4(0u, 0u, 0u, 0u);
        return;
    }
    float M[8], L[8];
    unpack8h(M, *(const uint4*)(msg + (size_t)w * D_H + lane * 8));
    unpack8h(L, *(const uint4*)(Pd + (size_t)w * 512 + 256 + lane * 8));
    float f[8];
    #pragma unroll
    for (int i = 0; i < 8; i++)
        f[i] = fmaxf(M[i] + L[i] + bias[lane * 8 + i], 0.f);
    *(uint4*)(orow + lane * 8) = pack8h(f);
}
__global__ void combine2_doc(const __half* __restrict__ msg2, const __half* __restrict__ Pd2,
                             const float* __restrict__ bias, const float* __restrict__ wscore,
                             const int* __restrict__ gid, float* __restrict__ out) {
    int w = (blockIdx.x * blockDim.x + threadIdx.x) >> 5;
    int lane = threadIdx.x & 31;
    if (w >= N_DOC) return;
    float M[4], L[4];
    unpack4h(M, *(const uint2*)(msg2 + (size_t)w * D_O + lane * 4));
    unpack4h(L, *(const uint2*)(Pd2 + (size_t)w * 256 + 128 + lane * 4));
    float4 B = ((const float4*)bias)[lane];
    float4 W = ((const float4*)wscore)[lane];
    float bb[4] = {B.x, B.y, B.z, B.w};
    float ww[4] = {W.x, W.y, W.z, W.w};
    float s = 0.f;
    #pragma unroll
    for (int i = 0; i < 4; i++)
        s += fmaxf(M[i] + L[i] + bb[i], 0.f) * ww[i];
    #pragma unroll
    for (int off = 16; off; off >>= 1) s += __shfl_down_sync(0xffffffffu, s, off);
    if (lane == 0) atomicAdd(&out[gid[w]], s);
}

// ---------------- layer-1 sent gather (warp per dst node) + combine + fp16 emit ----------
__global__ void gather1_sent(const __half* __restrict__ Ps, const __half* __restrict__ Pd,
                             const float* __restrict__ bias, __half* __restrict__ hout,
                             int w0, int w1) {
    int w = w0 + ((blockIdx.x * blockDim.x + threadIdx.x) >> 5);
    int lane = threadIdx.x & 31;
    if (w >= w1) return;
    __half* orow = hout + (size_t)w * D_H;
    if (w >= N_SENT) {
        *(uint4*)(orow + lane * 8) = make_uint4(0u, 0u, 0u, 0u);
        return;
    }
    float A[8] = {0.f}, Bv[8] = {0.f};
    int p = g_ptr_ss[w], d = g_deg_ss[w];
    int k = 0;
    for (; k + 1 < d; k += 2) {
        int s0 = g_adj_ss[p + k], s1 = g_adj_ss[p + k + 1];
        uint4 v0 = *(const uint4*)(Ps + (size_t)s0 * 768 + 256 + lane * 8);
        uint4 v1 = *(const uint4*)(Ps + (size_t)s1 * 768 + 256 + lane * 8);
        add8h(A, v0); add8h(A, v1);
    }
    if (k < d) {
        int s0 = g_adj_ss[p + k];
        add8h(A, *(const uint4*)(Ps + (size_t)s0 * 768 + 256 + lane * 8));
    }
    float sc = g_inv_ss[w];
    p = g_ptr_ds[w]; d = g_deg_ds[w];
    k = 0;
    for (; k + 1 < d; k += 2) {
        int s0 = g_adj_ds[p + k], s1 = g_adj_ds[p + k + 1];
        uint4 v0 = *(const uint4*)(Pd + (size_t)s0 * 512 + lane * 8);
        uint4 v1 = *(const uint4*)(Pd + (size_t)s1 * 512 + lane * 8);
        add8h(Bv, v0); add8h(Bv, v1);
    }
    if (k < d) {
        int s0 = g_adj_ds[p + k];
        add8h(Bv, *(const uint4*)(Pd + (size_t)s0 * 512 + lane * 8));
    }
    float sc2 = g_inv_ds[w];
    float L[8];
    unpack8h(L, *(const uint4*)(Ps + (size_t)w * 768 + 512 + lane * 8));
    float f[8];
    #pragma unroll
    for (int i = 0; i < 8; i++)
        f[i] = fmaxf(fmaf(A[i], sc, fmaf(Bv[i], sc2, L[i] + bias[lane * 8 + i])), 0.f);
    *(uint4*)(orow + lane * 8) = pack8h(f);
}

// ---------------- layer-2 sent gather + readout ----------------
__global__ void init_out(float* __restrict__ out, const float* __restrict__ b_score) {
    int g = threadIdx.x;
    if (g < NGRAPH) out[g] = b_score[0];
}
__global__ void gather2_sent(const __half* __restrict__ Ps2, const __half* __restrict__ Pd2,
                             const float* __restrict__ bias, const float* __restrict__ wscore,
                             const int* __restrict__ gid, float* __restrict__ out) {
    int w = (blockIdx.x * blockDim.x + threadIdx.x) >> 5;
    int lane = threadIdx.x & 31;
    if (w >= N_SENT) return;
    float A[4] = {0.f}, Bv[4] = {0.f};
    int p = g_ptr_ss[w], d = g_deg_ss[w];
    int k = 0;
    for (; k + 1 < d; k += 2) {
        int s0 = g_adj_ss[p + k], s1 = g_adj_ss[p + k + 1];
        uint2 v0 = *(const uint2*)(Ps2 + (size_t)s0 * 384 + 128 + lane * 4);
        uint2 v1 = *(const uint2*)(Ps2 + (size_t)s1 * 384 + 128 + lane * 4);
        add4h(A, v0); add4h(A, v1);
    }
    if (k < d) {
        int s0 = g_adj_ss[p + k];
        add4h(A, *(const uint2*)(Ps2 + (size_t)s0 * 384 + 128 + lane * 4));
    }
    float sc = g_inv_ss[w];
    p = g_ptr_ds[w]; d = g_deg_ds[w];
    k = 0;
    for (; k + 1 < d; k += 2) {
        int s0 = g_adj_ds[p + k], s1 = g_adj_ds[p + k + 1];
        uint2 v0 = *(const uint2*)(Pd2 + (size_t)s0 * 256 + lane * 4);
        uint2 v1 = *(const uint2*)(Pd2 + (size_t)s1 * 256 + lane * 4);
        add4h(Bv, v0); add4h(Bv, v1);
    }
    if (k < d) {
        int s0 = g_adj_ds[p + k];
        add4h(Bv, *(const uint2*)(Pd2 + (size_t)s0 * 256 + lane * 4));
    }
    float sc2 = g_inv_ds[w];
    float L[4] = {0.f};
    add4h(L, *(const uint2*)(Ps2 + (size_t)w * 384 + 256 + lane * 4));
    float4 B = ((const float4*)bias)[lane];
    float4 W = ((const float4*)wscore)[lane];
    float bb[4] = {B.x, B.y, B.z, B.w};
    float ww[4] = {W.x, W.y, W.z, W.w};
    float s = 0.f;
    #pragma unroll
    for (int i = 0; i < 4; i++)
        s += fmaxf(fmaf(A[i], sc, fmaf(Bv[i], sc2, L[i] + bb[i])), 0.f) * ww[i];
    #pragma unroll
    for (int off = 16; off; off >>= 1) s += __shfl_down_sync(0xffffffffu, s, off);
    if (lane == 0) atomicAdd(&out[gid[w]], s);
}

// ---------------- host launcher ----------------
static void* symaddr(const void* sym) {
    void* p = nullptr;
    cudaGetSymbolAddress(&p, sym);
    return p;
}

extern "C" void kernel_launch(void* const* d_in, const int* in_sizes, int n_in,
                              void* d_out, int out_size) {
    const float* x_sent  = (const float*)d_in[0];
    const float* x_doc   = (const float*)d_in[1];
    const float* coeff1  = (const float*)d_in[2];
    const float* basis1  = (const float*)d_in[3];
    const float* loop_w1 = (const float*)d_in[4];
    const float* bias1   = (const float*)d_in[5];
    const float* coeff2  = (const float*)d_in[6];
    const float* basis2  = (const float*)d_in[7];
    const float* loop_w2 = (const float*)d_in[8];
    const float* bias2   = (const float*)d_in[9];
    const float* w_score = (const float*)d_in[10];
    const float* b_score = (const float*)d_in[11];
    const int*   src_ss  = (const int*)d_in[12];
    const int*   dst_ss  = (const int*)d_in[13];
    const int*   src_sd  = (const int*)d_in[14];
    const int*   dst_sd  = (const int*)d_in[15];
    const int*   src_ds  = (const int*)d_in[16];
    const int*   dst_ds  = (const int*)d_in[17];
    const int*   gid_sent= (const int*)d_in[18];
    const int*   gid_doc = (const int*)d_in[19];
    float* out = (float*)d_out;

    __half* pB1sh = (__half*)symaddr(g_B1s_h);
    __half* pB1dh = (__half*)symaddr(g_B1d_h);
    __half* pB2sh = (__half*)symaddr(g_B2s_h);
    __half* pB2dh = (__half*)symaddr(g_B2d_h);
    __half* pXsh = (__half*)symaddr(g_xs_h);
    __half* pXdh = (__half*)symaddr(g_xd_h);
    __half* pHsh = (__half*)symaddr(g_hs_h);
    __half* pHdh = (__half*)symaddr(g_hd_h);
    __half* pPs  = (__half*)symaddr(g_Ps);
    __half* pPd  = (__half*)symaddr(g_Pd);
    __half* pPs2 = (__half*)symaddr(g_Ps2);
    __half* pPd2 = (__half*)symaddr(g_Pd2);
    __half* pAggx = (__half*)symaddr(g_aggx);
    __half* pMsg1 = (__half*)symaddr(g_msg1);
    __half* pAggh = (__half*)symaddr(g_aggh);
    __half* pMsg2 = (__half*)symaddr(g_msg2);

    cudaFuncSetAttribute(gemm4, cudaFuncAttributeMaxDynamicSharedMemorySize, GEMM_SMEM);

    static cudaStream_t s2 = nullptr, s3 = nullptr;
    static cudaEvent_t eFork = nullptr, ePd = nullptr, eD2 = nullptr,
                       eCvt0 = nullptr, eCvt1 = nullptr, eW1 = nullptr,
                       eH1 = nullptr, eM2 = nullptr;
    if (s2 == nullptr) {
        cudaStreamCreateWithFlags(&s2, cudaStreamNonBlocking);
        cudaStreamCreateWithFlags(&s3, cudaStreamNonBlocking);
        cudaEventCreateWithFlags(&eFork, cudaEventDisableTiming);
        cudaEventCreateWithFlags(&ePd, cudaEventDisableTiming);
        cudaEventCreateWithFlags(&eD2, cudaEventDisableTiming);
        cudaEventCreateWithFlags(&eCvt0, cudaEventDisableTiming);
        cudaEventCreateWithFlags(&eCvt1, cudaEventDisableTiming);
        cudaEventCreateWithFlags(&eW1, cudaEventDisableTiming);
        cudaEventCreateWithFlags(&eH1, cudaEventDisableTiming);
        cudaEventCreateWithFlags(&eM2, cudaEventDisableTiming);
    }

    cudaStream_t st = 0;

    // ---- head ----
    zero_deg<<<(N_SENT + 255) / 256, 256, 0, st>>>();
    cudaEventRecord(eFork, st);

    // s3: x_sent convert, row-chunked so the big GEMM starts at half-convert
    cudaStreamWaitEvent(s3, eFork, 0);
    {
        long long npadc = (long long)HALF_S * D_IN;
        cvt_f16<<<(unsigned)((npadc / 8 + 255) / 256), 256, 0, s3>>>(x_sent, pXsh, npadc, npadc);
        cudaEventRecord(eCvt0, s3);
        long long npadc2 = (long long)(SENT_PAD - HALF_S) * D_IN;
        long long nrealc2 = (long long)(N_SENT - HALF_S) * D_IN;
        cvt_f16<<<(unsigned)((npadc2 / 8 + 255) / 256), 256, 0, s3>>>(
            x_sent + (size_t)HALF_S * D_IN, pXsh + (size_t)HALF_S * D_IN, nrealc2, npadc2);
        cudaEventRecord(eCvt1, s3);
    }

    // main: B1s weights, then layer-1 sent GEMM (cols 256:768 ONLY — sd strip eliminated)
    build_w3t<<<(768 * 768 + 255) / 256, 256, 0, st>>>(coeff1, basis1, loop_w1, pB1sh, D_IN, D_H, 768, 0, 2);
    cudaEventRecord(eW1, st);
    cudaStreamWaitEvent(st, eCvt0, 0);
    {
        dim3 g(512 / 128, HALF_S / 128);
        gemm4<<<g, 256, GEMM_SMEM, st>>>(pXsh, pB1sh + (size_t)256 * D_IN, pPs + 256,
                                         N_SENT, 3 * D_H, D_IN);
    }
    cudaStreamWaitEvent(st, eCvt1, 0);
    {
        dim3 g(512 / 128, (SENT_PAD - HALF_S) / 128);
        gemm4<<<g, 256, GEMM_SMEM, st>>>(pXsh + (size_t)HALF_S * D_IN,
                                         pB1sh + (size_t)256 * D_IN,
                                         pPs + (size_t)HALF_S * 768 + 256,
                                         N_SENT - HALF_S, 3 * D_H, D_IN);
    }

    // ---- s2: CSR + doc prep + doc layer-1 GEMM + doc aggregate-first path ----
    cudaStreamWaitEvent(s2, eFork, 0);
    {
        int Etot = E_SS + E_DS + E_SD;
        count_all<<<(Etot + 255) / 256, 256, 0, s2>>>(dst_ss, dst_ds, dst_sd);
        scan_local_all<<<2 * NB_S + NB_D, 1024, 0, s2>>>();
        scan_block_all<<<3, 128, 0, s2>>>();
        scan_final_all<<<(2 * N_SENT + N_DOC + 255) / 256, 256, 0, s2>>>();
        fill_all<<<(Etot + 255) / 256, 256, 0, s2>>>(src_ss, dst_ss, src_ds, dst_ds, src_sd, dst_sd);
    }
    {
        long long nreal = (long long)N_DOC * D_IN, npad = (long long)DOC_PAD * D_IN;
        cvt_f16<<<(unsigned)((npad / 8 + 255) / 256), 256, 0, s2>>>(x_doc, pXdh, nreal, npad);
    }
    build_w2t<<<(512 * 768 + 255) / 256, 256, 0, s2>>>(coeff1, basis1, loop_w1, pB1dh, D_IN, D_H, 512, 1);
    build_w3t<<<(384 * 256 + 255) / 256, 256, 0, s2>>>(coeff2, basis2, loop_w2, pB2sh, D_H, D_O, 384, 0, 2);
    build_w2t<<<(256 * 256 + 255) / 256, 256, 0, s2>>>(coeff2, basis2, loop_w2, pB2dh, D_H, D_O, 256, 1);
    {
        dim3 g(512 / 128, DOC_PAD / 128);
        gemm4<<<g, 256, GEMM_SMEM, s2>>>(pXdh, pB1dh, pPd, N_DOC, 2 * D_H, D_IN);
    }
    cudaEventRecord(ePd, s2);

    // s2: aggregate-first sd path (runs under main's big GEMM)
    cudaStreamWaitEvent(s2, eCvt1, 0);   // full x_sent fp16
    gather_x_sd<<<(DOC_PAD * 32 + 255) / 256, 256, 0, s2>>>(pXsh, pAggx);
    cudaStreamWaitEvent(s2, eW1, 0);     // B1s built (rows 0:256 = W1_0)
    {
        dim3 g(256 / 128, DOC_PAD / 128);
        gemm4<<<g, 256, GEMM_SMEM, s2>>>(pAggx, pB1sh, pMsg1, N_DOC, 256, D_IN);
    }
    combine1_doc<<<(DOC_PAD * 32 + 255) / 256, 256, 0, s2>>>(pMsg1, pPd, bias1, pHdh);
    {
        dim3 g(256 / 128, DOC_PAD / 128);
        gemm4<<<g, 256, GEMM_SMEM, s2>>>(pHdh, pB2dh, pPd2, N_DOC, 2 * D_O, D_H);
    }
    cudaEventRecord(eD2, s2);

    // ---- main: gather1_sent (big GEMM done on this stream; needs Pd + CSR) ----
    cudaStreamWaitEvent(st, ePd, 0);
    gather1_sent<<<(SENT_PAD * 32 + 255) / 256, 256, 0, st>>>(pPs, pPd, bias1, pHsh, 0, SENT_PAD);
    cudaEventRecord(eH1, st);

    // s2: aggregate-first layer-2 sd path, concurrent with main's layer-2 GEMM
    cudaStreamWaitEvent(s2, eH1, 0);
    gather_h_sd<<<(DOC_PAD * 32 + 255) / 256, 256, 0, s2>>>(pHsh, pAggh);
    {
        dim3 g(128 / 128, DOC_PAD / 128);
        gemm4<<<g, 256, GEMM_SMEM, s2>>>(pAggh, pB2sh, pMsg2, N_DOC, 128, D_H);
    }
    cudaEventRecord(eM2, s2);

    // main: layer-2 sent GEMM (Ps2 cols 128:384 only — sd strip eliminated)
    {
        dim3 g(256 / 128, SENT_PAD / 128);
        gemm4<<<g, 256, GEMM_SMEM, st>>>(pHsh, pB2sh + (size_t)128 * D_H, pPs2 + 128,
                                         N_SENT, 3 * D_O, D_H);
    }

    // main: readout
    cudaStreamWaitEvent(st, eD2, 0);     // Pd2 ready
    init_out<<<1, 32, 0, st>>>(out, b_score);
    gather2_sent<<<(N_SENT * 32 + 255) / 256, 256, 0, st>>>(pPs2, pPd2, bias2, w_score, gid_sent, out);
    cudaStreamWaitEvent(st, eM2, 0);     // msg2 ready
    combine2_doc<<<(N_DOC * 32 + 255) / 256, 256, 0, st>>>(pMsg2, pPd2, bias2, w_score, gid_doc, out);
}

// round 17
// speedup vs baseline: 5.1100x; 1.0310x over previous
#include <cuda_runtime.h>
#include <cuda_fp16.h>
#include <cstdint>
#include <cstddef>

#define N_SENT 100000
#define N_DOC  10000
#define SENT_PAD 100096
#define DOC_PAD  10112
#define NGRAPH 32
#define D_IN   768
#define D_H    256
#define D_O    128
#define E_SS   400000
#define E_SD   100000
#define E_DS   100000

// ---------------- scratch (device globals: allocation-free) ----------------
__device__ __align__(16) __half g_B1s_h[768 * 768];
__device__ __align__(16) __half g_B1d_h[512 * 768];
__device__ __align__(16) __half g_B2s_h[384 * 256];
__device__ __align__(16) __half g_B2d_h[256 * 256];

__device__ __align__(16) __half g_xs_h[(size_t)SENT_PAD * D_IN];
__device__ __align__(16) __half g_xd_h[(size_t)DOC_PAD * D_IN];
__device__ __align__(16) __half g_hs_h[(size_t)SENT_PAD * D_H];
__device__ __align__(16) __half g_hd_h[(size_t)DOC_PAD * D_H];

__device__ __align__(16) __half g_Ps [(size_t)SENT_PAD * (3 * D_H)];
__device__ __align__(16) __half g_Pd [(size_t)N_DOC  * (2 * D_H)];
__device__ __align__(16) __half g_Ps2[(size_t)SENT_PAD * (3 * D_O)];
__device__ __align__(16) __half g_Pd2[(size_t)N_DOC  * (2 * D_O)];

// doc-side aggregate-first buffers
__device__ __align__(16) __half g_aggx[(size_t)DOC_PAD * D_IN];
__device__ __align__(16) __half g_msg1[(size_t)DOC_PAD * D_H];
__device__ __align__(16) __half g_aggh[(size_t)DOC_PAD * D_H];
__device__ __align__(16) __half g_msg2[(size_t)DOC_PAD * D_O];

// CSR structures (incoming edges per destination)
__device__ int   g_deg_ss[N_SENT], g_deg_ds[N_SENT], g_deg_sd[N_DOC];
__device__ int   g_ptr_ss[N_SENT], g_ptr_ds[N_SENT], g_ptr_sd[N_DOC];
__device__ int   g_cur_ss[N_SENT], g_cur_ds[N_SENT], g_cur_sd[N_DOC];
__device__ int   g_adj_ss[E_SS], g_adj_ds[E_DS], g_adj_sd[E_SD];
__device__ float g_inv_ss[N_SENT], g_inv_ds[N_SENT], g_inv_sd[N_DOC];
__device__ int   g_bsum_a[128], g_bsum_b[128], g_bsum_c[128];
__device__ int   g_part_ss[N_SENT], g_part_ds[N_SENT], g_part_sd[N_DOC];

// ---------------- PTX helpers ----------------
__device__ __forceinline__ uint32_t smem_u32(const void* p) {
    uint32_t a;
    asm("{ .reg .u64 t; cvta.to.shared.u64 t, %1; cvt.u32.u64 %0, t; }" : "=r"(a) : "l"(p));
    return a;
}

#define CP_ASYNC16(saddr, gaddr) \
    asm volatile("cp.async.cg.shared.global [%0], [%1], 16;" :: "r"(saddr), "l"(gaddr) : "memory")
#define CP_COMMIT() asm volatile("cp.async.commit_group;" ::: "memory")
#define CP_WAIT1()  asm volatile("cp.async.wait_group 1;" ::: "memory")

#define LDMX4(r0, r1, r2, r3, addr) \
    asm volatile("ldmatrix.sync.aligned.m8n8.x4.shared.b16 {%0,%1,%2,%3}, [%4];" \
                 : "=r"(r0), "=r"(r1), "=r"(r2), "=r"(r3) : "r"(addr))

#define MMA16816(d, a, b) \
    asm volatile("mma.sync.aligned.m16n8k16.row.col.f32.f16.f16.f32 " \
                 "{%0,%1,%2,%3}, {%4,%5,%6,%7}, {%8,%9}, {%0,%1,%2,%3};" \
                 : "+f"((d)[0]), "+f"((d)[1]), "+f"((d)[2]), "+f"((d)[3]) \
                 : "r"((a)[0]), "r"((a)[1]), "r"((a)[2]), "r"((a)[3]), "r"((b)[0]), "r"((b)[1]))

__device__ __forceinline__ uint4 pack8h(const float* f) {
    uint32_t hs[8];
    #pragma unroll
    for (int i = 0; i < 8; i++) hs[i] = (uint32_t)__half_as_ushort(__float2half(f[i]));
    return make_uint4(hs[0] | (hs[1] << 16), hs[2] | (hs[3] << 16), hs[4] | (hs[5] << 16), hs[6] | (hs[7] << 16));
}
__device__ __forceinline__ void add8h(float* A, uint4 v) {
    const __half2* h = (const __half2*)&v;
    #pragma unroll
    for (int i = 0; i < 4; i++) {
        float2 f = __half22float2(h[i]);
        A[2 * i] += f.x; A[2 * i + 1] += f.y;
    }
}
__device__ __forceinline__ void unpack8h(float* A, uint4 v) {
    const __half2* h = (const __half2*)&v;
    #pragma unroll
    for (int i = 0; i < 4; i++) {
        float2 f = __half22float2(h[i]);
        A[2 * i] = f.x; A[2 * i + 1] = f.y;
    }
}
__device__ __forceinline__ void add4h(float* A, uint2 v) {
    const __half2* h = (const __half2*)&v;
    #pragma unroll
    for (int i = 0; i < 2; i++) {
        float2 f = __half22float2(h[i]);
        A[2 * i] += f.x; A[2 * i + 1] += f.y;
    }
}
__device__ __forceinline__ void unpack4h(float* A, uint2 v) {
    const __half2* h = (const __half2*)&v;
    #pragma unroll
    for (int i = 0; i < 2; i++) {
        float2 f = __half22float2(h[i]);
        A[2 * i] = f.x; A[2 * i + 1] = f.y;
    }
}

#define ROWB   80

// ================= GEMM: fp16 x fp16 -> fp16, 3-stage single-sync, 128x128 =============
#define ST_SZ  20480
#define OFF_A  0
#define OFF_B  10240
#define NSTAGE 3
#define GEMM_SMEM (NSTAGE * ST_SZ)

__global__ __launch_bounds__(256, 2) void gemm4(
    const __half* __restrict__ A,
    const __half* __restrict__ Bt,
    __half* __restrict__ C, int M, int N, int K)
{
    extern __shared__ char smem[];
    uint32_t sb = smem_u32(smem);
    int tid = threadIdx.x;
    int lane = tid & 31, wid = tid >> 5;
    int warp_m = (wid & 3) * 32;
    int warp_n = (wid >> 2) * 64;
    int mrow0 = blockIdx.y * 128;
    int ncol0 = blockIdx.x * 128;
    int nk = K >> 5;

    int prow = tid >> 1;
    int pch  = (tid & 1) * 16;
    const __half* aP = A + (size_t)(mrow0 + prow) * K + pch;
    const __half* bP = Bt + (size_t)(ncol0 + prow) * K + pch;
    uint32_t sts = (uint32_t)(prow * ROWB + pch * 2);

    int ra = warp_m + (lane & 7) + (lane & 8);
    int ca = ((lane >> 4) << 3);
    uint32_t a_lm = (uint32_t)(ra * ROWB + ca * 2);
    int rb = warp_n + (lane & 7) + ((lane >> 4) << 3);
    int cb = (((lane >> 3) & 1) << 3);
    uint32_t b_lm = (uint32_t)(rb * ROWB + cb * 2);

    float acc[2][8][4];
    #pragma unroll
    for (int mi = 0; mi < 2; mi++)
        #pragma unroll
        for (int ni = 0; ni < 8; ni++)
            #pragma unroll
            for (int q = 0; q < 4; q++) acc[mi][ni][q] = 0.f;

    #pragma unroll
    for (int s = 0; s < 2; s++) {
        if (s < nk) {
            uint32_t base = sb + s * ST_SZ;
            const __half* ap = aP + s * 32;
            const __half* bp = bP + s * 32;
            CP_ASYNC16(base + OFF_A + sts, ap); CP_ASYNC16(base + OFF_A + sts + 16, ap + 8);
            CP_ASYNC16(base + OFF_B + sts, bp); CP_ASYNC16(base + OFF_B + sts + 16, bp + 8);
        }
        CP_COMMIT();
    }

    for (int kt = 0; kt < nk; kt++) {
        CP_WAIT1();
        __syncthreads();

        int pf = kt + 2;
        if (pf < nk) {
            uint32_t base = sb + (pf % NSTAGE) * ST_SZ;
            const __half* ap = aP + pf * 32;
            const __half* bp = bP + pf * 32;
            CP_ASYNC16(base + OFF_A + sts, ap); CP_ASYNC16(base + OFF_A + sts + 16, ap + 8);
            CP_ASYNC16(base + OFF_B + sts, bp); CP_ASYNC16(base + OFF_B + sts + 16, bp + 8);
        }
        CP_COMMIT();

        uint32_t bcur = sb + (kt % NSTAGE) * ST_SZ;
        #pragma unroll
        for (int ks = 0; ks < 2; ks++) {
            uint32_t koff = ks * 32;
            uint32_t af[2][4], bf[8][2];
            #pragma unroll
            for (int mi = 0; mi < 2; mi++)
                LDMX4(af[mi][0], af[mi][1], af[mi][2], af[mi][3],
                      bcur + OFF_A + a_lm + mi * (16 * ROWB) + koff);
            #pragma unroll
            for (int bg = 0; bg < 4; bg++)
                LDMX4(bf[bg * 2][0], bf[bg * 2][1], bf[bg * 2 + 1][0], bf[bg * 2 + 1][1],
                      bcur + OFF_B + b_lm + bg * (16 * ROWB) + koff);
            #pragma unroll
            for (int mi = 0; mi < 2; mi++)
                #pragma unroll
                for (int ni = 0; ni < 8; ni++)
                    MMA16816(acc[mi][ni], af[mi], bf[ni]);
        }
    }

    int g = lane >> 2, t4 = lane & 3;
    #pragma unroll
    for (int mi = 0; mi < 2; mi++) {
        int r0 = mrow0 + warp_m + mi * 16 + g;
        #pragma unroll
        for (int ni = 0; ni < 8; ni++) {
            int col = ncol0 + warp_n + ni * 8 + t4 * 2;
            if (r0 < M)
                *(__half2*)(C + (size_t)r0 * N + col) = __floats2half2_rn(acc[mi][ni][0], acc[mi][ni][1]);
            if (r0 + 8 < M)
                *(__half2*)(C + (size_t)(r0 + 8) * N + col) = __floats2half2_rn(acc[mi][ni][2], acc[mi][ni][3]);
        }
    }
}

// ---------------- fp32 -> fp16 convert (padded, zero-filled) ----------------
__global__ void cvt_f16(const float* __restrict__ x, __half* __restrict__ hi,
                        long long nreal, long long npad) {
    long long base = ((long long)blockIdx.x * blockDim.x + threadIdx.x) * 8;
    if (base >= npad) return;
    float f[8];
    if (base < nreal) {
        float4 v0 = *(const float4*)(x + base);
        float4 v1 = *(const float4*)(x + base + 4);
        f[0] = v0.x; f[1] = v0.y; f[2] = v0.z; f[3] = v0.w;
        f[4] = v1.x; f[5] = v1.y; f[6] = v1.z; f[7] = v1.w;
    } else {
        #pragma unroll
        for (int q = 0; q < 8; q++) f[q] = 0.f;
    }
    *(uint4*)(hi + base) = pack8h(f);
}

// ---------------- CSR construction (fused across the 3 relations) ----------------
__global__ void zero_deg() {
    int i = blockIdx.x * blockDim.x + threadIdx.x;
    if (i < N_SENT) { g_deg_ss[i] = 0; g_deg_ds[i] = 0; }
    if (i < N_DOC)  { g_deg_sd[i] = 0; }
}
__global__ void count_all(const int* __restrict__ dss, const int* __restrict__ dds,
                          const int* __restrict__ dsd) {
    int i = blockIdx.x * blockDim.x + threadIdx.x;
    if (i < E_SS) atomicAdd(&g_deg_ss[dss[i]], 1);
    else if (i < E_SS + E_DS) atomicAdd(&g_deg_ds[dds[i - E_SS]], 1);
    else if (i < E_SS + E_DS + E_SD) atomicAdd(&g_deg_sd[dsd[i - E_SS - E_DS]], 1);
}
#define NB_S 98
#define NB_D 10
__global__ void scan_local_all() {
    __shared__ int sm[1024];
    const int* deg; int* part; int* bsum; int n; int blk;
    if (blockIdx.x < NB_S) { deg = g_deg_ss; part = g_part_ss; bsum = g_bsum_a; n = N_SENT; blk = blockIdx.x; }
    else if (blockIdx.x < 2 * NB_S) { deg = g_deg_ds; part = g_part_ds; bsum = g_bsum_b; n = N_SENT; blk = blockIdx.x - NB_S; }
    else { deg = g_deg_sd; part = g_part_sd; bsum = g_bsum_c; n = N_DOC; blk = blockIdx.x - 2 * NB_S; }
    int i = blk * 1024 + threadIdx.x;
    int v = (i < n) ? deg[i] : 0;
    sm[threadIdx.x] = v;
    __syncthreads();
    #pragma unroll
    for (int off = 1; off < 1024; off <<= 1) {
        int t = (threadIdx.x >= off) ? sm[threadIdx.x - off] : 0;
        __syncthreads();
        sm[threadIdx.x] += t;
        __syncthreads();
    }
    if (i < n) part[i] = sm[threadIdx.x] - v;
    if (threadIdx.x == 1023) bsum[blk] = sm[1023];
}
__global__ void scan_block_all() {
    __shared__ int sm[128];
    int* bsum; int nb;
    if (blockIdx.x == 0) { bsum = g_bsum_a; nb = NB_S; }
    else if (blockIdx.x == 1) { bsum = g_bsum_b; nb = NB_S; }
    else { bsum = g_bsum_c; nb = NB_D; }
    int v = (threadIdx.x < nb) ? bsum[threadIdx.x] : 0;
    sm[threadIdx.x] = v;
    __syncthreads();
    #pragma unroll
    for (int off = 1; off < 128; off <<= 1) {
        int t = (threadIdx.x >= off) ? sm[threadIdx.x - off] : 0;
        __syncthreads();
        sm[threadIdx.x] += t;
        __syncthreads();
    }
    if (threadIdx.x < nb) bsum[threadIdx.x] = sm[threadIdx.x] - v;
}
__global__ void scan_final_all() {
    int i = blockIdx.x * blockDim.x + threadIdx.x;
    if (i < N_SENT) {
        int p = g_part_ss[i] + g_bsum_a[i >> 10];
        g_ptr_ss[i] = p; g_cur_ss[i] = p;
        g_inv_ss[i] = 1.0f / (float)max(g_deg_ss[i], 1);
    } else if (i < 2 * N_SENT) {
        int j = i - N_SENT;
        int p = g_part_ds[j] + g_bsum_b[j >> 10];
        g_ptr_ds[j] = p; g_cur_ds[j] = p;
        g_inv_ds[j] = 1.0f / (float)max(g_deg_ds[j], 1);
    } else if (i < 2 * N_SENT + N_DOC) {
        int j = i - 2 * N_SENT;
        int p = g_part_sd[j] + g_bsum_c[j >> 10];
        g_ptr_sd[j] = p; g_cur_sd[j] = p;
        g_inv_sd[j] = 1.0f / (float)max(g_deg_sd[j], 1);
    }
}
__global__ void fill_all(const int* __restrict__ sss, const int* __restrict__ dss,
                         const int* __restrict__ sds, const int* __restrict__ dds,
                         const int* __restrict__ ssd, const int* __restrict__ dsd) {
    int i = blockIdx.x * blockDim.x + threadIdx.x;
    if (i < E_SS) {
        int p = atomicAdd(&g_cur_ss[dss[i]], 1);
        g_adj_ss[p] = sss[i];
    } else if (i < E_SS + E_DS) {
        int e = i - E_SS;
        int p = atomicAdd(&g_cur_ds[dds[e]], 1);
        g_adj_ds[p] = sds[e];
    } else if (i < E_SS + E_DS + E_SD) {
        int e = i - E_SS - E_DS;
        int p = atomicAdd(&g_cur_sd[dsd[e]], 1);
        g_adj_sd[p] = ssd[e];
    }
}

// ---------------- weight build: transposed fp16 ----------------
__global__ void build_w3t(const float* __restrict__ coeff, const float* __restrict__ basis,
                          const float* __restrict__ loopw,
                          __half* __restrict__ outH,
                          int K, int D, int Npad, int r0, int r1) {
    int idx = blockIdx.x * blockDim.x + threadIdx.x;
    if (idx >= Npad * K) return;
    int o = idx / K;
    int k = idx % K;
    float v = 0.f;
    if (o < 3 * D) {
        int seg = o / D, od = o % D;
        if (seg == 2) v = loopw[k * D + od];
        else {
            int r = (seg == 0) ? r0 : r1;
            v = coeff[r * 2 + 0] * basis[(size_t)k * D + od]
              + coeff[r * 2 + 1] * basis[(size_t)K * D + (size_t)k * D + od];
        }
    }
    outH[idx] = __float2half(v);
}
__global__ void build_w2t(const float* __restrict__ coeff, const float* __restrict__ basis,
                          const float* __restrict__ loopw,
                          __half* __restrict__ outH,
                          int K, int D, int Npad, int r0) {
    int idx = blockIdx.x * blockDim.x + threadIdx.x;
    if (idx >= Npad * K) return;
    int o = idx / K;
    int k = idx % K;
    float v = 0.f;
    if (o < 2 * D) {
        int seg = o / D, od = o % D;
        if (seg == 1) v = loopw[k * D + od];
        else {
            v = coeff[r0 * 2 + 0] * basis[(size_t)k * D + od]
              + coeff[r0 * 2 + 1] * basis[(size_t)K * D + (size_t)k * D + od];
        }
    }
    outH[idx] = __float2half(v);
}

// ---------------- doc-side aggregate-first gathers ----------------
__global__ void gather_x_sd(const __half* __restrict__ xs, __half* __restrict__ aggx) {
    int w = (blockIdx.x * blockDim.x + threadIdx.x) >> 5;
    int lane = threadIdx.x & 31;
    if (w >= DOC_PAD) return;
    __half* orow = aggx + (size_t)w * D_IN;
    if (w >= N_DOC) {
        #pragma unroll
        for (int c = 0; c < 3; c++)
            *(uint4*)(orow + c * 256 + lane * 8) = make_uint4(0u, 0u, 0u, 0u);
        return;
    }
    float A[24];
    #pragma unroll
    for (int i = 0; i < 24; i++) A[i] = 0.f;
    int p = g_ptr_sd[w], d = g_deg_sd[w];
    for (int k = 0; k < d; k++) {
        int s = g_adj_sd[p + k];
        const __half* r = xs + (size_t)s * D_IN;
        add8h(A,      *(const uint4*)(r + lane * 8));
        add8h(A + 8,  *(const uint4*)(r + 256 + lane * 8));
        add8h(A + 16, *(const uint4*)(r + 512 + lane * 8));
    }
    float sc = g_inv_sd[w];
    #pragma unroll
    for (int c = 0; c < 3; c++) {
        float f[8];
        #pragma unroll
        for (int i = 0; i < 8; i++) f[i] = A[c * 8 + i] * sc;
        *(uint4*)(orow + c * 256 + lane * 8) = pack8h(f);
    }
}
__global__ void gather_h_sd(const __half* __restrict__ hs, __half* __restrict__ aggh) {
    int w = (blockIdx.x * blockDim.x + threadIdx.x) >> 5;
    int lane = threadIdx.x & 31;
    if (w >= DOC_PAD) return;
    __half* orow = aggh + (size_t)w * D_H;
    if (w >= N_DOC) {
        *(uint4*)(orow + lane * 8) = make_uint4(0u, 0u, 0u, 0u);
        return;
    }
    float A[8] = {0.f};
    int p = g_ptr_sd[w], d = g_deg_sd[w];
    for (int k = 0; k < d; k++) {
        int s = g_adj_sd[p + k];
        add8h(A, *(const uint4*)(hs + (size_t)s * D_H + lane * 8));
    }
    float sc = g_inv_sd[w];
    float f[8];
    #pragma unroll
    for (int i = 0; i < 8; i++) f[i] = A[i] * sc;
    *(uint4*)(orow + lane * 8) = pack8h(f);
}

// ---------------- doc combines (no edge loops) ----------------
__global__ void combine1_doc(const __half* __restrict__ msg, const __half* __restrict__ Pd,
                             const float* __restrict__ bias, __half* __restrict__ hout) {
    int w = (blockIdx.x * blockDim.x + threadIdx.x) >> 5;
    int lane = threadIdx.x & 31;
    if (w >= DOC_PAD) return;
    __half* orow = hout + (size_t)w * D_H;
    if (w >= N_DOC) {
        *(uint4*)(orow + lane * 8) = make_uint4(0u, 0u, 0u, 0u);
        return;
    }
    float M[8], L[8];
    unpack8h(M, *(const uint4*)(msg + (size_t)w * D_H + lane * 8));
    unpack8h(L, *(const uint4*)(Pd + (size_t)w * 512 + 256 + lane * 8));
    float f[8];
    #pragma unroll
    for (int i = 0; i < 8; i++)
        f[i] = fmaxf(M[i] + L[i] + bias[lane * 8 + i], 0.f);
    *(uint4*)(orow + lane * 8) = pack8h(f);
}
__global__ void combine2_doc(const __half* __restrict__ msg2, const __half* __restrict__ Pd2,
                             const float* __restrict__ bias, const float* __restrict__ wscore,
                             const int* __restrict__ gid, float* __restrict__ out) {
    int w = (blockIdx.x * blockDim.x + threadIdx.x) >> 5;
    int lane = threadIdx.x & 31;
    if (w >= N_DOC) return;
    float M[4], L[4];
    unpack4h(M, *(const uint2*)(msg2 + (size_t)w * D_O + lane * 4));
    unpack4h(L, *(const uint2*)(Pd2 + (size_t)w * 256 + 128 + lane * 4));
    float4 B = ((const float4*)bias)[lane];
    float4 W = ((const float4*)wscore)[lane];
    float bb[4] = {B.x, B.y, B.z, B.w};
    float ww[4] = {W.x, W.y, W.z, W.w};
    float s = 0.f;
    #pragma unroll
    for (int i = 0; i < 4; i++)
        s += fmaxf(M[i] + L[i] + bb[i], 0.f) * ww[i];
    #pragma unroll
    for (int off = 16; off; off >>= 1) s += __shfl_down_sync(0xffffffffu, s, off);
    if (lane == 0) atomicAdd(&out[gid[w]], s);
}

// ---------------- layer-1 sent gather (warp per dst node) + combine + fp16 emit ----------
__global__ void gather1_sent(const __half* __restrict__ Ps, const __half* __restrict__ Pd,
                             const float* __restrict__ bias, __half* __restrict__ hout,
                             int w0, int w1) {
    int w = w0 + ((blockIdx.x * blockDim.x + threadIdx.x) >> 5);
    int lane = threadIdx.x & 31;
    if (w >= w1) return;
    __half* orow = hout + (size_t)w * D_H;
    if (w >= N_SENT) {
        *(uint4*)(orow + lane * 8) = make_uint4(0u, 0u, 0u, 0u);
        return;
    }
    float A[8] = {0.f}, Bv[8] = {0.f};
    int p = g_ptr_ss[w], d = g_deg_ss[w];
    int k = 0;
    for (; k + 1 < d; k += 2) {
        int s0 = g_adj_ss[p + k], s1 = g_adj_ss[p + k + 1];
        uint4 v0 = *(const uint4*)(Ps + (size_t)s0 * 768 + 256 + lane * 8);
        uint4 v1 = *(const uint4*)(Ps + (size_t)s1 * 768 + 256 + lane * 8);
        add8h(A, v0); add8h(A, v1);
    }
    if (k < d) {
        int s0 = g_adj_ss[p + k];
        add8h(A, *(const uint4*)(Ps + (size_t)s0 * 768 + 256 + lane * 8));
    }
    float sc = g_inv_ss[w];
    p = g_ptr_ds[w]; d = g_deg_ds[w];
    k = 0;
    for (; k + 1 < d; k += 2) {
        int s0 = g_adj_ds[p + k], s1 = g_adj_ds[p + k + 1];
        uint4 v0 = *(const uint4*)(Pd + (size_t)s0 * 512 + lane * 8);
        uint4 v1 = *(const uint4*)(Pd + (size_t)s1 * 512 + lane * 8);
        add8h(Bv, v0); add8h(Bv, v1);
    }
    if (k < d) {
        int s0 = g_adj_ds[p + k];
        add8h(Bv, *(const uint4*)(Pd + (size_t)s0 * 512 + lane * 8));
    }
    float sc2 = g_inv_ds[w];
    float L[8];
    unpack8h(L, *(const uint4*)(Ps + (size_t)w * 768 + 512 + lane * 8));
    float f[8];
    #pragma unroll
    for (int i = 0; i < 8; i++)
        f[i] = fmaxf(fmaf(A[i], sc, fmaf(Bv[i], sc2, L[i] + bias[lane * 8 + i])), 0.f);
    *(uint4*)(orow + lane * 8) = pack8h(f);
}

// ---------------- layer-2 sent gather + readout ----------------
__global__ void init_out(float* __restrict__ out, const float* __restrict__ b_score) {
    int g = threadIdx.x;
    if (g < NGRAPH) out[g] = b_score[0];
}
__global__ void gather2_sent(const __half* __restrict__ Ps2, const __half* __restrict__ Pd2,
                             const float* __restrict__ bias, const float* __restrict__ wscore,
                             const int* __restrict__ gid, float* __restrict__ out) {
    int w = (blockIdx.x * blockDim.x + threadIdx.x) >> 5;
    int lane = threadIdx.x & 31;
    if (w >= N_SENT) return;
    float A[4] = {0.f}, Bv[4] = {0.f};
    int p = g_ptr_ss[w], d = g_deg_ss[w];
    int k = 0;
    for (; k + 1 < d; k += 2) {
        int s0 = g_adj_ss[p + k], s1 = g_adj_ss[p + k + 1];
        uint2 v0 = *(const uint2*)(Ps2 + (size_t)s0 * 384 + 128 + lane * 4);
        uint2 v1 = *(const uint2*)(Ps2 + (size_t)s1 * 384 + 128 + lane * 4);
        add4h(A, v0); add4h(A, v1);
    }
    if (k < d) {
        int s0 = g_adj_ss[p + k];
        add4h(A, *(const uint2*)(Ps2 + (size_t)s0 * 384 + 128 + lane * 4));
    }
    float sc = g_inv_ss[w];
    p = g_ptr_ds[w]; d = g_deg_ds[w];
    k = 0;
    for (; k + 1 < d; k += 2) {
        int s0 = g_adj_ds[p + k], s1 = g_adj_ds[p + k + 1];
        uint2 v0 = *(const uint2*)(Pd2 + (size_t)s0 * 256 + lane * 4);
        uint2 v1 = *(const uint2*)(Pd2 + (size_t)s1 * 256 + lane * 4);
        add4h(Bv, v0); add4h(Bv, v1);
    }
    if (k < d) {
        int s0 = g_adj_ds[p + k];
        add4h(Bv, *(const uint2*)(Pd2 + (size_t)s0 * 256 + lane * 4));
    }
    float sc2 = g_inv_ds[w];
    float L[4] = {0.f};
    add4h(L, *(const uint2*)(Ps2 + (size_t)w * 384 + 256 + lane * 4));
    float4 B = ((const float4*)bias)[lane];
    float4 W = ((const float4*)wscore)[lane];
    float bb[4] = {B.x, B.y, B.z, B.w};
    float ww[4] = {W.x, W.y, W.z, W.w};
    float s = 0.f;
    #pragma unroll
    for (int i = 0; i < 4; i++)
        s += fmaxf(fmaf(A[i], sc, fmaf(Bv[i], sc2, L[i] + bb[i])), 0.f) * ww[i];
    #pragma unroll
    for (int off = 16; off; off >>= 1) s += __shfl_down_sync(0xffffffffu, s, off);
    if (lane == 0) atomicAdd(&out[gid[w]], s);
}

// ---------------- host launcher ----------------
static void* symaddr(const void* sym) {
    void* p = nullptr;
    cudaGetSymbolAddress(&p, sym);
    return p;
}

extern "C" void kernel_launch(void* const* d_in, const int* in_sizes, int n_in,
                              void* d_out, int out_size) {
    const float* x_sent  = (const float*)d_in[0];
    const float* x_doc   = (const float*)d_in[1];
    const float* coeff1  = (const float*)d_in[2];
    const float* basis1  = (const float*)d_in[3];
    const float* loop_w1 = (const float*)d_in[4];
    const float* bias1   = (const float*)d_in[5];
    const float* coeff2  = (const float*)d_in[6];
    const float* basis2  = (const float*)d_in[7];
    const float* loop_w2 = (const float*)d_in[8];
    const float* bias2   = (const float*)d_in[9];
    const float* w_score = (const float*)d_in[10];
    const float* b_score = (const float*)d_in[11];
    const int*   src_ss  = (const int*)d_in[12];
    const int*   dst_ss  = (const int*)d_in[13];
    const int*   src_sd  = (const int*)d_in[14];
    const int*   dst_sd  = (const int*)d_in[15];
    const int*   src_ds  = (const int*)d_in[16];
    const int*   dst_ds  = (const int*)d_in[17];
    const int*   gid_sent= (const int*)d_in[18];
    const int*   gid_doc = (const int*)d_in[19];
    float* out = (float*)d_out;

    __half* pB1sh = (__half*)symaddr(g_B1s_h);
    __half* pB1dh = (__half*)symaddr(g_B1d_h);
    __half* pB2sh = (__half*)symaddr(g_B2s_h);
    __half* pB2dh = (__half*)symaddr(g_B2d_h);
    __half* pXsh = (__half*)symaddr(g_xs_h);
    __half* pXdh = (__half*)symaddr(g_xd_h);
    __half* pHsh = (__half*)symaddr(g_hs_h);
    __half* pHdh = (__half*)symaddr(g_hd_h);
    __half* pPs  = (__half*)symaddr(g_Ps);
    __half* pPd  = (__half*)symaddr(g_Pd);
    __half* pPs2 = (__half*)symaddr(g_Ps2);
    __half* pPd2 = (__half*)symaddr(g_Pd2);
    __half* pAggx = (__half*)symaddr(g_aggx);
    __half* pMsg1 = (__half*)symaddr(g_msg1);
    __half* pAggh = (__half*)symaddr(g_aggh);
    __half* pMsg2 = (__half*)symaddr(g_msg2);

    cudaFuncSetAttribute(gemm4, cudaFuncAttributeMaxDynamicSharedMemorySize, GEMM_SMEM);

    static cudaStream_t s2 = nullptr, s3 = nullptr;
    static cudaEvent_t eFork = nullptr, ePd = nullptr, eD2 = nullptr,
                       eW1 = nullptr, eH1 = nullptr, eM2 = nullptr,
                       eCvt[4] = {nullptr, nullptr, nullptr, nullptr};
    if (s2 == nullptr) {
        cudaStreamCreateWithFlags(&s2, cudaStreamNonBlocking);
        cudaStreamCreateWithFlags(&s3, cudaStreamNonBlocking);
        cudaEventCreateWithFlags(&eFork, cudaEventDisableTiming);
        cudaEventCreateWithFlags(&ePd, cudaEventDisableTiming);
        cudaEventCreateWithFlags(&eD2, cudaEventDisableTiming);
        cudaEventCreateWithFlags(&eW1, cudaEventDisableTiming);
        cudaEventCreateWithFlags(&eH1, cudaEventDisableTiming);
        cudaEventCreateWithFlags(&eM2, cudaEventDisableTiming);
        for (int c = 0; c < 4; c++)
            cudaEventCreateWithFlags(&eCvt[c], cudaEventDisableTiming);
    }

    cudaStream_t st = 0;

    // chunk boundaries for x_sent convert + big GEMM (all /128)
    static const int cb[5] = {0, 25088, 50176, 75264, SENT_PAD};

    // ---- head ----
    zero_deg<<<(N_SENT + 255) / 256, 256, 0, st>>>();
    cudaEventRecord(eFork, st);

    // s3: x_sent convert in 4 row-chunks
    cudaStreamWaitEvent(s3, eFork, 0);
    for (int c = 0; c < 4; c++) {
        long long rows = cb[c + 1] - cb[c];
        long long npadc = rows * D_IN;
        long long realRows = (N_SENT > cb[c]) ? ((N_SENT - cb[c] < rows) ? (N_SENT - cb[c]) : rows) : 0;
        long long nrealc = realRows * D_IN;
        cvt_f16<<<(unsigned)((npadc / 8 + 255) / 256), 256, 0, s3>>>(
            x_sent + (size_t)cb[c] * D_IN, pXsh + (size_t)cb[c] * D_IN, nrealc, npadc);
        cudaEventRecord(eCvt[c], s3);
    }

    // main: B1s weights, then layer-1 sent GEMM (cols 256:768) in 4 row-chunks
    build_w3t<<<(768 * 768 + 255) / 256, 256, 0, st>>>(coeff1, basis1, loop_w1, pB1sh, D_IN, D_H, 768, 0, 2);
    cudaEventRecord(eW1, st);
    for (int c = 0; c < 4; c++) {
        cudaStreamWaitEvent(st, eCvt[c], 0);
        int rows = cb[c + 1] - cb[c];
        int mreal = (N_SENT > cb[c]) ? (N_SENT - cb[c]) : 0;
        if (mreal > rows) mreal = rows;
        dim3 g(512 / 128, rows / 128);
        gemm4<<<g, 256, GEMM_SMEM, st>>>(pXsh + (size_t)cb[c] * D_IN,
                                         pB1sh + (size_t)256 * D_IN,
                                         pPs + (size_t)cb[c] * 768 + 256,
                                         mreal, 3 * D_H, D_IN);
    }

    // ---- s2: CSR + doc prep + doc layer-1 GEMM + doc aggregate-first path ----
    cudaStreamWaitEvent(s2, eFork, 0);
    {
        int Etot = E_SS + E_DS + E_SD;
        count_all<<<(Etot + 255) / 256, 256, 0, s2>>>(dst_ss, dst_ds, dst_sd);
        scan_local_all<<<2 * NB_S + NB_D, 1024, 0, s2>>>();
        scan_block_all<<<3, 128, 0, s2>>>();
        scan_final_all<<<(2 * N_SENT + N_DOC + 255) / 256, 256, 0, s2>>>();
        fill_all<<<(Etot + 255) / 256, 256, 0, s2>>>(src_ss, dst_ss, src_ds, dst_ds, src_sd, dst_sd);
    }
    {
        long long nreal = (long long)N_DOC * D_IN, npad = (long long)DOC_PAD * D_IN;
        cvt_f16<<<(unsigned)((npad / 8 + 255) / 256), 256, 0, s2>>>(x_doc, pXdh, nreal, npad);
    }
    build_w2t<<<(512 * 768 + 255) / 256, 256, 0, s2>>>(coeff1, basis1, loop_w1, pB1dh, D_IN, D_H, 512, 1);
    build_w3t<<<(384 * 256 + 255) / 256, 256, 0, s2>>>(coeff2, basis2, loop_w2, pB2sh, D_H, D_O, 384, 0, 2);
    build_w2t<<<(256 * 256 + 255) / 256, 256, 0, s2>>>(coeff2, basis2, loop_w2, pB2dh, D_H, D_O, 256, 1);
    {
        dim3 g(512 / 128, DOC_PAD / 128);
        gemm4<<<g, 256, GEMM_SMEM, s2>>>(pXdh, pB1dh, pPd, N_DOC, 2 * D_H, D_IN);
    }
    cudaEventRecord(ePd, s2);

    // s2: aggregate-first sd path (runs under main's big GEMM)
    cudaStreamWaitEvent(s2, eCvt[3], 0);   // full x_sent fp16
    gather_x_sd<<<(DOC_PAD * 32 + 255) / 256, 256, 0, s2>>>(pXsh, pAggx);
    cudaStreamWaitEvent(s2, eW1, 0);       // B1s built (rows 0:256 = W1_0)
    {
        dim3 g(256 / 128, DOC_PAD / 128);
        gemm4<<<g, 256, GEMM_SMEM, s2>>>(pAggx, pB1sh, pMsg1, N_DOC, 256, D_IN);
    }
    combine1_doc<<<(DOC_PAD * 32 + 255) / 256, 256, 0, s2>>>(pMsg1, pPd, bias1, pHdh);
    {
        dim3 g(256 / 128, DOC_PAD / 128);
        gemm4<<<g, 256, GEMM_SMEM, s2>>>(pHdh, pB2dh, pPd2, N_DOC, 2 * D_O, D_H);
    }
    cudaEventRecord(eD2, s2);

    // ---- main: gather1_sent (big GEMM done on this stream; needs Pd + CSR) ----
    cudaStreamWaitEvent(st, ePd, 0);
    gather1_sent<<<(SENT_PAD * 32 + 255) / 256, 256, 0, st>>>(pPs, pPd, bias1, pHsh, 0, SENT_PAD);
    cudaEventRecord(eH1, st);

    // s2: aggregate-first layer-2 sd path, concurrent with main's layer-2 GEMM
    cudaStreamWaitEvent(s2, eH1, 0);
    gather_h_sd<<<(DOC_PAD * 32 + 255) / 256, 256, 0, s2>>>(pHsh, pAggh);
    {
        dim3 g(128 / 128, DOC_PAD / 128);
        gemm4<<<g, 256, GEMM_SMEM, s2>>>(pAggh, pB2sh, pMsg2, N_DOC, 128, D_H);
    }
    cudaEventRecord(eM2, s2);

    // main: layer-2 sent GEMM (Ps2 cols 128:384 only)
    {
        dim3 g(256 / 128, SENT_PAD / 128);
        gemm4<<<g, 256, GEMM_SMEM, st>>>(pHsh, pB2sh + (size_t)128 * D_H, pPs2 + 128,
                                         N_SENT, 3 * D_O, D_H);
    }

    // main: readout
    cudaStreamWaitEvent(st, eD2, 0);     // Pd2 ready
    init_out<<<1, 32, 0, st>>>(out, b_score);
    gather2_sent<<<(N_SENT * 32 + 255) / 256, 256, 0, st>>>(pPs2, pPd2, bias2, w_score, gid_sent, out);
    cudaStreamWaitEvent(st, eM2, 0);     // msg2 ready
    combine2_doc<<<(N_DOC * 32 + 255) / 256, 256, 0, st>>>(pMsg2, pPd2, bias2, w_score, gid_doc, out);
}